// round 7
// baseline (speedup 1.0000x reference)
#include <cuda_runtime.h>
#include <cuda_fp16.h>
#include <math.h>
#include <stdint.h>

typedef __half hlf;

static constexpr int Dm = 512, Hn = 4, MIDm = 2048, Bm = 4, Sm = 2048;
static constexpr int BSm = Bm * Sm;                      // 8192
static constexpr long long BSD = (long long)BSm * Dm;    // 4194304
static constexpr long long SD  = (long long)Sm * Dm;     // 1048576
static constexpr long long DD  = (long long)Dm * Dm;     // 262144

// FFT-symmetry tile sizes
static constexpr int FR = 1152;   // rows computed (need 0..1024)
static constexpr int FC = 384;    // cols computed (need 0..256)
static constexpr int TN = 768;    // t12 width: 384 cos + 384 sin

// ---------------------------------------------------------------------------
// Static device scratch
// ---------------------------------------------------------------------------
__device__ __align__(256) hlf g_CSh[FR * Sm], g_CSl[FR * Sm];
__device__ __align__(256) hlf g_SSh[FR * Sm], g_SSl[FR * Sm];
__device__ __align__(256) hlf g_BDh[TN * Dm], g_BDl[TN * Dm];
__device__ __align__(256) hlf g_xdh[4194304], g_xdl[4194304];
__device__ __align__(256) hlf g_xeh[4194304], g_xel[4194304];
__device__ __align__(256) float g_t12[BSm * TN];                   // [8192,768]
__device__ __align__(256) hlf g_t12Th[4 * TN * Sm], g_t12Tl[4 * TN * Sm];
__device__ __align__(256) float g_cp[4 * FR * FC], g_sp[4 * FR * FC];
__device__ __align__(256) float g_xf[4194304];
__device__ __align__(256) float g_xd[4194304];
__device__ __align__(256) hlf g_xdsh[4194304], g_xdsl[4194304];
__device__ __align__(256) float g_qs[16777216], g_ks[16777216];    // [h][b,s,d]
__device__ __align__(256) hlf g_qsh[16777216], g_qsl[16777216];
__device__ __align__(256) hlf g_ksTh[16777216], g_ksTl[16777216];  // [z][D,S]
__device__ __align__(256) hlf g_vsTh[16777216], g_vsTl[16777216];  // [z][E,S]
__device__ __align__(256) hlf g_gcTh[4194304], g_gcTl[4194304];    // [z][E,D]
__device__ __align__(256) hlf g_oth[16777216], g_otl[16777216];    // [z][S,E]
__device__ __align__(256) hlf g_WqTh[1048576], g_WqTl[1048576];
__device__ __align__(256) hlf g_WkTh[1048576], g_WkTl[1048576];
__device__ __align__(256) hlf g_WvTh[1048576], g_WvTl[1048576];
__device__ __align__(256) hlf g_WoTh[1048576], g_WoTl[1048576];    // [h][512,512]
__device__ __align__(256) hlf g_W1Th[1048576], g_W1Tl[1048576];    // [2048,512]
__device__ __align__(256) hlf g_W2Th[1048576], g_W2Tl[1048576];    // [512,2048]
__device__ __align__(256) float g_attn[4194304];
__device__ __align__(256) float g_x2[4194304];
__device__ __align__(256) hlf g_x2h[4194304], g_x2l[4194304];
__device__ __align__(256) hlf g_midh[16777216], g_midl[16777216];
__device__ __align__(256) float g_ff[4194304];

// ---------------------------------------------------------------------------
// Helpers
// ---------------------------------------------------------------------------
__device__ __forceinline__ uint32_t smem_u32(const void* p) {
    uint32_t a;
    asm("{ .reg .u64 t; cvta.to.shared.u64 t, %1; cvt.u32.u64 %0, t; }" : "=r"(a) : "l"(p));
    return a;
}
__device__ __forceinline__ float selu_f(float x) {
    const float sc = 1.0507009873554805f, al = 1.6732632423543772f;
    return x > 0.f ? sc * x : sc * al * (expf(x) - 1.f);
}
__device__ __forceinline__ void split2(float x, hlf& h, hlf& l) {
    h = __float2half_rn(x);
    l = __float2half_rn(x - __half2float(h));
}
__device__ __forceinline__ uint32_t packhl(hlf a, hlf b) {
    return ((uint32_t)*(uint16_t*)&b << 16) | (uint32_t)*(uint16_t*)&a;
}

#define LDSM_X4(r0, r1, r2, r3, addr) \
    asm volatile("ldmatrix.sync.aligned.m8n8.x4.shared.b16 {%0,%1,%2,%3}, [%4];" \
        : "=r"(r0), "=r"(r1), "=r"(r2), "=r"(r3) : "r"(addr))

#define MMA_F16(d, a, b0, b1) \
    asm volatile("mma.sync.aligned.m16n8k16.row.col.f32.f16.f16.f32 " \
        "{%0,%1,%2,%3}, {%4,%5,%6,%7}, {%8,%9}, {%0,%1,%2,%3};" \
        : "+f"((d)[0]), "+f"((d)[1]), "+f"((d)[2]), "+f"((d)[3]) \
        : "r"((a)[0]), "r"((a)[1]), "r"((a)[2]), "r"((a)[3]), "r"(b0), "r"(b1))

#define CP_ASYNC16(dst, src) \
    asm volatile("cp.async.cg.shared.global [%0], [%1], 16;" :: "r"(dst), "l"(src))
#define CP_COMMIT() asm volatile("cp.async.commit_group;")
#define CP_WAIT1()  asm volatile("cp.async.wait_group 1;")

// ---------------------------------------------------------------------------
// HMMA GEMM, cp.async 3-stage pipeline, multi-pass accumulation.
// Templated on warp-N (WN=32: block 128x128, 2 CTA/SM; WN=64: block 128x256, 1 CTA/SM).
// C[z] = sum_p A_p[z>>shA] @ B_p[z&mskB]^T (+bias col/row)(+SELU)
// ---------------------------------------------------------------------------
struct TcPasses { const hlf* A[12]; const hlf* B[12]; };

static constexpr int BKg = 64;
static constexpr int LDSg = BKg + 8;
static constexpr int STAGES = 3;
static constexpr int TILE_A_B = 128 * LDSg * 2;          // A tile bytes (M=128 always)

template <int WN> struct GCfg {
    static constexpr int BN = WN * 4;
    static constexpr int TILE_B_B = BN * LDSg * 2;
    static constexpr int SMEM_B_OFF = STAGES * TILE_A_B;
    static constexpr int SMEM_BIAS_OFF = STAGES * (TILE_A_B + TILE_B_B);
    static constexpr int SMEM = SMEM_BIAS_OFF + (BN > 128 ? BN : 128) * 4;
    static constexpr int OCC = (WN == 64) ? 1 : 2;
};

template <int ACT, int SPLIT, int BMODE, int WN>   // BMODE: 0 none, 1 col, 2 row
__global__ __launch_bounds__(256, GCfg<WN>::OCC) void mma_gemm(
    TcPasses P, int npass,
    float* __restrict__ C, hlf* __restrict__ Chi, hlf* __restrict__ Clo,
    int K, int lda, int ldb, int ldc,
    long long sA, long long sB, long long sC,
    const float* __restrict__ bias, long long sBias,
    int shA, int mskB)
{
    constexpr int BN = GCfg<WN>::BN;
    constexpr int NI = WN / 8;       // 8-col mma tiles per warp
    constexpr int NJ = WN / 16;      // ldsm.x4 groups per warp (B side)
    constexpr int BCH = BN / 32;     // B copy iterations

    extern __shared__ char smem[];
    float* bias_s = (float*)(smem + GCfg<WN>::SMEM_BIAS_OFF);
    const uint32_t sA0 = smem_u32(smem);
    const uint32_t sB0 = sA0 + GCfg<WN>::SMEM_B_OFF;

    const int tid = threadIdx.x;
    const int lane = tid & 31;
    const int wid = tid >> 5;
    const int wm = (wid & 1) * 64;
    const int wn = (wid >> 1) * WN;
    const int z = blockIdx.z;
    const int za = z >> shA;
    const int zb = z & mskB;
    const int m0 = blockIdx.y * 128, n0 = blockIdx.x * BN;

    if (BMODE == 1) {
        for (int i = tid; i < BN; i += 256)
            bias_s[i] = bias[(long long)za * sBias + n0 + i];
    } else if (BMODE == 2) {
        if (tid < 128) bias_s[tid] = bias[(long long)za * sBias + m0 + tid];
    }

    float acc[4][NI][4];
#pragma unroll
    for (int i = 0; i < 4; i++)
#pragma unroll
        for (int j = 0; j < NI; j++)
#pragma unroll
            for (int k = 0; k < 4; k++) acc[i][j][k] = 0.f;

    const int cpp = K / BKg;
    const int total = npass * cpp;

    const int crow = tid >> 3;
    const int ccol = (tid & 7) * 8;

    auto loadStage = [&](int c, int stg) {
        int p = c / cpp;
        int k0 = (c - p * cpp) * BKg;
        const hlf* Ab = P.A[p] + (long long)za * sA + k0 + ccol;
        const hlf* Bb = P.B[p] + (long long)zb * sB + k0 + ccol;
        uint32_t da = sA0 + stg * TILE_A_B + (crow * LDSg + ccol) * 2;
        uint32_t db = sB0 + stg * GCfg<WN>::TILE_B_B + (crow * LDSg + ccol) * 2;
#pragma unroll
        for (int i = 0; i < 4; i++) {
            int row = crow + i * 32;
            CP_ASYNC16(da + i * 32 * LDSg * 2, Ab + (long long)(m0 + row) * lda);
        }
#pragma unroll
        for (int i = 0; i < BCH; i++) {
            int row = crow + i * 32;
            CP_ASYNC16(db + i * 32 * LDSg * 2, Bb + (long long)(n0 + row) * ldb);
        }
    };

    loadStage(0, 0); CP_COMMIT();
    loadStage(1, 1); CP_COMMIT();

    const int lrow16 = lane & 15;
    const int lhalf = lane >> 4;

    for (int c = 0; c < total; c++) {
        CP_WAIT1();
        __syncthreads();
        const int stg = c % STAGES;
        const uint32_t aB = sA0 + stg * TILE_A_B;
        const uint32_t bB = sB0 + stg * GCfg<WN>::TILE_B_B;
#pragma unroll
        for (int ks = 0; ks < 4; ks++) {
            uint32_t af[4][4];
#pragma unroll
            for (int mi = 0; mi < 4; mi++) {
                uint32_t addr = aB + (uint32_t)(((wm + mi * 16 + lrow16) * LDSg
                                                + ks * 16 + lhalf * 8) * 2);
                LDSM_X4(af[mi][0], af[mi][1], af[mi][2], af[mi][3], addr);
            }
            uint32_t bfr[NJ][4];
#pragma unroll
            for (int nj = 0; nj < NJ; nj++) {
                uint32_t addr = bB + (uint32_t)(((wn + nj * 16 + lrow16) * LDSg
                                                + ks * 16 + lhalf * 8) * 2);
                LDSM_X4(bfr[nj][0], bfr[nj][1], bfr[nj][2], bfr[nj][3], addr);
            }
#pragma unroll
            for (int mi = 0; mi < 4; mi++)
#pragma unroll
                for (int ni = 0; ni < NI; ni++) {
                    const int nj = ni >> 1, sub = ni & 1;
                    MMA_F16(acc[mi][ni], af[mi], bfr[nj][sub], bfr[nj][sub + 2]);
                }
        }
        if (c + 2 < total) loadStage(c + 2, (c + 2) % STAGES);
        CP_COMMIT();
    }

    const int cr = lane >> 2;
    const int cc = (lane & 3) * 2;
#pragma unroll
    for (int mi = 0; mi < 4; mi++) {
#pragma unroll
        for (int ni = 0; ni < NI; ni++) {
            const int bn = wn + ni * 8 + cc;
            const int gn = n0 + bn;
            const int rm = wm + mi * 16 + cr;
            const long long r0 = m0 + rm;
            const long long r1 = r0 + 8;
            float v0 = acc[mi][ni][0], v1 = acc[mi][ni][1];
            float v2 = acc[mi][ni][2], v3 = acc[mi][ni][3];
            if (BMODE == 1) {
                v0 += bias_s[bn]; v1 += bias_s[bn + 1];
                v2 += bias_s[bn]; v3 += bias_s[bn + 1];
            } else if (BMODE == 2) {
                v0 += bias_s[rm]; v1 += bias_s[rm];
                v2 += bias_s[rm + 8]; v3 += bias_s[rm + 8];
            }
            if (ACT == 1) { v0 = selu_f(v0); v1 = selu_f(v1); v2 = selu_f(v2); v3 = selu_f(v3); }
            if (SPLIT) {
                hlf h0, l0, h1, l1;
                split2(v0, h0, l0); split2(v1, h1, l1);
                *(uint32_t*)(Chi + (long long)z * sC + r0 * ldc + gn) = packhl(h0, h1);
                *(uint32_t*)(Clo + (long long)z * sC + r0 * ldc + gn) = packhl(l0, l1);
                split2(v2, h0, l0); split2(v3, h1, l1);
                *(uint32_t*)(Chi + (long long)z * sC + r1 * ldc + gn) = packhl(h0, h1);
                *(uint32_t*)(Clo + (long long)z * sC + r1 * ldc + gn) = packhl(l0, l1);
            } else {
                *(float2*)(C + (long long)z * sC + r0 * ldc + gn) = make_float2(v0, v1);
                *(float2*)(C + (long long)z * sC + r1 * ldc + gn) = make_float2(v2, v3);
            }
        }
    }
}

// ---------------------------------------------------------------------------
// Elementwise kernels (unchanged from R6)
// ---------------------------------------------------------------------------
__global__ void init_dft_rows(hlf* __restrict__ Ch, hlf* __restrict__ Cl,
                              hlf* __restrict__ Sh, hlf* __restrict__ Sl,
                              int rows, int N)
{
    long long idx = (long long)blockIdx.x * blockDim.x + threadIdx.x;
    if (idx >= (long long)rows * N) return;
    int i = (int)(idx / N), j = (int)(idx % N);
    int p = (int)(((long long)i * j) % N);
    float x = 2.0f * (float)p / (float)N;
    float s, c;
    sincospif(x, &s, &c);
    split2(c, Ch[idx], Cl[idx]);
    split2(s, Sh[idx], Sl[idx]);
}

__global__ void init_bd(hlf* __restrict__ h, hlf* __restrict__ l)
{
    long long idx = (long long)blockIdx.x * blockDim.x + threadIdx.x;
    if (idx >= (long long)TN * Dm) return;
    int n = (int)(idx / Dm), k = (int)(idx % Dm);
    int i = (n < FC) ? n : (n - FC);
    int p = (int)(((long long)i * k) % Dm);
    float x = 2.0f * (float)p / (float)Dm;
    float s, c;
    sincospif(x, &s, &c);
    float v = (n < FC) ? c : s;
    split2(v, h[idx], l[idx]);
}

__global__ void split_k8(const float* __restrict__ in, hlf* __restrict__ h,
                         hlf* __restrict__ l, long long n8)
{
    long long i = (long long)blockIdx.x * blockDim.x + threadIdx.x;
    if (i >= n8) return;
    long long base = i * 8;
    float4 a = *(const float4*)(in + base);
    float4 b = *(const float4*)(in + base + 4);
    hlf hh[8], ll[8];
    split2(a.x, hh[0], ll[0]); split2(a.y, hh[1], ll[1]);
    split2(a.z, hh[2], ll[2]); split2(a.w, hh[3], ll[3]);
    split2(b.x, hh[4], ll[4]); split2(b.y, hh[5], ll[5]);
    split2(b.z, hh[6], ll[6]); split2(b.w, hh[7], ll[7]);
    uint4 ho, lo;
    ho.x = packhl(hh[0], hh[1]); ho.y = packhl(hh[2], hh[3]);
    ho.z = packhl(hh[4], hh[5]); ho.w = packhl(hh[6], hh[7]);
    lo.x = packhl(ll[0], ll[1]); lo.y = packhl(ll[2], ll[3]);
    lo.z = packhl(ll[4], ll[5]); lo.w = packhl(ll[6], ll[7]);
    *(uint4*)(h + base) = ho;
    *(uint4*)(l + base) = lo;
}

__global__ void split_trans(const float* __restrict__ in, hlf* __restrict__ oh,
                            hlf* __restrict__ ol, int R, int C,
                            long long sIn, long long sOut)
{
    __shared__ float t[32][33];
    const int z = blockIdx.z;
    const float* ib = in + (long long)z * sIn;
    const int c0 = blockIdx.x * 32, r0 = blockIdx.y * 32;
    const int tx = threadIdx.x, ty = threadIdx.y;
#pragma unroll
    for (int i = 0; i < 4; i++)
        t[ty + i * 8][tx] = ib[(long long)(r0 + ty + i * 8) * C + c0 + tx];
    __syncthreads();
#pragma unroll
    for (int i = 0; i < 4; i++) {
        float v = t[tx][ty + i * 8];
        long long o = (long long)z * sOut + (long long)(c0 + ty + i * 8) * R + r0 + tx;
        split2(v, oh[o], ol[o]);
    }
}

__global__ void wo_split_trans(const float* __restrict__ Wo, hlf* __restrict__ oh,
                               hlf* __restrict__ ol)
{
    __shared__ float t[32][33];
    const int h = blockIdx.z;
    const int n0 = blockIdx.x * 32, d0 = blockIdx.y * 32;
    const int tx = threadIdx.x, ty = threadIdx.y;
#pragma unroll
    for (int i = 0; i < 4; i++) {
        int d = d0 + ty + i * 8;
        t[ty + i * 8][tx] = Wo[(long long)(d * 4 + h) * Dm + n0 + tx];
    }
    __syncthreads();
#pragma unroll
    for (int i = 0; i < 4; i++) {
        float v = t[tx][ty + i * 8];
        long long o = (long long)h * DD + (long long)(n0 + ty + i * 8) * Dm + d0 + tx;
        split2(v, oh[o], ol[o]);
    }
}

__global__ void fft_merge(const float* __restrict__ cp, const float* __restrict__ sp,
                          float* __restrict__ xf)
{
    const int b = blockIdx.y;
    long long idx = (long long)blockIdx.x * blockDim.x + threadIdx.x;
    const long long TOT = 1025LL * 257LL;
    if (idx >= TOT) return;
    int i = (int)(idx / 257);
    int d = (int)(idx % 257);
    long long src = (long long)b * FR * FC + (long long)i * FC + d;
    float c = cp[src], s = sp[src];
    float a = c - s, bb = c + s;
    int i2 = (Sm - i) & (Sm - 1);
    int d2 = (Dm - d) & (Dm - 1);
    float* x = xf + (long long)b * SD;
    x[(long long)i * Dm + d] = a;
    x[(long long)i2 * Dm + d] = bb;
    x[(long long)i * Dm + d2] = bb;
    x[(long long)i2 * Dm + d2] = a;
}

__global__ void softmax_split4(const float* __restrict__ q, hlf* __restrict__ oh,
                               hlf* __restrict__ ol)
{
    long long i4 = (long long)blockIdx.x * blockDim.x + threadIdx.x;
    if (i4 >= BSD / 4) return;
    long long base = i4 * 4;
    float4 v[4];
#pragma unroll
    for (int h = 0; h < 4; h++) v[h] = *(const float4*)(q + h * BSD + base);
    float r[4][4];
#pragma unroll
    for (int j = 0; j < 4; j++) {
        float a0 = ((const float*)&v[0])[j], a1 = ((const float*)&v[1])[j];
        float a2 = ((const float*)&v[2])[j], a3 = ((const float*)&v[3])[j];
        float m = fmaxf(fmaxf(a0, a1), fmaxf(a2, a3));
        float e0 = expf(a0 - m), e1 = expf(a1 - m), e2 = expf(a2 - m), e3 = expf(a3 - m);
        float inv = 1.f / (e0 + e1 + e2 + e3);
        r[0][j] = e0 * inv; r[1][j] = e1 * inv; r[2][j] = e2 * inv; r[3][j] = e3 * inv;
    }
#pragma unroll
    for (int h = 0; h < 4; h++) {
        hlf hh[4], ll[4];
#pragma unroll
        for (int j = 0; j < 4; j++) split2(r[h][j], hh[j], ll[j]);
        uint2 ho = make_uint2(packhl(hh[0], hh[1]), packhl(hh[2], hh[3]));
        uint2 lo = make_uint2(packhl(ll[0], ll[1]), packhl(ll[2], ll[3]));
        *(uint2*)(oh + h * BSD + base) = ho;
        *(uint2*)(ol + h * BSD + base) = lo;
    }
}

__global__ void softmax_split_trans(const float* __restrict__ ks, hlf* __restrict__ oh,
                                    hlf* __restrict__ ol)
{
    __shared__ float t[4][32][33];
    const int b = blockIdx.z;
    const int s0 = blockIdx.x * 32, d0 = blockIdx.y * 32;
    const int tx = threadIdx.x, ty = threadIdx.y;
#pragma unroll
    for (int h = 0; h < 4; h++)
#pragma unroll
        for (int i = 0; i < 4; i++)
            t[h][ty + i * 8][tx] =
                ks[((long long)(h * Bm + b) * Sm + s0 + ty + i * 8) * Dm + d0 + tx];
    __syncthreads();
#pragma unroll
    for (int i = 0; i < 4; i++) {
        float v0 = t[0][ty + i * 8][tx], v1 = t[1][ty + i * 8][tx];
        float v2 = t[2][ty + i * 8][tx], v3 = t[3][ty + i * 8][tx];
        float m = fmaxf(fmaxf(v0, v1), fmaxf(v2, v3));
        float e0 = expf(v0 - m), e1 = expf(v1 - m), e2 = expf(v2 - m), e3 = expf(v3 - m);
        float r = 1.f / (e0 + e1 + e2 + e3);
        t[0][ty + i * 8][tx] = e0 * r; t[1][ty + i * 8][tx] = e1 * r;
        t[2][ty + i * 8][tx] = e2 * r; t[3][ty + i * 8][tx] = e3 * r;
    }
    __syncthreads();
#pragma unroll
    for (int h = 0; h < 4; h++)
#pragma unroll
        for (int i = 0; i < 4; i++) {
            float v = t[h][tx][ty + i * 8];
            long long o = (long long)(h * Bm + b) * SD + (long long)(d0 + ty + i * 8) * Sm + s0 + tx;
            split2(v, oh[o], ol[o]);
        }
}

__global__ void ln_split(const float* __restrict__ a, const float* __restrict__ bres,
                         const float* __restrict__ g, const float* __restrict__ be,
                         float* __restrict__ out, hlf* __restrict__ oh, hlf* __restrict__ ol)
{
    __shared__ float red[4];
    long long row = blockIdx.x;
    int t = threadIdx.x;  // 128
    float4 va = ((const float4*)(a + row * Dm))[t];
    float4 vb = ((const float4*)(bres + row * Dm))[t];
    float4 v = make_float4(va.x + vb.x, va.y + vb.y, va.z + vb.z, va.w + vb.w);
    float s = v.x + v.y + v.z + v.w;
#pragma unroll
    for (int o = 16; o > 0; o >>= 1) s += __shfl_xor_sync(0xffffffffu, s, o);
    if ((t & 31) == 0) red[t >> 5] = s;
    __syncthreads();
    float mu = (red[0] + red[1] + red[2] + red[3]) * (1.f / (float)Dm);
    __syncthreads();
    float d0 = v.x - mu, d1 = v.y - mu, d2 = v.z - mu, d3 = v.w - mu;
    float q = d0 * d0 + d1 * d1 + d2 * d2 + d3 * d3;
#pragma unroll
    for (int o = 16; o > 0; o >>= 1) q += __shfl_xor_sync(0xffffffffu, q, o);
    if ((t & 31) == 0) red[t >> 5] = q;
    __syncthreads();
    float var = (red[0] + red[1] + red[2] + red[3]) * (1.f / (float)Dm);
    float rstd = rsqrtf(var + 1e-5f);
    float4 vg = ((const float4*)g)[t];
    float4 vbe = ((const float4*)be)[t];
    float4 o4;
    o4.x = fmaf(vg.x, d0 * rstd, vbe.x);
    o4.y = fmaf(vg.y, d1 * rstd, vbe.y);
    o4.z = fmaf(vg.z, d2 * rstd, vbe.z);
    o4.w = fmaf(vg.w, d3 * rstd, vbe.w);
    ((float4*)(out + row * Dm))[t] = o4;
    if (oh) {
        long long o = row * Dm + t * 4;
        hlf hh[4], ll[4];
        split2(o4.x, hh[0], ll[0]); split2(o4.y, hh[1], ll[1]);
        split2(o4.z, hh[2], ll[2]); split2(o4.w, hh[3], ll[3]);
        *(uint2*)(oh + o) = make_uint2(packhl(hh[0], hh[1]), packhl(hh[2], hh[3]));
        *(uint2*)(ol + o) = make_uint2(packhl(ll[0], ll[1]), packhl(ll[2], ll[3]));
    }
}

// ---------------------------------------------------------------------------
// Host
// ---------------------------------------------------------------------------
static TcPasses mk3(const hlf* Ah, const hlf* Al, const hlf* Bh, const hlf* Bl) {
    TcPasses P{};
    P.A[0] = Ah; P.B[0] = Bh;
    P.A[1] = Al; P.B[1] = Bh;
    P.A[2] = Ah; P.B[2] = Bl;
    return P;
}
static TcPasses mk2(const hlf* Ah, const hlf* Al, const hlf* Bh) {
    TcPasses P{};
    P.A[0] = Ah; P.B[0] = Bh;
    P.A[1] = Al; P.B[1] = Bh;
    return P;
}

template <int WN>
static void tcgT(const TcPasses& P, int np, float* C, hlf* Ch, hlf* Cl,
                 int M, int N, int K, int lda, int ldb, int ldc,
                 long long sA, long long sB, long long sC, int batch,
                 const float* bias, long long sBias, int act, int split, int bmode,
                 int shA = 0, int mskB = 0x7FFFFFFF)
{
    constexpr int SM = GCfg<WN>::SMEM;
    dim3 grid(N / GCfg<WN>::BN, M / 128, batch), block(256);
    if (act == 1)
        mma_gemm<1, 1, 1, WN><<<grid, block, SM>>>(P, np, C, Ch, Cl, K, lda, ldb, ldc, sA, sB, sC, bias, sBias, shA, mskB);
    else if (split == 1 && bmode == 2)
        mma_gemm<0, 1, 2, WN><<<grid, block, SM>>>(P, np, C, Ch, Cl, K, lda, ldb, ldc, sA, sB, sC, bias, sBias, shA, mskB);
    else if (split == 1)
        mma_gemm<0, 1, 0, WN><<<grid, block, SM>>>(P, np, C, Ch, Cl, K, lda, ldb, ldc, sA, sB, sC, bias, sBias, shA, mskB);
    else if (bmode == 1)
        mma_gemm<0, 0, 1, WN><<<grid, block, SM>>>(P, np, C, Ch, Cl, K, lda, ldb, ldc, sA, sB, sC, bias, sBias, shA, mskB);
    else
        mma_gemm<0, 0, 0, WN><<<grid, block, SM>>>(P, np, C, Ch, Cl, K, lda, ldb, ldc, sA, sB, sC, bias, sBias, shA, mskB);
}

#define GETSYM(var, sym) do { void* _p; cudaGetSymbolAddress(&_p, sym); var = (decltype(var))_p; } while (0)

extern "C" void kernel_launch(void* const* d_in, const int* in_sizes, int n_in,
                              void* d_out, int out_size)
{
    const float* x_enc = (const float*)d_in[0];
    const float* x_dec = (const float*)d_in[1];
    const float* Wq = (const float*)d_in[2];
    const float* bq = (const float*)d_in[3];
    const float* Wk = (const float*)d_in[4];
    const float* bk = (const float*)d_in[5];
    const float* Wv = (const float*)d_in[6];
    const float* bv = (const float*)d_in[7];
    const float* Wo = (const float*)d_in[8];
    const float* bo = (const float*)d_in[9];
    const float* ln1g = (const float*)d_in[10];
    const float* ln1b = (const float*)d_in[11];
    const float* ln2g = (const float*)d_in[12];
    const float* ln2b = (const float*)d_in[13];
    const float* W1 = (const float*)d_in[14];
    const float* b1 = (const float*)d_in[15];
    const float* W2 = (const float*)d_in[16];
    const float* b2 = (const float*)d_in[17];
    const float* ln3g = (const float*)d_in[18];
    const float* ln3b = (const float*)d_in[19];
    float* outp = (float*)d_out;

    hlf *CSh, *CSl, *SSh, *SSl, *BDh, *BDl;
    hlf *xdh, *xdl, *xeh, *xel, *t12Th, *t12Tl, *xdsh, *xdsl;
    hlf *qsh, *qsl, *ksTh, *ksTl, *vsTh, *vsTl, *gcTh, *gcTl, *oth, *otl;
    hlf *WqTh, *WqTl, *WkTh, *WkTl, *WvTh, *WvTl, *WoTh, *WoTl, *W1Th, *W1Tl, *W2Th, *W2Tl;
    hlf *x2h, *x2l, *midh, *midl;
    float *t12, *cp, *sp, *xf, *xd, *qs, *ks, *attn, *x2, *ff;
    GETSYM(CSh, g_CSh); GETSYM(CSl, g_CSl); GETSYM(SSh, g_SSh); GETSYM(SSl, g_SSl);
    GETSYM(BDh, g_BDh); GETSYM(BDl, g_BDl);
    GETSYM(xdh, g_xdh); GETSYM(xdl, g_xdl); GETSYM(xeh, g_xeh); GETSYM(xel, g_xel);
    GETSYM(t12, g_t12); GETSYM(t12Th, g_t12Th); GETSYM(t12Tl, g_t12Tl);
    GETSYM(cp, g_cp); GETSYM(sp, g_sp);
    GETSYM(xf, g_xf); GETSYM(xd, g_xd); GETSYM(xdsh, g_xdsh); GETSYM(xdsl, g_xdsl);
    GETSYM(qs, g_qs); GETSYM(ks, g_ks);
    GETSYM(qsh, g_qsh); GETSYM(qsl, g_qsl);
    GETSYM(ksTh, g_ksTh); GETSYM(ksTl, g_ksTl); GETSYM(vsTh, g_vsTh); GETSYM(vsTl, g_vsTl);
    GETSYM(gcTh, g_gcTh); GETSYM(gcTl, g_gcTl);
    GETSYM(oth, g_oth); GETSYM(otl, g_otl);
    GETSYM(WqTh, g_WqTh); GETSYM(WqTl, g_WqTl);
    GETSYM(WkTh, g_WkTh); GETSYM(WkTl, g_WkTl);
    GETSYM(WvTh, g_WvTh); GETSYM(WvTl, g_WvTl);
    GETSYM(WoTh, g_WoTh); GETSYM(WoTl, g_WoTl);
    GETSYM(W1Th, g_W1Th); GETSYM(W1Tl, g_W1Tl);
    GETSYM(W2Th, g_W2Th); GETSYM(W2Tl, g_W2Tl);
    GETSYM(attn, g_attn); GETSYM(x2, g_x2); GETSYM(x2h, g_x2h); GETSYM(x2l, g_x2l);
    GETSYM(midh, g_midh); GETSYM(midl, g_midl); GETSYM(ff, g_ff);

#define SETA(k, wn) cudaFuncSetAttribute((k), cudaFuncAttributeMaxDynamicSharedMemorySize, GCfg<wn>::SMEM)
    SETA((mma_gemm<0, 0, 0, 32>), 32);
    SETA((mma_gemm<0, 0, 0, 64>), 64);
    SETA((mma_gemm<0, 0, 1, 64>), 64);
    SETA((mma_gemm<0, 1, 0, 64>), 64);
    SETA((mma_gemm<0, 1, 2, 64>), 64);
    SETA((mma_gemm<1, 1, 1, 64>), 64);
#undef SETA

    dim3 tb(32, 8);

    // 0) DFT matrices
    init_dft_rows<<<(FR * Sm + 255) / 256, 256>>>(CSh, CSl, SSh, SSl, FR, Sm);
    init_bd<<<(TN * Dm + 255) / 256, 256>>>(BDh, BDl);

    // inputs split (vectorized)
    split_k8<<<(int)(BSD / 8 / 256), 256>>>(x_dec, xdh, xdl, BSD / 8);
    split_k8<<<(int)(BSD / 8 / 256), 256>>>(x_enc, xeh, xel, BSD / 8);

    // 1) t12 = x_dec @ BD^T  (M=8192, N=768, K=512) -- 3-pass (FFT chain)
    tcgT<64>(mk3(xdh, xdl, BDh, BDl), 3, t12, nullptr, nullptr,
             BSm, TN, Dm, Dm, Dm, TN, 0, 0, 0, 1, nullptr, 0, 0, 0, 0);
    split_trans<<<dim3(TN / 32, Sm / 32, Bm), tb>>>(t12, t12Th, t12Tl,
        Sm, TN, (long long)Sm * TN, (long long)TN * Sm);

    // 2) symmetric DFT parts: c = CS @ t1, s = SS @ t2 -- 3-pass (N=384 -> 128-tile)
    tcgT<32>(mk3(CSh, CSl, t12Th, t12Tl), 3, cp, nullptr, nullptr,
             FR, FC, Sm, Sm, Sm, FC, 0, (long long)TN * Sm, (long long)FR * FC, Bm,
             nullptr, 0, 0, 0, 0);
    {
        const hlf* t2h = t12Th + (long long)FC * Sm;
        const hlf* t2l = t12Tl + (long long)FC * Sm;
        tcgT<32>(mk3(SSh, SSl, t2h, t2l), 3, sp, nullptr, nullptr,
                 FR, FC, Sm, Sm, Sm, FC, 0, (long long)TN * Sm, (long long)FR * FC, Bm,
                 nullptr, 0, 0, 0, 0);
    }
    fft_merge<<<dim3((1025 * 257 + 255) / 256, Bm), 256>>>(cp, sp, xf);

    // 3) xd = LN1(x_dec + xf), fused split
    ln_split<<<BSm, 128>>>(x_dec, xf, ln1g, ln1b, xd, xdsh, xdsl);

    // 4) weight transposes
    split_trans<<<dim3(16, 16, Hn), tb>>>(Wq, WqTh, WqTl, Dm, Dm, DD, DD);
    split_trans<<<dim3(16, 16, Hn), tb>>>(Wk, WkTh, WkTl, Dm, Dm, DD, DD);
    split_trans<<<dim3(16, 16, Hn), tb>>>(Wv, WvTh, WvTl, Dm, Dm, DD, DD);
    wo_split_trans<<<dim3(16, 16, Hn), tb>>>(Wo, WoTh, WoTl);
    split_trans<<<dim3(MIDm / 32, Dm / 32, 1), tb>>>(W1, W1Th, W1Tl, Dm, MIDm, 0, 0);
    split_trans<<<dim3(Dm / 32, MIDm / 32, 1), tb>>>(W2, W2Th, W2Tl, MIDm, Dm, 0, 0);

    // 5) q/k projections (fp32, col bias), z = head -- 2-pass
    tcgT<64>(mk2(xdsh, xdsl, WqTh), 2, qs, nullptr, nullptr,
             BSm, Dm, Dm, Dm, Dm, Dm, 0, DD, BSD, Hn, bq, Dm, 0, 0, 1);
    tcgT<64>(mk2(xeh, xel, WkTh), 2, ks, nullptr, nullptr,
             BSm, Dm, Dm, Dm, Dm, Dm, 0, DD, BSD, Hn, bk, Dm, 0, 0, 1);

    // 6) vsT[z=h*4+b] = WvT_h @ x_enc[b]^T + bv_h (row bias), split direct; z=16
    tcgT<64>(mk2(WvTh, WvTl, xeh), 2, nullptr, vsTh, vsTl,
             Dm, Sm, Dm, Dm, Dm, Sm, DD, SD, SD, 16, bv, Dm, 0, 1, 2,
             /*shA=*/2, /*mskB=*/3);

    // 7) softmax over heads: q, k (+transpose)
    softmax_split4<<<(int)(BSD / 4 / 256), 256>>>(qs, qsh, qsl);
    softmax_split_trans<<<dim3(Sm / 32, Dm / 32, Bm), tb>>>(ks, ksTh, ksTl);

    // 8) gcT[z] = vsT @ ksT^T  ([e,d]; M=N=512, K=2048, z=16) -- 2-pass
    tcgT<64>(mk2(vsTh, vsTl, ksTh), 2, nullptr, gcTh, gcTl,
             Dm, Dm, Sm, Sm, Sm, Dm, SD, SD, DD, 16, nullptr, 0, 0, 1, 0);

    // 9) out[z] = qs @ gcT^T  ([s,e]; M=2048,N=512,K=512,z=16) -- 2-pass
    tcgT<64>(mk2(qsh, qsl, gcTh), 2, nullptr, oth, otl,
             Sm, Dm, Dm, Dm, Dm, Dm, SD, DD, SD, 16, nullptr, 0, 0, 1, 0);

    // 10) attn[b] = sum_h out_h[b] @ WoT_h^T + bo  (8 passes; M=2048,N=512,K=512,z=4)
    {
        TcPasses P{};
        for (int h = 0; h < Hn; h++) {
            const hlf* Ah = oth + (long long)h * Bm * SD;
            const hlf* Al = otl + (long long)h * Bm * SD;
            const hlf* Bh = WoTh + (long long)h * DD;
            P.A[h * 2 + 0] = Ah; P.B[h * 2 + 0] = Bh;
            P.A[h * 2 + 1] = Al; P.B[h * 2 + 1] = Bh;
        }
        tcgT<64>(P, 8, attn, nullptr, nullptr,
                 Sm, Dm, Dm, Dm, Dm, Dm, SD, 0, SD, Bm, bo, 0, 0, 0, 1);
    }

    // 11) x2 = LN2(xd + attn), fused split
    ln_split<<<BSm, 128>>>(xd, attn, ln2g, ln2b, x2, x2h, x2l);

    // 12) mid = selu(x2 @ W1 + b1), split direct -- 2-pass
    tcgT<64>(mk2(x2h, x2l, W1Th), 2, nullptr, midh, midl,
             BSm, MIDm, Dm, Dm, Dm, MIDm, 0, 0, 0, 1, b1, 0, 1, 1, 1);

    // 13) ff = mid @ W2 + b2 -- 2-pass
    tcgT<64>(mk2(midh, midl, W2Th), 2, ff, nullptr, nullptr,
             BSm, Dm, MIDm, MIDm, MIDm, Dm, 0, 0, 0, 1, b2, 0, 0, 0, 1);

    // 14) out = LN3(x2 + ff)
    ln_split<<<BSm, 128>>>(x2, ff, ln3g, ln3b, outp, nullptr, nullptr);
}

// round 8
// speedup vs baseline: 1.2044x; 1.2044x over previous
#include <cuda_runtime.h>
#include <cuda_fp16.h>
#include <math.h>
#include <stdint.h>

typedef __half hlf;

static constexpr int Dm = 512, Hn = 4, MIDm = 2048, Bm = 4, Sm = 2048;
static constexpr int BSm = Bm * Sm;                      // 8192
static constexpr long long BSD = (long long)BSm * Dm;    // 4194304
static constexpr long long SD  = (long long)Sm * Dm;     // 1048576
static constexpr long long DD  = (long long)Dm * Dm;     // 262144

// FFT-symmetry tile sizes
static constexpr int FR = 1152;   // rows computed (need 0..1024)
static constexpr int FC = 384;    // cols computed (need 0..256)
static constexpr int TN = 768;    // t12 width: 384 cos + 384 sin

// ---------------------------------------------------------------------------
// Static device scratch
// ---------------------------------------------------------------------------
__device__ __align__(256) hlf g_CSh[FR * Sm], g_CSl[FR * Sm];
__device__ __align__(256) hlf g_SSh[FR * Sm], g_SSl[FR * Sm];
__device__ __align__(256) hlf g_BDh[TN * Dm], g_BDl[TN * Dm];
__device__ __align__(256) hlf g_xdh[4194304], g_xdl[4194304];
__device__ __align__(256) float g_t12[BSm * TN];                   // [8192,768]
__device__ __align__(256) hlf g_t12Th[4 * TN * Sm], g_t12Tl[4 * TN * Sm];
__device__ __align__(256) float g_cp[4 * FR * FC], g_sp[4 * FR * FC];
__device__ __align__(256) float g_xf[4194304];
__device__ __align__(256) float g_xd[4194304];
// stacked A for merged q/k proj: [0..BSD)=LN1(xd) split, [BSD..2BSD)=x_enc split
__device__ __align__(256) hlf g_xqkh[8388608], g_xqkl[8388608];
__device__ __align__(256) float g_qk[33554432];                    // [8][b,s,d]
__device__ __align__(256) hlf g_qsh[16777216], g_qsl[16777216];
__device__ __align__(256) hlf g_ksTh[16777216], g_ksTl[16777216];  // [z][D,S]
__device__ __align__(256) hlf g_vsTh[16777216], g_vsTl[16777216];  // [z][E,S]
__device__ __align__(256) hlf g_gcTh[4194304], g_gcTl[4194304];    // [z][E,D]
__device__ __align__(256) hlf g_oth[16777216], g_otl[16777216];    // [z][S,E]
__device__ __align__(256) hlf g_WqkTh[2097152], g_WqkTl[2097152];  // [Wq0..3;Wk0..3]
__device__ __align__(256) float g_bqk[4096];                       // [bq;bk]
__device__ __align__(256) hlf g_WvTh[1048576], g_WvTl[1048576];
__device__ __align__(256) hlf g_WoTh[1048576], g_WoTl[1048576];    // [h][512,512]
__device__ __align__(256) hlf g_W1Th[1048576], g_W1Tl[1048576];    // [2048,512]
__device__ __align__(256) hlf g_W2Th[1048576], g_W2Tl[1048576];    // [512,2048]
__device__ __align__(256) float g_attn[4194304];
__device__ __align__(256) float g_x2[4194304];
__device__ __align__(256) hlf g_x2h[4194304], g_x2l[4194304];
__device__ __align__(256) hlf g_midh[16777216], g_midl[16777216];
__device__ __align__(256) float g_ff[4194304];

// ---------------------------------------------------------------------------
// Helpers
// ---------------------------------------------------------------------------
__device__ __forceinline__ uint32_t smem_u32(const void* p) {
    uint32_t a;
    asm("{ .reg .u64 t; cvta.to.shared.u64 t, %1; cvt.u32.u64 %0, t; }" : "=r"(a) : "l"(p));
    return a;
}
__device__ __forceinline__ float selu_f(float x) {
    const float sc = 1.0507009873554805f, al = 1.6732632423543772f;
    return x > 0.f ? sc * x : sc * al * (expf(x) - 1.f);
}
__device__ __forceinline__ void split2(float x, hlf& h, hlf& l) {
    h = __float2half_rn(x);
    l = __float2half_rn(x - __half2float(h));
}
__device__ __forceinline__ uint32_t packhl(hlf a, hlf b) {
    return ((uint32_t)*(uint16_t*)&b << 16) | (uint32_t)*(uint16_t*)&a;
}

#define LDSM_X4(r0, r1, r2, r3, addr) \
    asm volatile("ldmatrix.sync.aligned.m8n8.x4.shared.b16 {%0,%1,%2,%3}, [%4];" \
        : "=r"(r0), "=r"(r1), "=r"(r2), "=r"(r3) : "r"(addr))

#define MMA_F16(d, a, b0, b1) \
    asm volatile("mma.sync.aligned.m16n8k16.row.col.f32.f16.f16.f32 " \
        "{%0,%1,%2,%3}, {%4,%5,%6,%7}, {%8,%9}, {%0,%1,%2,%3};" \
        : "+f"((d)[0]), "+f"((d)[1]), "+f"((d)[2]), "+f"((d)[3]) \
        : "r"((a)[0]), "r"((a)[1]), "r"((a)[2]), "r"((a)[3]), "r"(b0), "r"(b1))

#define CP_ASYNC16(dst, src) \
    asm volatile("cp.async.cg.shared.global [%0], [%1], 16;" :: "r"(dst), "l"(src))
#define CP_COMMIT() asm volatile("cp.async.commit_group;")
#define CP_WAIT1()  asm volatile("cp.async.wait_group 1;")

// ---------------------------------------------------------------------------
// HMMA GEMM, cp.async 3-stage pipeline, multi-pass accumulation.
// Block 128x128, 8 warps, warp 64x32, BK=64, 2 CTA/SM (R6-proven config).
// C[z] = sum_p A_p[z>>shA] @ B_p[z&mskB]^T (+bias col[zb]/row[za])(+SELU)
// ---------------------------------------------------------------------------
struct TcPasses { const hlf* A[12]; const hlf* B[12]; };

static constexpr int BKg = 64;
static constexpr int LDSg = BKg + 8;
static constexpr int TILE_B = 128 * LDSg * 2;
static constexpr int STAGES = 3;
static constexpr int SMEM_B_OFF = STAGES * TILE_B;
static constexpr int SMEM_BIAS_OFF = 2 * STAGES * TILE_B;
static constexpr int SMEM_G = SMEM_BIAS_OFF + 128 * 4;

template <int ACT, int SPLIT, int BMODE>   // BMODE: 0 none, 1 col (zb), 2 row (za)
__global__ __launch_bounds__(256, 2) void mma_gemm(
    TcPasses P, int npass,
    float* __restrict__ C, hlf* __restrict__ Chi, hlf* __restrict__ Clo,
    int K, int lda, int ldb, int ldc,
    long long sA, long long sB, long long sC,
    const float* __restrict__ bias, long long sBias,
    int shA, int mskB)
{
    extern __shared__ char smem[];
    float* bias_s = (float*)(smem + SMEM_BIAS_OFF);
    const uint32_t sA0 = smem_u32(smem);
    const uint32_t sB0 = sA0 + SMEM_B_OFF;

    const int tid = threadIdx.x;
    const int lane = tid & 31;
    const int wid = tid >> 5;
    const int wm = (wid & 1) * 64;
    const int wn = (wid >> 1) * 32;
    const int z = blockIdx.z;
    const int za = z >> shA;
    const int zb = z & mskB;
    const int m0 = blockIdx.y * 128, n0 = blockIdx.x * 128;

    if (tid < 128) {
        if (BMODE == 0) bias_s[tid] = 0.f;
        else if (BMODE == 1) bias_s[tid] = bias[(long long)zb * sBias + n0 + tid];
        else bias_s[tid] = bias[(long long)za * sBias + m0 + tid];
    }

    float acc[4][4][4];
#pragma unroll
    for (int i = 0; i < 4; i++)
#pragma unroll
        for (int j = 0; j < 4; j++)
#pragma unroll
            for (int k = 0; k < 4; k++) acc[i][j][k] = 0.f;

    const int cpp = K / BKg;
    const int total = npass * cpp;

    const int crow = tid >> 3;
    const int ccol = (tid & 7) * 8;

    auto loadStage = [&](int c, int stg) {
        int p = c / cpp;
        int k0 = (c - p * cpp) * BKg;
        const hlf* Ab = P.A[p] + (long long)za * sA + k0 + ccol;
        const hlf* Bb = P.B[p] + (long long)zb * sB + k0 + ccol;
        uint32_t da = sA0 + stg * TILE_B + (crow * LDSg + ccol) * 2;
        uint32_t db = sB0 + stg * TILE_B + (crow * LDSg + ccol) * 2;
#pragma unroll
        for (int i = 0; i < 4; i++) {
            int row = crow + i * 32;
            CP_ASYNC16(da + i * 32 * LDSg * 2, Ab + (long long)(m0 + row) * lda);
            CP_ASYNC16(db + i * 32 * LDSg * 2, Bb + (long long)(n0 + row) * ldb);
        }
    };

    loadStage(0, 0); CP_COMMIT();
    loadStage(1, 1); CP_COMMIT();

    const int lrow16 = lane & 15;
    const int lhalf = lane >> 4;

    for (int c = 0; c < total; c++) {
        CP_WAIT1();
        __syncthreads();
        const int stg = c % STAGES;
        const uint32_t aB = sA0 + stg * TILE_B;
        const uint32_t bB = sB0 + stg * TILE_B;
#pragma unroll
        for (int ks = 0; ks < 4; ks++) {
            uint32_t af[4][4];
#pragma unroll
            for (int mi = 0; mi < 4; mi++) {
                uint32_t addr = aB + (uint32_t)(((wm + mi * 16 + lrow16) * LDSg
                                                + ks * 16 + lhalf * 8) * 2);
                LDSM_X4(af[mi][0], af[mi][1], af[mi][2], af[mi][3], addr);
            }
            uint32_t bfr[2][4];
#pragma unroll
            for (int nj = 0; nj < 2; nj++) {
                uint32_t addr = bB + (uint32_t)(((wn + nj * 16 + lrow16) * LDSg
                                                + ks * 16 + lhalf * 8) * 2);
                LDSM_X4(bfr[nj][0], bfr[nj][1], bfr[nj][2], bfr[nj][3], addr);
            }
#pragma unroll
            for (int mi = 0; mi < 4; mi++)
#pragma unroll
                for (int ni = 0; ni < 4; ni++) {
                    const int nj = ni >> 1, sub = ni & 1;
                    MMA_F16(acc[mi][ni], af[mi], bfr[nj][sub], bfr[nj][sub + 2]);
                }
        }
        if (c + 2 < total) loadStage(c + 2, (c + 2) % STAGES);
        CP_COMMIT();
    }

    const int cr = lane >> 2;
    const int cc = (lane & 3) * 2;
#pragma unroll
    for (int mi = 0; mi < 4; mi++) {
#pragma unroll
        for (int ni = 0; ni < 4; ni++) {
            const int bn = wn + ni * 8 + cc;
            const int gn = n0 + bn;
            const int rm = wm + mi * 16 + cr;
            const long long r0 = m0 + rm;
            const long long r1 = r0 + 8;
            float v0 = acc[mi][ni][0], v1 = acc[mi][ni][1];
            float v2 = acc[mi][ni][2], v3 = acc[mi][ni][3];
            if (BMODE == 1) {
                v0 += bias_s[bn]; v1 += bias_s[bn + 1];
                v2 += bias_s[bn]; v3 += bias_s[bn + 1];
            } else if (BMODE == 2) {
                v0 += bias_s[rm]; v1 += bias_s[rm];
                v2 += bias_s[rm + 8]; v3 += bias_s[rm + 8];
            }
            if (ACT == 1) { v0 = selu_f(v0); v1 = selu_f(v1); v2 = selu_f(v2); v3 = selu_f(v3); }
            if (SPLIT) {
                hlf h0, l0, h1, l1;
                split2(v0, h0, l0); split2(v1, h1, l1);
                *(uint32_t*)(Chi + (long long)z * sC + r0 * ldc + gn) = packhl(h0, h1);
                *(uint32_t*)(Clo + (long long)z * sC + r0 * ldc + gn) = packhl(l0, l1);
                split2(v2, h0, l0); split2(v3, h1, l1);
                *(uint32_t*)(Chi + (long long)z * sC + r1 * ldc + gn) = packhl(h0, h1);
                *(uint32_t*)(Clo + (long long)z * sC + r1 * ldc + gn) = packhl(l0, l1);
            } else {
                *(float2*)(C + (long long)z * sC + r0 * ldc + gn) = make_float2(v0, v1);
                *(float2*)(C + (long long)z * sC + r1 * ldc + gn) = make_float2(v2, v3);
            }
        }
    }
}

// ---------------------------------------------------------------------------
// Elementwise kernels
// ---------------------------------------------------------------------------
__global__ void init_dft_rows(hlf* __restrict__ Ch, hlf* __restrict__ Cl,
                              hlf* __restrict__ Sh, hlf* __restrict__ Sl,
                              int rows, int N)
{
    long long idx = (long long)blockIdx.x * blockDim.x + threadIdx.x;
    if (idx >= (long long)rows * N) return;
    int i = (int)(idx / N), j = (int)(idx % N);
    int p = (int)(((long long)i * j) % N);
    float x = 2.0f * (float)p / (float)N;
    float s, c;
    sincospif(x, &s, &c);
    split2(c, Ch[idx], Cl[idx]);
    split2(s, Sh[idx], Sl[idx]);
}

__global__ void init_bd(hlf* __restrict__ h, hlf* __restrict__ l)
{
    long long idx = (long long)blockIdx.x * blockDim.x + threadIdx.x;
    if (idx >= (long long)TN * Dm) return;
    int n = (int)(idx / Dm), k = (int)(idx % Dm);
    int i = (n < FC) ? n : (n - FC);
    int p = (int)(((long long)i * k) % Dm);
    float x = 2.0f * (float)p / (float)Dm;
    float s, c;
    sincospif(x, &s, &c);
    float v = (n < FC) ? c : s;
    split2(v, h[idx], l[idx]);
}

__global__ void split_k8(const float* __restrict__ in, hlf* __restrict__ h,
                         hlf* __restrict__ l, long long n8)
{
    long long i = (long long)blockIdx.x * blockDim.x + threadIdx.x;
    if (i >= n8) return;
    long long base = i * 8;
    float4 a = *(const float4*)(in + base);
    float4 b = *(const float4*)(in + base + 4);
    hlf hh[8], ll[8];
    split2(a.x, hh[0], ll[0]); split2(a.y, hh[1], ll[1]);
    split2(a.z, hh[2], ll[2]); split2(a.w, hh[3], ll[3]);
    split2(b.x, hh[4], ll[4]); split2(b.y, hh[5], ll[5]);
    split2(b.z, hh[6], ll[6]); split2(b.w, hh[7], ll[7]);
    uint4 ho, lo;
    ho.x = packhl(hh[0], hh[1]); ho.y = packhl(hh[2], hh[3]);
    ho.z = packhl(hh[4], hh[5]); ho.w = packhl(hh[6], hh[7]);
    lo.x = packhl(ll[0], ll[1]); lo.y = packhl(ll[2], ll[3]);
    lo.z = packhl(ll[4], ll[5]); lo.w = packhl(ll[6], ll[7]);
    *(uint4*)(h + base) = ho;
    *(uint4*)(l + base) = lo;
}

__global__ void split_trans(const float* __restrict__ in, hlf* __restrict__ oh,
                            hlf* __restrict__ ol, int R, int C,
                            long long sIn, long long sOut)
{
    __shared__ float t[32][33];
    const int z = blockIdx.z;
    const float* ib = in + (long long)z * sIn;
    const int c0 = blockIdx.x * 32, r0 = blockIdx.y * 32;
    const int tx = threadIdx.x, ty = threadIdx.y;
#pragma unroll
    for (int i = 0; i < 4; i++)
        t[ty + i * 8][tx] = ib[(long long)(r0 + ty + i * 8) * C + c0 + tx];
    __syncthreads();
#pragma unroll
    for (int i = 0; i < 4; i++) {
        float v = t[tx][ty + i * 8];
        long long o = (long long)z * sOut + (long long)(c0 + ty + i * 8) * R + r0 + tx;
        split2(v, oh[o], ol[o]);
    }
}

__global__ void wo_split_trans(const float* __restrict__ Wo, hlf* __restrict__ oh,
                               hlf* __restrict__ ol)
{
    __shared__ float t[32][33];
    const int h = blockIdx.z;
    const int n0 = blockIdx.x * 32, d0 = blockIdx.y * 32;
    const int tx = threadIdx.x, ty = threadIdx.y;
#pragma unroll
    for (int i = 0; i < 4; i++) {
        int d = d0 + ty + i * 8;
        t[ty + i * 8][tx] = Wo[(long long)(d * 4 + h) * Dm + n0 + tx];
    }
    __syncthreads();
#pragma unroll
    for (int i = 0; i < 4; i++) {
        float v = t[tx][ty + i * 8];
        long long o = (long long)h * DD + (long long)(n0 + ty + i * 8) * Dm + d0 + tx;
        split2(v, oh[o], ol[o]);
    }
}

__global__ void concat_bias(const float* __restrict__ a, const float* __restrict__ b,
                            float* __restrict__ o)
{
    int i = blockIdx.x * blockDim.x + threadIdx.x;
    if (i < 2048) o[i] = a[i];
    else if (i < 4096) o[i] = b[i - 2048];
}

__global__ void fft_merge(const float* __restrict__ cp, const float* __restrict__ sp,
                          float* __restrict__ xf)
{
    const int b = blockIdx.y;
    long long idx = (long long)blockIdx.x * blockDim.x + threadIdx.x;
    const long long TOT = 1025LL * 257LL;
    if (idx >= TOT) return;
    int i = (int)(idx / 257);
    int d = (int)(idx % 257);
    long long src = (long long)b * FR * FC + (long long)i * FC + d;
    float c = cp[src], s = sp[src];
    float a = c - s, bb = c + s;
    int i2 = (Sm - i) & (Sm - 1);
    int d2 = (Dm - d) & (Dm - 1);
    float* x = xf + (long long)b * SD;
    x[(long long)i * Dm + d] = a;
    x[(long long)i2 * Dm + d] = bb;
    x[(long long)i * Dm + d2] = bb;
    x[(long long)i2 * Dm + d2] = a;
}

__global__ void softmax_split4(const float* __restrict__ q, hlf* __restrict__ oh,
                               hlf* __restrict__ ol)
{
    long long i4 = (long long)blockIdx.x * blockDim.x + threadIdx.x;
    if (i4 >= BSD / 4) return;
    long long base = i4 * 4;
    float4 v[4];
#pragma unroll
    for (int h = 0; h < 4; h++) v[h] = *(const float4*)(q + h * BSD + base);
    float r[4][4];
#pragma unroll
    for (int j = 0; j < 4; j++) {
        float a0 = ((const float*)&v[0])[j], a1 = ((const float*)&v[1])[j];
        float a2 = ((const float*)&v[2])[j], a3 = ((const float*)&v[3])[j];
        float m = fmaxf(fmaxf(a0, a1), fmaxf(a2, a3));
        float e0 = expf(a0 - m), e1 = expf(a1 - m), e2 = expf(a2 - m), e3 = expf(a3 - m);
        float inv = 1.f / (e0 + e1 + e2 + e3);
        r[0][j] = e0 * inv; r[1][j] = e1 * inv; r[2][j] = e2 * inv; r[3][j] = e3 * inv;
    }
#pragma unroll
    for (int h = 0; h < 4; h++) {
        hlf hh[4], ll[4];
#pragma unroll
        for (int j = 0; j < 4; j++) split2(r[h][j], hh[j], ll[j]);
        uint2 ho = make_uint2(packhl(hh[0], hh[1]), packhl(hh[2], hh[3]));
        uint2 lo = make_uint2(packhl(ll[0], ll[1]), packhl(ll[2], ll[3]));
        *(uint2*)(oh + h * BSD + base) = ho;
        *(uint2*)(ol + h * BSD + base) = lo;
    }
}

__global__ void softmax_split_trans(const float* __restrict__ ks, hlf* __restrict__ oh,
                                    hlf* __restrict__ ol)
{
    __shared__ float t[4][32][33];
    const int b = blockIdx.z;
    const int s0 = blockIdx.x * 32, d0 = blockIdx.y * 32;
    const int tx = threadIdx.x, ty = threadIdx.y;
#pragma unroll
    for (int h = 0; h < 4; h++)
#pragma unroll
        for (int i = 0; i < 4; i++)
            t[h][ty + i * 8][tx] =
                ks[((long long)(h * Bm + b) * Sm + s0 + ty + i * 8) * Dm + d0 + tx];
    __syncthreads();
#pragma unroll
    for (int i = 0; i < 4; i++) {
        float v0 = t[0][ty + i * 8][tx], v1 = t[1][ty + i * 8][tx];
        float v2 = t[2][ty + i * 8][tx], v3 = t[3][ty + i * 8][tx];
        float m = fmaxf(fmaxf(v0, v1), fmaxf(v2, v3));
        float e0 = expf(v0 - m), e1 = expf(v1 - m), e2 = expf(v2 - m), e3 = expf(v3 - m);
        float r = 1.f / (e0 + e1 + e2 + e3);
        t[0][ty + i * 8][tx] = e0 * r; t[1][ty + i * 8][tx] = e1 * r;
        t[2][ty + i * 8][tx] = e2 * r; t[3][ty + i * 8][tx] = e3 * r;
    }
    __syncthreads();
#pragma unroll
    for (int h = 0; h < 4; h++)
#pragma unroll
        for (int i = 0; i < 4; i++) {
            float v = t[h][tx][ty + i * 8];
            long long o = (long long)(h * Bm + b) * SD + (long long)(d0 + ty + i * 8) * Sm + s0 + tx;
            split2(v, oh[o], ol[o]);
        }
}

__global__ void ln_split(const float* __restrict__ a, const float* __restrict__ bres,
                         const float* __restrict__ g, const float* __restrict__ be,
                         float* __restrict__ out, hlf* __restrict__ oh, hlf* __restrict__ ol)
{
    __shared__ float red[4];
    long long row = blockIdx.x;
    int t = threadIdx.x;  // 128
    float4 va = ((const float4*)(a + row * Dm))[t];
    float4 vb = ((const float4*)(bres + row * Dm))[t];
    float4 v = make_float4(va.x + vb.x, va.y + vb.y, va.z + vb.z, va.w + vb.w);
    float s = v.x + v.y + v.z + v.w;
#pragma unroll
    for (int o = 16; o > 0; o >>= 1) s += __shfl_xor_sync(0xffffffffu, s, o);
    if ((t & 31) == 0) red[t >> 5] = s;
    __syncthreads();
    float mu = (red[0] + red[1] + red[2] + red[3]) * (1.f / (float)Dm);
    __syncthreads();
    float d0 = v.x - mu, d1 = v.y - mu, d2 = v.z - mu, d3 = v.w - mu;
    float q = d0 * d0 + d1 * d1 + d2 * d2 + d3 * d3;
#pragma unroll
    for (int o = 16; o > 0; o >>= 1) q += __shfl_xor_sync(0xffffffffu, q, o);
    if ((t & 31) == 0) red[t >> 5] = q;
    __syncthreads();
    float var = (red[0] + red[1] + red[2] + red[3]) * (1.f / (float)Dm);
    float rstd = rsqrtf(var + 1e-5f);
    float4 vg = ((const float4*)g)[t];
    float4 vbe = ((const float4*)be)[t];
    float4 o4;
    o4.x = fmaf(vg.x, d0 * rstd, vbe.x);
    o4.y = fmaf(vg.y, d1 * rstd, vbe.y);
    o4.z = fmaf(vg.z, d2 * rstd, vbe.z);
    o4.w = fmaf(vg.w, d3 * rstd, vbe.w);
    ((float4*)(out + row * Dm))[t] = o4;
    if (oh) {
        long long o = row * Dm + t * 4;
        hlf hh[4], ll[4];
        split2(o4.x, hh[0], ll[0]); split2(o4.y, hh[1], ll[1]);
        split2(o4.z, hh[2], ll[2]); split2(o4.w, hh[3], ll[3]);
        *(uint2*)(oh + o) = make_uint2(packhl(hh[0], hh[1]), packhl(hh[2], hh[3]));
        *(uint2*)(ol + o) = make_uint2(packhl(ll[0], ll[1]), packhl(ll[2], ll[3]));
    }
}

// ---------------------------------------------------------------------------
// Host
// ---------------------------------------------------------------------------
static TcPasses mk3(const hlf* Ah, const hlf* Al, const hlf* Bh, const hlf* Bl) {
    TcPasses P{};
    P.A[0] = Ah; P.B[0] = Bh;
    P.A[1] = Al; P.B[1] = Bh;
    P.A[2] = Ah; P.B[2] = Bl;
    return P;
}
static TcPasses mk2(const hlf* Ah, const hlf* Al, const hlf* Bh) {
    TcPasses P{};
    P.A[0] = Ah; P.B[0] = Bh;
    P.A[1] = Al; P.B[1] = Bh;
    return P;
}
// keep B's low bits instead of A's (for exactly-known A matrices)
static TcPasses mk2b(const hlf* Ah, const hlf* Bh, const hlf* Bl) {
    TcPasses P{};
    P.A[0] = Ah; P.B[0] = Bh;
    P.A[1] = Ah; P.B[1] = Bl;
    return P;
}

static void tcg(const TcPasses& P, int np, float* C, hlf* Ch, hlf* Cl,
                int M, int N, int K, int lda, int ldb, int ldc,
                long long sA, long long sB, long long sC, int batch,
                const float* bias, long long sBias, int act, int split, int bmode,
                int shA = 0, int mskB = 0x7FFFFFFF)
{
    dim3 grid(N / 128, M / 128, batch), block(256);
    if (act == 1)
        mma_gemm<1, 1, 1><<<grid, block, SMEM_G>>>(P, np, C, Ch, Cl, K, lda, ldb, ldc, sA, sB, sC, bias, sBias, shA, mskB);
    else if (split == 1 && bmode == 2)
        mma_gemm<0, 1, 2><<<grid, block, SMEM_G>>>(P, np, C, Ch, Cl, K, lda, ldb, ldc, sA, sB, sC, bias, sBias, shA, mskB);
    else if (split == 1)
        mma_gemm<0, 1, 0><<<grid, block, SMEM_G>>>(P, np, C, Ch, Cl, K, lda, ldb, ldc, sA, sB, sC, bias, sBias, shA, mskB);
    else if (bmode == 1)
        mma_gemm<0, 0, 1><<<grid, block, SMEM_G>>>(P, np, C, Ch, Cl, K, lda, ldb, ldc, sA, sB, sC, bias, sBias, shA, mskB);
    else
        mma_gemm<0, 0, 0><<<grid, block, SMEM_G>>>(P, np, C, Ch, Cl, K, lda, ldb, ldc, sA, sB, sC, bias, sBias, shA, mskB);
}

#define GETSYM(var, sym) do { void* _p; cudaGetSymbolAddress(&_p, sym); var = (decltype(var))_p; } while (0)

extern "C" void kernel_launch(void* const* d_in, const int* in_sizes, int n_in,
                              void* d_out, int out_size)
{
    const float* x_enc = (const float*)d_in[0];
    const float* x_dec = (const float*)d_in[1];
    const float* Wq = (const float*)d_in[2];
    const float* bq = (const float*)d_in[3];
    const float* Wk = (const float*)d_in[4];
    const float* bk = (const float*)d_in[5];
    const float* Wv = (const float*)d_in[6];
    const float* bv = (const float*)d_in[7];
    const float* Wo = (const float*)d_in[8];
    const float* bo = (const float*)d_in[9];
    const float* ln1g = (const float*)d_in[10];
    const float* ln1b = (const float*)d_in[11];
    const float* ln2g = (const float*)d_in[12];
    const float* ln2b = (const float*)d_in[13];
    const float* W1 = (const float*)d_in[14];
    const float* b1 = (const float*)d_in[15];
    const float* W2 = (const float*)d_in[16];
    const float* b2 = (const float*)d_in[17];
    const float* ln3g = (const float*)d_in[18];
    const float* ln3b = (const float*)d_in[19];
    float* outp = (float*)d_out;

    hlf *CSh, *CSl, *SSh, *SSl, *BDh, *BDl;
    hlf *xdh, *xdl, *t12Th, *t12Tl, *xqkh, *xqkl;
    hlf *qsh, *qsl, *ksTh, *ksTl, *vsTh, *vsTl, *gcTh, *gcTl, *oth, *otl;
    hlf *WqkTh, *WqkTl, *WvTh, *WvTl, *WoTh, *WoTl, *W1Th, *W1Tl, *W2Th, *W2Tl;
    hlf *x2h, *x2l, *midh, *midl;
    float *t12, *cp, *sp, *xf, *xd, *qk, *bqk, *attn, *x2, *ff;
    GETSYM(CSh, g_CSh); GETSYM(CSl, g_CSl); GETSYM(SSh, g_SSh); GETSYM(SSl, g_SSl);
    GETSYM(BDh, g_BDh); GETSYM(BDl, g_BDl);
    GETSYM(xdh, g_xdh); GETSYM(xdl, g_xdl);
    GETSYM(t12, g_t12); GETSYM(t12Th, g_t12Th); GETSYM(t12Tl, g_t12Tl);
    GETSYM(cp, g_cp); GETSYM(sp, g_sp);
    GETSYM(xf, g_xf); GETSYM(xd, g_xd);
    GETSYM(xqkh, g_xqkh); GETSYM(xqkl, g_xqkl);
    GETSYM(qk, g_qk); GETSYM(bqk, g_bqk);
    GETSYM(qsh, g_qsh); GETSYM(qsl, g_qsl);
    GETSYM(ksTh, g_ksTh); GETSYM(ksTl, g_ksTl); GETSYM(vsTh, g_vsTh); GETSYM(vsTl, g_vsTl);
    GETSYM(gcTh, g_gcTh); GETSYM(gcTl, g_gcTl);
    GETSYM(oth, g_oth); GETSYM(otl, g_otl);
    GETSYM(WqkTh, g_WqkTh); GETSYM(WqkTl, g_WqkTl);
    GETSYM(WvTh, g_WvTh); GETSYM(WvTl, g_WvTl);
    GETSYM(WoTh, g_WoTh); GETSYM(WoTl, g_WoTl);
    GETSYM(W1Th, g_W1Th); GETSYM(W1Tl, g_W1Tl);
    GETSYM(W2Th, g_W2Th); GETSYM(W2Tl, g_W2Tl);
    GETSYM(attn, g_attn); GETSYM(x2, g_x2); GETSYM(x2h, g_x2h); GETSYM(x2l, g_x2l);
    GETSYM(midh, g_midh); GETSYM(midl, g_midl); GETSYM(ff, g_ff);

    cudaFuncSetAttribute(mma_gemm<0, 0, 0>, cudaFuncAttributeMaxDynamicSharedMemorySize, SMEM_G);
    cudaFuncSetAttribute(mma_gemm<0, 0, 1>, cudaFuncAttributeMaxDynamicSharedMemorySize, SMEM_G);
    cudaFuncSetAttribute(mma_gemm<0, 1, 0>, cudaFuncAttributeMaxDynamicSharedMemorySize, SMEM_G);
    cudaFuncSetAttribute(mma_gemm<0, 1, 2>, cudaFuncAttributeMaxDynamicSharedMemorySize, SMEM_G);
    cudaFuncSetAttribute(mma_gemm<1, 1, 1>, cudaFuncAttributeMaxDynamicSharedMemorySize, SMEM_G);

    dim3 tb(32, 8);

    // 0) DFT matrices
    init_dft_rows<<<(FR * Sm + 255) / 256, 256>>>(CSh, CSl, SSh, SSl, FR, Sm);
    init_bd<<<(TN * Dm + 255) / 256, 256>>>(BDh, BDl);

    // inputs split: x_dec -> xdh/l; x_enc -> second half of the stacked qk-A buffer
    split_k8<<<(int)(BSD / 8 / 256), 256>>>(x_dec, xdh, xdl, BSD / 8);
    split_k8<<<(int)(BSD / 8 / 256), 256>>>(x_enc, xqkh + BSD, xqkl + BSD, BSD / 8);

    // 1) t12 = x_dec @ BD^T  (M=8192, N=768, K=512) -- 2-pass (drop BD low; BD exact)
    tcg(mk2(xdh, xdl, BDh), 2, t12, nullptr, nullptr,
        BSm, TN, Dm, Dm, Dm, TN, 0, 0, 0, 1, nullptr, 0, 0, 0, 0);
    split_trans<<<dim3(TN / 32, Sm / 32, Bm), tb>>>(t12, t12Th, t12Tl,
        Sm, TN, (long long)Sm * TN, (long long)TN * Sm);

    // 2) c = CS @ t1, s = SS @ t2 -- 2-pass keeping t12's low (drop CS/SS low)
    tcg(mk2b(CSh, t12Th, t12Tl), 2, cp, nullptr, nullptr,
        FR, FC, Sm, Sm, Sm, FC, 0, (long long)TN * Sm, (long long)FR * FC, Bm,
        nullptr, 0, 0, 0, 0);
    {
        const hlf* t2h = t12Th + (long long)FC * Sm;
        const hlf* t2l = t12Tl + (long long)FC * Sm;
        tcg(mk2b(SSh, t2h, t2l), 2, sp, nullptr, nullptr,
            FR, FC, Sm, Sm, Sm, FC, 0, (long long)TN * Sm, (long long)FR * FC, Bm,
            nullptr, 0, 0, 0, 0);
    }
    fft_merge<<<dim3((1025 * 257 + 255) / 256, Bm), 256>>>(cp, sp, xf);

    // 3) xd = LN1(x_dec + xf), split into first half of stacked qk-A buffer
    ln_split<<<BSm, 128>>>(x_dec, xf, ln1g, ln1b, xd, xqkh, xqkl);

    // 4) weight transposes (+ combined q/k weights and biases)
    split_trans<<<dim3(16, 16, Hn), tb>>>(Wq, WqkTh, WqkTl, Dm, Dm, DD, DD);
    split_trans<<<dim3(16, 16, Hn), tb>>>(Wk, WqkTh + 4 * DD, WqkTl + 4 * DD, Dm, Dm, DD, DD);
    concat_bias<<<16, 256>>>(bq, bk, bqk);
    split_trans<<<dim3(16, 16, Hn), tb>>>(Wv, WvTh, WvTl, Dm, Dm, DD, DD);
    wo_split_trans<<<dim3(16, 16, Hn), tb>>>(Wo, WoTh, WoTl);
    split_trans<<<dim3(MIDm / 32, Dm / 32, 1), tb>>>(W1, W1Th, W1Tl, Dm, MIDm, 0, 0);
    split_trans<<<dim3(Dm / 32, MIDm / 32, 1), tb>>>(W2, W2Th, W2Tl, MIDm, Dm, 0, 0);

    // 5) merged q/k projections: z=8 (0-3: q heads from xd; 4-7: k heads from x_enc)
    tcg(mk2(xqkh, xqkl, WqkTh), 2, qk, nullptr, nullptr,
        BSm, Dm, Dm, Dm, Dm, Dm, BSD, DD, BSD, 8, bqk, Dm, 0, 0, 1,
        /*shA=*/2, /*mskB=*/7);

    // 6) vsT[z=h*4+b] = WvT_h @ x_enc[b]^T + bv_h (row bias), split direct; z=16
    tcg(mk2(WvTh, WvTl, xqkh + BSD), 2, nullptr, vsTh, vsTl,
        Dm, Sm, Dm, Dm, Dm, Sm, DD, SD, SD, 16, bv, Dm, 0, 1, 2,
        /*shA=*/2, /*mskB=*/3);

    // 7) softmax over heads: q, k (+transpose)
    softmax_split4<<<(int)(BSD / 4 / 256), 256>>>(qk, qsh, qsl);
    softmax_split_trans<<<dim3(Sm / 32, Dm / 32, Bm), tb>>>(qk + 4 * BSD, ksTh, ksTl);

    // 8) gcT[z] = vsT @ ksT^T  ([e,d]; M=N=512, K=2048, z=16) -- 2-pass
    tcg(mk2(vsTh, vsTl, ksTh), 2, nullptr, gcTh, gcTl,
        Dm, Dm, Sm, Sm, Sm, Dm, SD, SD, DD, 16, nullptr, 0, 0, 1, 0);

    // 9) out[z] = qs @ gcT^T  ([s,e]; M=2048,N=512,K=512,z=16) -- 2-pass
    tcg(mk2(qsh, qsl, gcTh), 2, nullptr, oth, otl,
        Sm, Dm, Dm, Dm, Dm, Dm, SD, DD, SD, 16, nullptr, 0, 0, 1, 0);

    // 10) attn[b] = sum_h out_h[b] @ WoT_h^T + bo  (8 passes; M=2048,N=512,K=512,z=4)
    {
        TcPasses P{};
        for (int h = 0; h < Hn; h++) {
            const hlf* Ah = oth + (long long)h * Bm * SD;
            const hlf* Al = otl + (long long)h * Bm * SD;
            const hlf* Bh = WoTh + (long long)h * DD;
            P.A[h * 2 + 0] = Ah; P.B[h * 2 + 0] = Bh;
            P.A[h * 2 + 1] = Al; P.B[h * 2 + 1] = Bh;
        }
        tcg(P, 8, attn, nullptr, nullptr,
            Sm, Dm, Dm, Dm, Dm, Dm, SD, 0, SD, Bm, bo, 0, 0, 0, 1);
    }

    // 11) x2 = LN2(xd + attn), fused split
    ln_split<<<BSm, 128>>>(xd, attn, ln2g, ln2b, x2, x2h, x2l);

    // 12) mid = selu(x2 @ W1 + b1), split direct -- 2-pass
    tcg(mk2(x2h, x2l, W1Th), 2, nullptr, midh, midl,
        BSm, MIDm, Dm, Dm, Dm, MIDm, 0, 0, 0, 1, b1, 0, 1, 1, 1);

    // 13) ff = mid @ W2 + b2 -- 2-pass
    tcg(mk2(midh, midl, W2Th), 2, ff, nullptr, nullptr,
        BSm, Dm, MIDm, MIDm, MIDm, Dm, 0, 0, 0, 1, b2, 0, 0, 0, 1);

    // 14) out = LN3(x2 + ff)
    ln_split<<<BSm, 128>>>(x2, ff, ln3g, ln3b, outp, nullptr, nullptr);
}

// round 9
// speedup vs baseline: 1.8543x; 1.5396x over previous
#include <cuda_runtime.h>
#include <cuda_fp16.h>
#include <math.h>
#include <stdint.h>

typedef __half hlf;

static constexpr int Dm = 512, Hn = 4, MIDm = 2048, Bm = 4, Sm = 2048;
static constexpr int BSm = Bm * Sm;                      // 8192
static constexpr long long BSD = (long long)BSm * Dm;    // 4194304
static constexpr long long SD  = (long long)Sm * Dm;     // 1048576
static constexpr long long DD  = (long long)Dm * Dm;     // 262144

// FFT-symmetry tile sizes
static constexpr int FR = 1152;   // rows computed (need 0..1024)
static constexpr int FC = 384;    // cols computed (need 0..256)
static constexpr int TN = 768;    // t12 width: 384 cos + 384 sin

// ---------------------------------------------------------------------------
// Static device scratch
// ---------------------------------------------------------------------------
__device__ __align__(256) hlf g_CSh[FR * Sm];
__device__ __align__(256) hlf g_SSh[FR * Sm];
__device__ __align__(256) hlf g_BDh[TN * Dm];
__device__ __align__(256) hlf g_xdh[4194304], g_xdl[4194304];
__device__ __align__(256) float g_t12[BSm * TN];                   // [8192,768]
__device__ __align__(256) hlf g_t12Th[4 * TN * Sm], g_t12Tl[4 * TN * Sm];
__device__ __align__(256) float g_cp[4 * FR * FC], g_sp[4 * FR * FC];
__device__ __align__(256) float g_xf[4194304];
__device__ __align__(256) float g_xd[4194304];
// stacked A for merged q/k proj: [0..BSD)=LN1(xd) fp16, [BSD..2BSD)=x_enc fp16
__device__ __align__(256) hlf g_xqkh[8388608];
__device__ __align__(256) float g_qk[33554432];                    // [8][b,s,d]
__device__ __align__(256) hlf g_qsh[16777216];
__device__ __align__(256) hlf g_ksTh[16777216];                    // [z][D,S]
__device__ __align__(256) hlf g_vsTh[16777216];                    // [z][E,S]
__device__ __align__(256) hlf g_gcTh[4194304];                     // [z][E,D]
__device__ __align__(256) hlf g_oth[16777216];                     // [z][S,E]
__device__ __align__(256) hlf g_WqkTh[2097152];                    // [Wq0..3;Wk0..3]
__device__ __align__(256) float g_bqk[4096];                       // [bq;bk]
__device__ __align__(256) hlf g_WvTh[1048576];
__device__ __align__(256) hlf g_WoTh[1048576];                     // [h][512,512]
__device__ __align__(256) hlf g_W1Th[1048576];                     // [2048,512]
__device__ __align__(256) hlf g_W2Th[1048576];                     // [512,2048]
__device__ __align__(256) float g_attn[4194304];
__device__ __align__(256) float g_x2[4194304];
__device__ __align__(256) hlf g_x2h[4194304];
__device__ __align__(256) hlf g_midh[16777216];
__device__ __align__(256) float g_ff[4194304];

// ---------------------------------------------------------------------------
// Helpers
// ---------------------------------------------------------------------------
__device__ __forceinline__ uint32_t smem_u32(const void* p) {
    uint32_t a;
    asm("{ .reg .u64 t; cvta.to.shared.u64 t, %1; cvt.u32.u64 %0, t; }" : "=r"(a) : "l"(p));
    return a;
}
__device__ __forceinline__ float selu_f(float x) {
    const float sc = 1.0507009873554805f, al = 1.6732632423543772f;
    return x > 0.f ? sc * x : sc * al * (expf(x) - 1.f);
}
__device__ __forceinline__ void split2(float x, hlf& h, hlf& l) {
    h = __float2half_rn(x);
    l = __float2half_rn(x - __half2float(h));
}
__device__ __forceinline__ uint32_t packhl(hlf a, hlf b) {
    return ((uint32_t)*(uint16_t*)&b << 16) | (uint32_t)*(uint16_t*)&a;
}
__device__ __forceinline__ uint32_t packf2(float a, float b) {
    hlf ha = __float2half_rn(a), hb = __float2half_rn(b);
    return packhl(ha, hb);
}

#define LDSM_X4(r0, r1, r2, r3, addr) \
    asm volatile("ldmatrix.sync.aligned.m8n8.x4.shared.b16 {%0,%1,%2,%3}, [%4];" \
        : "=r"(r0), "=r"(r1), "=r"(r2), "=r"(r3) : "r"(addr))

#define MMA_F16(d, a, b0, b1) \
    asm volatile("mma.sync.aligned.m16n8k16.row.col.f32.f16.f16.f32 " \
        "{%0,%1,%2,%3}, {%4,%5,%6,%7}, {%8,%9}, {%0,%1,%2,%3};" \
        : "+f"((d)[0]), "+f"((d)[1]), "+f"((d)[2]), "+f"((d)[3]) \
        : "r"((a)[0]), "r"((a)[1]), "r"((a)[2]), "r"((a)[3]), "r"(b0), "r"(b1))

#define CP_ASYNC16(dst, src) \
    asm volatile("cp.async.cg.shared.global [%0], [%1], 16;" :: "r"(dst), "l"(src))
#define CP_COMMIT() asm volatile("cp.async.commit_group;")
#define CP_WAIT1()  asm volatile("cp.async.wait_group 1;")

// ---------------------------------------------------------------------------
// HMMA GEMM, cp.async 3-stage pipeline, multi-pass accumulation.
// Block 128x128, 8 warps, warp 64x32, BK=64, 2 CTA/SM.
// C[z] = sum_p A_p[z>>shA] @ B_p[z&mskB]^T (+bias col[zb]/row[za])(+SELU)
// SPLIT: 0 = fp32 out, 2 = fp16 out.
// ---------------------------------------------------------------------------
struct TcPasses { const hlf* A[4]; const hlf* B[4]; };

static constexpr int BKg = 64;
static constexpr int LDSg = BKg + 8;
static constexpr int TILE_B = 128 * LDSg * 2;
static constexpr int STAGES = 3;
static constexpr int SMEM_B_OFF = STAGES * TILE_B;
static constexpr int SMEM_BIAS_OFF = 2 * STAGES * TILE_B;
static constexpr int SMEM_G = SMEM_BIAS_OFF + 128 * 4;

template <int ACT, int SPLIT, int BMODE>   // BMODE: 0 none, 1 col (zb), 2 row (za)
__global__ __launch_bounds__(256, 2) void mma_gemm(
    TcPasses P, int npass,
    float* __restrict__ C, hlf* __restrict__ Chi,
    int K, int lda, int ldb, int ldc,
    long long sA, long long sB, long long sC,
    const float* __restrict__ bias, long long sBias,
    int shA, int mskB)
{
    extern __shared__ char smem[];
    float* bias_s = (float*)(smem + SMEM_BIAS_OFF);
    const uint32_t sA0 = smem_u32(smem);
    const uint32_t sB0 = sA0 + SMEM_B_OFF;

    const int tid = threadIdx.x;
    const int lane = tid & 31;
    const int wid = tid >> 5;
    const int wm = (wid & 1) * 64;
    const int wn = (wid >> 1) * 32;
    const int z = blockIdx.z;
    const int za = z >> shA;
    const int zb = z & mskB;
    const int m0 = blockIdx.y * 128, n0 = blockIdx.x * 128;

    if (tid < 128) {
        if (BMODE == 0) bias_s[tid] = 0.f;
        else if (BMODE == 1) bias_s[tid] = bias[(long long)zb * sBias + n0 + tid];
        else bias_s[tid] = bias[(long long)za * sBias + m0 + tid];
    }

    float acc[4][4][4];
#pragma unroll
    for (int i = 0; i < 4; i++)
#pragma unroll
        for (int j = 0; j < 4; j++)
#pragma unroll
            for (int k = 0; k < 4; k++) acc[i][j][k] = 0.f;

    const int cpp = K / BKg;
    const int total = npass * cpp;

    const int crow = tid >> 3;
    const int ccol = (tid & 7) * 8;

    auto loadStage = [&](int c, int stg) {
        int p = c / cpp;
        int k0 = (c - p * cpp) * BKg;
        const hlf* Ab = P.A[p] + (long long)za * sA + k0 + ccol;
        const hlf* Bb = P.B[p] + (long long)zb * sB + k0 + ccol;
        uint32_t da = sA0 + stg * TILE_B + (crow * LDSg + ccol) * 2;
        uint32_t db = sB0 + stg * TILE_B + (crow * LDSg + ccol) * 2;
#pragma unroll
        for (int i = 0; i < 4; i++) {
            int row = crow + i * 32;
            CP_ASYNC16(da + i * 32 * LDSg * 2, Ab + (long long)(m0 + row) * lda);
            CP_ASYNC16(db + i * 32 * LDSg * 2, Bb + (long long)(n0 + row) * ldb);
        }
    };

    loadStage(0, 0); CP_COMMIT();
    loadStage(1, 1); CP_COMMIT();

    const int lrow16 = lane & 15;
    const int lhalf = lane >> 4;

    for (int c = 0; c < total; c++) {
        CP_WAIT1();
        __syncthreads();
        const int stg = c % STAGES;
        const uint32_t aB = sA0 + stg * TILE_B;
        const uint32_t bB = sB0 + stg * TILE_B;
#pragma unroll
        for (int ks = 0; ks < 4; ks++) {
            uint32_t af[4][4];
#pragma unroll
            for (int mi = 0; mi < 4; mi++) {
                uint32_t addr = aB + (uint32_t)(((wm + mi * 16 + lrow16) * LDSg
                                                + ks * 16 + lhalf * 8) * 2);
                LDSM_X4(af[mi][0], af[mi][1], af[mi][2], af[mi][3], addr);
            }
            uint32_t bfr[2][4];
#pragma unroll
            for (int nj = 0; nj < 2; nj++) {
                uint32_t addr = bB + (uint32_t)(((wn + nj * 16 + lrow16) * LDSg
                                                + ks * 16 + lhalf * 8) * 2);
                LDSM_X4(bfr[nj][0], bfr[nj][1], bfr[nj][2], bfr[nj][3], addr);
            }
#pragma unroll
            for (int mi = 0; mi < 4; mi++)
#pragma unroll
                for (int ni = 0; ni < 4; ni++) {
                    const int nj = ni >> 1, sub = ni & 1;
                    MMA_F16(acc[mi][ni], af[mi], bfr[nj][sub], bfr[nj][sub + 2]);
                }
        }
        if (c + 2 < total) loadStage(c + 2, (c + 2) % STAGES);
        CP_COMMIT();
    }

    const int cr = lane >> 2;
    const int cc = (lane & 3) * 2;
#pragma unroll
    for (int mi = 0; mi < 4; mi++) {
#pragma unroll
        for (int ni = 0; ni < 4; ni++) {
            const int bn = wn + ni * 8 + cc;
            const int gn = n0 + bn;
            const int rm = wm + mi * 16 + cr;
            const long long r0 = m0 + rm;
            const long long r1 = r0 + 8;
            float v0 = acc[mi][ni][0], v1 = acc[mi][ni][1];
            float v2 = acc[mi][ni][2], v3 = acc[mi][ni][3];
            if (BMODE == 1) {
                v0 += bias_s[bn]; v1 += bias_s[bn + 1];
                v2 += bias_s[bn]; v3 += bias_s[bn + 1];
            } else if (BMODE == 2) {
                v0 += bias_s[rm]; v1 += bias_s[rm];
                v2 += bias_s[rm + 8]; v3 += bias_s[rm + 8];
            }
            if (ACT == 1) { v0 = selu_f(v0); v1 = selu_f(v1); v2 = selu_f(v2); v3 = selu_f(v3); }
            if (SPLIT == 2) {
                *(uint32_t*)(Chi + (long long)z * sC + r0 * ldc + gn) = packf2(v0, v1);
                *(uint32_t*)(Chi + (long long)z * sC + r1 * ldc + gn) = packf2(v2, v3);
            } else {
                *(float2*)(C + (long long)z * sC + r0 * ldc + gn) = make_float2(v0, v1);
                *(float2*)(C + (long long)z * sC + r1 * ldc + gn) = make_float2(v2, v3);
            }
        }
    }
}

// ---------------------------------------------------------------------------
// Elementwise kernels
// ---------------------------------------------------------------------------
// DFT rows [0,rows): cos and sin matrices, fp16 hi only.
__global__ void init_dft_rows(hlf* __restrict__ Ch, hlf* __restrict__ Sh,
                              int rows, int N)
{
    long long idx = (long long)blockIdx.x * blockDim.x + threadIdx.x;
    if (idx >= (long long)rows * N) return;
    int i = (int)(idx / N), j = (int)(idx % N);
    int p = (int)(((long long)i * j) % N);
    float x = 2.0f * (float)p / (float)N;
    float s, c;
    sincospif(x, &s, &c);
    Ch[idx] = __float2half_rn(c);
    Sh[idx] = __float2half_rn(s);
}

__global__ void init_bd(hlf* __restrict__ h)
{
    long long idx = (long long)blockIdx.x * blockDim.x + threadIdx.x;
    if (idx >= (long long)TN * Dm) return;
    int n = (int)(idx / Dm), k = (int)(idx % Dm);
    int i = (n < FC) ? n : (n - FC);
    int p = (int)(((long long)i * k) % Dm);
    float x = 2.0f * (float)p / (float)Dm;
    float s, c;
    sincospif(x, &s, &c);
    h[idx] = __float2half_rn((n < FC) ? c : s);
}

// fp32 -> fp16 split (lo optional), 8 elems/thread
__global__ void split_k8(const float* __restrict__ in, hlf* __restrict__ h,
                         hlf* __restrict__ l, long long n8)
{
    long long i = (long long)blockIdx.x * blockDim.x + threadIdx.x;
    if (i >= n8) return;
    long long base = i * 8;
    float4 a = *(const float4*)(in + base);
    float4 b = *(const float4*)(in + base + 4);
    hlf hh[8], ll[8];
    split2(a.x, hh[0], ll[0]); split2(a.y, hh[1], ll[1]);
    split2(a.z, hh[2], ll[2]); split2(a.w, hh[3], ll[3]);
    split2(b.x, hh[4], ll[4]); split2(b.y, hh[5], ll[5]);
    split2(b.z, hh[6], ll[6]); split2(b.w, hh[7], ll[7]);
    uint4 ho;
    ho.x = packhl(hh[0], hh[1]); ho.y = packhl(hh[2], hh[3]);
    ho.z = packhl(hh[4], hh[5]); ho.w = packhl(hh[6], hh[7]);
    *(uint4*)(h + base) = ho;
    if (l) {
        uint4 lo;
        lo.x = packhl(ll[0], ll[1]); lo.y = packhl(ll[2], ll[3]);
        lo.z = packhl(ll[4], ll[5]); lo.w = packhl(ll[6], ll[7]);
        *(uint4*)(l + base) = lo;
    }
}

// [R,C] fp32 -> [C,R] fp16 split (lo optional), batched.
__global__ void split_trans(const float* __restrict__ in, hlf* __restrict__ oh,
                            hlf* __restrict__ ol, int R, int C,
                            long long sIn, long long sOut)
{
    __shared__ float t[32][33];
    const int z = blockIdx.z;
    const float* ib = in + (long long)z * sIn;
    const int c0 = blockIdx.x * 32, r0 = blockIdx.y * 32;
    const int tx = threadIdx.x, ty = threadIdx.y;
#pragma unroll
    for (int i = 0; i < 4; i++)
        t[ty + i * 8][tx] = ib[(long long)(r0 + ty + i * 8) * C + c0 + tx];
    __syncthreads();
#pragma unroll
    for (int i = 0; i < 4; i++) {
        float v = t[tx][ty + i * 8];
        long long o = (long long)z * sOut + (long long)(c0 + ty + i * 8) * R + r0 + tx;
        if (ol) { split2(v, oh[o], ol[o]); }
        else oh[o] = __float2half_rn(v);
    }
}

// Wo [2048,512] -> per-h transposed fp16: out[h][n,d] = Wo[d*4+h, n]
__global__ void wo_split_trans(const float* __restrict__ Wo, hlf* __restrict__ oh)
{
    __shared__ float t[32][33];
    const int h = blockIdx.z;
    const int n0 = blockIdx.x * 32, d0 = blockIdx.y * 32;
    const int tx = threadIdx.x, ty = threadIdx.y;
#pragma unroll
    for (int i = 0; i < 4; i++) {
        int d = d0 + ty + i * 8;
        t[ty + i * 8][tx] = Wo[(long long)(d * 4 + h) * Dm + n0 + tx];
    }
    __syncthreads();
#pragma unroll
    for (int i = 0; i < 4; i++) {
        float v = t[tx][ty + i * 8];
        long long o = (long long)h * DD + (long long)(n0 + ty + i * 8) * Dm + d0 + tx;
        oh[o] = __float2half_rn(v);
    }
}

__global__ void concat_bias(const float* __restrict__ a, const float* __restrict__ b,
                            float* __restrict__ o)
{
    int i = blockIdx.x * blockDim.x + threadIdx.x;
    if (i < 2048) o[i] = a[i];
    else if (i < 4096) o[i] = b[i - 2048];
}

__global__ void fft_merge(const float* __restrict__ cp, const float* __restrict__ sp,
                          float* __restrict__ xf)
{
    const int b = blockIdx.y;
    long long idx = (long long)blockIdx.x * blockDim.x + threadIdx.x;
    const long long TOT = 1025LL * 257LL;
    if (idx >= TOT) return;
    int i = (int)(idx / 257);
    int d = (int)(idx % 257);
    long long src = (long long)b * FR * FC + (long long)i * FC + d;
    float c = cp[src], s = sp[src];
    float a = c - s, bb = c + s;
    int i2 = (Sm - i) & (Sm - 1);
    int d2 = (Dm - d) & (Dm - 1);
    float* x = xf + (long long)b * SD;
    x[(long long)i * Dm + d] = a;
    x[(long long)i2 * Dm + d] = bb;
    x[(long long)i * Dm + d2] = bb;
    x[(long long)i2 * Dm + d2] = a;
}

// softmax over H=4 heads (stride BSD), fp16 out; 4 elems/thread
__global__ void softmax_h4(const float* __restrict__ q, hlf* __restrict__ oh)
{
    long long i4 = (long long)blockIdx.x * blockDim.x + threadIdx.x;
    if (i4 >= BSD / 4) return;
    long long base = i4 * 4;
    float4 v[4];
#pragma unroll
    for (int h = 0; h < 4; h++) v[h] = *(const float4*)(q + h * BSD + base);
    float r[4][4];
#pragma unroll
    for (int j = 0; j < 4; j++) {
        float a0 = ((const float*)&v[0])[j], a1 = ((const float*)&v[1])[j];
        float a2 = ((const float*)&v[2])[j], a3 = ((const float*)&v[3])[j];
        float m = fmaxf(fmaxf(a0, a1), fmaxf(a2, a3));
        float e0 = expf(a0 - m), e1 = expf(a1 - m), e2 = expf(a2 - m), e3 = expf(a3 - m);
        float inv = 1.f / (e0 + e1 + e2 + e3);
        r[0][j] = e0 * inv; r[1][j] = e1 * inv; r[2][j] = e2 * inv; r[3][j] = e3 * inv;
    }
#pragma unroll
    for (int h = 0; h < 4; h++) {
        uint2 ho = make_uint2(packf2(r[h][0], r[h][1]), packf2(r[h][2], r[h][3]));
        *(uint2*)(oh + h * BSD + base) = ho;
    }
}

// softmax over heads + transpose: ks[h][b][s,d] -> ksT[z=h*B+b][d,s] fp16.
__global__ void softmax_trans(const float* __restrict__ ks, hlf* __restrict__ oh)
{
    __shared__ float t[4][32][33];
    const int b = blockIdx.z;
    const int s0 = blockIdx.x * 32, d0 = blockIdx.y * 32;
    const int tx = threadIdx.x, ty = threadIdx.y;
#pragma unroll
    for (int h = 0; h < 4; h++)
#pragma unroll
        for (int i = 0; i < 4; i++)
            t[h][ty + i * 8][tx] =
                ks[((long long)(h * Bm + b) * Sm + s0 + ty + i * 8) * Dm + d0 + tx];
    __syncthreads();
#pragma unroll
    for (int i = 0; i < 4; i++) {
        float v0 = t[0][ty + i * 8][tx], v1 = t[1][ty + i * 8][tx];
        float v2 = t[2][ty + i * 8][tx], v3 = t[3][ty + i * 8][tx];
        float m = fmaxf(fmaxf(v0, v1), fmaxf(v2, v3));
        float e0 = expf(v0 - m), e1 = expf(v1 - m), e2 = expf(v2 - m), e3 = expf(v3 - m);
        float r = 1.f / (e0 + e1 + e2 + e3);
        t[0][ty + i * 8][tx] = e0 * r; t[1][ty + i * 8][tx] = e1 * r;
        t[2][ty + i * 8][tx] = e2 * r; t[3][ty + i * 8][tx] = e3 * r;
    }
    __syncthreads();
#pragma unroll
    for (int h = 0; h < 4; h++)
#pragma unroll
        for (int i = 0; i < 4; i++) {
            float v = t[h][tx][ty + i * 8];
            long long o = (long long)(h * Bm + b) * SD + (long long)(d0 + ty + i * 8) * Sm + s0 + tx;
            oh[o] = __float2half_rn(v);
        }
}

// LN over last dim (D=512) of (a+b); optional fp16 out (hi only).
__global__ void ln_split(const float* __restrict__ a, const float* __restrict__ bres,
                         const float* __restrict__ g, const float* __restrict__ be,
                         float* __restrict__ out, hlf* __restrict__ oh)
{
    __shared__ float red[4];
    long long row = blockIdx.x;
    int t = threadIdx.x;  // 128
    float4 va = ((const float4*)(a + row * Dm))[t];
    float4 vb = ((const float4*)(bres + row * Dm))[t];
    float4 v = make_float4(va.x + vb.x, va.y + vb.y, va.z + vb.z, va.w + vb.w);
    float s = v.x + v.y + v.z + v.w;
#pragma unroll
    for (int o = 16; o > 0; o >>= 1) s += __shfl_xor_sync(0xffffffffu, s, o);
    if ((t & 31) == 0) red[t >> 5] = s;
    __syncthreads();
    float mu = (red[0] + red[1] + red[2] + red[3]) * (1.f / (float)Dm);
    __syncthreads();
    float d0 = v.x - mu, d1 = v.y - mu, d2 = v.z - mu, d3 = v.w - mu;
    float q = d0 * d0 + d1 * d1 + d2 * d2 + d3 * d3;
#pragma unroll
    for (int o = 16; o > 0; o >>= 1) q += __shfl_xor_sync(0xffffffffu, q, o);
    if ((t & 31) == 0) red[t >> 5] = q;
    __syncthreads();
    float var = (red[0] + red[1] + red[2] + red[3]) * (1.f / (float)Dm);
    float rstd = rsqrtf(var + 1e-5f);
    float4 vg = ((const float4*)g)[t];
    float4 vbe = ((const float4*)be)[t];
    float4 o4;
    o4.x = fmaf(vg.x, d0 * rstd, vbe.x);
    o4.y = fmaf(vg.y, d1 * rstd, vbe.y);
    o4.z = fmaf(vg.z, d2 * rstd, vbe.z);
    o4.w = fmaf(vg.w, d3 * rstd, vbe.w);
    ((float4*)(out + row * Dm))[t] = o4;
    if (oh) {
        long long o = row * Dm + t * 4;
        *(uint2*)(oh + o) = make_uint2(packf2(o4.x, o4.y), packf2(o4.z, o4.w));
    }
}

// ---------------------------------------------------------------------------
// Host
// ---------------------------------------------------------------------------
static TcPasses mk1(const hlf* Ah, const hlf* Bh) {
    TcPasses P{};
    P.A[0] = Ah; P.B[0] = Bh;
    return P;
}
static TcPasses mk2(const hlf* Ah, const hlf* Al, const hlf* Bh) {
    TcPasses P{};
    P.A[0] = Ah; P.B[0] = Bh;
    P.A[1] = Al; P.B[1] = Bh;
    return P;
}
static TcPasses mk2b(const hlf* Ah, const hlf* Bh, const hlf* Bl) {
    TcPasses P{};
    P.A[0] = Ah; P.B[0] = Bh;
    P.A[1] = Ah; P.B[1] = Bl;
    return P;
}

static void tcg(const TcPasses& P, int np, float* C, hlf* Ch,
                int M, int N, int K, int lda, int ldb, int ldc,
                long long sA, long long sB, long long sC, int batch,
                const float* bias, long long sBias, int act, int split, int bmode,
                int shA = 0, int mskB = 0x7FFFFFFF)
{
    dim3 grid(N / 128, M / 128, batch), block(256);
    if (act == 1)
        mma_gemm<1, 2, 1><<<grid, block, SMEM_G>>>(P, np, C, Ch, K, lda, ldb, ldc, sA, sB, sC, bias, sBias, shA, mskB);
    else if (split == 2 && bmode == 2)
        mma_gemm<0, 2, 2><<<grid, block, SMEM_G>>>(P, np, C, Ch, K, lda, ldb, ldc, sA, sB, sC, bias, sBias, shA, mskB);
    else if (split == 2)
        mma_gemm<0, 2, 0><<<grid, block, SMEM_G>>>(P, np, C, Ch, K, lda, ldb, ldc, sA, sB, sC, bias, sBias, shA, mskB);
    else if (bmode == 1)
        mma_gemm<0, 0, 1><<<grid, block, SMEM_G>>>(P, np, C, Ch, K, lda, ldb, ldc, sA, sB, sC, bias, sBias, shA, mskB);
    else
        mma_gemm<0, 0, 0><<<grid, block, SMEM_G>>>(P, np, C, Ch, K, lda, ldb, ldc, sA, sB, sC, bias, sBias, shA, mskB);
}

#define GETSYM(var, sym) do { void* _p; cudaGetSymbolAddress(&_p, sym); var = (decltype(var))_p; } while (0)

extern "C" void kernel_launch(void* const* d_in, const int* in_sizes, int n_in,
                              void* d_out, int out_size)
{
    const float* x_enc = (const float*)d_in[0];
    const float* x_dec = (const float*)d_in[1];
    const float* Wq = (const float*)d_in[2];
    const float* bq = (const float*)d_in[3];
    const float* Wk = (const float*)d_in[4];
    const float* bk = (const float*)d_in[5];
    const float* Wv = (const float*)d_in[6];
    const float* bv = (const float*)d_in[7];
    const float* Wo = (const float*)d_in[8];
    const float* bo = (const float*)d_in[9];
    const float* ln1g = (const float*)d_in[10];
    const float* ln1b = (const float*)d_in[11];
    const float* ln2g = (const float*)d_in[12];
    const float* ln2b = (const float*)d_in[13];
    const float* W1 = (const float*)d_in[14];
    const float* b1 = (const float*)d_in[15];
    const float* W2 = (const float*)d_in[16];
    const float* b2 = (const float*)d_in[17];
    const float* ln3g = (const float*)d_in[18];
    const float* ln3b = (const float*)d_in[19];
    float* outp = (float*)d_out;

    hlf *CSh, *SSh, *BDh, *xdh, *xdl, *t12Th, *t12Tl, *xqkh;
    hlf *qsh, *ksTh, *vsTh, *gcTh, *oth;
    hlf *WqkTh, *WvTh, *WoTh, *W1Th, *W2Th, *x2h, *midh;
    float *t12, *cp, *sp, *xf, *xd, *qk, *bqk, *attn, *x2, *ff;
    GETSYM(CSh, g_CSh); GETSYM(SSh, g_SSh); GETSYM(BDh, g_BDh);
    GETSYM(xdh, g_xdh); GETSYM(xdl, g_xdl);
    GETSYM(t12, g_t12); GETSYM(t12Th, g_t12Th); GETSYM(t12Tl, g_t12Tl);
    GETSYM(cp, g_cp); GETSYM(sp, g_sp);
    GETSYM(xf, g_xf); GETSYM(xd, g_xd);
    GETSYM(xqkh, g_xqkh);
    GETSYM(qk, g_qk); GETSYM(bqk, g_bqk);
    GETSYM(qsh, g_qsh); GETSYM(ksTh, g_ksTh); GETSYM(vsTh, g_vsTh);
    GETSYM(gcTh, g_gcTh); GETSYM(oth, g_oth);
    GETSYM(WqkTh, g_WqkTh); GETSYM(WvTh, g_WvTh); GETSYM(WoTh, g_WoTh);
    GETSYM(W1Th, g_W1Th); GETSYM(W2Th, g_W2Th);
    GETSYM(attn, g_attn); GETSYM(x2, g_x2); GETSYM(x2h, g_x2h);
    GETSYM(midh, g_midh); GETSYM(ff, g_ff);

    cudaFuncSetAttribute(mma_gemm<0, 0, 0>, cudaFuncAttributeMaxDynamicSharedMemorySize, SMEM_G);
    cudaFuncSetAttribute(mma_gemm<0, 0, 1>, cudaFuncAttributeMaxDynamicSharedMemorySize, SMEM_G);
    cudaFuncSetAttribute(mma_gemm<0, 2, 0>, cudaFuncAttributeMaxDynamicSharedMemorySize, SMEM_G);
    cudaFuncSetAttribute(mma_gemm<0, 2, 2>, cudaFuncAttributeMaxDynamicSharedMemorySize, SMEM_G);
    cudaFuncSetAttribute(mma_gemm<1, 2, 1>, cudaFuncAttributeMaxDynamicSharedMemorySize, SMEM_G);

    dim3 tb(32, 8);

    // 0) DFT matrices (fp16 hi only)
    init_dft_rows<<<(FR * Sm + 255) / 256, 256>>>(CSh, SSh, FR, Sm);
    init_bd<<<(TN * Dm + 255) / 256, 256>>>(BDh);

    // inputs: x_dec split hi/lo (t12 2-pass); x_enc fp16 only
    split_k8<<<(int)(BSD / 8 / 256), 256>>>(x_dec, xdh, xdl, BSD / 8);
    split_k8<<<(int)(BSD / 8 / 256), 256>>>(x_enc, xqkh + BSD, nullptr, BSD / 8);

    // 1) t12 = x_dec @ BD^T  (M=8192, N=768, K=512) -- 2-pass
    tcg(mk2(xdh, xdl, BDh), 2, t12, nullptr,
        BSm, TN, Dm, Dm, Dm, TN, 0, 0, 0, 1, nullptr, 0, 0, 0, 0);
    split_trans<<<dim3(TN / 32, Sm / 32, Bm), tb>>>(t12, t12Th, t12Tl,
        Sm, TN, (long long)Sm * TN, (long long)TN * Sm);

    // 2) c = CS @ t1, s = SS @ t2 -- 2-pass keeping t12's low
    tcg(mk2b(CSh, t12Th, t12Tl), 2, cp, nullptr,
        FR, FC, Sm, Sm, Sm, FC, 0, (long long)TN * Sm, (long long)FR * FC, Bm,
        nullptr, 0, 0, 0, 0);
    {
        const hlf* t2h = t12Th + (long long)FC * Sm;
        const hlf* t2l = t12Tl + (long long)FC * Sm;
        tcg(mk2b(SSh, t2h, t2l), 2, sp, nullptr,
            FR, FC, Sm, Sm, Sm, FC, 0, (long long)TN * Sm, (long long)FR * FC, Bm,
            nullptr, 0, 0, 0, 0);
    }
    fft_merge<<<dim3((1025 * 257 + 255) / 256, Bm), 256>>>(cp, sp, xf);

    // 3) xd = LN1(x_dec + xf), fp16 into first half of stacked qk-A buffer
    ln_split<<<BSm, 128>>>(x_dec, xf, ln1g, ln1b, xd, xqkh);

    // 4) weight transposes (fp16 hi only)
    split_trans<<<dim3(16, 16, Hn), tb>>>(Wq, WqkTh, nullptr, Dm, Dm, DD, DD);
    split_trans<<<dim3(16, 16, Hn), tb>>>(Wk, WqkTh + 4 * DD, nullptr, Dm, Dm, DD, DD);
    concat_bias<<<16, 256>>>(bq, bk, bqk);
    split_trans<<<dim3(16, 16, Hn), tb>>>(Wv, WvTh, nullptr, Dm, Dm, DD, DD);
    wo_split_trans<<<dim3(16, 16, Hn), tb>>>(Wo, WoTh);
    split_trans<<<dim3(MIDm / 32, Dm / 32, 1), tb>>>(W1, W1Th, nullptr, Dm, MIDm, 0, 0);
    split_trans<<<dim3(Dm / 32, MIDm / 32, 1), tb>>>(W2, W2Th, nullptr, MIDm, Dm, 0, 0);

    // 5) merged q/k projections: z=8, 1-pass
    tcg(mk1(xqkh, WqkTh), 1, qk, nullptr,
        BSm, Dm, Dm, Dm, Dm, Dm, BSD, DD, BSD, 8, bqk, Dm, 0, 0, 1,
        /*shA=*/2, /*mskB=*/7);

    // 6) vsT[z=h*4+b] = WvT_h @ x_enc[b]^T + bv_h, fp16 out, 1-pass; z=16
    tcg(mk1(WvTh, xqkh + BSD), 1, nullptr, vsTh,
        Dm, Sm, Dm, Dm, Dm, Sm, DD, SD, SD, 16, bv, Dm, 0, 2, 2,
        /*shA=*/2, /*mskB=*/3);

    // 7) softmax over heads: q, k (+transpose), fp16 out
    softmax_h4<<<(int)(BSD / 4 / 256), 256>>>(qk, qsh);
    softmax_trans<<<dim3(Sm / 32, Dm / 32, Bm), tb>>>(qk + 4 * BSD, ksTh);

    // 8) gcT[z] = vsT @ ksT^T  (M=N=512, K=2048, z=16) -- 1-pass, fp16 out
    tcg(mk1(vsTh, ksTh), 1, nullptr, gcTh,
        Dm, Dm, Sm, Sm, Sm, Dm, SD, SD, DD, 16, nullptr, 0, 0, 2, 0);

    // 9) out[z] = qs @ gcT^T  (M=2048,N=512,K=512,z=16) -- 1-pass, fp16 out
    tcg(mk1(qsh, gcTh), 1, nullptr, oth,
        Sm, Dm, Dm, Dm, Dm, Dm, SD, DD, SD, 16, nullptr, 0, 0, 2, 0);

    // 10) attn[b] = sum_h out_h[b] @ WoT_h^T + bo  (4 passes; z=4)
    {
        TcPasses P{};
        for (int h = 0; h < Hn; h++) {
            P.A[h] = oth + (long long)h * Bm * SD;
            P.B[h] = WoTh + (long long)h * DD;
        }
        tcg(P, 4, attn, nullptr,
            Sm, Dm, Dm, Dm, Dm, Dm, SD, 0, SD, Bm, bo, 0, 0, 0, 1);
    }

    // 11) x2 = LN2(xd + attn), fp16 out
    ln_split<<<BSm, 128>>>(xd, attn, ln2g, ln2b, x2, x2h);

    // 12) mid = selu(x2 @ W1 + b1), fp16 out, 1-pass
    tcg(mk1(x2h, W1Th), 1, nullptr, midh,
        BSm, MIDm, Dm, Dm, Dm, MIDm, 0, 0, 0, 1, b1, 0, 1, 2, 1);

    // 13) ff = mid @ W2 + b2, 1-pass
    tcg(mk1(midh, W2Th), 1, ff, nullptr,
        BSm, Dm, MIDm, MIDm, MIDm, Dm, 0, 0, 0, 1, b2, 0, 0, 0, 1);

    // 14) out = LN3(x2 + ff)
    ln_split<<<BSm, 128>>>(x2, ff, ln3g, ln3b, outp, nullptr);
}

// round 10
// speedup vs baseline: 1.8728x; 1.0100x over previous
#include <cuda_runtime.h>
#include <cuda_fp16.h>
#include <math.h>
#include <stdint.h>

typedef __half hlf;

static constexpr int Dm = 512, Hn = 4, MIDm = 2048, Bm = 4, Sm = 2048;
static constexpr int BSm = Bm * Sm;                      // 8192
static constexpr long long BSD = (long long)BSm * Dm;    // 4194304
static constexpr long long SD  = (long long)Sm * Dm;     // 1048576
static constexpr long long DD  = (long long)Dm * Dm;     // 262144

// FFT-symmetry tile sizes
static constexpr int FR = 1152;   // rows computed (need 0..1024)
static constexpr int FC = 384;    // cols computed (need 0..256)
static constexpr int TN = 768;    // t12 width: 384 cos + 384 sin

// ---------------------------------------------------------------------------
// Static device scratch
// ---------------------------------------------------------------------------
__device__ __align__(256) hlf g_CSh[FR * Sm];
__device__ __align__(256) hlf g_SSh[FR * Sm];
__device__ __align__(256) hlf g_BDh[TN * Dm];
__device__ __align__(256) hlf g_xdh[4194304], g_xdl[4194304];
__device__ __align__(256) hlf g_t12Th[4 * TN * Sm], g_t12Tl[4 * TN * Sm]; // [b][768,2048]
__device__ __align__(256) float g_cp[4 * FR * FC], g_sp[4 * FR * FC];
__device__ __align__(256) float g_xf[4194304];
__device__ __align__(256) float g_xd[4194304];
// stacked A for merged q/k proj: [0..BSD)=LN1(xd) fp16, [BSD..2BSD)=x_enc fp16
__device__ __align__(256) hlf g_xqkh[8388608];
__device__ __align__(256) hlf g_qkh[33554432];                     // [8][b,s,d] fp16 logits
__device__ __align__(256) hlf g_qsh[16777216];
__device__ __align__(256) hlf g_ksTh[16777216];                    // [z][D,S]
__device__ __align__(256) hlf g_vsTh[16777216];                    // [z][E,S]
__device__ __align__(256) hlf g_gcTh[4194304];                     // [z][E,D]
__device__ __align__(256) hlf g_oth[16777216];                     // [z][S,E]
__device__ __align__(256) hlf g_WqkTh[2097152];                    // [Wq0..3;Wk0..3]
__device__ __align__(256) float g_bqk[4096];                       // [bq;bk]
__device__ __align__(256) hlf g_WvTh[1048576];
__device__ __align__(256) hlf g_WoTh[1048576];                     // [h][512,512]
__device__ __align__(256) hlf g_W1Th[1048576];                     // [2048,512]
__device__ __align__(256) hlf g_W2Th[1048576];                     // [512,2048]
__device__ __align__(256) float g_attn[4194304];
__device__ __align__(256) float g_x2[4194304];
__device__ __align__(256) hlf g_x2h[4194304];
__device__ __align__(256) hlf g_midh[16777216];
__device__ __align__(256) float g_ff[4194304];

// ---------------------------------------------------------------------------
// Helpers
// ---------------------------------------------------------------------------
__device__ __forceinline__ uint32_t smem_u32(const void* p) {
    uint32_t a;
    asm("{ .reg .u64 t; cvta.to.shared.u64 t, %1; cvt.u32.u64 %0, t; }" : "=r"(a) : "l"(p));
    return a;
}
__device__ __forceinline__ float selu_f(float x) {
    const float sc = 1.0507009873554805f, al = 1.6732632423543772f;
    return x > 0.f ? sc * x : sc * al * (expf(x) - 1.f);
}
__device__ __forceinline__ void split2(float x, hlf& h, hlf& l) {
    h = __float2half_rn(x);
    l = __float2half_rn(x - __half2float(h));
}
__device__ __forceinline__ uint32_t packhl(hlf a, hlf b) {
    return ((uint32_t)*(uint16_t*)&b << 16) | (uint32_t)*(uint16_t*)&a;
}
__device__ __forceinline__ uint32_t packf2(float a, float b) {
    hlf ha = __float2half_rn(a), hb = __float2half_rn(b);
    return packhl(ha, hb);
}

#define LDSM_X4(r0, r1, r2, r3, addr) \
    asm volatile("ldmatrix.sync.aligned.m8n8.x4.shared.b16 {%0,%1,%2,%3}, [%4];" \
        : "=r"(r0), "=r"(r1), "=r"(r2), "=r"(r3) : "r"(addr))

#define MMA_F16(d, a, b0, b1) \
    asm volatile("mma.sync.aligned.m16n8k16.row.col.f32.f16.f16.f32 " \
        "{%0,%1,%2,%3}, {%4,%5,%6,%7}, {%8,%9}, {%0,%1,%2,%3};" \
        : "+f"((d)[0]), "+f"((d)[1]), "+f"((d)[2]), "+f"((d)[3]) \
        : "r"((a)[0]), "r"((a)[1]), "r"((a)[2]), "r"((a)[3]), "r"(b0), "r"(b1))

#define CP_ASYNC16(dst, src) \
    asm volatile("cp.async.cg.shared.global [%0], [%1], 16;" :: "r"(dst), "l"(src))
#define CP_COMMIT() asm volatile("cp.async.commit_group;")
#define CP_WAIT1()  asm volatile("cp.async.wait_group 1;")

// ---------------------------------------------------------------------------
// HMMA GEMM, cp.async 3-stage pipeline, multi-pass accumulation.
// Block 128x128, 8 warps, warp 64x32, BK=64, 2 CTA/SM.
// C[z] = sum_p A_p[z>>shA] @ B_p[z&mskB]^T (+bias col[zb]/row[za])(+SELU)
// SPLIT: 0 = fp32 out, 1 = fp16 hi+lo out, 2 = fp16 hi out.
// ---------------------------------------------------------------------------
struct TcPasses { const hlf* A[4]; const hlf* B[4]; };

static constexpr int BKg = 64;
static constexpr int LDSg = BKg + 8;
static constexpr int TILE_B = 128 * LDSg * 2;
static constexpr int STAGES = 3;
static constexpr int SMEM_B_OFF = STAGES * TILE_B;
static constexpr int SMEM_BIAS_OFF = 2 * STAGES * TILE_B;
static constexpr int SMEM_G = SMEM_BIAS_OFF + 128 * 4;

template <int ACT, int SPLIT, int BMODE>   // BMODE: 0 none, 1 col (zb), 2 row (za)
__global__ __launch_bounds__(256, 2) void mma_gemm(
    TcPasses P, int npass,
    float* __restrict__ C, hlf* __restrict__ Chi, hlf* __restrict__ Clo,
    int K, int lda, int ldb, int ldc,
    long long sA, long long sB, long long sC,
    const float* __restrict__ bias, long long sBias,
    int shA, int mskB)
{
    extern __shared__ char smem[];
    float* bias_s = (float*)(smem + SMEM_BIAS_OFF);
    const uint32_t sA0 = smem_u32(smem);
    const uint32_t sB0 = sA0 + SMEM_B_OFF;

    const int tid = threadIdx.x;
    const int lane = tid & 31;
    const int wid = tid >> 5;
    const int wm = (wid & 1) * 64;
    const int wn = (wid >> 1) * 32;
    const int z = blockIdx.z;
    const int za = z >> shA;
    const int zb = z & mskB;
    const int m0 = blockIdx.y * 128, n0 = blockIdx.x * 128;

    if (tid < 128) {
        if (BMODE == 0) bias_s[tid] = 0.f;
        else if (BMODE == 1) bias_s[tid] = bias[(long long)zb * sBias + n0 + tid];
        else bias_s[tid] = bias[(long long)za * sBias + m0 + tid];
    }

    float acc[4][4][4];
#pragma unroll
    for (int i = 0; i < 4; i++)
#pragma unroll
        for (int j = 0; j < 4; j++)
#pragma unroll
            for (int k = 0; k < 4; k++) acc[i][j][k] = 0.f;

    const int cpp = K / BKg;
    const int total = npass * cpp;

    const int crow = tid >> 3;
    const int ccol = (tid & 7) * 8;

    auto loadStage = [&](int c, int stg) {
        int p = c / cpp;
        int k0 = (c - p * cpp) * BKg;
        const hlf* Ab = P.A[p] + (long long)za * sA + k0 + ccol;
        const hlf* Bb = P.B[p] + (long long)zb * sB + k0 + ccol;
        uint32_t da = sA0 + stg * TILE_B + (crow * LDSg + ccol) * 2;
        uint32_t db = sB0 + stg * TILE_B + (crow * LDSg + ccol) * 2;
#pragma unroll
        for (int i = 0; i < 4; i++) {
            int row = crow + i * 32;
            CP_ASYNC16(da + i * 32 * LDSg * 2, Ab + (long long)(m0 + row) * lda);
            CP_ASYNC16(db + i * 32 * LDSg * 2, Bb + (long long)(n0 + row) * ldb);
        }
    };

    loadStage(0, 0); CP_COMMIT();
    loadStage(1, 1); CP_COMMIT();

    const int lrow16 = lane & 15;
    const int lhalf = lane >> 4;

    for (int c = 0; c < total; c++) {
        CP_WAIT1();
        __syncthreads();
        const int stg = c % STAGES;
        const uint32_t aB = sA0 + stg * TILE_B;
        const uint32_t bB = sB0 + stg * TILE_B;
#pragma unroll
        for (int ks = 0; ks < 4; ks++) {
            uint32_t af[4][4];
#pragma unroll
            for (int mi = 0; mi < 4; mi++) {
                uint32_t addr = aB + (uint32_t)(((wm + mi * 16 + lrow16) * LDSg
                                                + ks * 16 + lhalf * 8) * 2);
                LDSM_X4(af[mi][0], af[mi][1], af[mi][2], af[mi][3], addr);
            }
            uint32_t bfr[2][4];
#pragma unroll
            for (int nj = 0; nj < 2; nj++) {
                uint32_t addr = bB + (uint32_t)(((wn + nj * 16 + lrow16) * LDSg
                                                + ks * 16 + lhalf * 8) * 2);
                LDSM_X4(bfr[nj][0], bfr[nj][1], bfr[nj][2], bfr[nj][3], addr);
            }
#pragma unroll
            for (int mi = 0; mi < 4; mi++)
#pragma unroll
                for (int ni = 0; ni < 4; ni++) {
                    const int nj = ni >> 1, sub = ni & 1;
                    MMA_F16(acc[mi][ni], af[mi], bfr[nj][sub], bfr[nj][sub + 2]);
                }
        }
        if (c + 2 < total) loadStage(c + 2, (c + 2) % STAGES);
        CP_COMMIT();
    }

    const int cr = lane >> 2;
    const int cc = (lane & 3) * 2;
#pragma unroll
    for (int mi = 0; mi < 4; mi++) {
#pragma unroll
        for (int ni = 0; ni < 4; ni++) {
            const int bn = wn + ni * 8 + cc;
            const int gn = n0 + bn;
            const int rm = wm + mi * 16 + cr;
            const long long r0 = m0 + rm;
            const long long r1 = r0 + 8;
            float v0 = acc[mi][ni][0], v1 = acc[mi][ni][1];
            float v2 = acc[mi][ni][2], v3 = acc[mi][ni][3];
            if (BMODE == 1) {
                v0 += bias_s[bn]; v1 += bias_s[bn + 1];
                v2 += bias_s[bn]; v3 += bias_s[bn + 1];
            } else if (BMODE == 2) {
                v0 += bias_s[rm]; v1 += bias_s[rm];
                v2 += bias_s[rm + 8]; v3 += bias_s[rm + 8];
            }
            if (ACT == 1) { v0 = selu_f(v0); v1 = selu_f(v1); v2 = selu_f(v2); v3 = selu_f(v3); }
            if (SPLIT == 1) {
                hlf h0, l0, h1, l1;
                split2(v0, h0, l0); split2(v1, h1, l1);
                *(uint32_t*)(Chi + (long long)z * sC + r0 * ldc + gn) = packhl(h0, h1);
                *(uint32_t*)(Clo + (long long)z * sC + r0 * ldc + gn) = packhl(l0, l1);
                split2(v2, h0, l0); split2(v3, h1, l1);
                *(uint32_t*)(Chi + (long long)z * sC + r1 * ldc + gn) = packhl(h0, h1);
                *(uint32_t*)(Clo + (long long)z * sC + r1 * ldc + gn) = packhl(l0, l1);
            } else if (SPLIT == 2) {
                *(uint32_t*)(Chi + (long long)z * sC + r0 * ldc + gn) = packf2(v0, v1);
                *(uint32_t*)(Chi + (long long)z * sC + r1 * ldc + gn) = packf2(v2, v3);
            } else {
                *(float2*)(C + (long long)z * sC + r0 * ldc + gn) = make_float2(v0, v1);
                *(float2*)(C + (long long)z * sC + r1 * ldc + gn) = make_float2(v2, v3);
            }
        }
    }
}

// ---------------------------------------------------------------------------
// Elementwise kernels
// ---------------------------------------------------------------------------
__global__ void init_dft_rows(hlf* __restrict__ Ch, hlf* __restrict__ Sh,
                              int rows, int N)
{
    long long idx = (long long)blockIdx.x * blockDim.x + threadIdx.x;
    if (idx >= (long long)rows * N) return;
    int i = (int)(idx / N), j = (int)(idx % N);
    int p = (int)(((long long)i * j) % N);
    float x = 2.0f * (float)p / (float)N;
    float s, c;
    sincospif(x, &s, &c);
    Ch[idx] = __float2half_rn(c);
    Sh[idx] = __float2half_rn(s);
}

__global__ void init_bd(hlf* __restrict__ h)
{
    long long idx = (long long)blockIdx.x * blockDim.x + threadIdx.x;
    if (idx >= (long long)TN * Dm) return;
    int n = (int)(idx / Dm), k = (int)(idx % Dm);
    int i = (n < FC) ? n : (n - FC);
    int p = (int)(((long long)i * k) % Dm);
    float x = 2.0f * (float)p / (float)Dm;
    float s, c;
    sincospif(x, &s, &c);
    h[idx] = __float2half_rn((n < FC) ? c : s);
}

__global__ void split_k8(const float* __restrict__ in, hlf* __restrict__ h,
                         hlf* __restrict__ l, long long n8)
{
    long long i = (long long)blockIdx.x * blockDim.x + threadIdx.x;
    if (i >= n8) return;
    long long base = i * 8;
    float4 a = *(const float4*)(in + base);
    float4 b = *(const float4*)(in + base + 4);
    hlf hh[8], ll[8];
    split2(a.x, hh[0], ll[0]); split2(a.y, hh[1], ll[1]);
    split2(a.z, hh[2], ll[2]); split2(a.w, hh[3], ll[3]);
    split2(b.x, hh[4], ll[4]); split2(b.y, hh[5], ll[5]);
    split2(b.z, hh[6], ll[6]); split2(b.w, hh[7], ll[7]);
    uint4 ho;
    ho.x = packhl(hh[0], hh[1]); ho.y = packhl(hh[2], hh[3]);
    ho.z = packhl(hh[4], hh[5]); ho.w = packhl(hh[6], hh[7]);
    *(uint4*)(h + base) = ho;
    if (l) {
        uint4 lo;
        lo.x = packhl(ll[0], ll[1]); lo.y = packhl(ll[2], ll[3]);
        lo.z = packhl(ll[4], ll[5]); lo.w = packhl(ll[6], ll[7]);
        *(uint4*)(l + base) = lo;
    }
}

// [R,C] fp32 -> [C,R] fp16 (hi only), batched.
__global__ void split_trans(const float* __restrict__ in, hlf* __restrict__ oh,
                            int R, int C, long long sIn, long long sOut)
{
    __shared__ float t[32][33];
    const int z = blockIdx.z;
    const float* ib = in + (long long)z * sIn;
    const int c0 = blockIdx.x * 32, r0 = blockIdx.y * 32;
    const int tx = threadIdx.x, ty = threadIdx.y;
#pragma unroll
    for (int i = 0; i < 4; i++)
        t[ty + i * 8][tx] = ib[(long long)(r0 + ty + i * 8) * C + c0 + tx];
    __syncthreads();
#pragma unroll
    for (int i = 0; i < 4; i++) {
        float v = t[tx][ty + i * 8];
        long long o = (long long)z * sOut + (long long)(c0 + ty + i * 8) * R + r0 + tx;
        oh[o] = __float2half_rn(v);
    }
}

__global__ void wo_split_trans(const float* __restrict__ Wo, hlf* __restrict__ oh)
{
    __shared__ float t[32][33];
    const int h = blockIdx.z;
    const int n0 = blockIdx.x * 32, d0 = blockIdx.y * 32;
    const int tx = threadIdx.x, ty = threadIdx.y;
#pragma unroll
    for (int i = 0; i < 4; i++) {
        int d = d0 + ty + i * 8;
        t[ty + i * 8][tx] = Wo[(long long)(d * 4 + h) * Dm + n0 + tx];
    }
    __syncthreads();
#pragma unroll
    for (int i = 0; i < 4; i++) {
        float v = t[tx][ty + i * 8];
        long long o = (long long)h * DD + (long long)(n0 + ty + i * 8) * Dm + d0 + tx;
        oh[o] = __float2half_rn(v);
    }
}

__global__ void concat_bias(const float* __restrict__ a, const float* __restrict__ b,
                            float* __restrict__ o)
{
    int i = blockIdx.x * blockDim.x + threadIdx.x;
    if (i < 2048) o[i] = a[i];
    else if (i < 4096) o[i] = b[i - 2048];
}

__global__ void fft_merge(const float* __restrict__ cp, const float* __restrict__ sp,
                          float* __restrict__ xf)
{
    const int b = blockIdx.y;
    long long idx = (long long)blockIdx.x * blockDim.x + threadIdx.x;
    const long long TOT = 1025LL * 257LL;
    if (idx >= TOT) return;
    int i = (int)(idx / 257);
    int d = (int)(idx % 257);
    long long src = (long long)b * FR * FC + (long long)i * FC + d;
    float c = cp[src], s = sp[src];
    float a = c - s, bb = c + s;
    int i2 = (Sm - i) & (Sm - 1);
    int d2 = (Dm - d) & (Dm - 1);
    float* x = xf + (long long)b * SD;
    x[(long long)i * Dm + d] = a;
    x[(long long)i2 * Dm + d] = bb;
    x[(long long)i * Dm + d2] = bb;
    x[(long long)i2 * Dm + d2] = a;
}

// softmax over H=4 heads (stride BSD), fp16 in/out; 4 elems/thread
__global__ void softmax_h4(const hlf* __restrict__ q, hlf* __restrict__ oh)
{
    long long i4 = (long long)blockIdx.x * blockDim.x + threadIdx.x;
    if (i4 >= BSD / 4) return;
    long long base = i4 * 4;
    float v[4][4];
#pragma unroll
    for (int h = 0; h < 4; h++) {
        uint2 raw = *(const uint2*)(q + h * BSD + base);
        hlf* hp = (hlf*)&raw;
#pragma unroll
        for (int j = 0; j < 4; j++) v[h][j] = __half2float(hp[j]);
    }
    float r[4][4];
#pragma unroll
    for (int j = 0; j < 4; j++) {
        float m = fmaxf(fmaxf(v[0][j], v[1][j]), fmaxf(v[2][j], v[3][j]));
        float e0 = expf(v[0][j] - m), e1 = expf(v[1][j] - m);
        float e2 = expf(v[2][j] - m), e3 = expf(v[3][j] - m);
        float inv = 1.f / (e0 + e1 + e2 + e3);
        r[0][j] = e0 * inv; r[1][j] = e1 * inv; r[2][j] = e2 * inv; r[3][j] = e3 * inv;
    }
#pragma unroll
    for (int h = 0; h < 4; h++) {
        uint2 ho = make_uint2(packf2(r[h][0], r[h][1]), packf2(r[h][2], r[h][3]));
        *(uint2*)(oh + h * BSD + base) = ho;
    }
}

// softmax over heads + transpose: ks[h][b][s,d] fp16 -> ksT[z=h*B+b][d,s] fp16.
__global__ void softmax_trans(const hlf* __restrict__ ks, hlf* __restrict__ oh)
{
    __shared__ float t[4][32][33];
    const int b = blockIdx.z;
    const int s0 = blockIdx.x * 32, d0 = blockIdx.y * 32;
    const int tx = threadIdx.x, ty = threadIdx.y;
#pragma unroll
    for (int h = 0; h < 4; h++)
#pragma unroll
        for (int i = 0; i < 4; i++)
            t[h][ty + i * 8][tx] = __half2float(
                ks[((long long)(h * Bm + b) * Sm + s0 + ty + i * 8) * Dm + d0 + tx]);
    __syncthreads();
#pragma unroll
    for (int i = 0; i < 4; i++) {
        float v0 = t[0][ty + i * 8][tx], v1 = t[1][ty + i * 8][tx];
        float v2 = t[2][ty + i * 8][tx], v3 = t[3][ty + i * 8][tx];
        float m = fmaxf(fmaxf(v0, v1), fmaxf(v2, v3));
        float e0 = expf(v0 - m), e1 = expf(v1 - m), e2 = expf(v2 - m), e3 = expf(v3 - m);
        float r = 1.f / (e0 + e1 + e2 + e3);
        t[0][ty + i * 8][tx] = e0 * r; t[1][ty + i * 8][tx] = e1 * r;
        t[2][ty + i * 8][tx] = e2 * r; t[3][ty + i * 8][tx] = e3 * r;
    }
    __syncthreads();
#pragma unroll
    for (int h = 0; h < 4; h++)
#pragma unroll
        for (int i = 0; i < 4; i++) {
            float v = t[h][tx][ty + i * 8];
            long long o = (long long)(h * Bm + b) * SD + (long long)(d0 + ty + i * 8) * Sm + s0 + tx;
            oh[o] = __float2half_rn(v);
        }
}

// LN over last dim (D=512) of (a+b); optional fp16 out (hi only).
__global__ void ln_split(const float* __restrict__ a, const float* __restrict__ bres,
                         const float* __restrict__ g, const float* __restrict__ be,
                         float* __restrict__ out, hlf* __restrict__ oh)
{
    __shared__ float red[4];
    long long row = blockIdx.x;
    int t = threadIdx.x;  // 128
    float4 va = ((const float4*)(a + row * Dm))[t];
    float4 vb = ((const float4*)(bres + row * Dm))[t];
    float4 v = make_float4(va.x + vb.x, va.y + vb.y, va.z + vb.z, va.w + vb.w);
    float s = v.x + v.y + v.z + v.w;
#pragma unroll
    for (int o = 16; o > 0; o >>= 1) s += __shfl_xor_sync(0xffffffffu, s, o);
    if ((t & 31) == 0) red[t >> 5] = s;
    __syncthreads();
    float mu = (red[0] + red[1] + red[2] + red[3]) * (1.f / (float)Dm);
    __syncthreads();
    float d0 = v.x - mu, d1 = v.y - mu, d2 = v.z - mu, d3 = v.w - mu;
    float q = d0 * d0 + d1 * d1 + d2 * d2 + d3 * d3;
#pragma unroll
    for (int o = 16; o > 0; o >>= 1) q += __shfl_xor_sync(0xffffffffu, q, o);
    if ((t & 31) == 0) red[t >> 5] = q;
    __syncthreads();
    float var = (red[0] + red[1] + red[2] + red[3]) * (1.f / (float)Dm);
    float rstd = rsqrtf(var + 1e-5f);
    float4 vg = ((const float4*)g)[t];
    float4 vbe = ((const float4*)be)[t];
    float4 o4;
    o4.x = fmaf(vg.x, d0 * rstd, vbe.x);
    o4.y = fmaf(vg.y, d1 * rstd, vbe.y);
    o4.z = fmaf(vg.z, d2 * rstd, vbe.z);
    o4.w = fmaf(vg.w, d3 * rstd, vbe.w);
    ((float4*)(out + row * Dm))[t] = o4;
    if (oh) {
        long long o = row * Dm + t * 4;
        *(uint2*)(oh + o) = make_uint2(packf2(o4.x, o4.y), packf2(o4.z, o4.w));
    }
}

// ---------------------------------------------------------------------------
// Host
// ---------------------------------------------------------------------------
static TcPasses mk1(const hlf* Ah, const hlf* Bh) {
    TcPasses P{};
    P.A[0] = Ah; P.B[0] = Bh;
    return P;
}
static TcPasses mk2b(const hlf* Ah, const hlf* Bh, const hlf* Bl) {
    TcPasses P{};
    P.A[0] = Ah; P.B[0] = Bh;
    P.A[1] = Ah; P.B[1] = Bl;
    return P;
}

static void tcg(const TcPasses& P, int np, float* C, hlf* Ch, hlf* Cl,
                int M, int N, int K, int lda, int ldb, int ldc,
                long long sA, long long sB, long long sC, int batch,
                const float* bias, long long sBias, int act, int split, int bmode,
                int shA = 0, int mskB = 0x7FFFFFFF)
{
    dim3 grid(N / 128, M / 128, batch), block(256);
    if (act == 1)
        mma_gemm<1, 2, 1><<<grid, block, SMEM_G>>>(P, np, C, Ch, Cl, K, lda, ldb, ldc, sA, sB, sC, bias, sBias, shA, mskB);
    else if (split == 1)
        mma_gemm<0, 1, 0><<<grid, block, SMEM_G>>>(P, np, C, Ch, Cl, K, lda, ldb, ldc, sA, sB, sC, bias, sBias, shA, mskB);
    else if (split == 2 && bmode == 2)
        mma_gemm<0, 2, 2><<<grid, block, SMEM_G>>>(P, np, C, Ch, Cl, K, lda, ldb, ldc, sA, sB, sC, bias, sBias, shA, mskB);
    else if (split == 2 && bmode == 1)
        mma_gemm<0, 2, 1><<<grid, block, SMEM_G>>>(P, np, C, Ch, Cl, K, lda, ldb, ldc, sA, sB, sC, bias, sBias, shA, mskB);
    else if (split == 2)
        mma_gemm<0, 2, 0><<<grid, block, SMEM_G>>>(P, np, C, Ch, Cl, K, lda, ldb, ldc, sA, sB, sC, bias, sBias, shA, mskB);
    else if (bmode == 1)
        mma_gemm<0, 0, 1><<<grid, block, SMEM_G>>>(P, np, C, Ch, Cl, K, lda, ldb, ldc, sA, sB, sC, bias, sBias, shA, mskB);
    else
        mma_gemm<0, 0, 0><<<grid, block, SMEM_G>>>(P, np, C, Ch, Cl, K, lda, ldb, ldc, sA, sB, sC, bias, sBias, shA, mskB);
}

#define GETSYM(var, sym) do { void* _p; cudaGetSymbolAddress(&_p, sym); var = (decltype(var))_p; } while (0)

extern "C" void kernel_launch(void* const* d_in, const int* in_sizes, int n_in,
                              void* d_out, int out_size)
{
    const float* x_enc = (const float*)d_in[0];
    const float* x_dec = (const float*)d_in[1];
    const float* Wq = (const float*)d_in[2];
    const float* bq = (const float*)d_in[3];
    const float* Wk = (const float*)d_in[4];
    const float* bk = (const float*)d_in[5];
    const float* Wv = (const float*)d_in[6];
    const float* bv = (const float*)d_in[7];
    const float* Wo = (const float*)d_in[8];
    const float* bo = (const float*)d_in[9];
    const float* ln1g = (const float*)d_in[10];
    const float* ln1b = (const float*)d_in[11];
    const float* ln2g = (const float*)d_in[12];
    const float* ln2b = (const float*)d_in[13];
    const float* W1 = (const float*)d_in[14];
    const float* b1 = (const float*)d_in[15];
    const float* W2 = (const float*)d_in[16];
    const float* b2 = (const float*)d_in[17];
    const float* ln3g = (const float*)d_in[18];
    const float* ln3b = (const float*)d_in[19];
    float* outp = (float*)d_out;

    hlf *CSh, *SSh, *BDh, *xdh, *xdl, *t12Th, *t12Tl, *xqkh, *qkh;
    hlf *qsh, *ksTh, *vsTh, *gcTh, *oth;
    hlf *WqkTh, *WvTh, *WoTh, *W1Th, *W2Th, *x2h, *midh;
    float *cp, *sp, *xf, *xd, *bqk, *attn, *x2, *ff;
    GETSYM(CSh, g_CSh); GETSYM(SSh, g_SSh); GETSYM(BDh, g_BDh);
    GETSYM(xdh, g_xdh); GETSYM(xdl, g_xdl);
    GETSYM(t12Th, g_t12Th); GETSYM(t12Tl, g_t12Tl);
    GETSYM(cp, g_cp); GETSYM(sp, g_sp);
    GETSYM(xf, g_xf); GETSYM(xd, g_xd);
    GETSYM(xqkh, g_xqkh); GETSYM(qkh, g_qkh);
    GETSYM(bqk, g_bqk);
    GETSYM(qsh, g_qsh); GETSYM(ksTh, g_ksTh); GETSYM(vsTh, g_vsTh);
    GETSYM(gcTh, g_gcTh); GETSYM(oth, g_oth);
    GETSYM(WqkTh, g_WqkTh); GETSYM(WvTh, g_WvTh); GETSYM(WoTh, g_WoTh);
    GETSYM(W1Th, g_W1Th); GETSYM(W2Th, g_W2Th);
    GETSYM(attn, g_attn); GETSYM(x2, g_x2); GETSYM(x2h, g_x2h);
    GETSYM(midh, g_midh); GETSYM(ff, g_ff);

    cudaFuncSetAttribute(mma_gemm<0, 0, 0>, cudaFuncAttributeMaxDynamicSharedMemorySize, SMEM_G);
    cudaFuncSetAttribute(mma_gemm<0, 0, 1>, cudaFuncAttributeMaxDynamicSharedMemorySize, SMEM_G);
    cudaFuncSetAttribute(mma_gemm<0, 1, 0>, cudaFuncAttributeMaxDynamicSharedMemorySize, SMEM_G);
    cudaFuncSetAttribute(mma_gemm<0, 2, 0>, cudaFuncAttributeMaxDynamicSharedMemorySize, SMEM_G);
    cudaFuncSetAttribute(mma_gemm<0, 2, 1>, cudaFuncAttributeMaxDynamicSharedMemorySize, SMEM_G);
    cudaFuncSetAttribute(mma_gemm<0, 2, 2>, cudaFuncAttributeMaxDynamicSharedMemorySize, SMEM_G);
    cudaFuncSetAttribute(mma_gemm<1, 2, 1>, cudaFuncAttributeMaxDynamicSharedMemorySize, SMEM_G);

    dim3 tb(32, 8);

    // 0) DFT matrices (fp16 hi only)
    init_dft_rows<<<(FR * Sm + 255) / 256, 256>>>(CSh, SSh, FR, Sm);
    init_bd<<<(TN * Dm + 255) / 256, 256>>>(BDh);

    // inputs: x_dec split hi/lo (t12T 2-pass); x_enc fp16 only
    split_k8<<<(int)(BSD / 8 / 256), 256>>>(x_dec, xdh, xdl, BSD / 8);
    split_k8<<<(int)(BSD / 8 / 256), 256>>>(x_enc, xqkh + BSD, nullptr, BSD / 8);

    // 1) t12T[b] = BD @ x_dec[b]^T  (M=768, N=2048, K=512, z=4), 2-pass (B-side lo),
    //    fp16 hi/lo split written directly -- no fp32 buffer, no transpose kernel.
    tcg(mk2b(BDh, xdh, xdl), 2, nullptr, t12Th, t12Tl,
        TN, Sm, Dm, Dm, Dm, Sm, 0, SD, (long long)TN * Sm, Bm,
        nullptr, 0, 0, 1, 0, /*shA=*/30, /*mskB=*/0x7FFFFFFF);

    // 2) c = CS @ t1, s = SS @ t2 -- 2-pass keeping t12's low
    tcg(mk2b(CSh, t12Th, t12Tl), 2, cp, nullptr, nullptr,
        FR, FC, Sm, Sm, Sm, FC, 0, (long long)TN * Sm, (long long)FR * FC, Bm,
        nullptr, 0, 0, 0, 0);
    {
        const hlf* t2h = t12Th + (long long)FC * Sm;
        const hlf* t2l = t12Tl + (long long)FC * Sm;
        tcg(mk2b(SSh, t2h, t2l), 2, sp, nullptr, nullptr,
            FR, FC, Sm, Sm, Sm, FC, 0, (long long)TN * Sm, (long long)FR * FC, Bm,
            nullptr, 0, 0, 0, 0);
    }
    fft_merge<<<dim3((1025 * 257 + 255) / 256, Bm), 256>>>(cp, sp, xf);

    // 3) xd = LN1(x_dec + xf), fp16 into first half of stacked qk-A buffer
    ln_split<<<BSm, 128>>>(x_dec, xf, ln1g, ln1b, xd, xqkh);

    // 4) weight transposes (fp16 hi only)
    split_trans<<<dim3(16, 16, Hn), tb>>>(Wq, WqkTh, Dm, Dm, DD, DD);
    split_trans<<<dim3(16, 16, Hn), tb>>>(Wk, WqkTh + 4 * DD, Dm, Dm, DD, DD);
    concat_bias<<<16, 256>>>(bq, bk, bqk);
    split_trans<<<dim3(16, 16, Hn), tb>>>(Wv, WvTh, Dm, Dm, DD, DD);
    wo_split_trans<<<dim3(16, 16, Hn), tb>>>(Wo, WoTh);
    split_trans<<<dim3(MIDm / 32, Dm / 32, 1), tb>>>(W1, W1Th, Dm, MIDm, 0, 0);
    split_trans<<<dim3(Dm / 32, MIDm / 32, 1), tb>>>(W2, W2Th, MIDm, Dm, 0, 0);

    // 5) merged q/k projections: z=8, 1-pass, fp16 logits out
    tcg(mk1(xqkh, WqkTh), 1, nullptr, qkh, nullptr,
        BSm, Dm, Dm, Dm, Dm, Dm, BSD, DD, BSD, 8, bqk, Dm, 0, 2, 1,
        /*shA=*/2, /*mskB=*/7);

    // 6) vsT[z=h*4+b] = WvT_h @ x_enc[b]^T + bv_h, fp16 out, 1-pass; z=16
    tcg(mk1(WvTh, xqkh + BSD), 1, nullptr, vsTh, nullptr,
        Dm, Sm, Dm, Dm, Dm, Sm, DD, SD, SD, 16, bv, Dm, 0, 2, 2,
        /*shA=*/2, /*mskB=*/3);

    // 7) softmax over heads: q, k (+transpose), fp16 in/out
    softmax_h4<<<(int)(BSD / 4 / 256), 256>>>(qkh, qsh);
    softmax_trans<<<dim3(Sm / 32, Dm / 32, Bm), tb>>>(qkh + 4 * BSD, ksTh);

    // 8) gcT[z] = vsT @ ksT^T  (M=N=512, K=2048, z=16) -- 1-pass, fp16 out
    tcg(mk1(vsTh, ksTh), 1, nullptr, gcTh, nullptr,
        Dm, Dm, Sm, Sm, Sm, Dm, SD, SD, DD, 16, nullptr, 0, 0, 2, 0);

    // 9) out[z] = qs @ gcT^T  (M=2048,N=512,K=512,z=16) -- 1-pass, fp16 out
    tcg(mk1(qsh, gcTh), 1, nullptr, oth, nullptr,
        Sm, Dm, Dm, Dm, Dm, Dm, SD, DD, SD, 16, nullptr, 0, 0, 2, 0);

    // 10) attn[b] = sum_h out_h[b] @ WoT_h^T + bo  (4 passes; z=4)
    {
        TcPasses P{};
        for (int h = 0; h < Hn; h++) {
            P.A[h] = oth + (long long)h * Bm * SD;
            P.B[h] = WoTh + (long long)h * DD;
        }
        tcg(P, 4, attn, nullptr, nullptr,
            Sm, Dm, Dm, Dm, Dm, Dm, SD, 0, SD, Bm, bo, 0, 0, 0, 1);
    }

    // 11) x2 = LN2(xd + attn), fp16 out
    ln_split<<<BSm, 128>>>(xd, attn, ln2g, ln2b, x2, x2h);

    // 12) mid = selu(x2 @ W1 + b1), fp16 out, 1-pass
    tcg(mk1(x2h, W1Th), 1, nullptr, midh, nullptr,
        BSm, MIDm, Dm, Dm, Dm, MIDm, 0, 0, 0, 1, b1, 0, 1, 2, 1);

    // 13) ff = mid @ W2 + b2, 1-pass
    tcg(mk1(midh, W2Th), 1, ff, nullptr, nullptr,
        BSm, Dm, MIDm, MIDm, MIDm, Dm, 0, 0, 0, 1, b2, 0, 0, 0, 1);

    // 14) out = LN3(x2 + ff)
    ln_split<<<BSm, 128>>>(x2, ff, ln3g, ln3b, outp, nullptr);
}

// round 11
// speedup vs baseline: 2.2416x; 1.1969x over previous
#include <cuda_runtime.h>
#include <cuda_fp16.h>
#include <math.h>
#include <stdint.h>

typedef __half hlf;

static constexpr int Dm = 512, Hn = 4, MIDm = 2048, Bm = 4, Sm = 2048;
static constexpr int BSm = Bm * Sm;                      // 8192
static constexpr long long BSD = (long long)BSm * Dm;    // 4194304
static constexpr long long SD  = (long long)Sm * Dm;     // 1048576
static constexpr long long DD  = (long long)Dm * Dm;     // 262144

// FFT-symmetry tile sizes
static constexpr int FR = 1152;   // rows computed (need 0..1024)
static constexpr int FC = 384;    // cols computed (need 0..256)
static constexpr int TN = 768;    // t12 width: 384 cos + 384 sin
static constexpr int KF = 1088;   // folded K for cp/sp (1025 padded to /64)

// ---------------------------------------------------------------------------
// Static device scratch
// ---------------------------------------------------------------------------
__device__ __align__(256) hlf g_CSf[2 * FR * KF];                  // [cos;sin] folded
__device__ __align__(256) hlf g_BDh[TN * Dm];
__device__ __align__(256) hlf g_xdh[4194304];
__device__ __align__(256) hlf g_t12Th[4 * TN * Sm];                // [b][768,2048]
__device__ __align__(256) hlf g_t12Tf[8 * 384 * KF];               // [half*4+b][384,1088]
__device__ __align__(256) float g_cps[8 * FR * FC];                // cp z=0..3, sp z=4..7
__device__ __align__(256) float g_xf[4194304];
__device__ __align__(256) float g_xd[4194304];
// stacked A for merged q/k proj: [0..BSD)=LN1(xd) fp16, [BSD..2BSD)=x_enc fp16
__device__ __align__(256) hlf g_xqkh[8388608];
__device__ __align__(256) hlf g_qkh[33554432];                     // [8][b,s,d] fp16 logits
__device__ __align__(256) hlf g_qsh[16777216];
__device__ __align__(256) hlf g_ksTh[16777216];                    // [z][D,S]
__device__ __align__(256) hlf g_vsTh[16777216];                    // [z][E,S]
__device__ __align__(256) hlf g_gcTh[4194304];                     // [z][E,D]
__device__ __align__(256) hlf g_oth[16777216];                     // [z][S,E]
__device__ __align__(256) hlf g_WqkTh[2097152];                    // [Wq0..3;Wk0..3]
__device__ __align__(256) float g_bqk[4096];                       // [bq;bk]
__device__ __align__(256) hlf g_WvTh[1048576];
__device__ __align__(256) hlf g_WoTh[1048576];                     // [h][512,512]
__device__ __align__(256) hlf g_W1Th[1048576];                     // [2048,512]
__device__ __align__(256) hlf g_W2Th[1048576];                     // [512,2048]
__device__ __align__(256) float g_attn[4194304];
__device__ __align__(256) float g_x2[4194304];
__device__ __align__(256) hlf g_x2h[4194304];
__device__ __align__(256) hlf g_midh[16777216];
__device__ __align__(256) float g_ff[4194304];

// ---------------------------------------------------------------------------
// Helpers
// ---------------------------------------------------------------------------
__device__ __forceinline__ uint32_t smem_u32(const void* p) {
    uint32_t a;
    asm("{ .reg .u64 t; cvta.to.shared.u64 t, %1; cvt.u32.u64 %0, t; }" : "=r"(a) : "l"(p));
    return a;
}
__device__ __forceinline__ float selu_f(float x) {
    const float sc = 1.0507009873554805f, al = 1.6732632423543772f;
    return x > 0.f ? sc * x : sc * al * (expf(x) - 1.f);
}
__device__ __forceinline__ void split2(float x, hlf& h, hlf& l) {
    h = __float2half_rn(x);
    l = __float2half_rn(x - __half2float(h));
}
__device__ __forceinline__ uint32_t packhl(hlf a, hlf b) {
    return ((uint32_t)*(uint16_t*)&b << 16) | (uint32_t)*(uint16_t*)&a;
}
__device__ __forceinline__ uint32_t packf2(float a, float b) {
    hlf ha = __float2half_rn(a), hb = __float2half_rn(b);
    return packhl(ha, hb);
}

#define LDSM_X4(r0, r1, r2, r3, addr) \
    asm volatile("ldmatrix.sync.aligned.m8n8.x4.shared.b16 {%0,%1,%2,%3}, [%4];" \
        : "=r"(r0), "=r"(r1), "=r"(r2), "=r"(r3) : "r"(addr))

#define MMA_F16(d, a, b0, b1) \
    asm volatile("mma.sync.aligned.m16n8k16.row.col.f32.f16.f16.f32 " \
        "{%0,%1,%2,%3}, {%4,%5,%6,%7}, {%8,%9}, {%0,%1,%2,%3};" \
        : "+f"((d)[0]), "+f"((d)[1]), "+f"((d)[2]), "+f"((d)[3]) \
        : "r"((a)[0]), "r"((a)[1]), "r"((a)[2]), "r"((a)[3]), "r"(b0), "r"(b1))

#define CP_ASYNC16(dst, src) \
    asm volatile("cp.async.cg.shared.global [%0], [%1], 16;" :: "r"(dst), "l"(src))
#define CP_COMMIT() asm volatile("cp.async.commit_group;")
#define CP_WAIT1()  asm volatile("cp.async.wait_group 1;")

// ---------------------------------------------------------------------------
// HMMA GEMM, cp.async 3-stage pipeline, multi-pass accumulation.
// Block 128x128, 8 warps, warp 64x32, BK=64, 2 CTA/SM.
// C[z] = sum_p A_p[z>>shA] @ B_p[z&mskB]^T (+bias col[zb]/row[za])(+SELU)
// SPLIT: 0 = fp32 out, 2 = fp16 out.
// ---------------------------------------------------------------------------
struct TcPasses { const hlf* A[4]; const hlf* B[4]; };

static constexpr int BKg = 64;
static constexpr int LDSg = BKg + 8;
static constexpr int TILE_B = 128 * LDSg * 2;
static constexpr int STAGES = 3;
static constexpr int SMEM_B_OFF = STAGES * TILE_B;
static constexpr int SMEM_BIAS_OFF = 2 * STAGES * TILE_B;
static constexpr int SMEM_G = SMEM_BIAS_OFF + 128 * 4;

template <int ACT, int SPLIT, int BMODE>   // BMODE: 0 none, 1 col (zb), 2 row (za)
__global__ __launch_bounds__(256, 2) void mma_gemm(
    TcPasses P, int npass,
    float* __restrict__ C, hlf* __restrict__ Chi,
    int K, int lda, int ldb, int ldc,
    long long sA, long long sB, long long sC,
    const float* __restrict__ bias, long long sBias,
    int shA, int mskB)
{
    extern __shared__ char smem[];
    float* bias_s = (float*)(smem + SMEM_BIAS_OFF);
    const uint32_t sA0 = smem_u32(smem);
    const uint32_t sB0 = sA0 + SMEM_B_OFF;

    const int tid = threadIdx.x;
    const int lane = tid & 31;
    const int wid = tid >> 5;
    const int wm = (wid & 1) * 64;
    const int wn = (wid >> 1) * 32;
    const int z = blockIdx.z;
    const int za = z >> shA;
    const int zb = z & mskB;
    const int m0 = blockIdx.y * 128, n0 = blockIdx.x * 128;

    if (tid < 128) {
        if (BMODE == 0) bias_s[tid] = 0.f;
        else if (BMODE == 1) bias_s[tid] = bias[(long long)zb * sBias + n0 + tid];
        else bias_s[tid] = bias[(long long)za * sBias + m0 + tid];
    }

    float acc[4][4][4];
#pragma unroll
    for (int i = 0; i < 4; i++)
#pragma unroll
        for (int j = 0; j < 4; j++)
#pragma unroll
            for (int k = 0; k < 4; k++) acc[i][j][k] = 0.f;

    const int cpp = K / BKg;
    const int total = npass * cpp;

    const int crow = tid >> 3;
    const int ccol = (tid & 7) * 8;

    auto loadStage = [&](int c, int stg) {
        int p = c / cpp;
        int k0 = (c - p * cpp) * BKg;
        const hlf* Ab = P.A[p] + (long long)za * sA + k0 + ccol;
        const hlf* Bb = P.B[p] + (long long)zb * sB + k0 + ccol;
        uint32_t da = sA0 + stg * TILE_B + (crow * LDSg + ccol) * 2;
        uint32_t db = sB0 + stg * TILE_B + (crow * LDSg + ccol) * 2;
#pragma unroll
        for (int i = 0; i < 4; i++) {
            int row = crow + i * 32;
            CP_ASYNC16(da + i * 32 * LDSg * 2, Ab + (long long)(m0 + row) * lda);
            CP_ASYNC16(db + i * 32 * LDSg * 2, Bb + (long long)(n0 + row) * ldb);
        }
    };

    loadStage(0, 0); CP_COMMIT();
    loadStage(1, 1); CP_COMMIT();

    const int lrow16 = lane & 15;
    const int lhalf = lane >> 4;

    for (int c = 0; c < total; c++) {
        CP_WAIT1();
        __syncthreads();
        const int stg = c % STAGES;
        const uint32_t aB = sA0 + stg * TILE_B;
        const uint32_t bB = sB0 + stg * TILE_B;
#pragma unroll
        for (int ks = 0; ks < 4; ks++) {
            uint32_t af[4][4];
#pragma unroll
            for (int mi = 0; mi < 4; mi++) {
                uint32_t addr = aB + (uint32_t)(((wm + mi * 16 + lrow16) * LDSg
                                                + ks * 16 + lhalf * 8) * 2);
                LDSM_X4(af[mi][0], af[mi][1], af[mi][2], af[mi][3], addr);
            }
            uint32_t bfr[2][4];
#pragma unroll
            for (int nj = 0; nj < 2; nj++) {
                uint32_t addr = bB + (uint32_t)(((wn + nj * 16 + lrow16) * LDSg
                                                + ks * 16 + lhalf * 8) * 2);
                LDSM_X4(bfr[nj][0], bfr[nj][1], bfr[nj][2], bfr[nj][3], addr);
            }
#pragma unroll
            for (int mi = 0; mi < 4; mi++)
#pragma unroll
                for (int ni = 0; ni < 4; ni++) {
                    const int nj = ni >> 1, sub = ni & 1;
                    MMA_F16(acc[mi][ni], af[mi], bfr[nj][sub], bfr[nj][sub + 2]);
                }
        }
        if (c + 2 < total) loadStage(c + 2, (c + 2) % STAGES);
        CP_COMMIT();
    }

    const int cr = lane >> 2;
    const int cc = (lane & 3) * 2;
#pragma unroll
    for (int mi = 0; mi < 4; mi++) {
#pragma unroll
        for (int ni = 0; ni < 4; ni++) {
            const int bn = wn + ni * 8 + cc;
            const int gn = n0 + bn;
            const int rm = wm + mi * 16 + cr;
            const long long r0 = m0 + rm;
            const long long r1 = r0 + 8;
            float v0 = acc[mi][ni][0], v1 = acc[mi][ni][1];
            float v2 = acc[mi][ni][2], v3 = acc[mi][ni][3];
            if (BMODE == 1) {
                v0 += bias_s[bn]; v1 += bias_s[bn + 1];
                v2 += bias_s[bn]; v3 += bias_s[bn + 1];
            } else if (BMODE == 2) {
                v0 += bias_s[rm]; v1 += bias_s[rm];
                v2 += bias_s[rm + 8]; v3 += bias_s[rm + 8];
            }
            if (ACT == 1) { v0 = selu_f(v0); v1 = selu_f(v1); v2 = selu_f(v2); v3 = selu_f(v3); }
            if (SPLIT == 2) {
                *(uint32_t*)(Chi + (long long)z * sC + r0 * ldc + gn) = packf2(v0, v1);
                *(uint32_t*)(Chi + (long long)z * sC + r1 * ldc + gn) = packf2(v2, v3);
            } else {
                *(float2*)(C + (long long)z * sC + r0 * ldc + gn) = make_float2(v0, v1);
                *(float2*)(C + (long long)z * sC + r1 * ldc + gn) = make_float2(v2, v3);
            }
        }
    }
}

// ---------------------------------------------------------------------------
// Elementwise kernels
// ---------------------------------------------------------------------------
// Folded DFT matrices: [cos;sin], each [FR, KF], cols > 1024 zero-padded.
__global__ void init_dft_fold(hlf* __restrict__ o)
{
    long long idx = (long long)blockIdx.x * blockDim.x + threadIdx.x;
    if (idx >= 2LL * FR * KF) return;
    int half = (int)(idx / ((long long)FR * KF));
    int rem = (int)(idx % ((long long)FR * KF));
    int i = rem / KF, j = rem % KF;
    float v = 0.f;
    if (j <= 1024) {
        int p = (int)(((long long)i * j) % Sm);
        float x = 2.0f * (float)p / (float)Sm;
        float s, c;
        sincospif(x, &s, &c);
        v = half ? s : c;
    }
    o[idx] = __float2half_rn(v);
}

__global__ void init_bd(hlf* __restrict__ h)
{
    long long idx = (long long)blockIdx.x * blockDim.x + threadIdx.x;
    if (idx >= (long long)TN * Dm) return;
    int n = (int)(idx / Dm), k = (int)(idx % Dm);
    int i = (n < FC) ? n : (n - FC);
    int p = (int)(((long long)i * k) % Dm);
    float x = 2.0f * (float)p / (float)Dm;
    float s, c;
    sincospif(x, &s, &c);
    h[idx] = __float2half_rn((n < FC) ? c : s);
}

// Fold t12T over s: out[(half*4+b)][rr, j] = t[j] +/- t[2048-j] (j<=1024; pad 0).
__global__ void fold_t12(const hlf* __restrict__ in, hlf* __restrict__ out)
{
    long long idx = (long long)blockIdx.x * blockDim.x + threadIdx.x;
    const long long TOT = 8LL * 384 * KF;
    if (idx >= TOT) return;
    int j = (int)(idx % KF);
    int rr = (int)((idx / KF) % 384);
    int z = (int)(idx / ((long long)384 * KF));
    int half = z >> 2, b = z & 3;
    float v = 0.f;
    if (j <= 1024) {
        const hlf* row = in + (long long)b * TN * Sm + (long long)(half * 384 + rr) * Sm;
        float a = __half2float(row[j]);
        if (j == 0 || j == 1024) {
            v = a;
        } else {
            float c = __half2float(row[Sm - j]);
            v = half ? (a - c) : (a + c);
        }
    }
    out[idx] = __float2half_rn(v);
}

// fp32 -> fp16 (hi; optional lo), 8 elems/thread
__global__ void split_k8(const float* __restrict__ in, hlf* __restrict__ h,
                         hlf* __restrict__ l, long long n8)
{
    long long i = (long long)blockIdx.x * blockDim.x + threadIdx.x;
    if (i >= n8) return;
    long long base = i * 8;
    float4 a = *(const float4*)(in + base);
    float4 b = *(const float4*)(in + base + 4);
    hlf hh[8], ll[8];
    split2(a.x, hh[0], ll[0]); split2(a.y, hh[1], ll[1]);
    split2(a.z, hh[2], ll[2]); split2(a.w, hh[3], ll[3]);
    split2(b.x, hh[4], ll[4]); split2(b.y, hh[5], ll[5]);
    split2(b.z, hh[6], ll[6]); split2(b.w, hh[7], ll[7]);
    uint4 ho;
    ho.x = packhl(hh[0], hh[1]); ho.y = packhl(hh[2], hh[3]);
    ho.z = packhl(hh[4], hh[5]); ho.w = packhl(hh[6], hh[7]);
    *(uint4*)(h + base) = ho;
    if (l) {
        uint4 lo;
        lo.x = packhl(ll[0], ll[1]); lo.y = packhl(ll[2], ll[3]);
        lo.z = packhl(ll[4], ll[5]); lo.w = packhl(ll[6], ll[7]);
        *(uint4*)(l + base) = lo;
    }
}

// [R,C] fp32 -> [C,R] fp16 (hi only), batched.
__global__ void split_trans(const float* __restrict__ in, hlf* __restrict__ oh,
                            int R, int C, long long sIn, long long sOut)
{
    __shared__ float t[32][33];
    const int z = blockIdx.z;
    const float* ib = in + (long long)z * sIn;
    const int c0 = blockIdx.x * 32, r0 = blockIdx.y * 32;
    const int tx = threadIdx.x, ty = threadIdx.y;
#pragma unroll
    for (int i = 0; i < 4; i++)
        t[ty + i * 8][tx] = ib[(long long)(r0 + ty + i * 8) * C + c0 + tx];
    __syncthreads();
#pragma unroll
    for (int i = 0; i < 4; i++) {
        float v = t[tx][ty + i * 8];
        long long o = (long long)z * sOut + (long long)(c0 + ty + i * 8) * R + r0 + tx;
        oh[o] = __float2half_rn(v);
    }
}

__global__ void wo_split_trans(const float* __restrict__ Wo, hlf* __restrict__ oh)
{
    __shared__ float t[32][33];
    const int h = blockIdx.z;
    const int n0 = blockIdx.x * 32, d0 = blockIdx.y * 32;
    const int tx = threadIdx.x, ty = threadIdx.y;
#pragma unroll
    for (int i = 0; i < 4; i++) {
        int d = d0 + ty + i * 8;
        t[ty + i * 8][tx] = Wo[(long long)(d * 4 + h) * Dm + n0 + tx];
    }
    __syncthreads();
#pragma unroll
    for (int i = 0; i < 4; i++) {
        float v = t[tx][ty + i * 8];
        long long o = (long long)h * DD + (long long)(n0 + ty + i * 8) * Dm + d0 + tx;
        oh[o] = __float2half_rn(v);
    }
}

__global__ void concat_bias(const float* __restrict__ a, const float* __restrict__ b,
                            float* __restrict__ o)
{
    int i = blockIdx.x * blockDim.x + threadIdx.x;
    if (i < 2048) o[i] = a[i];
    else if (i < 4096) o[i] = b[i - 2048];
}

__global__ void fft_merge(const float* __restrict__ cp, const float* __restrict__ sp,
                          float* __restrict__ xf)
{
    const int b = blockIdx.y;
    long long idx = (long long)blockIdx.x * blockDim.x + threadIdx.x;
    const long long TOT = 1025LL * 257LL;
    if (idx >= TOT) return;
    int i = (int)(idx / 257);
    int d = (int)(idx % 257);
    long long src = (long long)b * FR * FC + (long long)i * FC + d;
    float c = cp[src], s = sp[src];
    float a = c - s, bb = c + s;
    int i2 = (Sm - i) & (Sm - 1);
    int d2 = (Dm - d) & (Dm - 1);
    float* x = xf + (long long)b * SD;
    x[(long long)i * Dm + d] = a;
    x[(long long)i2 * Dm + d] = bb;
    x[(long long)i * Dm + d2] = bb;
    x[(long long)i2 * Dm + d2] = a;
}

// softmax over H=4 heads (stride BSD), fp16 in/out; 4 elems/thread
__global__ void softmax_h4(const hlf* __restrict__ q, hlf* __restrict__ oh)
{
    long long i4 = (long long)blockIdx.x * blockDim.x + threadIdx.x;
    if (i4 >= BSD / 4) return;
    long long base = i4 * 4;
    float v[4][4];
#pragma unroll
    for (int h = 0; h < 4; h++) {
        uint2 raw = *(const uint2*)(q + h * BSD + base);
        hlf* hp = (hlf*)&raw;
#pragma unroll
        for (int j = 0; j < 4; j++) v[h][j] = __half2float(hp[j]);
    }
    float r[4][4];
#pragma unroll
    for (int j = 0; j < 4; j++) {
        float m = fmaxf(fmaxf(v[0][j], v[1][j]), fmaxf(v[2][j], v[3][j]));
        float e0 = expf(v[0][j] - m), e1 = expf(v[1][j] - m);
        float e2 = expf(v[2][j] - m), e3 = expf(v[3][j] - m);
        float inv = 1.f / (e0 + e1 + e2 + e3);
        r[0][j] = e0 * inv; r[1][j] = e1 * inv; r[2][j] = e2 * inv; r[3][j] = e3 * inv;
    }
#pragma unroll
    for (int h = 0; h < 4; h++) {
        uint2 ho = make_uint2(packf2(r[h][0], r[h][1]), packf2(r[h][2], r[h][3]));
        *(uint2*)(oh + h * BSD + base) = ho;
    }
}

// softmax over heads + transpose: ks[h][b][s,d] fp16 -> ksT[z=h*B+b][d,s] fp16.
__global__ void softmax_trans(const hlf* __restrict__ ks, hlf* __restrict__ oh)
{
    __shared__ float t[4][32][33];
    const int b = blockIdx.z;
    const int s0 = blockIdx.x * 32, d0 = blockIdx.y * 32;
    const int tx = threadIdx.x, ty = threadIdx.y;
#pragma unroll
    for (int h = 0; h < 4; h++)
#pragma unroll
        for (int i = 0; i < 4; i++)
            t[h][ty + i * 8][tx] = __half2float(
                ks[((long long)(h * Bm + b) * Sm + s0 + ty + i * 8) * Dm + d0 + tx]);
    __syncthreads();
#pragma unroll
    for (int i = 0; i < 4; i++) {
        float v0 = t[0][ty + i * 8][tx], v1 = t[1][ty + i * 8][tx];
        float v2 = t[2][ty + i * 8][tx], v3 = t[3][ty + i * 8][tx];
        float m = fmaxf(fmaxf(v0, v1), fmaxf(v2, v3));
        float e0 = expf(v0 - m), e1 = expf(v1 - m), e2 = expf(v2 - m), e3 = expf(v3 - m);
        float r = 1.f / (e0 + e1 + e2 + e3);
        t[0][ty + i * 8][tx] = e0 * r; t[1][ty + i * 8][tx] = e1 * r;
        t[2][ty + i * 8][tx] = e2 * r; t[3][ty + i * 8][tx] = e3 * r;
    }
    __syncthreads();
#pragma unroll
    for (int h = 0; h < 4; h++)
#pragma unroll
        for (int i = 0; i < 4; i++) {
            float v = t[h][tx][ty + i * 8];
            long long o = (long long)(h * Bm + b) * SD + (long long)(d0 + ty + i * 8) * Sm + s0 + tx;
            oh[o] = __float2half_rn(v);
        }
}

// LN over last dim (D=512) of (a+b); optional fp16 out (hi only).
__global__ void ln_split(const float* __restrict__ a, const float* __restrict__ bres,
                         const float* __restrict__ g, const float* __restrict__ be,
                         float* __restrict__ out, hlf* __restrict__ oh)
{
    __shared__ float red[4];
    long long row = blockIdx.x;
    int t = threadIdx.x;  // 128
    float4 va = ((const float4*)(a + row * Dm))[t];
    float4 vb = ((const float4*)(bres + row * Dm))[t];
    float4 v = make_float4(va.x + vb.x, va.y + vb.y, va.z + vb.z, va.w + vb.w);
    float s = v.x + v.y + v.z + v.w;
#pragma unroll
    for (int o = 16; o > 0; o >>= 1) s += __shfl_xor_sync(0xffffffffu, s, o);
    if ((t & 31) == 0) red[t >> 5] = s;
    __syncthreads();
    float mu = (red[0] + red[1] + red[2] + red[3]) * (1.f / (float)Dm);
    __syncthreads();
    float d0 = v.x - mu, d1 = v.y - mu, d2 = v.z - mu, d3 = v.w - mu;
    float q = d0 * d0 + d1 * d1 + d2 * d2 + d3 * d3;
#pragma unroll
    for (int o = 16; o > 0; o >>= 1) q += __shfl_xor_sync(0xffffffffu, q, o);
    if ((t & 31) == 0) red[t >> 5] = q;
    __syncthreads();
    float var = (red[0] + red[1] + red[2] + red[3]) * (1.f / (float)Dm);
    float rstd = rsqrtf(var + 1e-5f);
    float4 vg = ((const float4*)g)[t];
    float4 vbe = ((const float4*)be)[t];
    float4 o4;
    o4.x = fmaf(vg.x, d0 * rstd, vbe.x);
    o4.y = fmaf(vg.y, d1 * rstd, vbe.y);
    o4.z = fmaf(vg.z, d2 * rstd, vbe.z);
    o4.w = fmaf(vg.w, d3 * rstd, vbe.w);
    ((float4*)(out + row * Dm))[t] = o4;
    if (oh) {
        long long o = row * Dm + t * 4;
        *(uint2*)(oh + o) = make_uint2(packf2(o4.x, o4.y), packf2(o4.z, o4.w));
    }
}

// ---------------------------------------------------------------------------
// Host
// ---------------------------------------------------------------------------
static TcPasses mk1(const hlf* Ah, const hlf* Bh) {
    TcPasses P{};
    P.A[0] = Ah; P.B[0] = Bh;
    return P;
}

static void tcg(const TcPasses& P, int np, float* C, hlf* Ch,
                int M, int N, int K, int lda, int ldb, int ldc,
                long long sA, long long sB, long long sC, int batch,
                const float* bias, long long sBias, int act, int split, int bmode,
                int shA = 0, int mskB = 0x7FFFFFFF)
{
    dim3 grid(N / 128, M / 128, batch), block(256);
    if (act == 1)
        mma_gemm<1, 2, 1><<<grid, block, SMEM_G>>>(P, np, C, Ch, K, lda, ldb, ldc, sA, sB, sC, bias, sBias, shA, mskB);
    else if (split == 2 && bmode == 2)
        mma_gemm<0, 2, 2><<<grid, block, SMEM_G>>>(P, np, C, Ch, K, lda, ldb, ldc, sA, sB, sC, bias, sBias, shA, mskB);
    else if (split == 2 && bmode == 1)
        mma_gemm<0, 2, 1><<<grid, block, SMEM_G>>>(P, np, C, Ch, K, lda, ldb, ldc, sA, sB, sC, bias, sBias, shA, mskB);
    else if (split == 2)
        mma_gemm<0, 2, 0><<<grid, block, SMEM_G>>>(P, np, C, Ch, K, lda, ldb, ldc, sA, sB, sC, bias, sBias, shA, mskB);
    else if (bmode == 1)
        mma_gemm<0, 0, 1><<<grid, block, SMEM_G>>>(P, np, C, Ch, K, lda, ldb, ldc, sA, sB, sC, bias, sBias, shA, mskB);
    else
        mma_gemm<0, 0, 0><<<grid, block, SMEM_G>>>(P, np, C, Ch, K, lda, ldb, ldc, sA, sB, sC, bias, sBias, shA, mskB);
}

#define GETSYM(var, sym) do { void* _p; cudaGetSymbolAddress(&_p, sym); var = (decltype(var))_p; } while (0)

extern "C" void kernel_launch(void* const* d_in, const int* in_sizes, int n_in,
                              void* d_out, int out_size)
{
    const float* x_enc = (const float*)d_in[0];
    const float* x_dec = (const float*)d_in[1];
    const float* Wq = (const float*)d_in[2];
    const float* bq = (const float*)d_in[3];
    const float* Wk = (const float*)d_in[4];
    const float* bk = (const float*)d_in[5];
    const float* Wv = (const float*)d_in[6];
    const float* bv = (const float*)d_in[7];
    const float* Wo = (const float*)d_in[8];
    const float* bo = (const float*)d_in[9];
    const float* ln1g = (const float*)d_in[10];
    const float* ln1b = (const float*)d_in[11];
    const float* ln2g = (const float*)d_in[12];
    const float* ln2b = (const float*)d_in[13];
    const float* W1 = (const float*)d_in[14];
    const float* b1 = (const float*)d_in[15];
    const float* W2 = (const float*)d_in[16];
    const float* b2 = (const float*)d_in[17];
    const float* ln3g = (const float*)d_in[18];
    const float* ln3b = (const float*)d_in[19];
    float* outp = (float*)d_out;

    hlf *CSf, *BDh, *xdh, *t12Th, *t12Tf, *xqkh, *qkh;
    hlf *qsh, *ksTh, *vsTh, *gcTh, *oth;
    hlf *WqkTh, *WvTh, *WoTh, *W1Th, *W2Th, *x2h, *midh;
    float *cps, *xf, *xd, *bqk, *attn, *x2, *ff;
    GETSYM(CSf, g_CSf); GETSYM(BDh, g_BDh);
    GETSYM(xdh, g_xdh);
    GETSYM(t12Th, g_t12Th); GETSYM(t12Tf, g_t12Tf);
    GETSYM(cps, g_cps);
    GETSYM(xf, g_xf); GETSYM(xd, g_xd);
    GETSYM(xqkh, g_xqkh); GETSYM(qkh, g_qkh);
    GETSYM(bqk, g_bqk);
    GETSYM(qsh, g_qsh); GETSYM(ksTh, g_ksTh); GETSYM(vsTh, g_vsTh);
    GETSYM(gcTh, g_gcTh); GETSYM(oth, g_oth);
    GETSYM(WqkTh, g_WqkTh); GETSYM(WvTh, g_WvTh); GETSYM(WoTh, g_WoTh);
    GETSYM(W1Th, g_W1Th); GETSYM(W2Th, g_W2Th);
    GETSYM(attn, g_attn); GETSYM(x2, g_x2); GETSYM(x2h, g_x2h);
    GETSYM(midh, g_midh); GETSYM(ff, g_ff);

    cudaFuncSetAttribute(mma_gemm<0, 0, 0>, cudaFuncAttributeMaxDynamicSharedMemorySize, SMEM_G);
    cudaFuncSetAttribute(mma_gemm<0, 0, 1>, cudaFuncAttributeMaxDynamicSharedMemorySize, SMEM_G);
    cudaFuncSetAttribute(mma_gemm<0, 2, 0>, cudaFuncAttributeMaxDynamicSharedMemorySize, SMEM_G);
    cudaFuncSetAttribute(mma_gemm<0, 2, 1>, cudaFuncAttributeMaxDynamicSharedMemorySize, SMEM_G);
    cudaFuncSetAttribute(mma_gemm<0, 2, 2>, cudaFuncAttributeMaxDynamicSharedMemorySize, SMEM_G);
    cudaFuncSetAttribute(mma_gemm<1, 2, 1>, cudaFuncAttributeMaxDynamicSharedMemorySize, SMEM_G);

    dim3 tb(32, 8);

    // 0) folded DFT matrices + BD (fp16)
    init_dft_fold<<<(int)((2LL * FR * KF + 255) / 256), 256>>>(CSf);
    init_bd<<<(TN * Dm + 255) / 256, 256>>>(BDh);

    // inputs: both fp16 hi only
    split_k8<<<(int)(BSD / 8 / 256), 256>>>(x_dec, xdh, nullptr, BSD / 8);
    split_k8<<<(int)(BSD / 8 / 256), 256>>>(x_enc, xqkh + BSD, nullptr, BSD / 8);

    // 1) t12T[b] = BD @ x_dec[b]^T  (M=768, N=2048, K=512, z=4), 1-pass, fp16 out
    tcg(mk1(BDh, xdh), 1, nullptr, t12Th,
        TN, Sm, Dm, Dm, Dm, Sm, 0, SD, (long long)TN * Sm, Bm,
        nullptr, 0, 0, 2, 0, /*shA=*/30, /*mskB=*/0x7FFFFFFF);

    // 1b) fold over s: t12Tf[half*4+b][384, KF]
    fold_t12<<<(int)((8LL * 384 * KF + 255) / 256), 256>>>(t12Th, t12Tf);

    // 2) merged cp/sp: cps[z] = CSf[z>>2] @ t12Tf[z]^T  (M=1152,N=384,K=1088,z=8)
    tcg(mk1(CSf, t12Tf), 1, cps, nullptr,
        FR, FC, KF, KF, KF, FC, (long long)FR * KF, 384LL * KF, (long long)FR * FC, 8,
        nullptr, 0, 0, 0, 0, /*shA=*/2, /*mskB=*/7);

    fft_merge<<<dim3((1025 * 257 + 255) / 256, Bm), 256>>>(cps, cps + 4LL * FR * FC, xf);

    // 3) xd = LN1(x_dec + xf), fp16 into first half of stacked qk-A buffer
    ln_split<<<BSm, 128>>>(x_dec, xf, ln1g, ln1b, xd, xqkh);

    // 4) weight transposes (fp16 hi only)
    split_trans<<<dim3(16, 16, Hn), tb>>>(Wq, WqkTh, Dm, Dm, DD, DD);
    split_trans<<<dim3(16, 16, Hn), tb>>>(Wk, WqkTh + 4 * DD, Dm, Dm, DD, DD);
    concat_bias<<<16, 256>>>(bq, bk, bqk);
    split_trans<<<dim3(16, 16, Hn), tb>>>(Wv, WvTh, Dm, Dm, DD, DD);
    wo_split_trans<<<dim3(16, 16, Hn), tb>>>(Wo, WoTh);
    split_trans<<<dim3(MIDm / 32, Dm / 32, 1), tb>>>(W1, W1Th, Dm, MIDm, 0, 0);
    split_trans<<<dim3(Dm / 32, MIDm / 32, 1), tb>>>(W2, W2Th, MIDm, Dm, 0, 0);

    // 5) merged q/k projections: z=8, 1-pass, fp16 logits out
    tcg(mk1(xqkh, WqkTh), 1, nullptr, qkh,
        BSm, Dm, Dm, Dm, Dm, Dm, BSD, DD, BSD, 8, bqk, Dm, 0, 2, 1,
        /*shA=*/2, /*mskB=*/7);

    // 6) vsT[z=h*4+b] = WvT_h @ x_enc[b]^T + bv_h, fp16 out, 1-pass; z=16
    tcg(mk1(WvTh, xqkh + BSD), 1, nullptr, vsTh,
        Dm, Sm, Dm, Dm, Dm, Sm, DD, SD, SD, 16, bv, Dm, 0, 2, 2,
        /*shA=*/2, /*mskB=*/3);

    // 7) softmax over heads: q, k (+transpose), fp16 in/out
    softmax_h4<<<(int)(BSD / 4 / 256), 256>>>(qkh, qsh);
    softmax_trans<<<dim3(Sm / 32, Dm / 32, Bm), tb>>>(qkh + 4 * BSD, ksTh);

    // 8) gcT[z] = vsT @ ksT^T  (M=N=512, K=2048, z=16) -- 1-pass, fp16 out
    tcg(mk1(vsTh, ksTh), 1, nullptr, gcTh,
        Dm, Dm, Sm, Sm, Sm, Dm, SD, SD, DD, 16, nullptr, 0, 0, 2, 0);

    // 9) out[z] = qs @ gcT^T  (M=2048,N=512,K=512,z=16) -- 1-pass, fp16 out
    tcg(mk1(qsh, gcTh), 1, nullptr, oth,
        Sm, Dm, Dm, Dm, Dm, Dm, SD, DD, SD, 16, nullptr, 0, 0, 2, 0);

    // 10) attn[b] = sum_h out_h[b] @ WoT_h^T + bo  (4 passes; z=4)
    {
        TcPasses P{};
        for (int h = 0; h < Hn; h++) {
            P.A[h] = oth + (long long)h * Bm * SD;
            P.B[h] = WoTh + (long long)h * DD;
        }
        tcg(P, 4, attn, nullptr,
            Sm, Dm, Dm, Dm, Dm, Dm, SD, 0, SD, Bm, bo, 0, 0, 0, 1);
    }

    // 11) x2 = LN2(xd + attn), fp16 out
    ln_split<<<BSm, 128>>>(xd, attn, ln2g, ln2b, x2, x2h);

    // 12) mid = selu(x2 @ W1 + b1), fp16 out, 1-pass
    tcg(mk1(x2h, W1Th), 1, nullptr, midh,
        BSm, MIDm, Dm, Dm, Dm, MIDm, 0, 0, 0, 1, b1, 0, 1, 2, 1);

    // 13) ff = mid @ W2 + b2, 1-pass
    tcg(mk1(midh, W2Th), 1, ff, nullptr,
        BSm, Dm, MIDm, MIDm, MIDm, Dm, 0, 0, 0, 1, b2, 0, 0, 0, 1);

    // 14) out = LN3(x2 + ff)
    ln_split<<<BSm, 128>>>(x2, ff, ln3g, ln3b, outp, nullptr);
}

// round 12
// speedup vs baseline: 2.4037x; 1.0723x over previous
#include <cuda_runtime.h>
#include <cuda_fp16.h>
#include <math.h>
#include <stdint.h>

typedef __half hlf;

static constexpr int Dm = 512, Hn = 4, MIDm = 2048, Bm = 4, Sm = 2048;
static constexpr int BSm = Bm * Sm;                      // 8192
static constexpr long long BSD = (long long)BSm * Dm;    // 4194304
static constexpr long long SD  = (long long)Sm * Dm;     // 1048576
static constexpr long long DD  = (long long)Dm * Dm;     // 262144

// FFT-symmetry tile sizes
static constexpr int FR = 1152;   // rows computed (need 0..1024)
static constexpr int FC = 384;    // cols computed (need 0..256)
static constexpr int TN = 768;    // t12 width: 384 cos + 384 sin
static constexpr int KF = 1088;   // folded K for cp/sp (1025 padded to /64)

// ---------------------------------------------------------------------------
// Static device scratch
// ---------------------------------------------------------------------------
__device__ __align__(256) hlf g_CSf[2 * FR * KF];                  // [cos;sin] folded
__device__ __align__(256) hlf g_BDh[TN * Dm];
__device__ __align__(256) hlf g_xdh[4194304];
__device__ __align__(256) hlf g_t12Th[4 * TN * Sm];                // [b][768,2048]
__device__ __align__(256) hlf g_t12Tf[8 * 384 * KF];               // [half*4+b][384,1088]
__device__ __align__(256) float g_cps[8 * FR * FC];                // cp z=0..3, sp z=4..7
__device__ __align__(256) float g_xf[4194304];
__device__ __align__(256) float g_xd[4194304];
// stacked A for merged q/k proj: [0..BSD)=LN1(xd) fp16, [BSD..2BSD)=x_enc fp16
__device__ __align__(256) hlf g_xqkh[8388608];
__device__ __align__(256) hlf g_qkh[33554432];                     // [8][b,s,d] fp16 logits
__device__ __align__(256) hlf g_qsh[16777216];
__device__ __align__(256) hlf g_ksTh[16777216];                    // [z][D,S]
__device__ __align__(256) hlf g_vsTh[16777216];                    // [z][E,S]
__device__ __align__(256) hlf g_gcDE[4194304];                     // [z][D,E] (d,e)
__device__ __align__(256) hlf g_Mth[4194304];                      // [z][N,D] = WoT_h @ gc^T
__device__ __align__(256) hlf g_WqkTh[2097152];                    // [Wq0..3;Wk0..3]
__device__ __align__(256) float g_bqk[4096];                       // [bq;bk]
__device__ __align__(256) hlf g_WvTh[1048576];
__device__ __align__(256) hlf g_WoTh[1048576];                     // [h][512,512] (n,e)
__device__ __align__(256) hlf g_W1Th[1048576];                     // [2048,512]
__device__ __align__(256) hlf g_W2Th[1048576];                     // [512,2048]
__device__ __align__(256) float g_attn[4194304];
__device__ __align__(256) float g_x2[4194304];
__device__ __align__(256) hlf g_x2h[4194304];
__device__ __align__(256) hlf g_midh[16777216];
__device__ __align__(256) float g_ff[4194304];

// ---------------------------------------------------------------------------
// Helpers
// ---------------------------------------------------------------------------
__device__ __forceinline__ uint32_t smem_u32(const void* p) {
    uint32_t a;
    asm("{ .reg .u64 t; cvta.to.shared.u64 t, %1; cvt.u32.u64 %0, t; }" : "=r"(a) : "l"(p));
    return a;
}
__device__ __forceinline__ float selu_f(float x) {
    const float sc = 1.0507009873554805f, al = 1.6732632423543772f;
    return x > 0.f ? sc * x : sc * al * (expf(x) - 1.f);
}
__device__ __forceinline__ uint32_t packhl(hlf a, hlf b) {
    return ((uint32_t)*(uint16_t*)&b << 16) | (uint32_t)*(uint16_t*)&a;
}
__device__ __forceinline__ uint32_t packf2(float a, float b) {
    hlf ha = __float2half_rn(a), hb = __float2half_rn(b);
    return packhl(ha, hb);
}

#define LDSM_X4(r0, r1, r2, r3, addr) \
    asm volatile("ldmatrix.sync.aligned.m8n8.x4.shared.b16 {%0,%1,%2,%3}, [%4];" \
        : "=r"(r0), "=r"(r1), "=r"(r2), "=r"(r3) : "r"(addr))

#define MMA_F16(d, a, b0, b1) \
    asm volatile("mma.sync.aligned.m16n8k16.row.col.f32.f16.f16.f32 " \
        "{%0,%1,%2,%3}, {%4,%5,%6,%7}, {%8,%9}, {%0,%1,%2,%3};" \
        : "+f"((d)[0]), "+f"((d)[1]), "+f"((d)[2]), "+f"((d)[3]) \
        : "r"((a)[0]), "r"((a)[1]), "r"((a)[2]), "r"((a)[3]), "r"(b0), "r"(b1))

#define CP_ASYNC16(dst, src) \
    asm volatile("cp.async.cg.shared.global [%0], [%1], 16;" :: "r"(dst), "l"(src))
#define CP_COMMIT() asm volatile("cp.async.commit_group;")
#define CP_WAIT1()  asm volatile("cp.async.wait_group 1;")

// ---------------------------------------------------------------------------
// HMMA GEMM, cp.async 3-stage pipeline, multi-pass accumulation.
// Block 128x128, 8 warps, warp 64x32, BK=64, 2 CTA/SM.
// C[z] = sum_p A_p[z>>shA] @ B_p[z&mskB]^T (+bias col[zb]/row[za])(+SELU)
// SPLIT: 0 = fp32 out, 2 = fp16 out.
// ---------------------------------------------------------------------------
struct TcPasses { const hlf* A[4]; const hlf* B[4]; };

static constexpr int BKg = 64;
static constexpr int LDSg = BKg + 8;
static constexpr int TILE_B = 128 * LDSg * 2;
static constexpr int STAGES = 3;
static constexpr int SMEM_B_OFF = STAGES * TILE_B;
static constexpr int SMEM_BIAS_OFF = 2 * STAGES * TILE_B;
static constexpr int SMEM_G = SMEM_BIAS_OFF + 128 * 4;

template <int ACT, int SPLIT, int BMODE>   // BMODE: 0 none, 1 col (zb), 2 row (za)
__global__ __launch_bounds__(256, 2) void mma_gemm(
    TcPasses P, int npass,
    float* __restrict__ C, hlf* __restrict__ Chi,
    int K, int lda, int ldb, int ldc,
    long long sA, long long sB, long long sC,
    const float* __restrict__ bias, long long sBias,
    int shA, int mskB)
{
    extern __shared__ char smem[];
    float* bias_s = (float*)(smem + SMEM_BIAS_OFF);
    const uint32_t sA0 = smem_u32(smem);
    const uint32_t sB0 = sA0 + SMEM_B_OFF;

    const int tid = threadIdx.x;
    const int lane = tid & 31;
    const int wid = tid >> 5;
    const int wm = (wid & 1) * 64;
    const int wn = (wid >> 1) * 32;
    const int z = blockIdx.z;
    const int za = z >> shA;
    const int zb = z & mskB;
    const int m0 = blockIdx.y * 128, n0 = blockIdx.x * 128;

    if (tid < 128) {
        if (BMODE == 0) bias_s[tid] = 0.f;
        else if (BMODE == 1) bias_s[tid] = bias[(long long)zb * sBias + n0 + tid];
        else bias_s[tid] = bias[(long long)za * sBias + m0 + tid];
    }

    float acc[4][4][4];
#pragma unroll
    for (int i = 0; i < 4; i++)
#pragma unroll
        for (int j = 0; j < 4; j++)
#pragma unroll
            for (int k = 0; k < 4; k++) acc[i][j][k] = 0.f;

    const int cpp = K / BKg;
    const int total = npass * cpp;

    const int crow = tid >> 3;
    const int ccol = (tid & 7) * 8;

    auto loadStage = [&](int c, int stg) {
        int p = c / cpp;
        int k0 = (c - p * cpp) * BKg;
        const hlf* Ab = P.A[p] + (long long)za * sA + k0 + ccol;
        const hlf* Bb = P.B[p] + (long long)zb * sB + k0 + ccol;
        uint32_t da = sA0 + stg * TILE_B + (crow * LDSg + ccol) * 2;
        uint32_t db = sB0 + stg * TILE_B + (crow * LDSg + ccol) * 2;
#pragma unroll
        for (int i = 0; i < 4; i++) {
            int row = crow + i * 32;
            CP_ASYNC16(da + i * 32 * LDSg * 2, Ab + (long long)(m0 + row) * lda);
            CP_ASYNC16(db + i * 32 * LDSg * 2, Bb + (long long)(n0 + row) * ldb);
        }
    };

    loadStage(0, 0); CP_COMMIT();
    loadStage(1, 1); CP_COMMIT();

    const int lrow16 = lane & 15;
    const int lhalf = lane >> 4;

    for (int c = 0; c < total; c++) {
        CP_WAIT1();
        __syncthreads();
        const int stg = c % STAGES;
        const uint32_t aB = sA0 + stg * TILE_B;
        const uint32_t bB = sB0 + stg * TILE_B;
#pragma unroll
        for (int ks = 0; ks < 4; ks++) {
            uint32_t af[4][4];
#pragma unroll
            for (int mi = 0; mi < 4; mi++) {
                uint32_t addr = aB + (uint32_t)(((wm + mi * 16 + lrow16) * LDSg
                                                + ks * 16 + lhalf * 8) * 2);
                LDSM_X4(af[mi][0], af[mi][1], af[mi][2], af[mi][3], addr);
            }
            uint32_t bfr[2][4];
#pragma unroll
            for (int nj = 0; nj < 2; nj++) {
                uint32_t addr = bB + (uint32_t)(((wn + nj * 16 + lrow16) * LDSg
                                                + ks * 16 + lhalf * 8) * 2);
                LDSM_X4(bfr[nj][0], bfr[nj][1], bfr[nj][2], bfr[nj][3], addr);
            }
#pragma unroll
            for (int mi = 0; mi < 4; mi++)
#pragma unroll
                for (int ni = 0; ni < 4; ni++) {
                    const int nj = ni >> 1, sub = ni & 1;
                    MMA_F16(acc[mi][ni], af[mi], bfr[nj][sub], bfr[nj][sub + 2]);
                }
        }
        if (c + 2 < total) loadStage(c + 2, (c + 2) % STAGES);
        CP_COMMIT();
    }

    const int cr = lane >> 2;
    const int cc = (lane & 3) * 2;
#pragma unroll
    for (int mi = 0; mi < 4; mi++) {
#pragma unroll
        for (int ni = 0; ni < 4; ni++) {
            const int bn = wn + ni * 8 + cc;
            const int gn = n0 + bn;
            const int rm = wm + mi * 16 + cr;
            const long long r0 = m0 + rm;
            const long long r1 = r0 + 8;
            float v0 = acc[mi][ni][0], v1 = acc[mi][ni][1];
            float v2 = acc[mi][ni][2], v3 = acc[mi][ni][3];
            if (BMODE == 1) {
                v0 += bias_s[bn]; v1 += bias_s[bn + 1];
                v2 += bias_s[bn]; v3 += bias_s[bn + 1];
            } else if (BMODE == 2) {
                v0 += bias_s[rm]; v1 += bias_s[rm];
                v2 += bias_s[rm + 8]; v3 += bias_s[rm + 8];
            }
            if (ACT == 1) { v0 = selu_f(v0); v1 = selu_f(v1); v2 = selu_f(v2); v3 = selu_f(v3); }
            if (SPLIT == 2) {
                *(uint32_t*)(Chi + (long long)z * sC + r0 * ldc + gn) = packf2(v0, v1);
                *(uint32_t*)(Chi + (long long)z * sC + r1 * ldc + gn) = packf2(v2, v3);
            } else {
                *(float2*)(C + (long long)z * sC + r0 * ldc + gn) = make_float2(v0, v1);
                *(float2*)(C + (long long)z * sC + r1 * ldc + gn) = make_float2(v2, v3);
            }
        }
    }
}

// ---------------------------------------------------------------------------
// Elementwise kernels
// ---------------------------------------------------------------------------
// Folded DFT matrices: [cos;sin], each [FR, KF], cols > 1024 zero-padded.
__global__ void init_dft_fold(hlf* __restrict__ o)
{
    long long idx = (long long)blockIdx.x * blockDim.x + threadIdx.x;
    if (idx >= 2LL * FR * KF) return;
    int half = (int)(idx / ((long long)FR * KF));
    int rem = (int)(idx % ((long long)FR * KF));
    int i = rem / KF, j = rem % KF;
    float v = 0.f;
    if (j <= 1024) {
        int p = (int)(((long long)i * j) % Sm);
        float x = 2.0f * (float)p / (float)Sm;
        float s, c;
        sincospif(x, &s, &c);
        v = half ? s : c;
    }
    o[idx] = __float2half_rn(v);
}

__global__ void init_bd(hlf* __restrict__ h)
{
    long long idx = (long long)blockIdx.x * blockDim.x + threadIdx.x;
    if (idx >= (long long)TN * Dm) return;
    int n = (int)(idx / Dm), k = (int)(idx % Dm);
    int i = (n < FC) ? n : (n - FC);
    int p = (int)(((long long)i * k) % Dm);
    float x = 2.0f * (float)p / (float)Dm;
    float s, c;
    sincospif(x, &s, &c);
    h[idx] = __float2half_rn((n < FC) ? c : s);
}

// Fold t12T over s: out[(half*4+b)][rr, j] = t[j] +/- t[2048-j] (j<=1024; pad 0).
__global__ void fold_t12(const hlf* __restrict__ in, hlf* __restrict__ out)
{
    long long idx = (long long)blockIdx.x * blockDim.x + threadIdx.x;
    const long long TOT = 8LL * 384 * KF;
    if (idx >= TOT) return;
    int j = (int)(idx % KF);
    int rr = (int)((idx / KF) % 384);
    int z = (int)(idx / ((long long)384 * KF));
    int half = z >> 2, b = z & 3;
    float v = 0.f;
    if (j <= 1024) {
        const hlf* row = in + (long long)b * TN * Sm + (long long)(half * 384 + rr) * Sm;
        float a = __half2float(row[j]);
        if (j == 0 || j == 1024) {
            v = a;
        } else {
            float c = __half2float(row[Sm - j]);
            v = half ? (a - c) : (a + c);
        }
    }
    out[idx] = __float2half_rn(v);
}

// fp32 -> fp16 (hi only), 8 elems/thread
__global__ void split_k8(const float* __restrict__ in, hlf* __restrict__ h, long long n8)
{
    long long i = (long long)blockIdx.x * blockDim.x + threadIdx.x;
    if (i >= n8) return;
    long long base = i * 8;
    float4 a = *(const float4*)(in + base);
    float4 b = *(const float4*)(in + base + 4);
    uint4 ho;
    ho.x = packf2(a.x, a.y); ho.y = packf2(a.z, a.w);
    ho.z = packf2(b.x, b.y); ho.w = packf2(b.z, b.w);
    *(uint4*)(h + base) = ho;
}

// [R,C] fp32 -> [C,R] fp16 (hi only), batched.
__global__ void split_trans(const float* __restrict__ in, hlf* __restrict__ oh,
                            int R, int C, long long sIn, long long sOut)
{
    __shared__ float t[32][33];
    const int z = blockIdx.z;
    const float* ib = in + (long long)z * sIn;
    const int c0 = blockIdx.x * 32, r0 = blockIdx.y * 32;
    const int tx = threadIdx.x, ty = threadIdx.y;
#pragma unroll
    for (int i = 0; i < 4; i++)
        t[ty + i * 8][tx] = ib[(long long)(r0 + ty + i * 8) * C + c0 + tx];
    __syncthreads();
#pragma unroll
    for (int i = 0; i < 4; i++) {
        float v = t[tx][ty + i * 8];
        long long o = (long long)z * sOut + (long long)(c0 + ty + i * 8) * R + r0 + tx;
        oh[o] = __float2half_rn(v);
    }
}

__global__ void wo_split_trans(const float* __restrict__ Wo, hlf* __restrict__ oh)
{
    __shared__ float t[32][33];
    const int h = blockIdx.z;
    const int n0 = blockIdx.x * 32, d0 = blockIdx.y * 32;
    const int tx = threadIdx.x, ty = threadIdx.y;
#pragma unroll
    for (int i = 0; i < 4; i++) {
        int d = d0 + ty + i * 8;
        t[ty + i * 8][tx] = Wo[(long long)(d * 4 + h) * Dm + n0 + tx];
    }
    __syncthreads();
#pragma unroll
    for (int i = 0; i < 4; i++) {
        float v = t[tx][ty + i * 8];
        long long o = (long long)h * DD + (long long)(n0 + ty + i * 8) * Dm + d0 + tx;
        oh[o] = __float2half_rn(v);
    }
}

__global__ void concat_bias(const float* __restrict__ a, const float* __restrict__ b,
                            float* __restrict__ o)
{
    int i = blockIdx.x * blockDim.x + threadIdx.x;
    if (i < 2048) o[i] = a[i];
    else if (i < 4096) o[i] = b[i - 2048];
}

__global__ void fft_merge(const float* __restrict__ cp, const float* __restrict__ sp,
                          float* __restrict__ xf)
{
    const int b = blockIdx.y;
    long long idx = (long long)blockIdx.x * blockDim.x + threadIdx.x;
    const long long TOT = 1025LL * 257LL;
    if (idx >= TOT) return;
    int i = (int)(idx / 257);
    int d = (int)(idx % 257);
    long long src = (long long)b * FR * FC + (long long)i * FC + d;
    float c = cp[src], s = sp[src];
    float a = c - s, bb = c + s;
    int i2 = (Sm - i) & (Sm - 1);
    int d2 = (Dm - d) & (Dm - 1);
    float* x = xf + (long long)b * SD;
    x[(long long)i * Dm + d] = a;
    x[(long long)i2 * Dm + d] = bb;
    x[(long long)i * Dm + d2] = bb;
    x[(long long)i2 * Dm + d2] = a;
}

// softmax over H=4 heads (stride BSD), fp16 in/out; 4 elems/thread
__global__ void softmax_h4(const hlf* __restrict__ q, hlf* __restrict__ oh)
{
    long long i4 = (long long)blockIdx.x * blockDim.x + threadIdx.x;
    if (i4 >= BSD / 4) return;
    long long base = i4 * 4;
    float v[4][4];
#pragma unroll
    for (int h = 0; h < 4; h++) {
        uint2 raw = *(const uint2*)(q + h * BSD + base);
        hlf* hp = (hlf*)&raw;
#pragma unroll
        for (int j = 0; j < 4; j++) v[h][j] = __half2float(hp[j]);
    }
    float r[4][4];
#pragma unroll
    for (int j = 0; j < 4; j++) {
        float m = fmaxf(fmaxf(v[0][j], v[1][j]), fmaxf(v[2][j], v[3][j]));
        float e0 = expf(v[0][j] - m), e1 = expf(v[1][j] - m);
        float e2 = expf(v[2][j] - m), e3 = expf(v[3][j] - m);
        float inv = 1.f / (e0 + e1 + e2 + e3);
        r[0][j] = e0 * inv; r[1][j] = e1 * inv; r[2][j] = e2 * inv; r[3][j] = e3 * inv;
    }
#pragma unroll
    for (int h = 0; h < 4; h++) {
        uint2 ho = make_uint2(packf2(r[h][0], r[h][1]), packf2(r[h][2], r[h][3]));
        *(uint2*)(oh + h * BSD + base) = ho;
    }
}

// softmax over heads + transpose: ks[h][b][s,d] fp16 -> ksT[z=h*B+b][d,s] fp16.
__global__ void softmax_trans(const hlf* __restrict__ ks, hlf* __restrict__ oh)
{
    __shared__ float t[4][32][33];
    const int b = blockIdx.z;
    const int s0 = blockIdx.x * 32, d0 = blockIdx.y * 32;
    const int tx = threadIdx.x, ty = threadIdx.y;
#pragma unroll
    for (int h = 0; h < 4; h++)
#pragma unroll
        for (int i = 0; i < 4; i++)
            t[h][ty + i * 8][tx] = __half2float(
                ks[((long long)(h * Bm + b) * Sm + s0 + ty + i * 8) * Dm + d0 + tx]);
    __syncthreads();
#pragma unroll
    for (int i = 0; i < 4; i++) {
        float v0 = t[0][ty + i * 8][tx], v1 = t[1][ty + i * 8][tx];
        float v2 = t[2][ty + i * 8][tx], v3 = t[3][ty + i * 8][tx];
        float m = fmaxf(fmaxf(v0, v1), fmaxf(v2, v3));
        float e0 = expf(v0 - m), e1 = expf(v1 - m), e2 = expf(v2 - m), e3 = expf(v3 - m);
        float r = 1.f / (e0 + e1 + e2 + e3);
        t[0][ty + i * 8][tx] = e0 * r; t[1][ty + i * 8][tx] = e1 * r;
        t[2][ty + i * 8][tx] = e2 * r; t[3][ty + i * 8][tx] = e3 * r;
    }
    __syncthreads();
#pragma unroll
    for (int h = 0; h < 4; h++)
#pragma unroll
        for (int i = 0; i < 4; i++) {
            float v = t[h][tx][ty + i * 8];
            long long o = (long long)(h * Bm + b) * SD + (long long)(d0 + ty + i * 8) * Sm + s0 + tx;
            oh[o] = __float2half_rn(v);
        }
}

// LN over last dim (D=512) of (a+b); optional fp16 out (hi only).
__global__ void ln_split(const float* __restrict__ a, const float* __restrict__ bres,
                         const float* __restrict__ g, const float* __restrict__ be,
                         float* __restrict__ out, hlf* __restrict__ oh)
{
    __shared__ float red[4];
    long long row = blockIdx.x;
    int t = threadIdx.x;  // 128
    float4 va = ((const float4*)(a + row * Dm))[t];
    float4 vb = ((const float4*)(bres + row * Dm))[t];
    float4 v = make_float4(va.x + vb.x, va.y + vb.y, va.z + vb.z, va.w + vb.w);
    float s = v.x + v.y + v.z + v.w;
#pragma unroll
    for (int o = 16; o > 0; o >>= 1) s += __shfl_xor_sync(0xffffffffu, s, o);
    if ((t & 31) == 0) red[t >> 5] = s;
    __syncthreads();
    float mu = (red[0] + red[1] + red[2] + red[3]) * (1.f / (float)Dm);
    __syncthreads();
    float d0 = v.x - mu, d1 = v.y - mu, d2 = v.z - mu, d3 = v.w - mu;
    float q = d0 * d0 + d1 * d1 + d2 * d2 + d3 * d3;
#pragma unroll
    for (int o = 16; o > 0; o >>= 1) q += __shfl_xor_sync(0xffffffffu, q, o);
    if ((t & 31) == 0) red[t >> 5] = q;
    __syncthreads();
    float var = (red[0] + red[1] + red[2] + red[3]) * (1.f / (float)Dm);
    float rstd = rsqrtf(var + 1e-5f);
    float4 vg = ((const float4*)g)[t];
    float4 vbe = ((const float4*)be)[t];
    float4 o4;
    o4.x = fmaf(vg.x, d0 * rstd, vbe.x);
    o4.y = fmaf(vg.y, d1 * rstd, vbe.y);
    o4.z = fmaf(vg.z, d2 * rstd, vbe.z);
    o4.w = fmaf(vg.w, d3 * rstd, vbe.w);
    ((float4*)(out + row * Dm))[t] = o4;
    if (oh) {
        long long o = row * Dm + t * 4;
        *(uint2*)(oh + o) = make_uint2(packf2(o4.x, o4.y), packf2(o4.z, o4.w));
    }
}

// ---------------------------------------------------------------------------
// Host
// ---------------------------------------------------------------------------
static TcPasses mk1(const hlf* Ah, const hlf* Bh) {
    TcPasses P{};
    P.A[0] = Ah; P.B[0] = Bh;
    return P;
}

static void tcg(const TcPasses& P, int np, float* C, hlf* Ch,
                int M, int N, int K, int lda, int ldb, int ldc,
                long long sA, long long sB, long long sC, int batch,
                const float* bias, long long sBias, int act, int split, int bmode,
                int shA = 0, int mskB = 0x7FFFFFFF)
{
    dim3 grid(N / 128, M / 128, batch), block(256);
    if (act == 1)
        mma_gemm<1, 2, 1><<<grid, block, SMEM_G>>>(P, np, C, Ch, K, lda, ldb, ldc, sA, sB, sC, bias, sBias, shA, mskB);
    else if (split == 2 && bmode == 2)
        mma_gemm<0, 2, 2><<<grid, block, SMEM_G>>>(P, np, C, Ch, K, lda, ldb, ldc, sA, sB, sC, bias, sBias, shA, mskB);
    else if (split == 2 && bmode == 1)
        mma_gemm<0, 2, 1><<<grid, block, SMEM_G>>>(P, np, C, Ch, K, lda, ldb, ldc, sA, sB, sC, bias, sBias, shA, mskB);
    else if (split == 2)
        mma_gemm<0, 2, 0><<<grid, block, SMEM_G>>>(P, np, C, Ch, K, lda, ldb, ldc, sA, sB, sC, bias, sBias, shA, mskB);
    else if (bmode == 1)
        mma_gemm<0, 0, 1><<<grid, block, SMEM_G>>>(P, np, C, Ch, K, lda, ldb, ldc, sA, sB, sC, bias, sBias, shA, mskB);
    else
        mma_gemm<0, 0, 0><<<grid, block, SMEM_G>>>(P, np, C, Ch, K, lda, ldb, ldc, sA, sB, sC, bias, sBias, shA, mskB);
}

#define GETSYM(var, sym) do { void* _p; cudaGetSymbolAddress(&_p, sym); var = (decltype(var))_p; } while (0)

extern "C" void kernel_launch(void* const* d_in, const int* in_sizes, int n_in,
                              void* d_out, int out_size)
{
    const float* x_enc = (const float*)d_in[0];
    const float* x_dec = (const float*)d_in[1];
    const float* Wq = (const float*)d_in[2];
    const float* bq = (const float*)d_in[3];
    const float* Wk = (const float*)d_in[4];
    const float* bk = (const float*)d_in[5];
    const float* Wv = (const float*)d_in[6];
    const float* bv = (const float*)d_in[7];
    const float* Wo = (const float*)d_in[8];
    const float* bo = (const float*)d_in[9];
    const float* ln1g = (const float*)d_in[10];
    const float* ln1b = (const float*)d_in[11];
    const float* ln2g = (const float*)d_in[12];
    const float* ln2b = (const float*)d_in[13];
    const float* W1 = (const float*)d_in[14];
    const float* b1 = (const float*)d_in[15];
    const float* W2 = (const float*)d_in[16];
    const float* b2 = (const float*)d_in[17];
    const float* ln3g = (const float*)d_in[18];
    const float* ln3b = (const float*)d_in[19];
    float* outp = (float*)d_out;

    hlf *CSf, *BDh, *xdh, *t12Th, *t12Tf, *xqkh, *qkh;
    hlf *qsh, *ksTh, *vsTh, *gcDE, *Mth;
    hlf *WqkTh, *WvTh, *WoTh, *W1Th, *W2Th, *x2h, *midh;
    float *cps, *xf, *xd, *bqk, *attn, *x2, *ff;
    GETSYM(CSf, g_CSf); GETSYM(BDh, g_BDh);
    GETSYM(xdh, g_xdh);
    GETSYM(t12Th, g_t12Th); GETSYM(t12Tf, g_t12Tf);
    GETSYM(cps, g_cps);
    GETSYM(xf, g_xf); GETSYM(xd, g_xd);
    GETSYM(xqkh, g_xqkh); GETSYM(qkh, g_qkh);
    GETSYM(bqk, g_bqk);
    GETSYM(qsh, g_qsh); GETSYM(ksTh, g_ksTh); GETSYM(vsTh, g_vsTh);
    GETSYM(gcDE, g_gcDE); GETSYM(Mth, g_Mth);
    GETSYM(WqkTh, g_WqkTh); GETSYM(WvTh, g_WvTh); GETSYM(WoTh, g_WoTh);
    GETSYM(W1Th, g_W1Th); GETSYM(W2Th, g_W2Th);
    GETSYM(attn, g_attn); GETSYM(x2, g_x2); GETSYM(x2h, g_x2h);
    GETSYM(midh, g_midh); GETSYM(ff, g_ff);

    cudaFuncSetAttribute(mma_gemm<0, 0, 0>, cudaFuncAttributeMaxDynamicSharedMemorySize, SMEM_G);
    cudaFuncSetAttribute(mma_gemm<0, 0, 1>, cudaFuncAttributeMaxDynamicSharedMemorySize, SMEM_G);
    cudaFuncSetAttribute(mma_gemm<0, 2, 0>, cudaFuncAttributeMaxDynamicSharedMemorySize, SMEM_G);
    cudaFuncSetAttribute(mma_gemm<0, 2, 1>, cudaFuncAttributeMaxDynamicSharedMemorySize, SMEM_G);
    cudaFuncSetAttribute(mma_gemm<0, 2, 2>, cudaFuncAttributeMaxDynamicSharedMemorySize, SMEM_G);
    cudaFuncSetAttribute(mma_gemm<1, 2, 1>, cudaFuncAttributeMaxDynamicSharedMemorySize, SMEM_G);

    dim3 tb(32, 8);

    // 0) folded DFT matrices + BD (fp16)
    init_dft_fold<<<(int)((2LL * FR * KF + 255) / 256), 256>>>(CSf);
    init_bd<<<(TN * Dm + 255) / 256, 256>>>(BDh);

    // inputs: both fp16 hi only
    split_k8<<<(int)(BSD / 8 / 256), 256>>>(x_dec, xdh, BSD / 8);
    split_k8<<<(int)(BSD / 8 / 256), 256>>>(x_enc, xqkh + BSD, BSD / 8);

    // 1) t12T[b] = BD @ x_dec[b]^T  (M=768, N=2048, K=512, z=4), 1-pass, fp16 out
    tcg(mk1(BDh, xdh), 1, nullptr, t12Th,
        TN, Sm, Dm, Dm, Dm, Sm, 0, SD, (long long)TN * Sm, Bm,
        nullptr, 0, 0, 2, 0, /*shA=*/30, /*mskB=*/0x7FFFFFFF);

    // 1b) fold over s: t12Tf[half*4+b][384, KF]
    fold_t12<<<(int)((8LL * 384 * KF + 255) / 256), 256>>>(t12Th, t12Tf);

    // 2) merged cp/sp: cps[z] = CSf[z>>2] @ t12Tf[z]^T  (M=1152,N=384,K=1088,z=8)
    tcg(mk1(CSf, t12Tf), 1, cps, nullptr,
        FR, FC, KF, KF, KF, FC, (long long)FR * KF, 384LL * KF, (long long)FR * FC, 8,
        nullptr, 0, 0, 0, 0, /*shA=*/2, /*mskB=*/7);

    fft_merge<<<dim3((1025 * 257 + 255) / 256, Bm), 256>>>(cps, cps + 4LL * FR * FC, xf);

    // 3) xd = LN1(x_dec + xf), fp16 into first half of stacked qk-A buffer
    ln_split<<<BSm, 128>>>(x_dec, xf, ln1g, ln1b, xd, xqkh);

    // 4) weight transposes (fp16 hi only)
    split_trans<<<dim3(16, 16, Hn), tb>>>(Wq, WqkTh, Dm, Dm, DD, DD);
    split_trans<<<dim3(16, 16, Hn), tb>>>(Wk, WqkTh + 4 * DD, Dm, Dm, DD, DD);
    concat_bias<<<16, 256>>>(bq, bk, bqk);
    split_trans<<<dim3(16, 16, Hn), tb>>>(Wv, WvTh, Dm, Dm, DD, DD);
    wo_split_trans<<<dim3(16, 16, Hn), tb>>>(Wo, WoTh);
    split_trans<<<dim3(MIDm / 32, Dm / 32, 1), tb>>>(W1, W1Th, Dm, MIDm, 0, 0);
    split_trans<<<dim3(Dm / 32, MIDm / 32, 1), tb>>>(W2, W2Th, MIDm, Dm, 0, 0);

    // 5) merged q/k projections: z=8, 1-pass, fp16 logits out
    tcg(mk1(xqkh, WqkTh), 1, nullptr, qkh,
        BSm, Dm, Dm, Dm, Dm, Dm, BSD, DD, BSD, 8, bqk, Dm, 0, 2, 1,
        /*shA=*/2, /*mskB=*/7);

    // 6) vsT[z=h*4+b] = WvT_h @ x_enc[b]^T + bv_h, fp16 out, 1-pass; z=16
    tcg(mk1(WvTh, xqkh + BSD), 1, nullptr, vsTh,
        Dm, Sm, Dm, Dm, Dm, Sm, DD, SD, SD, 16, bv, Dm, 0, 2, 2,
        /*shA=*/2, /*mskB=*/3);

    // 7) softmax over heads: q, k (+transpose), fp16 in/out
    softmax_h4<<<(int)(BSD / 4 / 256), 256>>>(qkh, qsh);
    softmax_trans<<<dim3(Sm / 32, Dm / 32, Bm), tb>>>(qkh + 4 * BSD, ksTh);

    // 8) gcDE[z][d,e] = ksT @ vsT^T  (M=512(d), N=512(e), K=2048, z=16), fp16 out
    tcg(mk1(ksTh, vsTh), 1, nullptr, gcDE,
        Dm, Dm, Sm, Sm, Sm, Dm, SD, SD, DD, 16, nullptr, 0, 0, 2, 0);

    // 9) Mt[z][n,d] = WoT_{z>>2} @ gcDE[z]^T  (M=512(n), N=512(d), K=512(e), z=16)
    tcg(mk1(WoTh, gcDE), 1, nullptr, Mth,
        Dm, Dm, Dm, Dm, Dm, Dm, DD, DD, DD, 16, nullptr, 0, 0, 2, 0,
        /*shA=*/2, /*mskB=*/15);

    // 10) attn[b][s,n] = sum_h qs_h[b] @ Mt[h*4+b]^T + bo  (4 passes; z=4)
    {
        TcPasses P{};
        for (int h = 0; h < Hn; h++) {
            P.A[h] = qsh + (long long)h * Bm * SD;
            P.B[h] = Mth + (long long)h * Bm * DD;
        }
        tcg(P, 4, attn, nullptr,
            Sm, Dm, Dm, Dm, Dm, Dm, SD, DD, SD, Bm, bo, 0, 0, 0, 1,
            /*shA=*/0, /*mskB=*/3);
    }

    // 11) x2 = LN2(xd + attn), fp16 out
    ln_split<<<BSm, 128>>>(xd, attn, ln2g, ln2b, x2, x2h);

    // 12) mid = selu(x2 @ W1 + b1), fp16 out, 1-pass
    tcg(mk1(x2h, W1Th), 1, nullptr, midh,
        BSm, MIDm, Dm, Dm, Dm, MIDm, 0, 0, 0, 1, b1, 0, 1, 2, 1);

    // 13) ff = mid @ W2 + b2, 1-pass
    tcg(mk1(midh, W2Th), 1, ff, nullptr,
        BSm, Dm, MIDm, MIDm, MIDm, Dm, 0, 0, 0, 1, b2, 0, 0, 0, 1);

    // 14) out = LN3(x2 + ff)
    ln_split<<<BSm, 128>>>(x2, ff, ln3g, ln3b, outp, nullptr);
}

// round 13
// speedup vs baseline: 2.4674x; 1.0265x over previous
#include <cuda_runtime.h>
#include <cuda_fp16.h>
#include <math.h>
#include <stdint.h>

typedef __half hlf;

static constexpr int Dm = 512, Hn = 4, MIDm = 2048, Bm = 4, Sm = 2048;
static constexpr int BSm = Bm * Sm;                      // 8192
static constexpr long long BSD = (long long)BSm * Dm;    // 4194304
static constexpr long long SD  = (long long)Sm * Dm;     // 1048576
static constexpr long long DD  = (long long)Dm * Dm;     // 262144

// FFT-symmetry tile sizes
static constexpr int FR = 1152;   // S-axis rows computed (need 0..1024)
static constexpr int FC = 384;    // D-axis cols computed (need 0..256)
static constexpr int TN = 768;    // t12 width: 384 cos + 384 sin
static constexpr int KF = 1088;   // folded K for cp/sp (1025 padded to /64)
static constexpr int KD = 320;    // folded K for t12 (257 padded to /64)

// ---------------------------------------------------------------------------
// Static device scratch
// ---------------------------------------------------------------------------
__device__ __align__(256) hlf g_CSf[2 * FR * KF];                  // [cos;sin] S-folded
__device__ __align__(256) hlf g_BDf[2 * 384 * KD];                 // [cos;sin] D-folded
__device__ __align__(256) hlf g_xdf[8 * Sm * KD];                  // [b*2+half][2048,320]
__device__ __align__(256) hlf g_t12Th[4 * TN * Sm];                // [b][768,2048]
__device__ __align__(256) hlf g_t12Tf[8 * 384 * KF];               // [half*4+b][384,1088]
__device__ __align__(256) float g_cps[8 * FR * FC];                // cp z=0..3, sp z=4..7
__device__ __align__(256) float g_xd[4194304];
// stacked A for merged q/k proj: [0..BSD)=LN1(xd) fp16, [BSD..2BSD)=x_enc fp16
__device__ __align__(256) hlf g_xqkh[8388608];
__device__ __align__(256) hlf g_qkh[33554432];                     // [8][b,s,d] fp16 logits
__device__ __align__(256) hlf g_qsh[16777216];
__device__ __align__(256) hlf g_ksTh[16777216];                    // [z][D,S]
__device__ __align__(256) hlf g_vsTh[16777216];                    // [z][E,S]
__device__ __align__(256) hlf g_gcDE[4194304];                     // [z][D,E]
__device__ __align__(256) hlf g_Mth[4194304];                      // [z][N,D]
__device__ __align__(256) hlf g_WqkTh[2097152];                    // [Wq0..3;Wk0..3]
__device__ __align__(256) float g_bqk[4096];                       // [bq;bk]
__device__ __align__(256) hlf g_WvTh[1048576];
__device__ __align__(256) hlf g_WoTh[1048576];                     // [h][512,512] (n,e)
__device__ __align__(256) hlf g_W1Th[1048576];                     // [2048,512]
__device__ __align__(256) hlf g_W2Th[1048576];                     // [512,2048]
__device__ __align__(256) float g_attn[4194304];
__device__ __align__(256) float g_x2[4194304];
__device__ __align__(256) hlf g_x2h[4194304];
__device__ __align__(256) hlf g_midh[16777216];
__device__ __align__(256) float g_ff[4194304];

// ---------------------------------------------------------------------------
// Helpers
// ---------------------------------------------------------------------------
__device__ __forceinline__ uint32_t smem_u32(const void* p) {
    uint32_t a;
    asm("{ .reg .u64 t; cvta.to.shared.u64 t, %1; cvt.u32.u64 %0, t; }" : "=r"(a) : "l"(p));
    return a;
}
__device__ __forceinline__ float selu_f(float x) {
    const float sc = 1.0507009873554805f, al = 1.6732632423543772f;
    return x > 0.f ? sc * x : sc * al * (expf(x) - 1.f);
}
__device__ __forceinline__ uint32_t packhl(hlf a, hlf b) {
    return ((uint32_t)*(uint16_t*)&b << 16) | (uint32_t)*(uint16_t*)&a;
}
__device__ __forceinline__ uint32_t packf2(float a, float b) {
    hlf ha = __float2half_rn(a), hb = __float2half_rn(b);
    return packhl(ha, hb);
}

#define LDSM_X4(r0, r1, r2, r3, addr) \
    asm volatile("ldmatrix.sync.aligned.m8n8.x4.shared.b16 {%0,%1,%2,%3}, [%4];" \
        : "=r"(r0), "=r"(r1), "=r"(r2), "=r"(r3) : "r"(addr))

#define MMA_F16(d, a, b0, b1) \
    asm volatile("mma.sync.aligned.m16n8k16.row.col.f32.f16.f16.f32 " \
        "{%0,%1,%2,%3}, {%4,%5,%6,%7}, {%8,%9}, {%0,%1,%2,%3};" \
        : "+f"((d)[0]), "+f"((d)[1]), "+f"((d)[2]), "+f"((d)[3]) \
        : "r"((a)[0]), "r"((a)[1]), "r"((a)[2]), "r"((a)[3]), "r"(b0), "r"(b1))

#define CP_ASYNC16(dst, src) \
    asm volatile("cp.async.cg.shared.global [%0], [%1], 16;" :: "r"(dst), "l"(src))
#define CP_COMMIT() asm volatile("cp.async.commit_group;")
#define CP_WAIT1()  asm volatile("cp.async.wait_group 1;")

// ---------------------------------------------------------------------------
// HMMA GEMM, cp.async 3-stage pipeline.
// Block 128x128, 8 warps, warp 64x32, BK=64, 2 CTA/SM.
// C[z] = sum_p A_p[(z>>shA)&mskA] @ B_p[z&mskB]^T (+bias col[zb]/row[za])(+SELU)
// SPLIT: 0 = fp32 out, 2 = fp16 out.
// ---------------------------------------------------------------------------
struct TcPasses { const hlf* A[4]; const hlf* B[4]; };

static constexpr int BKg = 64;
static constexpr int LDSg = BKg + 8;
static constexpr int TILE_B = 128 * LDSg * 2;
static constexpr int STAGES = 3;
static constexpr int SMEM_B_OFF = STAGES * TILE_B;
static constexpr int SMEM_BIAS_OFF = 2 * STAGES * TILE_B;
static constexpr int SMEM_G = SMEM_BIAS_OFF + 128 * 4;

template <int ACT, int SPLIT, int BMODE>   // BMODE: 0 none, 1 col (zb), 2 row (za)
__global__ __launch_bounds__(256, 2) void mma_gemm(
    TcPasses P, int npass,
    float* __restrict__ C, hlf* __restrict__ Chi,
    int K, int lda, int ldb, int ldc,
    long long sA, long long sB, long long sC,
    const float* __restrict__ bias, long long sBias,
    int shA, int mskA, int mskB)
{
    extern __shared__ char smem[];
    float* bias_s = (float*)(smem + SMEM_BIAS_OFF);
    const uint32_t sA0 = smem_u32(smem);
    const uint32_t sB0 = sA0 + SMEM_B_OFF;

    const int tid = threadIdx.x;
    const int lane = tid & 31;
    const int wid = tid >> 5;
    const int wm = (wid & 1) * 64;
    const int wn = (wid >> 1) * 32;
    const int z = blockIdx.z;
    const int za = (z >> shA) & mskA;
    const int zb = z & mskB;
    const int m0 = blockIdx.y * 128, n0 = blockIdx.x * 128;

    if (tid < 128) {
        if (BMODE == 0) bias_s[tid] = 0.f;
        else if (BMODE == 1) bias_s[tid] = bias[(long long)zb * sBias + n0 + tid];
        else bias_s[tid] = bias[(long long)za * sBias + m0 + tid];
    }

    float acc[4][4][4];
#pragma unroll
    for (int i = 0; i < 4; i++)
#pragma unroll
        for (int j = 0; j < 4; j++)
#pragma unroll
            for (int k = 0; k < 4; k++) acc[i][j][k] = 0.f;

    const int cpp = K / BKg;
    const int total = npass * cpp;

    const int crow = tid >> 3;
    const int ccol = (tid & 7) * 8;

    auto loadStage = [&](int c, int stg) {
        int p = c / cpp;
        int k0 = (c - p * cpp) * BKg;
        const hlf* Ab = P.A[p] + (long long)za * sA + k0 + ccol;
        const hlf* Bb = P.B[p] + (long long)zb * sB + k0 + ccol;
        uint32_t da = sA0 + stg * TILE_B + (crow * LDSg + ccol) * 2;
        uint32_t db = sB0 + stg * TILE_B + (crow * LDSg + ccol) * 2;
#pragma unroll
        for (int i = 0; i < 4; i++) {
            int row = crow + i * 32;
            CP_ASYNC16(da + i * 32 * LDSg * 2, Ab + (long long)(m0 + row) * lda);
            CP_ASYNC16(db + i * 32 * LDSg * 2, Bb + (long long)(n0 + row) * ldb);
        }
    };

    loadStage(0, 0); CP_COMMIT();
    loadStage(1, 1); CP_COMMIT();

    const int lrow16 = lane & 15;
    const int lhalf = lane >> 4;

    for (int c = 0; c < total; c++) {
        CP_WAIT1();
        __syncthreads();
        const int stg = c % STAGES;
        const uint32_t aB = sA0 + stg * TILE_B;
        const uint32_t bB = sB0 + stg * TILE_B;
#pragma unroll
        for (int ks = 0; ks < 4; ks++) {
            uint32_t af[4][4];
#pragma unroll
            for (int mi = 0; mi < 4; mi++) {
                uint32_t addr = aB + (uint32_t)(((wm + mi * 16 + lrow16) * LDSg
                                                + ks * 16 + lhalf * 8) * 2);
                LDSM_X4(af[mi][0], af[mi][1], af[mi][2], af[mi][3], addr);
            }
            uint32_t bfr[2][4];
#pragma unroll
            for (int nj = 0; nj < 2; nj++) {
                uint32_t addr = bB + (uint32_t)(((wn + nj * 16 + lrow16) * LDSg
                                                + ks * 16 + lhalf * 8) * 2);
                LDSM_X4(bfr[nj][0], bfr[nj][1], bfr[nj][2], bfr[nj][3], addr);
            }
#pragma unroll
            for (int mi = 0; mi < 4; mi++)
#pragma unroll
                for (int ni = 0; ni < 4; ni++) {
                    const int nj = ni >> 1, sub = ni & 1;
                    MMA_F16(acc[mi][ni], af[mi], bfr[nj][sub], bfr[nj][sub + 2]);
                }
        }
        if (c + 2 < total) loadStage(c + 2, (c + 2) % STAGES);
        CP_COMMIT();
    }

    const int cr = lane >> 2;
    const int cc = (lane & 3) * 2;
#pragma unroll
    for (int mi = 0; mi < 4; mi++) {
#pragma unroll
        for (int ni = 0; ni < 4; ni++) {
            const int bn = wn + ni * 8 + cc;
            const int gn = n0 + bn;
            const int rm = wm + mi * 16 + cr;
            const long long r0 = m0 + rm;
            const long long r1 = r0 + 8;
            float v0 = acc[mi][ni][0], v1 = acc[mi][ni][1];
            float v2 = acc[mi][ni][2], v3 = acc[mi][ni][3];
            if (BMODE == 1) {
                v0 += bias_s[bn]; v1 += bias_s[bn + 1];
                v2 += bias_s[bn]; v3 += bias_s[bn + 1];
            } else if (BMODE == 2) {
                v0 += bias_s[rm]; v1 += bias_s[rm];
                v2 += bias_s[rm + 8]; v3 += bias_s[rm + 8];
            }
            if (ACT == 1) { v0 = selu_f(v0); v1 = selu_f(v1); v2 = selu_f(v2); v3 = selu_f(v3); }
            if (SPLIT == 2) {
                *(uint32_t*)(Chi + (long long)z * sC + r0 * ldc + gn) = packf2(v0, v1);
                *(uint32_t*)(Chi + (long long)z * sC + r1 * ldc + gn) = packf2(v2, v3);
            } else {
                *(float2*)(C + (long long)z * sC + r0 * ldc + gn) = make_float2(v0, v1);
                *(float2*)(C + (long long)z * sC + r1 * ldc + gn) = make_float2(v2, v3);
            }
        }
    }
}

// ---------------------------------------------------------------------------
// Elementwise kernels
// ---------------------------------------------------------------------------
// Folded S-axis DFT: [cos;sin], each [FR, KF], cols > 1024 zero-padded.
__global__ void init_dft_fold(hlf* __restrict__ o)
{
    long long idx = (long long)blockIdx.x * blockDim.x + threadIdx.x;
    if (idx >= 2LL * FR * KF) return;
    int half = (int)(idx / ((long long)FR * KF));
    int rem = (int)(idx % ((long long)FR * KF));
    int i = rem / KF, j = rem % KF;
    float v = 0.f;
    if (j <= 1024) {
        int p = (int)(((long long)i * j) % Sm);
        float x = 2.0f * (float)p / (float)Sm;
        float s, c;
        sincospif(x, &s, &c);
        v = half ? s : c;
    }
    o[idx] = __float2half_rn(v);
}

// Folded D-axis DFT: [cos;sin], each [384, KD], cols > 256 zero-padded.
__global__ void init_bdf(hlf* __restrict__ o)
{
    long long idx = (long long)blockIdx.x * blockDim.x + threadIdx.x;
    if (idx >= 2LL * 384 * KD) return;
    int half = (int)(idx / (384 * KD));
    int rem = (int)(idx % (384 * KD));
    int i = rem / KD, k = rem % KD;
    float v = 0.f;
    if (k <= 256) {
        int p = (int)(((long long)i * k) % Dm);
        float x = 2.0f * (float)p / (float)Dm;
        float s, c;
        sincospif(x, &s, &c);
        v = half ? s : c;
    }
    o[idx] = __float2half_rn(v);
}

// Fold x_dec over d: xdf[b*2+0][s,k]=x[k]+x[512-k] (cos), [b*2+1]=x[k]-x[512-k] (sin).
// One block (128 thr) per row.
__global__ void xdec_fold(const float* __restrict__ x, hlf* __restrict__ xdf)
{
    __shared__ float row[512];
    const long long r = blockIdx.x;          // b*2048+s
    const int b = (int)(r >> 11);
    const long long s = r & 2047;
    const int t = threadIdx.x;
    ((float4*)row)[t] = ((const float4*)(x + r * Dm))[t];
    __syncthreads();
    hlf* co = xdf + ((long long)(b * 2) * Sm + s) * KD;
    hlf* si = co + (long long)Sm * KD;
#pragma unroll
    for (int q = 0; q < 3; q++) {
        int k = t + q * 128;
        if (k >= KD) break;
        float cv = 0.f, sv = 0.f;
        if (k == 0) { cv = row[0]; }
        else if (k == 256) { cv = row[256]; }
        else if (k < 256) {
            float a = row[k], bb = row[512 - k];
            cv = a + bb; sv = a - bb;
        }
        co[k] = __float2half_rn(cv);
        si[k] = __float2half_rn(sv);
    }
}

// Fold t12T over s: out[(half*4+b)][rr, j] = t[j] +/- t[2048-j] (j<=1024; pad 0).
__global__ void fold_t12(const hlf* __restrict__ in, hlf* __restrict__ out)
{
    long long idx = (long long)blockIdx.x * blockDim.x + threadIdx.x;
    const long long TOT = 8LL * 384 * KF;
    if (idx >= TOT) return;
    int j = (int)(idx % KF);
    int rr = (int)((idx / KF) % 384);
    int z = (int)(idx / ((long long)384 * KF));
    int half = z >> 2, b = z & 3;
    float v = 0.f;
    if (j <= 1024) {
        const hlf* row = in + (long long)b * TN * Sm + (long long)(half * 384 + rr) * Sm;
        float a = __half2float(row[j]);
        if (j == 0 || j == 1024) {
            v = a;
        } else {
            float c = __half2float(row[Sm - j]);
            v = half ? (a - c) : (a + c);
        }
    }
    out[idx] = __float2half_rn(v);
}

// fp32 -> fp16 (hi only), 8 elems/thread
__global__ void split_k8(const float* __restrict__ in, hlf* __restrict__ h, long long n8)
{
    long long i = (long long)blockIdx.x * blockDim.x + threadIdx.x;
    if (i >= n8) return;
    long long base = i * 8;
    float4 a = *(const float4*)(in + base);
    float4 b = *(const float4*)(in + base + 4);
    uint4 ho;
    ho.x = packf2(a.x, a.y); ho.y = packf2(a.z, a.w);
    ho.z = packf2(b.x, b.y); ho.w = packf2(b.z, b.w);
    *(uint4*)(h + base) = ho;
}

// All six weight transposes in one launch; every segment is exactly 1024 tiles.
struct WSeg { const float* in; hlf* out; int nTx, nTy, wo; long long sIn, sOut; int R, C; };
struct WPrep { WSeg s[6]; };

__global__ void weights_prep(WPrep P)
{
    __shared__ float t[32][33];
    const int seg = blockIdx.x >> 10;
    const int id = blockIdx.x & 1023;
    const WSeg w = P.s[seg];
    const int tilesPerZ = w.nTx * w.nTy;
    const int bz = id / tilesPerZ;
    const int rem = id % tilesPerZ;
    const int bx = rem % w.nTx;
    const int by = rem / w.nTx;
    const int tx = threadIdx.x, ty = threadIdx.y;
    if (!w.wo) {
        const int c0 = bx * 32, r0 = by * 32;
        const float* ib = w.in + (long long)bz * w.sIn;
#pragma unroll
        for (int i = 0; i < 4; i++)
            t[ty + i * 8][tx] = ib[(long long)(r0 + ty + i * 8) * w.C + c0 + tx];
        __syncthreads();
#pragma unroll
        for (int i = 0; i < 4; i++) {
            float v = t[tx][ty + i * 8];
            long long o = (long long)bz * w.sOut + (long long)(c0 + ty + i * 8) * w.R + r0 + tx;
            w.out[o] = __float2half_rn(v);
        }
    } else {
        const int n0 = bx * 32, d0 = by * 32, h = bz;
#pragma unroll
        for (int i = 0; i < 4; i++) {
            int d = d0 + ty + i * 8;
            t[ty + i * 8][tx] = w.in[(long long)(d * 4 + h) * Dm + n0 + tx];
        }
        __syncthreads();
#pragma unroll
        for (int i = 0; i < 4; i++) {
            float v = t[tx][ty + i * 8];
            long long o = (long long)h * DD + (long long)(n0 + ty + i * 8) * Dm + d0 + tx;
            w.out[o] = __float2half_rn(v);
        }
    }
}

__global__ void concat_bias(const float* __restrict__ a, const float* __restrict__ b,
                            float* __restrict__ o)
{
    int i = blockIdx.x * blockDim.x + threadIdx.x;
    if (i < 2048) o[i] = a[i];
    else if (i < 4096) o[i] = b[i - 2048];
}

// softmax over H=4 heads (stride BSD), fp16 in/out; 4 elems/thread
__global__ void softmax_h4(const hlf* __restrict__ q, hlf* __restrict__ oh)
{
    long long i4 = (long long)blockIdx.x * blockDim.x + threadIdx.x;
    if (i4 >= BSD / 4) return;
    long long base = i4 * 4;
    float v[4][4];
#pragma unroll
    for (int h = 0; h < 4; h++) {
        uint2 raw = *(const uint2*)(q + h * BSD + base);
        hlf* hp = (hlf*)&raw;
#pragma unroll
        for (int j = 0; j < 4; j++) v[h][j] = __half2float(hp[j]);
    }
    float r[4][4];
#pragma unroll
    for (int j = 0; j < 4; j++) {
        float m = fmaxf(fmaxf(v[0][j], v[1][j]), fmaxf(v[2][j], v[3][j]));
        float e0 = expf(v[0][j] - m), e1 = expf(v[1][j] - m);
        float e2 = expf(v[2][j] - m), e3 = expf(v[3][j] - m);
        float inv = 1.f / (e0 + e1 + e2 + e3);
        r[0][j] = e0 * inv; r[1][j] = e1 * inv; r[2][j] = e2 * inv; r[3][j] = e3 * inv;
    }
#pragma unroll
    for (int h = 0; h < 4; h++) {
        uint2 ho = make_uint2(packf2(r[h][0], r[h][1]), packf2(r[h][2], r[h][3]));
        *(uint2*)(oh + h * BSD + base) = ho;
    }
}

// softmax over heads + transpose: ks[h][b][s,d] fp16 -> ksT[z=h*B+b][d,s] fp16.
__global__ void softmax_trans(const hlf* __restrict__ ks, hlf* __restrict__ oh)
{
    __shared__ float t[4][32][33];
    const int b = blockIdx.z;
    const int s0 = blockIdx.x * 32, d0 = blockIdx.y * 32;
    const int tx = threadIdx.x, ty = threadIdx.y;
#pragma unroll
    for (int h = 0; h < 4; h++)
#pragma unroll
        for (int i = 0; i < 4; i++)
            t[h][ty + i * 8][tx] = __half2float(
                ks[((long long)(h * Bm + b) * Sm + s0 + ty + i * 8) * Dm + d0 + tx]);
    __syncthreads();
#pragma unroll
    for (int i = 0; i < 4; i++) {
        float v0 = t[0][ty + i * 8][tx], v1 = t[1][ty + i * 8][tx];
        float v2 = t[2][ty + i * 8][tx], v3 = t[3][ty + i * 8][tx];
        float m = fmaxf(fmaxf(v0, v1), fmaxf(v2, v3));
        float e0 = expf(v0 - m), e1 = expf(v1 - m), e2 = expf(v2 - m), e3 = expf(v3 - m);
        float r = 1.f / (e0 + e1 + e2 + e3);
        t[0][ty + i * 8][tx] = e0 * r; t[1][ty + i * 8][tx] = e1 * r;
        t[2][ty + i * 8][tx] = e2 * r; t[3][ty + i * 8][tx] = e3 * r;
    }
    __syncthreads();
#pragma unroll
    for (int h = 0; h < 4; h++)
#pragma unroll
        for (int i = 0; i < 4; i++) {
            float v = t[h][tx][ty + i * 8];
            long long o = (long long)(h * Bm + b) * SD + (long long)(d0 + ty + i * 8) * Sm + s0 + tx;
            oh[o] = __float2half_rn(v);
        }
}

// LN1 fused with FFT quadrant reconstruction:
// xf[s,d] = cp[i',d'] + (flip_i^flip_d ? +1 : -1) * sp[i',d'],
// then LN(x_dec + xf); writes xd fp32 and fp16.
__global__ void ln1_fft(const float* __restrict__ x_dec, const float* __restrict__ cps,
                        const float* __restrict__ g, const float* __restrict__ be,
                        float* __restrict__ out, hlf* __restrict__ oh)
{
    __shared__ float red[4];
    const long long row = blockIdx.x;        // b*2048 + s
    const int b = (int)(row >> 11);
    const int s = (int)(row & 2047);
    const int t = threadIdx.x;               // 128

    const int ip = (s <= 1024) ? s : (Sm - s);
    const bool fi = (s > 1024);
    const float* cpr = cps + (long long)b * FR * FC + (long long)ip * FC;
    const float* spr = cpr + 4LL * FR * FC;

    float4 vx = ((const float4*)(x_dec + row * Dm))[t];
    float v4[4];
#pragma unroll
    for (int j = 0; j < 4; j++) {
        int d = t * 4 + j;
        int dp = (d <= 256) ? d : (Dm - d);
        bool fd = (d > 256);
        float c = cpr[dp], sv = spr[dp];
        float xfv = c + ((fi != fd) ? sv : -sv);
        v4[j] = ((const float*)&vx)[j] + xfv;
    }

    float ssum = v4[0] + v4[1] + v4[2] + v4[3];
#pragma unroll
    for (int o = 16; o > 0; o >>= 1) ssum += __shfl_xor_sync(0xffffffffu, ssum, o);
    if ((t & 31) == 0) red[t >> 5] = ssum;
    __syncthreads();
    float mu = (red[0] + red[1] + red[2] + red[3]) * (1.f / (float)Dm);
    __syncthreads();
    float d0 = v4[0] - mu, d1 = v4[1] - mu, d2 = v4[2] - mu, d3 = v4[3] - mu;
    float q = d0 * d0 + d1 * d1 + d2 * d2 + d3 * d3;
#pragma unroll
    for (int o = 16; o > 0; o >>= 1) q += __shfl_xor_sync(0xffffffffu, q, o);
    if ((t & 31) == 0) red[t >> 5] = q;
    __syncthreads();
    float var = (red[0] + red[1] + red[2] + red[3]) * (1.f / (float)Dm);
    float rstd = rsqrtf(var + 1e-5f);
    float4 vg = ((const float4*)g)[t];
    float4 vbe = ((const float4*)be)[t];
    float4 o4;
    o4.x = fmaf(vg.x, d0 * rstd, vbe.x);
    o4.y = fmaf(vg.y, d1 * rstd, vbe.y);
    o4.z = fmaf(vg.z, d2 * rstd, vbe.z);
    o4.w = fmaf(vg.w, d3 * rstd, vbe.w);
    ((float4*)(out + row * Dm))[t] = o4;
    long long o = row * Dm + t * 4;
    *(uint2*)(oh + o) = make_uint2(packf2(o4.x, o4.y), packf2(o4.z, o4.w));
}

// LN over last dim (D=512) of (a+b); optional fp16 out (hi only).
__global__ void ln_split(const float* __restrict__ a, const float* __restrict__ bres,
                         const float* __restrict__ g, const float* __restrict__ be,
                         float* __restrict__ out, hlf* __restrict__ oh)
{
    __shared__ float red[4];
    long long row = blockIdx.x;
    int t = threadIdx.x;  // 128
    float4 va = ((const float4*)(a + row * Dm))[t];
    float4 vb = ((const float4*)(bres + row * Dm))[t];
    float4 v = make_float4(va.x + vb.x, va.y + vb.y, va.z + vb.z, va.w + vb.w);
    float s = v.x + v.y + v.z + v.w;
#pragma unroll
    for (int o = 16; o > 0; o >>= 1) s += __shfl_xor_sync(0xffffffffu, s, o);
    if ((t & 31) == 0) red[t >> 5] = s;
    __syncthreads();
    float mu = (red[0] + red[1] + red[2] + red[3]) * (1.f / (float)Dm);
    __syncthreads();
    float d0 = v.x - mu, d1 = v.y - mu, d2 = v.z - mu, d3 = v.w - mu;
    float q = d0 * d0 + d1 * d1 + d2 * d2 + d3 * d3;
#pragma unroll
    for (int o = 16; o > 0; o >>= 1) q += __shfl_xor_sync(0xffffffffu, q, o);
    if ((t & 31) == 0) red[t >> 5] = q;
    __syncthreads();
    float var = (red[0] + red[1] + red[2] + red[3]) * (1.f / (float)Dm);
    float rstd = rsqrtf(var + 1e-5f);
    float4 vg = ((const float4*)g)[t];
    float4 vbe = ((const float4*)be)[t];
    float4 o4;
    o4.x = fmaf(vg.x, d0 * rstd, vbe.x);
    o4.y = fmaf(vg.y, d1 * rstd, vbe.y);
    o4.z = fmaf(vg.z, d2 * rstd, vbe.z);
    o4.w = fmaf(vg.w, d3 * rstd, vbe.w);
    ((float4*)(out + row * Dm))[t] = o4;
    if (oh) {
        long long o = row * Dm + t * 4;
        *(uint2*)(oh + o) = make_uint2(packf2(o4.x, o4.y), packf2(o4.z, o4.w));
    }
}

// ---------------------------------------------------------------------------
// Host
// ---------------------------------------------------------------------------
static TcPasses mk1(const hlf* Ah, const hlf* Bh) {
    TcPasses P{};
    P.A[0] = Ah; P.B[0] = Bh;
    return P;
}

static void tcg(const TcPasses& P, int np, float* C, hlf* Ch,
                int M, int N, int K, int lda, int ldb, int ldc,
                long long sA, long long sB, long long sC, int batch,
                const float* bias, long long sBias, int act, int split, int bmode,
                int shA = 0, int mskA = 0x7FFFFFFF, int mskB = 0x7FFFFFFF)
{
    dim3 grid(N / 128, M / 128, batch), block(256);
    if (act == 1)
        mma_gemm<1, 2, 1><<<grid, block, SMEM_G>>>(P, np, C, Ch, K, lda, ldb, ldc, sA, sB, sC, bias, sBias, shA, mskA, mskB);
    else if (split == 2 && bmode == 2)
        mma_gemm<0, 2, 2><<<grid, block, SMEM_G>>>(P, np, C, Ch, K, lda, ldb, ldc, sA, sB, sC, bias, sBias, shA, mskA, mskB);
    else if (split == 2 && bmode == 1)
        mma_gemm<0, 2, 1><<<grid, block, SMEM_G>>>(P, np, C, Ch, K, lda, ldb, ldc, sA, sB, sC, bias, sBias, shA, mskA, mskB);
    else if (split == 2)
        mma_gemm<0, 2, 0><<<grid, block, SMEM_G>>>(P, np, C, Ch, K, lda, ldb, ldc, sA, sB, sC, bias, sBias, shA, mskA, mskB);
    else if (bmode == 1)
        mma_gemm<0, 0, 1><<<grid, block, SMEM_G>>>(P, np, C, Ch, K, lda, ldb, ldc, sA, sB, sC, bias, sBias, shA, mskA, mskB);
    else
        mma_gemm<0, 0, 0><<<grid, block, SMEM_G>>>(P, np, C, Ch, K, lda, ldb, ldc, sA, sB, sC, bias, sBias, shA, mskA, mskB);
}

#define GETSYM(var, sym) do { void* _p; cudaGetSymbolAddress(&_p, sym); var = (decltype(var))_p; } while (0)

extern "C" void kernel_launch(void* const* d_in, const int* in_sizes, int n_in,
                              void* d_out, int out_size)
{
    const float* x_enc = (const float*)d_in[0];
    const float* x_dec = (const float*)d_in[1];
    const float* Wq = (const float*)d_in[2];
    const float* bq = (const float*)d_in[3];
    const float* Wk = (const float*)d_in[4];
    const float* bk = (const float*)d_in[5];
    const float* Wv = (const float*)d_in[6];
    const float* bv = (const float*)d_in[7];
    const float* Wo = (const float*)d_in[8];
    const float* bo = (const float*)d_in[9];
    const float* ln1g = (const float*)d_in[10];
    const float* ln1b = (const float*)d_in[11];
    const float* ln2g = (const float*)d_in[12];
    const float* ln2b = (const float*)d_in[13];
    const float* W1 = (const float*)d_in[14];
    const float* b1 = (const float*)d_in[15];
    const float* W2 = (const float*)d_in[16];
    const float* b2 = (const float*)d_in[17];
    const float* ln3g = (const float*)d_in[18];
    const float* ln3b = (const float*)d_in[19];
    float* outp = (float*)d_out;

    hlf *CSf, *BDf, *xdf, *t12Th, *t12Tf, *xqkh, *qkh;
    hlf *qsh, *ksTh, *vsTh, *gcDE, *Mth;
    hlf *WqkTh, *WvTh, *WoTh, *W1Th, *W2Th, *x2h, *midh;
    float *cps, *xd, *bqk, *attn, *x2, *ff;
    GETSYM(CSf, g_CSf); GETSYM(BDf, g_BDf); GETSYM(xdf, g_xdf);
    GETSYM(t12Th, g_t12Th); GETSYM(t12Tf, g_t12Tf);
    GETSYM(cps, g_cps);
    GETSYM(xd, g_xd);
    GETSYM(xqkh, g_xqkh); GETSYM(qkh, g_qkh);
    GETSYM(bqk, g_bqk);
    GETSYM(qsh, g_qsh); GETSYM(ksTh, g_ksTh); GETSYM(vsTh, g_vsTh);
    GETSYM(gcDE, g_gcDE); GETSYM(Mth, g_Mth);
    GETSYM(WqkTh, g_WqkTh); GETSYM(WvTh, g_WvTh); GETSYM(WoTh, g_WoTh);
    GETSYM(W1Th, g_W1Th); GETSYM(W2Th, g_W2Th);
    GETSYM(attn, g_attn); GETSYM(x2, g_x2); GETSYM(x2h, g_x2h);
    GETSYM(midh, g_midh); GETSYM(ff, g_ff);

    cudaFuncSetAttribute(mma_gemm<0, 0, 0>, cudaFuncAttributeMaxDynamicSharedMemorySize, SMEM_G);
    cudaFuncSetAttribute(mma_gemm<0, 0, 1>, cudaFuncAttributeMaxDynamicSharedMemorySize, SMEM_G);
    cudaFuncSetAttribute(mma_gemm<0, 2, 0>, cudaFuncAttributeMaxDynamicSharedMemorySize, SMEM_G);
    cudaFuncSetAttribute(mma_gemm<0, 2, 1>, cudaFuncAttributeMaxDynamicSharedMemorySize, SMEM_G);
    cudaFuncSetAttribute(mma_gemm<0, 2, 2>, cudaFuncAttributeMaxDynamicSharedMemorySize, SMEM_G);
    cudaFuncSetAttribute(mma_gemm<1, 2, 1>, cudaFuncAttributeMaxDynamicSharedMemorySize, SMEM_G);

    dim3 tb(32, 8);

    // 0) folded DFT matrices (fp16)
    init_dft_fold<<<(int)((2LL * FR * KF + 255) / 256), 256>>>(CSf);
    init_bdf<<<(int)((2LL * 384 * KD + 255) / 256), 256>>>(BDf);

    // inputs: x_enc fp16; x_dec folded over d
    split_k8<<<(int)(BSD / 8 / 256), 256>>>(x_enc, xqkh + BSD, BSD / 8);
    xdec_fold<<<BSm, 128>>>(x_dec, xdf);

    // weight prep: one launch, 6 segments x 1024 tiles
    {
        WPrep P{};
        P.s[0] = {Wq, WqkTh, 16, 16, 0, DD, DD, Dm, Dm};
        P.s[1] = {Wk, WqkTh + 4 * DD, 16, 16, 0, DD, DD, Dm, Dm};
        P.s[2] = {Wv, WvTh, 16, 16, 0, DD, DD, Dm, Dm};
        P.s[3] = {Wo, WoTh, 16, 16, 1, 0, 0, Dm, Dm};
        P.s[4] = {W1, W1Th, 64, 16, 0, 0, 0, Dm, MIDm};
        P.s[5] = {W2, W2Th, 16, 64, 0, 0, 0, MIDm, Dm};
        weights_prep<<<6144, tb>>>(P);
    }
    concat_bias<<<16, 256>>>(bq, bk, bqk);

    // 1) t12T[z=b*2+half] = BDf[half] @ xdf[z]^T  (M=384, N=2048, K=320, z=8)
    tcg(mk1(BDf, xdf), 1, nullptr, t12Th,
        384, Sm, KD, KD, KD, Sm, 384LL * KD, (long long)Sm * KD, 384LL * Sm, 8,
        nullptr, 0, 0, 2, 0, /*shA=*/0, /*mskA=*/1, /*mskB=*/0x7FFFFFFF);

    // 1b) fold over s: t12Tf[half*4+b][384, KF]
    fold_t12<<<(int)((8LL * 384 * KF + 255) / 256), 256>>>(t12Th, t12Tf);

    // 2) merged cp/sp: cps[z] = CSf[z>>2] @ t12Tf[z]^T  (M=1152,N=384,K=1088,z=8)
    tcg(mk1(CSf, t12Tf), 1, cps, nullptr,
        FR, FC, KF, KF, KF, FC, (long long)FR * KF, 384LL * KF, (long long)FR * FC, 8,
        nullptr, 0, 0, 0, 0, /*shA=*/2, /*mskA=*/0x7FFFFFFF, /*mskB=*/7);

    // 3) xd = LN1(x_dec + fftmerge(cps)), fused; fp16 into stacked qk-A buffer
    ln1_fft<<<BSm, 128>>>(x_dec, cps, ln1g, ln1b, xd, xqkh);

    // 5) merged q/k projections: z=8, 1-pass, fp16 logits out
    tcg(mk1(xqkh, WqkTh), 1, nullptr, qkh,
        BSm, Dm, Dm, Dm, Dm, Dm, BSD, DD, BSD, 8, bqk, Dm, 0, 2, 1,
        /*shA=*/2, /*mskA=*/0x7FFFFFFF, /*mskB=*/7);

    // 6) vsT[z=h*4+b] = WvT_h @ x_enc[b]^T + bv_h, fp16 out, 1-pass; z=16
    tcg(mk1(WvTh, xqkh + BSD), 1, nullptr, vsTh,
        Dm, Sm, Dm, Dm, Dm, Sm, DD, SD, SD, 16, bv, Dm, 0, 2, 2,
        /*shA=*/2, /*mskA=*/0x7FFFFFFF, /*mskB=*/3);

    // 7) softmax over heads: q, k (+transpose), fp16 in/out
    softmax_h4<<<(int)(BSD / 4 / 256), 256>>>(qkh, qsh);
    softmax_trans<<<dim3(Sm / 32, Dm / 32, Bm), tb>>>(qkh + 4 * BSD, ksTh);

    // 8) gcDE[z][d,e] = ksT @ vsT^T  (M=512(d), N=512(e), K=2048, z=16), fp16 out
    tcg(mk1(ksTh, vsTh), 1, nullptr, gcDE,
        Dm, Dm, Sm, Sm, Sm, Dm, SD, SD, DD, 16, nullptr, 0, 0, 2, 0);

    // 9) Mt[z][n,d] = WoT_{z>>2} @ gcDE[z]^T  (M=N=K=512, z=16)
    tcg(mk1(WoTh, gcDE), 1, nullptr, Mth,
        Dm, Dm, Dm, Dm, Dm, Dm, DD, DD, DD, 16, nullptr, 0, 0, 2, 0,
        /*shA=*/2, /*mskA=*/0x7FFFFFFF, /*mskB=*/15);

    // 10) attn[b][s,n] = sum_h qs_h[b] @ Mt[h*4+b]^T + bo  (4 passes; z=4)
    {
        TcPasses P{};
        for (int h = 0; h < Hn; h++) {
            P.A[h] = qsh + (long long)h * Bm * SD;
            P.B[h] = Mth + (long long)h * Bm * DD;
        }
        tcg(P, 4, attn, nullptr,
            Sm, Dm, Dm, Dm, Dm, Dm, SD, DD, SD, Bm, bo, 0, 0, 0, 1,
            /*shA=*/0, /*mskA=*/0x7FFFFFFF, /*mskB=*/3);
    }

    // 11) x2 = LN2(xd + attn), fp16 out
    ln_split<<<BSm, 128>>>(xd, attn, ln2g, ln2b, x2, x2h);

    // 12) mid = selu(x2 @ W1 + b1), fp16 out, 1-pass
    tcg(mk1(x2h, W1Th), 1, nullptr, midh,
        BSm, MIDm, Dm, Dm, Dm, MIDm, 0, 0, 0, 1, b1, 0, 1, 2, 1);

    // 13) ff = mid @ W2 + b2, 1-pass
    tcg(mk1(midh, W2Th), 1, ff, nullptr,
        BSm, Dm, MIDm, MIDm, MIDm, Dm, 0, 0, 0, 1, b2, 0, 0, 0, 1);

    // 14) out = LN3(x2 + ff)
    ln_split<<<BSm, 128>>>(x2, ff, ln3g, ln3b, outp, nullptr);
}

// round 14
// speedup vs baseline: 2.5537x; 1.0350x over previous
#include <cuda_runtime.h>
#include <cuda_fp16.h>
#include <math.h>
#include <stdint.h>

typedef __half hlf;

static constexpr int Dm = 512, Hn = 4, MIDm = 2048, Bm = 4, Sm = 2048;
static constexpr int BSm = Bm * Sm;                      // 8192
static constexpr long long BSD = (long long)BSm * Dm;    // 4194304
static constexpr long long SD  = (long long)Sm * Dm;     // 1048576
static constexpr long long DD  = (long long)Dm * Dm;     // 262144

// FFT-symmetry tile sizes
static constexpr int FR = 1152;   // S-axis rows computed (need 0..1024)
static constexpr int FC = 384;    // D-axis cols computed (need 0..256)
static constexpr int KF = 1152;   // folded S length (1025 padded; /128 for GEMM N)
static constexpr int KD = 320;    // folded D length (257 padded to /64)

// ---------------------------------------------------------------------------
// Static device scratch
// ---------------------------------------------------------------------------
__device__ __align__(256) hlf g_CSf[2 * FR * KF];                  // [cos;sin] S-folded
__device__ __align__(256) hlf g_BDf[2 * 384 * KD];                 // [cos;sin] D-folded
__device__ __align__(256) hlf g_xdff[8 * KF * KD];                 // [half*4+b][1152,320]
__device__ __align__(256) hlf g_t12Tf[8 * 384 * KF];               // [half*4+b][384,1152]
__device__ __align__(256) float g_cps[8 * FR * FC];                // cp z=0..3, sp z=4..7
__device__ __align__(256) float g_xd[4194304];
// stacked A: [0..BSD)=LN1(xd) fp16, [BSD..2BSD)=x_enc fp16
__device__ __align__(256) hlf g_xqkh[8388608];
__device__ __align__(256) hlf g_qkh[16777216];                     // [4][b,s,d] q logits
__device__ __align__(256) hlf g_qsh[16777216];
__device__ __align__(256) hlf g_kvTh[33554432];                    // [32][.,S]: k z<16, v z>=16
__device__ __align__(256) hlf g_gcDE[4194304];                     // [z][D,E]
__device__ __align__(256) hlf g_Mth[4194304];                      // [z][N,D]
__device__ __align__(256) hlf g_WqTh[1048576];                     // [h][512,512]
__device__ __align__(256) hlf g_WkvTh[2097152];                    // [Wk0..3;Wv0..3]
__device__ __align__(256) float g_bkv[4096];                       // [bk;bv]
__device__ __align__(256) hlf g_WoTh[1048576];                     // [h][512,512] (n,e)
__device__ __align__(256) hlf g_W1Th[1048576];                     // [2048,512]
__device__ __align__(256) hlf g_W2Th[1048576];                     // [512,2048]
__device__ __align__(256) hlf g_attnh[4194304];
__device__ __align__(256) float g_x2[4194304];
__device__ __align__(256) hlf g_x2h[4194304];
__device__ __align__(256) hlf g_midh[16777216];
__device__ __align__(256) hlf g_ffh[4194304];

// ---------------------------------------------------------------------------
// Helpers
// ---------------------------------------------------------------------------
__device__ __forceinline__ uint32_t smem_u32(const void* p) {
    uint32_t a;
    asm("{ .reg .u64 t; cvta.to.shared.u64 t, %1; cvt.u32.u64 %0, t; }" : "=r"(a) : "l"(p));
    return a;
}
__device__ __forceinline__ float selu_f(float x) {
    const float sc = 1.0507009873554805f, al = 1.6732632423543772f;
    return x > 0.f ? sc * x : sc * al * (expf(x) - 1.f);
}
__device__ __forceinline__ uint32_t packhl(hlf a, hlf b) {
    return ((uint32_t)*(uint16_t*)&b << 16) | (uint32_t)*(uint16_t*)&a;
}
__device__ __forceinline__ uint32_t packf2(float a, float b) {
    hlf ha = __float2half_rn(a), hb = __float2half_rn(b);
    return packhl(ha, hb);
}

#define LDSM_X4(r0, r1, r2, r3, addr) \
    asm volatile("ldmatrix.sync.aligned.m8n8.x4.shared.b16 {%0,%1,%2,%3}, [%4];" \
        : "=r"(r0), "=r"(r1), "=r"(r2), "=r"(r3) : "r"(addr))

#define MMA_F16(d, a, b0, b1) \
    asm volatile("mma.sync.aligned.m16n8k16.row.col.f32.f16.f16.f32 " \
        "{%0,%1,%2,%3}, {%4,%5,%6,%7}, {%8,%9}, {%0,%1,%2,%3};" \
        : "+f"((d)[0]), "+f"((d)[1]), "+f"((d)[2]), "+f"((d)[3]) \
        : "r"((a)[0]), "r"((a)[1]), "r"((a)[2]), "r"((a)[3]), "r"(b0), "r"(b1))

#define CP_ASYNC16(dst, src) \
    asm volatile("cp.async.cg.shared.global [%0], [%1], 16;" :: "r"(dst), "l"(src))
#define CP_COMMIT() asm volatile("cp.async.commit_group;")
#define CP_WAIT1()  asm volatile("cp.async.wait_group 1;")

// ---------------------------------------------------------------------------
// HMMA GEMM, cp.async 3-stage pipeline.
// Block 128x128, 8 warps, warp 64x32, BK=64, 2 CTA/SM.
// C[z] = sum_p A_p[(z>>shA)&mskA] @ B_p[z&mskB]^T (+bias col[zb]/row[za])(+SELU)
// SPLIT: 0 = fp32 out, 2 = fp16 out.
// ---------------------------------------------------------------------------
struct TcPasses { const hlf* A[4]; const hlf* B[4]; };

static constexpr int BKg = 64;
static constexpr int LDSg = BKg + 8;
static constexpr int TILE_B = 128 * LDSg * 2;
static constexpr int STAGES = 3;
static constexpr int SMEM_B_OFF = STAGES * TILE_B;
static constexpr int SMEM_BIAS_OFF = 2 * STAGES * TILE_B;
static constexpr int SMEM_G = SMEM_BIAS_OFF + 128 * 4;

template <int ACT, int SPLIT, int BMODE>   // BMODE: 0 none, 1 col (zb), 2 row (za)
__global__ __launch_bounds__(256, 2) void mma_gemm(
    TcPasses P, int npass,
    float* __restrict__ C, hlf* __restrict__ Chi,
    int K, int lda, int ldb, int ldc,
    long long sA, long long sB, long long sC,
    const float* __restrict__ bias, long long sBias,
    int shA, int mskA, int mskB)
{
    extern __shared__ char smem[];
    float* bias_s = (float*)(smem + SMEM_BIAS_OFF);
    const uint32_t sA0 = smem_u32(smem);
    const uint32_t sB0 = sA0 + SMEM_B_OFF;

    const int tid = threadIdx.x;
    const int lane = tid & 31;
    const int wid = tid >> 5;
    const int wm = (wid & 1) * 64;
    const int wn = (wid >> 1) * 32;
    const int z = blockIdx.z;
    const int za = (z >> shA) & mskA;
    const int zb = z & mskB;
    const int m0 = blockIdx.y * 128, n0 = blockIdx.x * 128;

    if (tid < 128) {
        if (BMODE == 0) bias_s[tid] = 0.f;
        else if (BMODE == 1) bias_s[tid] = bias[(long long)zb * sBias + n0 + tid];
        else bias_s[tid] = bias[(long long)za * sBias + m0 + tid];
    }

    float acc[4][4][4];
#pragma unroll
    for (int i = 0; i < 4; i++)
#pragma unroll
        for (int j = 0; j < 4; j++)
#pragma unroll
            for (int k = 0; k < 4; k++) acc[i][j][k] = 0.f;

    const int cpp = K / BKg;
    const int total = npass * cpp;

    const int crow = tid >> 3;
    const int ccol = (tid & 7) * 8;

    auto loadStage = [&](int c, int stg) {
        int p = c / cpp;
        int k0 = (c - p * cpp) * BKg;
        const hlf* Ab = P.A[p] + (long long)za * sA + k0 + ccol;
        const hlf* Bb = P.B[p] + (long long)zb * sB + k0 + ccol;
        uint32_t da = sA0 + stg * TILE_B + (crow * LDSg + ccol) * 2;
        uint32_t db = sB0 + stg * TILE_B + (crow * LDSg + ccol) * 2;
#pragma unroll
        for (int i = 0; i < 4; i++) {
            int row = crow + i * 32;
            CP_ASYNC16(da + i * 32 * LDSg * 2, Ab + (long long)(m0 + row) * lda);
            CP_ASYNC16(db + i * 32 * LDSg * 2, Bb + (long long)(n0 + row) * ldb);
        }
    };

    loadStage(0, 0); CP_COMMIT();
    loadStage(1, 1); CP_COMMIT();

    const int lrow16 = lane & 15;
    const int lhalf = lane >> 4;

    for (int c = 0; c < total; c++) {
        CP_WAIT1();
        __syncthreads();
        const int stg = c % STAGES;
        const uint32_t aB = sA0 + stg * TILE_B;
        const uint32_t bB = sB0 + stg * TILE_B;
#pragma unroll
        for (int ks = 0; ks < 4; ks++) {
            uint32_t af[4][4];
#pragma unroll
            for (int mi = 0; mi < 4; mi++) {
                uint32_t addr = aB + (uint32_t)(((wm + mi * 16 + lrow16) * LDSg
                                                + ks * 16 + lhalf * 8) * 2);
                LDSM_X4(af[mi][0], af[mi][1], af[mi][2], af[mi][3], addr);
            }
            uint32_t bfr[2][4];
#pragma unroll
            for (int nj = 0; nj < 2; nj++) {
                uint32_t addr = bB + (uint32_t)(((wn + nj * 16 + lrow16) * LDSg
                                                + ks * 16 + lhalf * 8) * 2);
                LDSM_X4(bfr[nj][0], bfr[nj][1], bfr[nj][2], bfr[nj][3], addr);
            }
#pragma unroll
            for (int mi = 0; mi < 4; mi++)
#pragma unroll
                for (int ni = 0; ni < 4; ni++) {
                    const int nj = ni >> 1, sub = ni & 1;
                    MMA_F16(acc[mi][ni], af[mi], bfr[nj][sub], bfr[nj][sub + 2]);
                }
        }
        if (c + 2 < total) loadStage(c + 2, (c + 2) % STAGES);
        CP_COMMIT();
    }

    const int cr = lane >> 2;
    const int cc = (lane & 3) * 2;
#pragma unroll
    for (int mi = 0; mi < 4; mi++) {
#pragma unroll
        for (int ni = 0; ni < 4; ni++) {
            const int bn = wn + ni * 8 + cc;
            const int gn = n0 + bn;
            const int rm = wm + mi * 16 + cr;
            const long long r0 = m0 + rm;
            const long long r1 = r0 + 8;
            float v0 = acc[mi][ni][0], v1 = acc[mi][ni][1];
            float v2 = acc[mi][ni][2], v3 = acc[mi][ni][3];
            if (BMODE == 1) {
                v0 += bias_s[bn]; v1 += bias_s[bn + 1];
                v2 += bias_s[bn]; v3 += bias_s[bn + 1];
            } else if (BMODE == 2) {
                v0 += bias_s[rm]; v1 += bias_s[rm];
                v2 += bias_s[rm + 8]; v3 += bias_s[rm + 8];
            }
            if (ACT == 1) { v0 = selu_f(v0); v1 = selu_f(v1); v2 = selu_f(v2); v3 = selu_f(v3); }
            if (SPLIT == 2) {
                *(uint32_t*)(Chi + (long long)z * sC + r0 * ldc + gn) = packf2(v0, v1);
                *(uint32_t*)(Chi + (long long)z * sC + r1 * ldc + gn) = packf2(v2, v3);
            } else {
                *(float2*)(C + (long long)z * sC + r0 * ldc + gn) = make_float2(v0, v1);
                *(float2*)(C + (long long)z * sC + r1 * ldc + gn) = make_float2(v2, v3);
            }
        }
    }
}

// ---------------------------------------------------------------------------
// Elementwise kernels
// ---------------------------------------------------------------------------
// Folded S-axis DFT: [cos;sin], each [FR, KF], cols > 1024 zero-padded.
__global__ void init_dft_fold(hlf* __restrict__ o)
{
    long long idx = (long long)blockIdx.x * blockDim.x + threadIdx.x;
    if (idx >= 2LL * FR * KF) return;
    int half = (int)(idx / ((long long)FR * KF));
    int rem = (int)(idx % ((long long)FR * KF));
    int i = rem / KF, j = rem % KF;
    float v = 0.f;
    if (j <= 1024) {
        int p = (int)(((long long)i * j) % Sm);
        float x = 2.0f * (float)p / (float)Sm;
        float s, c;
        sincospif(x, &s, &c);
        v = half ? s : c;
    }
    o[idx] = __float2half_rn(v);
}

// Folded D-axis DFT: [cos;sin], each [384, KD], cols > 256 zero-padded.
__global__ void init_bdf(hlf* __restrict__ o)
{
    long long idx = (long long)blockIdx.x * blockDim.x + threadIdx.x;
    if (idx >= 2LL * 384 * KD) return;
    int half = (int)(idx / (384 * KD));
    int rem = (int)(idx % (384 * KD));
    int i = rem / KD, k = rem % KD;
    float v = 0.f;
    if (k <= 256) {
        int p = (int)(((long long)i * k) % Dm);
        float x = 2.0f * (float)p / (float)Dm;
        float s, c;
        sincospif(x, &s, &c);
        v = half ? s : c;
    }
    o[idx] = __float2half_rn(v);
}

// Double fold of x_dec: S-fold (rows j, 2048-j) then D-fold, both halves.
// xdff[(half*4+b)][j,k]: half=0: cosD fold of (row_j+row_m); half=1: sinD fold of (row_j-row_m).
// One block per (b, j).
__global__ void xdec_fold2(const float* __restrict__ x, hlf* __restrict__ xdff)
{
    __shared__ float rj[512], rm[512];
    const int j = blockIdx.x % KF;
    const int b = blockIdx.x / KF;
    const int t = threadIdx.x;                 // 128
    hlf* co = xdff + ((long long)(0 * 4 + b) * KF + j) * KD;
    hlf* si = xdff + ((long long)(1 * 4 + b) * KF + j) * KD;
    if (j > 1024) {
#pragma unroll
        for (int q = 0; q < 3; q++) {
            int k = t + q * 128;
            if (k < KD) { co[k] = __float2half_rn(0.f); si[k] = __float2half_rn(0.f); }
        }
        return;
    }
    const float* xb = x + (long long)b * SD;
    ((float4*)rj)[t] = ((const float4*)(xb + (long long)j * Dm))[t];
    if (j >= 1 && j <= 1023)
        ((float4*)rm)[t] = ((const float4*)(xb + (long long)(Sm - j) * Dm))[t];
    else
        ((float4*)rm)[t] = make_float4(0.f, 0.f, 0.f, 0.f);
    __syncthreads();
#pragma unroll
    for (int q = 0; q < 3; q++) {
        int k = t + q * 128;
        if (k >= KD) break;
        float cv = 0.f, sv = 0.f;
        if (k == 0) {
            cv = rj[0] + rm[0];
        } else if (k == 256) {
            cv = rj[256] + rm[256];
        } else if (k < 256) {
            float yck = rj[k] + rm[k], yck2 = rj[512 - k] + rm[512 - k];
            float ysk = rj[k] - rm[k], ysk2 = rj[512 - k] - rm[512 - k];
            cv = yck + yck2;
            sv = ysk - ysk2;
        }
        co[k] = __float2half_rn(cv);
        si[k] = __float2half_rn(sv);
    }
}

// fp32 -> fp16 (hi only), 8 elems/thread
__global__ void split_k8(const float* __restrict__ in, hlf* __restrict__ h, long long n8)
{
    long long i = (long long)blockIdx.x * blockDim.x + threadIdx.x;
    if (i >= n8) return;
    long long base = i * 8;
    float4 a = *(const float4*)(in + base);
    float4 b = *(const float4*)(in + base + 4);
    uint4 ho;
    ho.x = packf2(a.x, a.y); ho.y = packf2(a.z, a.w);
    ho.z = packf2(b.x, b.y); ho.w = packf2(b.z, b.w);
    *(uint4*)(h + base) = ho;
}

// All six weight transposes in one launch; every segment is exactly 1024 tiles.
struct WSeg { const float* in; hlf* out; int nTx, nTy, wo; long long sIn, sOut; int R, C; };
struct WPrep { WSeg s[6]; };

__global__ void weights_prep(WPrep P)
{
    __shared__ float t[32][33];
    const int seg = blockIdx.x >> 10;
    const int id = blockIdx.x & 1023;
    const WSeg w = P.s[seg];
    const int tilesPerZ = w.nTx * w.nTy;
    const int bz = id / tilesPerZ;
    const int rem = id % tilesPerZ;
    const int bx = rem % w.nTx;
    const int by = rem / w.nTx;
    const int tx = threadIdx.x, ty = threadIdx.y;
    if (!w.wo) {
        const int c0 = bx * 32, r0 = by * 32;
        const float* ib = w.in + (long long)bz * w.sIn;
#pragma unroll
        for (int i = 0; i < 4; i++)
            t[ty + i * 8][tx] = ib[(long long)(r0 + ty + i * 8) * w.C + c0 + tx];
        __syncthreads();
#pragma unroll
        for (int i = 0; i < 4; i++) {
            float v = t[tx][ty + i * 8];
            long long o = (long long)bz * w.sOut + (long long)(c0 + ty + i * 8) * w.R + r0 + tx;
            w.out[o] = __float2half_rn(v);
        }
    } else {
        const int n0 = bx * 32, d0 = by * 32, h = bz;
#pragma unroll
        for (int i = 0; i < 4; i++) {
            int d = d0 + ty + i * 8;
            t[ty + i * 8][tx] = w.in[(long long)(d * 4 + h) * Dm + n0 + tx];
        }
        __syncthreads();
#pragma unroll
        for (int i = 0; i < 4; i++) {
            float v = t[tx][ty + i * 8];
            long long o = (long long)h * DD + (long long)(n0 + ty + i * 8) * Dm + d0 + tx;
            w.out[o] = __float2half_rn(v);
        }
    }
}

__global__ void concat_bias(const float* __restrict__ a, const float* __restrict__ b,
                            float* __restrict__ o)
{
    int i = blockIdx.x * blockDim.x + threadIdx.x;
    if (i < 2048) o[i] = a[i];
    else if (i < 4096) o[i] = b[i - 2048];
}

// softmax over H=4 heads (stride BSD), fp16 in/out; 4 elems/thread
__global__ void softmax_h4(const hlf* __restrict__ q, hlf* __restrict__ oh)
{
    long long i4 = (long long)blockIdx.x * blockDim.x + threadIdx.x;
    if (i4 >= BSD / 4) return;
    long long base = i4 * 4;
    float v[4][4];
#pragma unroll
    for (int h = 0; h < 4; h++) {
        uint2 raw = *(const uint2*)(q + h * BSD + base);
        hlf* hp = (hlf*)&raw;
#pragma unroll
        for (int j = 0; j < 4; j++) v[h][j] = __half2float(hp[j]);
    }
    float r[4][4];
#pragma unroll
    for (int j = 0; j < 4; j++) {
        float m = fmaxf(fmaxf(v[0][j], v[1][j]), fmaxf(v[2][j], v[3][j]));
        float e0 = expf(v[0][j] - m), e1 = expf(v[1][j] - m);
        float e2 = expf(v[2][j] - m), e3 = expf(v[3][j] - m);
        float inv = 1.f / (e0 + e1 + e2 + e3);
        r[0][j] = e0 * inv; r[1][j] = e1 * inv; r[2][j] = e2 * inv; r[3][j] = e3 * inv;
    }
#pragma unroll
    for (int h = 0; h < 4; h++) {
        uint2 ho = make_uint2(packf2(r[h][0], r[h][1]), packf2(r[h][2], r[h][3]));
        *(uint2*)(oh + h * BSD + base) = ho;
    }
}

// in-place softmax over h for ksT region: elems kv[(h*4+b)*SD + off], 8/thread
__global__ void softmax_kT(hlf* __restrict__ kv)
{
    long long idx = (long long)blockIdx.x * blockDim.x + threadIdx.x;
    const long long PER_B = SD / 8;           // 131072
    if (idx >= 4 * PER_B) return;
    const int b = (int)(idx / PER_B);
    const long long off = (idx % PER_B) * 8;
    uint4 raw[4];
#pragma unroll
    for (int h = 0; h < 4; h++)
        raw[h] = *(const uint4*)(kv + (long long)(h * 4 + b) * SD + off);
    float v[4][8];
#pragma unroll
    for (int h = 0; h < 4; h++) {
        hlf* hp = (hlf*)&raw[h];
#pragma unroll
        for (int j = 0; j < 8; j++) v[h][j] = __half2float(hp[j]);
    }
#pragma unroll
    for (int j = 0; j < 8; j++) {
        float m = fmaxf(fmaxf(v[0][j], v[1][j]), fmaxf(v[2][j], v[3][j]));
        float e0 = expf(v[0][j] - m), e1 = expf(v[1][j] - m);
        float e2 = expf(v[2][j] - m), e3 = expf(v[3][j] - m);
        float inv = 1.f / (e0 + e1 + e2 + e3);
        v[0][j] = e0 * inv; v[1][j] = e1 * inv; v[2][j] = e2 * inv; v[3][j] = e3 * inv;
    }
#pragma unroll
    for (int h = 0; h < 4; h++) {
        uint4 o;
        o.x = packf2(v[h][0], v[h][1]); o.y = packf2(v[h][2], v[h][3]);
        o.z = packf2(v[h][4], v[h][5]); o.w = packf2(v[h][6], v[h][7]);
        *(uint4*)(kv + (long long)(h * 4 + b) * SD + off) = o;
    }
}

// LN1 fused with FFT quadrant reconstruction (cps layout unchanged).
__global__ void ln1_fft(const float* __restrict__ x_dec, const float* __restrict__ cps,
                        const float* __restrict__ g, const float* __restrict__ be,
                        float* __restrict__ out, hlf* __restrict__ oh)
{
    __shared__ float red[4];
    const long long row = blockIdx.x;        // b*2048 + s
    const int b = (int)(row >> 11);
    const int s = (int)(row & 2047);
    const int t = threadIdx.x;               // 128

    const int ip = (s <= 1024) ? s : (Sm - s);
    const bool fi = (s > 1024);
    const float* cpr = cps + (long long)b * FR * FC + (long long)ip * FC;
    const float* spr = cpr + 4LL * FR * FC;

    float4 vx = ((const float4*)(x_dec + row * Dm))[t];
    float v4[4];
#pragma unroll
    for (int j = 0; j < 4; j++) {
        int d = t * 4 + j;
        int dp = (d <= 256) ? d : (Dm - d);
        bool fd = (d > 256);
        float c = cpr[dp], sv = spr[dp];
        float xfv = c + ((fi != fd) ? sv : -sv);
        v4[j] = ((const float*)&vx)[j] + xfv;
    }

    float ssum = v4[0] + v4[1] + v4[2] + v4[3];
#pragma unroll
    for (int o = 16; o > 0; o >>= 1) ssum += __shfl_xor_sync(0xffffffffu, ssum, o);
    if ((t & 31) == 0) red[t >> 5] = ssum;
    __syncthreads();
    float mu = (red[0] + red[1] + red[2] + red[3]) * (1.f / (float)Dm);
    __syncthreads();
    float d0 = v4[0] - mu, d1 = v4[1] - mu, d2 = v4[2] - mu, d3 = v4[3] - mu;
    float q = d0 * d0 + d1 * d1 + d2 * d2 + d3 * d3;
#pragma unroll
    for (int o = 16; o > 0; o >>= 1) q += __shfl_xor_sync(0xffffffffu, q, o);
    if ((t & 31) == 0) red[t >> 5] = q;
    __syncthreads();
    float var = (red[0] + red[1] + red[2] + red[3]) * (1.f / (float)Dm);
    float rstd = rsqrtf(var + 1e-5f);
    float4 vg = ((const float4*)g)[t];
    float4 vbe = ((const float4*)be)[t];
    float4 o4;
    o4.x = fmaf(vg.x, d0 * rstd, vbe.x);
    o4.y = fmaf(vg.y, d1 * rstd, vbe.y);
    o4.z = fmaf(vg.z, d2 * rstd, vbe.z);
    o4.w = fmaf(vg.w, d3 * rstd, vbe.w);
    ((float4*)(out + row * Dm))[t] = o4;
    long long o = row * Dm + t * 4;
    *(uint2*)(oh + o) = make_uint2(packf2(o4.x, o4.y), packf2(o4.z, o4.w));
}

// LN over last dim of (a fp32 + b fp16); outputs fp32 and optional fp16.
__global__ void ln_hb(const float* __restrict__ a, const hlf* __restrict__ bres,
                      const float* __restrict__ g, const float* __restrict__ be,
                      float* __restrict__ out, hlf* __restrict__ oh)
{
    __shared__ float red[4];
    long long row = blockIdx.x;
    int t = threadIdx.x;  // 128
    float4 va = ((const float4*)(a + row * Dm))[t];
    uint2 vbr = ((const uint2*)(bres + row * Dm))[t];
    hlf* bp = (hlf*)&vbr;
    float4 v = make_float4(va.x + __half2float(bp[0]), va.y + __half2float(bp[1]),
                           va.z + __half2float(bp[2]), va.w + __half2float(bp[3]));
    float s = v.x + v.y + v.z + v.w;
#pragma unroll
    for (int o = 16; o > 0; o >>= 1) s += __shfl_xor_sync(0xffffffffu, s, o);
    if ((t & 31) == 0) red[t >> 5] = s;
    __syncthreads();
    float mu = (red[0] + red[1] + red[2] + red[3]) * (1.f / (float)Dm);
    __syncthreads();
    float d0 = v.x - mu, d1 = v.y - mu, d2 = v.z - mu, d3 = v.w - mu;
    float q = d0 * d0 + d1 * d1 + d2 * d2 + d3 * d3;
#pragma unroll
    for (int o = 16; o > 0; o >>= 1) q += __shfl_xor_sync(0xffffffffu, q, o);
    if ((t & 31) == 0) red[t >> 5] = q;
    __syncthreads();
    float var = (red[0] + red[1] + red[2] + red[3]) * (1.f / (float)Dm);
    float rstd = rsqrtf(var + 1e-5f);
    float4 vg = ((const float4*)g)[t];
    float4 vbe = ((const float4*)be)[t];
    float4 o4;
    o4.x = fmaf(vg.x, d0 * rstd, vbe.x);
    o4.y = fmaf(vg.y, d1 * rstd, vbe.y);
    o4.z = fmaf(vg.z, d2 * rstd, vbe.z);
    o4.w = fmaf(vg.w, d3 * rstd, vbe.w);
    ((float4*)(out + row * Dm))[t] = o4;
    if (oh) {
        long long o = row * Dm + t * 4;
        *(uint2*)(oh + o) = make_uint2(packf2(o4.x, o4.y), packf2(o4.z, o4.w));
    }
}

// ---------------------------------------------------------------------------
// Host
// ---------------------------------------------------------------------------
static TcPasses mk1(const hlf* Ah, const hlf* Bh) {
    TcPasses P{};
    P.A[0] = Ah; P.B[0] = Bh;
    return P;
}

static void tcg(const TcPasses& P, int np, float* C, hlf* Ch,
                int M, int N, int K, int lda, int ldb, int ldc,
                long long sA, long long sB, long long sC, int batch,
                const float* bias, long long sBias, int act, int split, int bmode,
                int shA = 0, int mskA = 0x7FFFFFFF, int mskB = 0x7FFFFFFF)
{
    dim3 grid(N / 128, M / 128, batch), block(256);
    if (act == 1)
        mma_gemm<1, 2, 1><<<grid, block, SMEM_G>>>(P, np, C, Ch, K, lda, ldb, ldc, sA, sB, sC, bias, sBias, shA, mskA, mskB);
    else if (split == 2 && bmode == 2)
        mma_gemm<0, 2, 2><<<grid, block, SMEM_G>>>(P, np, C, Ch, K, lda, ldb, ldc, sA, sB, sC, bias, sBias, shA, mskA, mskB);
    else if (split == 2 && bmode == 1)
        mma_gemm<0, 2, 1><<<grid, block, SMEM_G>>>(P, np, C, Ch, K, lda, ldb, ldc, sA, sB, sC, bias, sBias, shA, mskA, mskB);
    else if (split == 2)
        mma_gemm<0, 2, 0><<<grid, block, SMEM_G>>>(P, np, C, Ch, K, lda, ldb, ldc, sA, sB, sC, bias, sBias, shA, mskA, mskB);
    else if (bmode == 1)
        mma_gemm<0, 0, 1><<<grid, block, SMEM_G>>>(P, np, C, Ch, K, lda, ldb, ldc, sA, sB, sC, bias, sBias, shA, mskA, mskB);
    else
        mma_gemm<0, 0, 0><<<grid, block, SMEM_G>>>(P, np, C, Ch, K, lda, ldb, ldc, sA, sB, sC, bias, sBias, shA, mskA, mskB);
}

#define GETSYM(var, sym) do { void* _p; cudaGetSymbolAddress(&_p, sym); var = (decltype(var))_p; } while (0)

extern "C" void kernel_launch(void* const* d_in, const int* in_sizes, int n_in,
                              void* d_out, int out_size)
{
    const float* x_enc = (const float*)d_in[0];
    const float* x_dec = (const float*)d_in[1];
    const float* Wq = (const float*)d_in[2];
    const float* bq = (const float*)d_in[3];
    const float* Wk = (const float*)d_in[4];
    const float* bk = (const float*)d_in[5];
    const float* Wv = (const float*)d_in[6];
    const float* bv = (const float*)d_in[7];
    const float* Wo = (const float*)d_in[8];
    const float* bo = (const float*)d_in[9];
    const float* ln1g = (const float*)d_in[10];
    const float* ln1b = (const float*)d_in[11];
    const float* ln2g = (const float*)d_in[12];
    const float* ln2b = (const float*)d_in[13];
    const float* W1 = (const float*)d_in[14];
    const float* b1 = (const float*)d_in[15];
    const float* W2 = (const float*)d_in[16];
    const float* b2 = (const float*)d_in[17];
    const float* ln3g = (const float*)d_in[18];
    const float* ln3b = (const float*)d_in[19];
    float* outp = (float*)d_out;

    hlf *CSf, *BDf, *xdff, *t12Tf, *xqkh, *qkh;
    hlf *qsh, *kvTh, *gcDE, *Mth;
    hlf *WqTh, *WkvTh, *WoTh, *W1Th, *W2Th, *x2h, *midh, *attnh, *ffh;
    float *cps, *xd, *bkv, *x2;
    GETSYM(CSf, g_CSf); GETSYM(BDf, g_BDf); GETSYM(xdff, g_xdff);
    GETSYM(t12Tf, g_t12Tf);
    GETSYM(cps, g_cps);
    GETSYM(xd, g_xd);
    GETSYM(xqkh, g_xqkh); GETSYM(qkh, g_qkh);
    GETSYM(bkv, g_bkv);
    GETSYM(qsh, g_qsh); GETSYM(kvTh, g_kvTh);
    GETSYM(gcDE, g_gcDE); GETSYM(Mth, g_Mth);
    GETSYM(WqTh, g_WqTh); GETSYM(WkvTh, g_WkvTh); GETSYM(WoTh, g_WoTh);
    GETSYM(W1Th, g_W1Th); GETSYM(W2Th, g_W2Th);
    GETSYM(attnh, g_attnh); GETSYM(x2, g_x2); GETSYM(x2h, g_x2h);
    GETSYM(midh, g_midh); GETSYM(ffh, g_ffh);

    cudaFuncSetAttribute(mma_gemm<0, 0, 0>, cudaFuncAttributeMaxDynamicSharedMemorySize, SMEM_G);
    cudaFuncSetAttribute(mma_gemm<0, 0, 1>, cudaFuncAttributeMaxDynamicSharedMemorySize, SMEM_G);
    cudaFuncSetAttribute(mma_gemm<0, 2, 0>, cudaFuncAttributeMaxDynamicSharedMemorySize, SMEM_G);
    cudaFuncSetAttribute(mma_gemm<0, 2, 1>, cudaFuncAttributeMaxDynamicSharedMemorySize, SMEM_G);
    cudaFuncSetAttribute(mma_gemm<0, 2, 2>, cudaFuncAttributeMaxDynamicSharedMemorySize, SMEM_G);
    cudaFuncSetAttribute(mma_gemm<1, 2, 1>, cudaFuncAttributeMaxDynamicSharedMemorySize, SMEM_G);

    dim3 tb(32, 8);

    // 0) folded DFT matrices (fp16)
    init_dft_fold<<<(int)((2LL * FR * KF + 255) / 256), 256>>>(CSf);
    init_bdf<<<(int)((2LL * 384 * KD + 255) / 256), 256>>>(BDf);

    // inputs: x_enc fp16; x_dec double-folded
    split_k8<<<(int)(BSD / 8 / 256), 256>>>(x_enc, xqkh + BSD, BSD / 8);
    xdec_fold2<<<Bm * KF, 128>>>(x_dec, xdff);

    // weight prep: one launch, 6 segments x 1024 tiles
    {
        WPrep P{};
        P.s[0] = {Wq, WqTh, 16, 16, 0, DD, DD, Dm, Dm};
        P.s[1] = {Wk, WkvTh, 16, 16, 0, DD, DD, Dm, Dm};
        P.s[2] = {Wv, WkvTh + 4 * DD, 16, 16, 0, DD, DD, Dm, Dm};
        P.s[3] = {Wo, WoTh, 16, 16, 1, 0, 0, Dm, Dm};
        P.s[4] = {W1, W1Th, 64, 16, 0, 0, 0, Dm, MIDm};
        P.s[5] = {W2, W2Th, 16, 64, 0, 0, 0, MIDm, Dm};
        weights_prep<<<6144, tb>>>(P);
    }
    concat_bias<<<16, 256>>>(bk, bv, bkv);

    // 1) t12Tf[z=half*4+b] = BDf[half] @ xdff[z]^T  (M=384, N=1152, K=320, z=8)
    tcg(mk1(BDf, xdff), 1, nullptr, t12Tf,
        384, KF, KD, KD, KD, KF, 384LL * KD, (long long)KF * KD, 384LL * KF, 8,
        nullptr, 0, 0, 2, 0, /*shA=*/2, /*mskA=*/0x7FFFFFFF, /*mskB=*/7);

    // 2) merged cp/sp: cps[z] = CSf[z>>2] @ t12Tf[z]^T  (M=1152,N=384,K=1152,z=8)
    tcg(mk1(CSf, t12Tf), 1, cps, nullptr,
        FR, FC, KF, KF, KF, FC, (long long)FR * KF, 384LL * KF, (long long)FR * FC, 8,
        nullptr, 0, 0, 0, 0, /*shA=*/2, /*mskA=*/0x7FFFFFFF, /*mskB=*/7);

    // 3) xd = LN1(x_dec + fftmerge(cps)), fused; fp16 into stacked buffer
    ln1_fft<<<BSm, 128>>>(x_dec, cps, ln1g, ln1b, xd, xqkh);

    // 4) kvT[z=kv*16+h*4+b] = Wkv_{z>>2}^T @ x_enc[b]^T + bkv (row), fp16; z=32
    tcg(mk1(WkvTh, xqkh + BSD), 1, nullptr, kvTh,
        Dm, Sm, Dm, Dm, Dm, Sm, DD, SD, SD, 32, bkv, Dm, 0, 2, 2,
        /*shA=*/2, /*mskA=*/0x7FFFFFFF, /*mskB=*/3);

    // 5) q projections: z=4 (h), 1-pass, fp16 logits
    tcg(mk1(xqkh, WqTh), 1, nullptr, qkh,
        BSm, Dm, Dm, Dm, Dm, Dm, 0, DD, BSD, 4, bq, Dm, 0, 2, 1,
        /*shA=*/0, /*mskA=*/0, /*mskB=*/3);

    // 6) softmax over heads: q (stride BSD), k (in-place on kvT, stride 4*SD)
    softmax_h4<<<(int)(BSD / 4 / 256), 256>>>(qkh, qsh);
    softmax_kT<<<(int)(4 * (SD / 8) / 256), 256>>>(kvTh);

    // 7) gcDE[z][d,e] = ksT @ vsT^T  (M=N=512, K=2048, z=16), fp16 out
    tcg(mk1(kvTh, kvTh + 16 * SD), 1, nullptr, gcDE,
        Dm, Dm, Sm, Sm, Sm, Dm, SD, SD, DD, 16, nullptr, 0, 0, 2, 0);

    // 8) Mt[z][n,d] = WoT_{z>>2} @ gcDE[z]^T  (M=N=K=512, z=16)
    tcg(mk1(WoTh, gcDE), 1, nullptr, Mth,
        Dm, Dm, Dm, Dm, Dm, Dm, DD, DD, DD, 16, nullptr, 0, 0, 2, 0,
        /*shA=*/2, /*mskA=*/0x7FFFFFFF, /*mskB=*/15);

    // 9) attn[b][s,n] = sum_h qs_h[b] @ Mt[h*4+b]^T + bo  (4 passes; z=4), fp16 out
    {
        TcPasses P{};
        for (int h = 0; h < Hn; h++) {
            P.A[h] = qsh + (long long)h * Bm * SD;
            P.B[h] = Mth + (long long)h * Bm * DD;
        }
        tcg(P, 4, nullptr, attnh,
            Sm, Dm, Dm, Dm, Dm, Dm, SD, DD, SD, Bm, bo, 0, 0, 2, 1,
            /*shA=*/0, /*mskA=*/0x7FFFFFFF, /*mskB=*/3);
    }

    // 10) x2 = LN2(xd + attn), fp16 residual in, fp16 out
    ln_hb<<<BSm, 128>>>(xd, attnh, ln2g, ln2b, x2, x2h);

    // 11) mid = selu(x2 @ W1 + b1), fp16 out, 1-pass
    tcg(mk1(x2h, W1Th), 1, nullptr, midh,
        BSm, MIDm, Dm, Dm, Dm, MIDm, 0, 0, 0, 1, b1, 0, 1, 2, 1);

    // 12) ff = mid @ W2 + b2, fp16 out, 1-pass
    tcg(mk1(midh, W2Th), 1, nullptr, ffh,
        BSm, Dm, MIDm, MIDm, MIDm, Dm, 0, 0, 0, 1, b2, 0, 0, 2, 1);

    // 13) out = LN3(x2 + ff)
    ln_hb<<<BSm, 128>>>(x2, ffh, ln3g, ln3b, outp, nullptr);
}

// round 15
// speedup vs baseline: 2.5914x; 1.0148x over previous
#include <cuda_runtime.h>
#include <cuda_fp16.h>
#include <math.h>
#include <stdint.h>

typedef __half hlf;

static constexpr int Dm = 512, Hn = 4, MIDm = 2048, Bm = 4, Sm = 2048;
static constexpr int BSm = Bm * Sm;                      // 8192
static constexpr long long BSD = (long long)BSm * Dm;    // 4194304
static constexpr long long SD  = (long long)Sm * Dm;     // 1048576
static constexpr long long DD  = (long long)Dm * Dm;     // 262144

// FFT-symmetry tile sizes
static constexpr int FR = 1152;   // S-axis rows computed (need 0..1024)
static constexpr int FC = 384;    // D-axis cols computed (need 0..256)
static constexpr int KF = 1152;   // folded S length (1025 padded; /128 for GEMM N)
static constexpr int KFK = 1088;  // K actually used in cps GEMM (1025 pad /64)
static constexpr int KD = 320;    // folded D length (257 padded to /64)

// ---------------------------------------------------------------------------
// Static device scratch
// ---------------------------------------------------------------------------
__device__ __align__(256) hlf g_CSf[2 * FR * KF];                  // [cos;sin] S-folded
__device__ __align__(256) hlf g_BDf[2 * 384 * KD];                 // [cos;sin] D-folded
__device__ __align__(256) hlf g_xdff[8 * KF * KD];                 // [half*4+b][1152,320]
__device__ __align__(256) hlf g_t12Tf[8 * 384 * KF];               // [half*4+b][384,1152]
__device__ __align__(256) float g_cps[8 * FR * FC];                // cp z=0..3, sp z=4..7
// stacked A: [0..BSD)=LN1(xd) fp16, [BSD..2BSD)=x_enc fp16
__device__ __align__(256) hlf g_xqkh[8388608];
__device__ __align__(256) hlf g_qkh[16777216];                     // [4][b,s,d] q logits
__device__ __align__(256) hlf g_qsh[16777216];
__device__ __align__(256) hlf g_kvTh[33554432];                    // [32][.,S]: k z<16, v z>=16
__device__ __align__(256) hlf g_gcDE[4194304];                     // [z][D,E]
__device__ __align__(256) hlf g_Mth[4194304];                      // [z][N,D]
__device__ __align__(256) hlf g_WqTh[1048576];                     // [h][512,512]
__device__ __align__(256) hlf g_WkvTh[2097152];                    // [Wk0..3;Wv0..3]
__device__ __align__(256) float g_bkv[4096];                       // [bk;bv]
__device__ __align__(256) hlf g_WoTh[1048576];                     // [h][512,512] (n,e)
__device__ __align__(256) hlf g_W1Th[1048576];                     // [2048,512]
__device__ __align__(256) hlf g_W2Th[1048576];                     // [512,2048]
__device__ __align__(256) hlf g_attnh[4194304];
__device__ __align__(256) float g_x2[4194304];
__device__ __align__(256) hlf g_x2h[4194304];
__device__ __align__(256) hlf g_midh[16777216];
__device__ __align__(256) hlf g_ffh[4194304];

// ---------------------------------------------------------------------------
// Helpers
// ---------------------------------------------------------------------------
__device__ __forceinline__ uint32_t smem_u32(const void* p) {
    uint32_t a;
    asm("{ .reg .u64 t; cvta.to.shared.u64 t, %1; cvt.u32.u64 %0, t; }" : "=r"(a) : "l"(p));
    return a;
}
__device__ __forceinline__ float selu_f(float x) {
    const float sc = 1.0507009873554805f, al = 1.6732632423543772f;
    return x > 0.f ? sc * x : sc * al * (expf(x) - 1.f);
}
__device__ __forceinline__ uint32_t packhl(hlf a, hlf b) {
    return ((uint32_t)*(uint16_t*)&b << 16) | (uint32_t)*(uint16_t*)&a;
}
__device__ __forceinline__ uint32_t packf2(float a, float b) {
    hlf ha = __float2half_rn(a), hb = __float2half_rn(b);
    return packhl(ha, hb);
}

#define LDSM_X4(r0, r1, r2, r3, addr) \
    asm volatile("ldmatrix.sync.aligned.m8n8.x4.shared.b16 {%0,%1,%2,%3}, [%4];" \
        : "=r"(r0), "=r"(r1), "=r"(r2), "=r"(r3) : "r"(addr))

#define MMA_F16(d, a, b0, b1) \
    asm volatile("mma.sync.aligned.m16n8k16.row.col.f32.f16.f16.f32 " \
        "{%0,%1,%2,%3}, {%4,%5,%6,%7}, {%8,%9}, {%0,%1,%2,%3};" \
        : "+f"((d)[0]), "+f"((d)[1]), "+f"((d)[2]), "+f"((d)[3]) \
        : "r"((a)[0]), "r"((a)[1]), "r"((a)[2]), "r"((a)[3]), "r"(b0), "r"(b1))

#define CP_ASYNC16(dst, src) \
    asm volatile("cp.async.cg.shared.global [%0], [%1], 16;" :: "r"(dst), "l"(src))
#define CP_COMMIT() asm volatile("cp.async.commit_group;")
#define CP_WAIT1()  asm volatile("cp.async.wait_group 1;")

// ---------------------------------------------------------------------------
// HMMA GEMM, cp.async 3-stage pipeline.
// Block 128x128, 8 warps, warp 64x32, BK=64, 2 CTA/SM.
// C[z] = sum_p A_p[(z>>shA)&mskA] @ B_p[z&mskB]^T (+bias col[zb]/row[za])(+SELU)
// SPLIT: 0 = fp32 out, 2 = fp16 out.
// ---------------------------------------------------------------------------
struct TcPasses { const hlf* A[4]; const hlf* B[4]; };

static constexpr int BKg = 64;
static constexpr int LDSg = BKg + 8;
static constexpr int TILE_B = 128 * LDSg * 2;
static constexpr int STAGES = 3;
static constexpr int SMEM_B_OFF = STAGES * TILE_B;
static constexpr int SMEM_BIAS_OFF = 2 * STAGES * TILE_B;
static constexpr int SMEM_G = SMEM_BIAS_OFF + 128 * 4;

template <int ACT, int SPLIT, int BMODE>   // BMODE: 0 none, 1 col (zb), 2 row (za)
__global__ __launch_bounds__(256, 2) void mma_gemm(
    TcPasses P, int npass,
    float* __restrict__ C, hlf* __restrict__ Chi,
    int K, int lda, int ldb, int ldc,
    long long sA, long long sB, long long sC,
    const float* __restrict__ bias, long long sBias,
    int shA, int mskA, int mskB)
{
    extern __shared__ char smem[];
    float* bias_s = (float*)(smem + SMEM_BIAS_OFF);
    const uint32_t sA0 = smem_u32(smem);
    const uint32_t sB0 = sA0 + SMEM_B_OFF;

    const int tid = threadIdx.x;
    const int lane = tid & 31;
    const int wid = tid >> 5;
    const int wm = (wid & 1) * 64;
    const int wn = (wid >> 1) * 32;
    const int z = blockIdx.z;
    const int za = (z >> shA) & mskA;
    const int zb = z & mskB;
    const int m0 = blockIdx.y * 128, n0 = blockIdx.x * 128;

    if (tid < 128) {
        if (BMODE == 0) bias_s[tid] = 0.f;
        else if (BMODE == 1) bias_s[tid] = bias[(long long)zb * sBias + n0 + tid];
        else bias_s[tid] = bias[(long long)za * sBias + m0 + tid];
    }

    float acc[4][4][4];
#pragma unroll
    for (int i = 0; i < 4; i++)
#pragma unroll
        for (int j = 0; j < 4; j++)
#pragma unroll
            for (int k = 0; k < 4; k++) acc[i][j][k] = 0.f;

    const int cpp = K / BKg;
    const int total = npass * cpp;

    const int crow = tid >> 3;
    const int ccol = (tid & 7) * 8;

    auto loadStage = [&](int c, int stg) {
        int p = c / cpp;
        int k0 = (c - p * cpp) * BKg;
        const hlf* Ab = P.A[p] + (long long)za * sA + k0 + ccol;
        const hlf* Bb = P.B[p] + (long long)zb * sB + k0 + ccol;
        uint32_t da = sA0 + stg * TILE_B + (crow * LDSg + ccol) * 2;
        uint32_t db = sB0 + stg * TILE_B + (crow * LDSg + ccol) * 2;
#pragma unroll
        for (int i = 0; i < 4; i++) {
            int row = crow + i * 32;
            CP_ASYNC16(da + i * 32 * LDSg * 2, Ab + (long long)(m0 + row) * lda);
            CP_ASYNC16(db + i * 32 * LDSg * 2, Bb + (long long)(n0 + row) * ldb);
        }
    };

    loadStage(0, 0); CP_COMMIT();
    loadStage(1, 1); CP_COMMIT();

    const int lrow16 = lane & 15;
    const int lhalf = lane >> 4;

    for (int c = 0; c < total; c++) {
        CP_WAIT1();
        __syncthreads();
        const int stg = c % STAGES;
        const uint32_t aB = sA0 + stg * TILE_B;
        const uint32_t bB = sB0 + stg * TILE_B;
#pragma unroll
        for (int ks = 0; ks < 4; ks++) {
            uint32_t af[4][4];
#pragma unroll
            for (int mi = 0; mi < 4; mi++) {
                uint32_t addr = aB + (uint32_t)(((wm + mi * 16 + lrow16) * LDSg
                                                + ks * 16 + lhalf * 8) * 2);
                LDSM_X4(af[mi][0], af[mi][1], af[mi][2], af[mi][3], addr);
            }
            uint32_t bfr[2][4];
#pragma unroll
            for (int nj = 0; nj < 2; nj++) {
                uint32_t addr = bB + (uint32_t)(((wn + nj * 16 + lrow16) * LDSg
                                                + ks * 16 + lhalf * 8) * 2);
                LDSM_X4(bfr[nj][0], bfr[nj][1], bfr[nj][2], bfr[nj][3], addr);
            }
#pragma unroll
            for (int mi = 0; mi < 4; mi++)
#pragma unroll
                for (int ni = 0; ni < 4; ni++) {
                    const int nj = ni >> 1, sub = ni & 1;
                    MMA_F16(acc[mi][ni], af[mi], bfr[nj][sub], bfr[nj][sub + 2]);
                }
        }
        if (c + 2 < total) loadStage(c + 2, (c + 2) % STAGES);
        CP_COMMIT();
    }

    const int cr = lane >> 2;
    const int cc = (lane & 3) * 2;
#pragma unroll
    for (int mi = 0; mi < 4; mi++) {
#pragma unroll
        for (int ni = 0; ni < 4; ni++) {
            const int bn = wn + ni * 8 + cc;
            const int gn = n0 + bn;
            const int rm = wm + mi * 16 + cr;
            const long long r0 = m0 + rm;
            const long long r1 = r0 + 8;
            float v0 = acc[mi][ni][0], v1 = acc[mi][ni][1];
            float v2 = acc[mi][ni][2], v3 = acc[mi][ni][3];
            if (BMODE == 1) {
                v0 += bias_s[bn]; v1 += bias_s[bn + 1];
                v2 += bias_s[bn]; v3 += bias_s[bn + 1];
            } else if (BMODE == 2) {
                v0 += bias_s[rm]; v1 += bias_s[rm];
                v2 += bias_s[rm + 8]; v3 += bias_s[rm + 8];
            }
            if (ACT == 1) { v0 = selu_f(v0); v1 = selu_f(v1); v2 = selu_f(v2); v3 = selu_f(v3); }
            if (SPLIT == 2) {
                *(uint32_t*)(Chi + (long long)z * sC + r0 * ldc + gn) = packf2(v0, v1);
                *(uint32_t*)(Chi + (long long)z * sC + r1 * ldc + gn) = packf2(v2, v3);
            } else {
                *(float2*)(C + (long long)z * sC + r0 * ldc + gn) = make_float2(v0, v1);
                *(float2*)(C + (long long)z * sC + r1 * ldc + gn) = make_float2(v2, v3);
            }
        }
    }
}

// ---------------------------------------------------------------------------
// Elementwise kernels
// ---------------------------------------------------------------------------
// Merged init: CSf (blocks [0, NB_CS)), BDf (next NB_BD), bias concat (last 16).
static constexpr int NB_CS = (2 * FR * KF) / 256;        // 10368
static constexpr int NB_BD = (2 * 384 * KD + 255) / 256; // 960
__global__ void init_all(hlf* __restrict__ CSf, hlf* __restrict__ BDf,
                         const float* __restrict__ bk, const float* __restrict__ bv,
                         float* __restrict__ bkv)
{
    const int blk = blockIdx.x;
    if (blk < NB_CS) {
        long long idx = (long long)blk * 256 + threadIdx.x;
        int half = (int)(idx / ((long long)FR * KF));
        int rem = (int)(idx % ((long long)FR * KF));
        int i = rem / KF, j = rem % KF;
        float v = 0.f;
        if (j <= 1024) {
            int p = (int)(((long long)i * j) % Sm);
            float x = 2.0f * (float)p / (float)Sm;
            float s, c;
            sincospif(x, &s, &c);
            v = half ? s : c;
        }
        CSf[idx] = __float2half_rn(v);
    } else if (blk < NB_CS + NB_BD) {
        long long idx = (long long)(blk - NB_CS) * 256 + threadIdx.x;
        if (idx >= 2LL * 384 * KD) return;
        int half = (int)(idx / (384 * KD));
        int rem = (int)(idx % (384 * KD));
        int i = rem / KD, k = rem % KD;
        float v = 0.f;
        if (k <= 256) {
            int p = (int)(((long long)i * k) % Dm);
            float x = 2.0f * (float)p / (float)Dm;
            float s, c;
            sincospif(x, &s, &c);
            v = half ? s : c;
        }
        BDf[idx] = __float2half_rn(v);
    } else {
        int i = (blk - NB_CS - NB_BD) * 256 + threadIdx.x;
        if (i < 2048) bkv[i] = bk[i];
        else if (i < 4096) bkv[i] = bv[i - 2048];
    }
}

// Double fold of x_dec (S then D), both halves. One block per (b, j).
__global__ void xdec_fold2(const float* __restrict__ x, hlf* __restrict__ xdff)
{
    __shared__ float rj[512], rm[512];
    const int j = blockIdx.x % KF;
    const int b = blockIdx.x / KF;
    const int t = threadIdx.x;                 // 128
    hlf* co = xdff + ((long long)(0 * 4 + b) * KF + j) * KD;
    hlf* si = xdff + ((long long)(1 * 4 + b) * KF + j) * KD;
    if (j > 1024) {
#pragma unroll
        for (int q = 0; q < 3; q++) {
            int k = t + q * 128;
            if (k < KD) { co[k] = __float2half_rn(0.f); si[k] = __float2half_rn(0.f); }
        }
        return;
    }
    const float* xb = x + (long long)b * SD;
    ((float4*)rj)[t] = ((const float4*)(xb + (long long)j * Dm))[t];
    if (j >= 1 && j <= 1023)
        ((float4*)rm)[t] = ((const float4*)(xb + (long long)(Sm - j) * Dm))[t];
    else
        ((float4*)rm)[t] = make_float4(0.f, 0.f, 0.f, 0.f);
    __syncthreads();
#pragma unroll
    for (int q = 0; q < 3; q++) {
        int k = t + q * 128;
        if (k >= KD) break;
        float cv = 0.f, sv = 0.f;
        if (k == 0) {
            cv = rj[0] + rm[0];
        } else if (k == 256) {
            cv = rj[256] + rm[256];
        } else if (k < 256) {
            float yck = rj[k] + rm[k], yck2 = rj[512 - k] + rm[512 - k];
            float ysk = rj[k] - rm[k], ysk2 = rj[512 - k] - rm[512 - k];
            cv = yck + yck2;
            sv = ysk - ysk2;
        }
        co[k] = __float2half_rn(cv);
        si[k] = __float2half_rn(sv);
    }
}

// fp32 -> fp16 (hi only), 8 elems/thread
__global__ void split_k8(const float* __restrict__ in, hlf* __restrict__ h, long long n8)
{
    long long i = (long long)blockIdx.x * blockDim.x + threadIdx.x;
    if (i >= n8) return;
    long long base = i * 8;
    float4 a = *(const float4*)(in + base);
    float4 b = *(const float4*)(in + base + 4);
    uint4 ho;
    ho.x = packf2(a.x, a.y); ho.y = packf2(a.z, a.w);
    ho.z = packf2(b.x, b.y); ho.w = packf2(b.z, b.w);
    *(uint4*)(h + base) = ho;
}

// All six weight transposes in one launch; every segment is exactly 1024 tiles.
struct WSeg { const float* in; hlf* out; int nTx, nTy, wo; long long sIn, sOut; int R, C; };
struct WPrep { WSeg s[6]; };

__global__ void weights_prep(WPrep P)
{
    __shared__ float t[32][33];
    const int seg = blockIdx.x >> 10;
    const int id = blockIdx.x & 1023;
    const WSeg w = P.s[seg];
    const int tilesPerZ = w.nTx * w.nTy;
    const int bz = id / tilesPerZ;
    const int rem = id % tilesPerZ;
    const int bx = rem % w.nTx;
    const int by = rem / w.nTx;
    const int tx = threadIdx.x, ty = threadIdx.y;
    if (!w.wo) {
        const int c0 = bx * 32, r0 = by * 32;
        const float* ib = w.in + (long long)bz * w.sIn;
#pragma unroll
        for (int i = 0; i < 4; i++)
            t[ty + i * 8][tx] = ib[(long long)(r0 + ty + i * 8) * w.C + c0 + tx];
        __syncthreads();
#pragma unroll
        for (int i = 0; i < 4; i++) {
            float v = t[tx][ty + i * 8];
            long long o = (long long)bz * w.sOut + (long long)(c0 + ty + i * 8) * w.R + r0 + tx;
            w.out[o] = __float2half_rn(v);
        }
    } else {
        const int n0 = bx * 32, d0 = by * 32, h = bz;
#pragma unroll
        for (int i = 0; i < 4; i++) {
            int d = d0 + ty + i * 8;
            t[ty + i * 8][tx] = w.in[(long long)(d * 4 + h) * Dm + n0 + tx];
        }
        __syncthreads();
#pragma unroll
        for (int i = 0; i < 4; i++) {
            float v = t[tx][ty + i * 8];
            long long o = (long long)h * DD + (long long)(n0 + ty + i * 8) * Dm + d0 + tx;
            w.out[o] = __float2half_rn(v);
        }
    }
}

// Merged softmax: blocks [0, 4096) -> q (qkh->qsh, h-stride BSD, 4/thread);
// blocks [4096, 6144) -> kT in-place (kvTh, h-stride 4*SD, 8/thread).
__global__ void softmax_all(const hlf* __restrict__ qk, hlf* __restrict__ qs,
                            hlf* __restrict__ kv)
{
    const int blk = blockIdx.x;
    if (blk < 4096) {
        long long i4 = (long long)blk * 256 + threadIdx.x;
        long long base = i4 * 4;
        float v[4][4];
#pragma unroll
        for (int h = 0; h < 4; h++) {
            uint2 raw = *(const uint2*)(qk + h * BSD + base);
            hlf* hp = (hlf*)&raw;
#pragma unroll
            for (int j = 0; j < 4; j++) v[h][j] = __half2float(hp[j]);
        }
#pragma unroll
        for (int j = 0; j < 4; j++) {
            float m = fmaxf(fmaxf(v[0][j], v[1][j]), fmaxf(v[2][j], v[3][j]));
            float e0 = expf(v[0][j] - m), e1 = expf(v[1][j] - m);
            float e2 = expf(v[2][j] - m), e3 = expf(v[3][j] - m);
            float inv = 1.f / (e0 + e1 + e2 + e3);
            v[0][j] = e0 * inv; v[1][j] = e1 * inv; v[2][j] = e2 * inv; v[3][j] = e3 * inv;
        }
#pragma unroll
        for (int h = 0; h < 4; h++) {
            uint2 ho = make_uint2(packf2(v[h][0], v[h][1]), packf2(v[h][2], v[h][3]));
            *(uint2*)(qs + h * BSD + base) = ho;
        }
    } else {
        long long idx = (long long)(blk - 4096) * 256 + threadIdx.x;
        const long long PER_B = SD / 8;
        const int b = (int)(idx / PER_B);
        const long long off = (idx % PER_B) * 8;
        uint4 raw[4];
#pragma unroll
        for (int h = 0; h < 4; h++)
            raw[h] = *(const uint4*)(kv + (long long)(h * 4 + b) * SD + off);
        float v[4][8];
#pragma unroll
        for (int h = 0; h < 4; h++) {
            hlf* hp = (hlf*)&raw[h];
#pragma unroll
            for (int j = 0; j < 8; j++) v[h][j] = __half2float(hp[j]);
        }
#pragma unroll
        for (int j = 0; j < 8; j++) {
            float m = fmaxf(fmaxf(v[0][j], v[1][j]), fmaxf(v[2][j], v[3][j]));
            float e0 = expf(v[0][j] - m), e1 = expf(v[1][j] - m);
            float e2 = expf(v[2][j] - m), e3 = expf(v[3][j] - m);
            float inv = 1.f / (e0 + e1 + e2 + e3);
            v[0][j] = e0 * inv; v[1][j] = e1 * inv; v[2][j] = e2 * inv; v[3][j] = e3 * inv;
        }
#pragma unroll
        for (int h = 0; h < 4; h++) {
            uint4 o;
            o.x = packf2(v[h][0], v[h][1]); o.y = packf2(v[h][2], v[h][3]);
            o.z = packf2(v[h][4], v[h][5]); o.w = packf2(v[h][6], v[h][7]);
            *(uint4*)(kv + (long long)(h * 4 + b) * SD + off) = o;
        }
    }
}

// LN1 fused with FFT quadrant reconstruction; fp16 out only.
__global__ void ln1_fft(const float* __restrict__ x_dec, const float* __restrict__ cps,
                        const float* __restrict__ g, const float* __restrict__ be,
                        hlf* __restrict__ oh)
{
    __shared__ float red[4];
    const long long row = blockIdx.x;        // b*2048 + s
    const int b = (int)(row >> 11);
    const int s = (int)(row & 2047);
    const int t = threadIdx.x;               // 128

    const int ip = (s <= 1024) ? s : (Sm - s);
    const bool fi = (s > 1024);
    const float* cpr = cps + (long long)b * FR * FC + (long long)ip * FC;
    const float* spr = cpr + 4LL * FR * FC;

    float4 vx = ((const float4*)(x_dec + row * Dm))[t];
    float v4[4];
#pragma unroll
    for (int j = 0; j < 4; j++) {
        int d = t * 4 + j;
        int dp = (d <= 256) ? d : (Dm - d);
        bool fd = (d > 256);
        float c = cpr[dp], sv = spr[dp];
        float xfv = c + ((fi != fd) ? sv : -sv);
        v4[j] = ((const float*)&vx)[j] + xfv;
    }

    float ssum = v4[0] + v4[1] + v4[2] + v4[3];
#pragma unroll
    for (int o = 16; o > 0; o >>= 1) ssum += __shfl_xor_sync(0xffffffffu, ssum, o);
    if ((t & 31) == 0) red[t >> 5] = ssum;
    __syncthreads();
    float mu = (red[0] + red[1] + red[2] + red[3]) * (1.f / (float)Dm);
    __syncthreads();
    float d0 = v4[0] - mu, d1 = v4[1] - mu, d2 = v4[2] - mu, d3 = v4[3] - mu;
    float q = d0 * d0 + d1 * d1 + d2 * d2 + d3 * d3;
#pragma unroll
    for (int o = 16; o > 0; o >>= 1) q += __shfl_xor_sync(0xffffffffu, q, o);
    if ((t & 31) == 0) red[t >> 5] = q;
    __syncthreads();
    float var = (red[0] + red[1] + red[2] + red[3]) * (1.f / (float)Dm);
    float rstd = rsqrtf(var + 1e-5f);
    float4 vg = ((const float4*)g)[t];
    float4 vbe = ((const float4*)be)[t];
    float o0 = fmaf(vg.x, d0 * rstd, vbe.x);
    float o1 = fmaf(vg.y, d1 * rstd, vbe.y);
    float o2 = fmaf(vg.z, d2 * rstd, vbe.z);
    float o3 = fmaf(vg.w, d3 * rstd, vbe.w);
    long long o = row * Dm + t * 4;
    *(uint2*)(oh + o) = make_uint2(packf2(o0, o1), packf2(o2, o3));
}

// LN of (a fp16 + b fp16); fp32 out (optional) + fp16 out (optional).
__global__ void ln_hh(const hlf* __restrict__ a, const hlf* __restrict__ bres,
                      const float* __restrict__ g, const float* __restrict__ be,
                      float* __restrict__ out, hlf* __restrict__ oh)
{
    __shared__ float red[4];
    long long row = blockIdx.x;
    int t = threadIdx.x;  // 128
    uint2 var_ = ((const uint2*)(a + row * Dm))[t];
    uint2 vbr = ((const uint2*)(bres + row * Dm))[t];
    hlf* ap = (hlf*)&var_;
    hlf* bp = (hlf*)&vbr;
    float4 v = make_float4(__half2float(ap[0]) + __half2float(bp[0]),
                           __half2float(ap[1]) + __half2float(bp[1]),
                           __half2float(ap[2]) + __half2float(bp[2]),
                           __half2float(ap[3]) + __half2float(bp[3]));
    float s = v.x + v.y + v.z + v.w;
#pragma unroll
    for (int o = 16; o > 0; o >>= 1) s += __shfl_xor_sync(0xffffffffu, s, o);
    if ((t & 31) == 0) red[t >> 5] = s;
    __syncthreads();
    float mu = (red[0] + red[1] + red[2] + red[3]) * (1.f / (float)Dm);
    __syncthreads();
    float d0 = v.x - mu, d1 = v.y - mu, d2 = v.z - mu, d3 = v.w - mu;
    float q = d0 * d0 + d1 * d1 + d2 * d2 + d3 * d3;
#pragma unroll
    for (int o = 16; o > 0; o >>= 1) q += __shfl_xor_sync(0xffffffffu, q, o);
    if ((t & 31) == 0) red[t >> 5] = q;
    __syncthreads();
    float var = (red[0] + red[1] + red[2] + red[3]) * (1.f / (float)Dm);
    float rstd = rsqrtf(var + 1e-5f);
    float4 vg = ((const float4*)g)[t];
    float4 vbe = ((const float4*)be)[t];
    float4 o4;
    o4.x = fmaf(vg.x, d0 * rstd, vbe.x);
    o4.y = fmaf(vg.y, d1 * rstd, vbe.y);
    o4.z = fmaf(vg.z, d2 * rstd, vbe.z);
    o4.w = fmaf(vg.w, d3 * rstd, vbe.w);
    if (out) ((float4*)(out + row * Dm))[t] = o4;
    if (oh) {
        long long o = row * Dm + t * 4;
        *(uint2*)(oh + o) = make_uint2(packf2(o4.x, o4.y), packf2(o4.z, o4.w));
    }
}

// LN of (a fp32 + b fp16); fp32 out.
__global__ void ln_hb(const float* __restrict__ a, const hlf* __restrict__ bres,
                      const float* __restrict__ g, const float* __restrict__ be,
                      float* __restrict__ out)
{
    __shared__ float red[4];
    long long row = blockIdx.x;
    int t = threadIdx.x;  // 128
    float4 va = ((const float4*)(a + row * Dm))[t];
    uint2 vbr = ((const uint2*)(bres + row * Dm))[t];
    hlf* bp = (hlf*)&vbr;
    float4 v = make_float4(va.x + __half2float(bp[0]), va.y + __half2float(bp[1]),
                           va.z + __half2float(bp[2]), va.w + __half2float(bp[3]));
    float s = v.x + v.y + v.z + v.w;
#pragma unroll
    for (int o = 16; o > 0; o >>= 1) s += __shfl_xor_sync(0xffffffffu, s, o);
    if ((t & 31) == 0) red[t >> 5] = s;
    __syncthreads();
    float mu = (red[0] + red[1] + red[2] + red[3]) * (1.f / (float)Dm);
    __syncthreads();
    float d0 = v.x - mu, d1 = v.y - mu, d2 = v.z - mu, d3 = v.w - mu;
    float q = d0 * d0 + d1 * d1 + d2 * d2 + d3 * d3;
#pragma unroll
    for (int o = 16; o > 0; o >>= 1) q += __shfl_xor_sync(0xffffffffu, q, o);
    if ((t & 31) == 0) red[t >> 5] = q;
    __syncthreads();
    float var = (red[0] + red[1] + red[2] + red[3]) * (1.f / (float)Dm);
    float rstd = rsqrtf(var + 1e-5f);
    float4 vg = ((const float4*)g)[t];
    float4 vbe = ((const float4*)be)[t];
    float4 o4;
    o4.x = fmaf(vg.x, d0 * rstd, vbe.x);
    o4.y = fmaf(vg.y, d1 * rstd, vbe.y);
    o4.z = fmaf(vg.z, d2 * rstd, vbe.z);
    o4.w = fmaf(vg.w, d3 * rstd, vbe.w);
    ((float4*)(out + row * Dm))[t] = o4;
}

// ---------------------------------------------------------------------------
// Host
// ---------------------------------------------------------------------------
static TcPasses mk1(const hlf* Ah, const hlf* Bh) {
    TcPasses P{};
    P.A[0] = Ah; P.B[0] = Bh;
    return P;
}

static void tcg(const TcPasses& P, int np, float* C, hlf* Ch,
                int M, int N, int K, int lda, int ldb, int ldc,
                long long sA, long long sB, long long sC, int batch,
                const float* bias, long long sBias, int act, int split, int bmode,
                int shA = 0, int mskA = 0x7FFFFFFF, int mskB = 0x7FFFFFFF)
{
    dim3 grid(N / 128, M / 128, batch), block(256);
    if (act == 1)
        mma_gemm<1, 2, 1><<<grid, block, SMEM_G>>>(P, np, C, Ch, K, lda, ldb, ldc, sA, sB, sC, bias, sBias, shA, mskA, mskB);
    else if (split == 2 && bmode == 2)
        mma_gemm<0, 2, 2><<<grid, block, SMEM_G>>>(P, np, C, Ch, K, lda, ldb, ldc, sA, sB, sC, bias, sBias, shA, mskA, mskB);
    else if (split == 2 && bmode == 1)
        mma_gemm<0, 2, 1><<<grid, block, SMEM_G>>>(P, np, C, Ch, K, lda, ldb, ldc, sA, sB, sC, bias, sBias, shA, mskA, mskB);
    else if (split == 2)
        mma_gemm<0, 2, 0><<<grid, block, SMEM_G>>>(P, np, C, Ch, K, lda, ldb, ldc, sA, sB, sC, bias, sBias, shA, mskA, mskB);
    else if (bmode == 1)
        mma_gemm<0, 0, 1><<<grid, block, SMEM_G>>>(P, np, C, Ch, K, lda, ldb, ldc, sA, sB, sC, bias, sBias, shA, mskA, mskB);
    else
        mma_gemm<0, 0, 0><<<grid, block, SMEM_G>>>(P, np, C, Ch, K, lda, ldb, ldc, sA, sB, sC, bias, sBias, shA, mskA, mskB);
}

#define GETSYM(var, sym) do { void* _p; cudaGetSymbolAddress(&_p, sym); var = (decltype(var))_p; } while (0)

extern "C" void kernel_launch(void* const* d_in, const int* in_sizes, int n_in,
                              void* d_out, int out_size)
{
    const float* x_enc = (const float*)d_in[0];
    const float* x_dec = (const float*)d_in[1];
    const float* Wq = (const float*)d_in[2];
    const float* bq = (const float*)d_in[3];
    const float* Wk = (const float*)d_in[4];
    const float* bk = (const float*)d_in[5];
    const float* Wv = (const float*)d_in[6];
    const float* bv = (const float*)d_in[7];
    const float* Wo = (const float*)d_in[8];
    const float* bo = (const float*)d_in[9];
    const float* ln1g = (const float*)d_in[10];
    const float* ln1b = (const float*)d_in[11];
    const float* ln2g = (const float*)d_in[12];
    const float* ln2b = (const float*)d_in[13];
    const float* W1 = (const float*)d_in[14];
    const float* b1 = (const float*)d_in[15];
    const float* W2 = (const float*)d_in[16];
    const float* b2 = (const float*)d_in[17];
    const float* ln3g = (const float*)d_in[18];
    const float* ln3b = (const float*)d_in[19];
    float* outp = (float*)d_out;

    hlf *CSf, *BDf, *xdff, *t12Tf, *xqkh, *qkh;
    hlf *qsh, *kvTh, *gcDE, *Mth;
    hlf *WqTh, *WkvTh, *WoTh, *W1Th, *W2Th, *x2h, *midh, *attnh, *ffh;
    float *cps, *bkv, *x2;
    GETSYM(CSf, g_CSf); GETSYM(BDf, g_BDf); GETSYM(xdff, g_xdff);
    GETSYM(t12Tf, g_t12Tf);
    GETSYM(cps, g_cps);
    GETSYM(xqkh, g_xqkh); GETSYM(qkh, g_qkh);
    GETSYM(bkv, g_bkv);
    GETSYM(qsh, g_qsh); GETSYM(kvTh, g_kvTh);
    GETSYM(gcDE, g_gcDE); GETSYM(Mth, g_Mth);
    GETSYM(WqTh, g_WqTh); GETSYM(WkvTh, g_WkvTh); GETSYM(WoTh, g_WoTh);
    GETSYM(W1Th, g_W1Th); GETSYM(W2Th, g_W2Th);
    GETSYM(attnh, g_attnh); GETSYM(x2, g_x2); GETSYM(x2h, g_x2h);
    GETSYM(midh, g_midh); GETSYM(ffh, g_ffh);

    cudaFuncSetAttribute(mma_gemm<0, 0, 0>, cudaFuncAttributeMaxDynamicSharedMemorySize, SMEM_G);
    cudaFuncSetAttribute(mma_gemm<0, 0, 1>, cudaFuncAttributeMaxDynamicSharedMemorySize, SMEM_G);
    cudaFuncSetAttribute(mma_gemm<0, 2, 0>, cudaFuncAttributeMaxDynamicSharedMemorySize, SMEM_G);
    cudaFuncSetAttribute(mma_gemm<0, 2, 1>, cudaFuncAttributeMaxDynamicSharedMemorySize, SMEM_G);
    cudaFuncSetAttribute(mma_gemm<0, 2, 2>, cudaFuncAttributeMaxDynamicSharedMemorySize, SMEM_G);
    cudaFuncSetAttribute(mma_gemm<1, 2, 1>, cudaFuncAttributeMaxDynamicSharedMemorySize, SMEM_G);

    dim3 tb(32, 8);

    // 0) folded DFT matrices + bias concat: one launch
    init_all<<<NB_CS + NB_BD + 16, 256>>>(CSf, BDf, bk, bv, bkv);

    // inputs: x_enc fp16; x_dec double-folded
    split_k8<<<(int)(BSD / 8 / 256), 256>>>(x_enc, xqkh + BSD, BSD / 8);
    xdec_fold2<<<Bm * KF, 128>>>(x_dec, xdff);

    // weight prep: one launch, 6 segments x 1024 tiles
    {
        WPrep P{};
        P.s[0] = {Wq, WqTh, 16, 16, 0, DD, DD, Dm, Dm};
        P.s[1] = {Wk, WkvTh, 16, 16, 0, DD, DD, Dm, Dm};
        P.s[2] = {Wv, WkvTh + 4 * DD, 16, 16, 0, DD, DD, Dm, Dm};
        P.s[3] = {Wo, WoTh, 16, 16, 1, 0, 0, Dm, Dm};
        P.s[4] = {W1, W1Th, 64, 16, 0, 0, 0, Dm, MIDm};
        P.s[5] = {W2, W2Th, 16, 64, 0, 0, 0, MIDm, Dm};
        weights_prep<<<6144, tb>>>(P);
    }

    // 1) t12Tf[z=half*4+b] = BDf[half] @ xdff[z]^T  (M=384, N=1152, K=320, z=8)
    tcg(mk1(BDf, xdff), 1, nullptr, t12Tf,
        384, KF, KD, KD, KD, KF, 384LL * KD, (long long)KF * KD, 384LL * KF, 8,
        nullptr, 0, 0, 2, 0, /*shA=*/2, /*mskA=*/0x7FFFFFFF, /*mskB=*/7);

    // 2) merged cp/sp: cps[z] = CSf[z>>2] @ t12Tf[z]^T  (M=1152,N=384,K=1088,z=8)
    tcg(mk1(CSf, t12Tf), 1, cps, nullptr,
        FR, FC, KFK, KF, KF, FC, (long long)FR * KF, 384LL * KF, (long long)FR * FC, 8,
        nullptr, 0, 0, 0, 0, /*shA=*/2, /*mskA=*/0x7FFFFFFF, /*mskB=*/7);

    // 3) xd = LN1(x_dec + fftmerge(cps)); fp16 only into stacked buffer
    ln1_fft<<<BSm, 128>>>(x_dec, cps, ln1g, ln1b, xqkh);

    // 4) kvT[z=kv*16+h*4+b] = Wkv_{z>>2}^T @ x_enc[b]^T + bkv (row), fp16; z=32
    tcg(mk1(WkvTh, xqkh + BSD), 1, nullptr, kvTh,
        Dm, Sm, Dm, Dm, Dm, Sm, DD, SD, SD, 32, bkv, Dm, 0, 2, 2,
        /*shA=*/2, /*mskA=*/0x7FFFFFFF, /*mskB=*/3);

    // 5) q projections: z=4 (h), 1-pass, fp16 logits
    tcg(mk1(xqkh, WqTh), 1, nullptr, qkh,
        BSm, Dm, Dm, Dm, Dm, Dm, 0, DD, BSD, 4, bq, Dm, 0, 2, 1,
        /*shA=*/0, /*mskA=*/0, /*mskB=*/3);

    // 6) merged softmax over heads: q (->qsh) and kT (in-place)
    softmax_all<<<6144, 256>>>(qkh, qsh, kvTh);

    // 7) gcDE[z][d,e] = ksT @ vsT^T  (M=N=512, K=2048, z=16), fp16 out
    tcg(mk1(kvTh, kvTh + 16 * SD), 1, nullptr, gcDE,
        Dm, Dm, Sm, Sm, Sm, Dm, SD, SD, DD, 16, nullptr, 0, 0, 2, 0);

    // 8) Mt[z][n,d] = WoT_{z>>2} @ gcDE[z]^T  (M=N=K=512, z=16)
    tcg(mk1(WoTh, gcDE), 1, nullptr, Mth,
        Dm, Dm, Dm, Dm, Dm, Dm, DD, DD, DD, 16, nullptr, 0, 0, 2, 0,
        /*shA=*/2, /*mskA=*/0x7FFFFFFF, /*mskB=*/15);

    // 9) attn[b][s,n] = sum_h qs_h[b] @ Mt[h*4+b]^T + bo  (4 passes; z=4), fp16 out
    {
        TcPasses P{};
        for (int h = 0; h < Hn; h++) {
            P.A[h] = qsh + (long long)h * Bm * SD;
            P.B[h] = Mth + (long long)h * Bm * DD;
        }
        tcg(P, 4, nullptr, attnh,
            Sm, Dm, Dm, Dm, Dm, Dm, SD, DD, SD, Bm, bo, 0, 0, 2, 1,
            /*shA=*/0, /*mskA=*/0x7FFFFFFF, /*mskB=*/3);
    }

    // 10) x2 = LN2(xd fp16 + attn fp16); fp32 + fp16 out
    ln_hh<<<BSm, 128>>>(xqkh, attnh, ln2g, ln2b, x2, x2h);

    // 11) mid = selu(x2 @ W1 + b1), fp16 out, 1-pass
    tcg(mk1(x2h, W1Th), 1, nullptr, midh,
        BSm, MIDm, Dm, Dm, Dm, MIDm, 0, 0, 0, 1, b1, 0, 1, 2, 1);

    // 12) ff = mid @ W2 + b2, fp16 out, 1-pass
    tcg(mk1(midh, W2Th), 1, nullptr, ffh,
        BSm, Dm, MIDm, MIDm, MIDm, Dm, 0, 0, 0, 1, b2, 0, 0, 2, 1);

    // 13) out = LN3(x2 fp32 + ff fp16)
    ln_hb<<<BSm, 128>>>(x2, ffh, ln3g, ln3b, outp);
}

// round 16
// speedup vs baseline: 2.5924x; 1.0004x over previous
#include <cuda_runtime.h>
#include <cuda_fp16.h>
#include <math.h>
#include <stdint.h>

typedef __half hlf;

static constexpr int Dm = 512, Hn = 4, MIDm = 2048, Bm = 4, Sm = 2048;
static constexpr int BSm = Bm * Sm;                      // 8192
static constexpr long long BSD = (long long)BSm * Dm;    // 4194304
static constexpr long long SD  = (long long)Sm * Dm;     // 1048576
static constexpr long long DD  = (long long)Dm * Dm;     // 262144

// FFT-symmetry tile sizes
static constexpr int FR = 1152;   // S-axis rows computed (need 0..1024)
static constexpr int FC = 384;    // D-axis cols computed (need 0..256)
static constexpr int KF = 1152;   // folded S length (1025 padded; /128 for GEMM N)
static constexpr int KFK = 1088;  // K actually used in cps GEMM (1025 pad /64)
static constexpr int KD = 320;    // folded D length (257 padded to /64)

// ---------------------------------------------------------------------------
// Static device scratch
// ---------------------------------------------------------------------------
__device__ __align__(256) hlf g_CSf[2 * FR * KF];                  // [cos;sin] S-folded
__device__ __align__(256) hlf g_BDf[2 * 384 * KD];                 // [cos;sin] D-folded
__device__ __align__(256) hlf g_xdff[8 * KF * KD];                 // [half*4+b][1152,320]
__device__ __align__(256) hlf g_t12Tf[8 * 384 * KF];               // [half*4+b][384,1152]
__device__ __align__(256) float g_cps[8 * FR * FC];                // cp z=0..3, sp z=4..7
// stacked A: [0..BSD)=LN1(xd) fp16, [BSD..2BSD)=x_enc fp16
__device__ __align__(256) hlf g_xqkh[8388608];
__device__ __align__(256) hlf g_qkh[16777216];                     // [4][b,s,d] q logits
__device__ __align__(256) hlf g_qsh[16777216];
__device__ __align__(256) hlf g_kvTh[33554432];                    // [32][.,S]: k z<16, v z>=16
__device__ __align__(256) hlf g_gcDE[4194304];                     // [z][D,E]
__device__ __align__(256) hlf g_Mth[4194304];                      // [z][N,D]
__device__ __align__(256) hlf g_WqTh[1048576];                     // [h][512,512]
__device__ __align__(256) hlf g_WkvTh[2097152];                    // [Wk0..3;Wv0..3]
__device__ __align__(256) float g_bkv[4096];                       // [bk;bv]
__device__ __align__(256) hlf g_WoTh[1048576];                     // [h][512,512] (n,e)
__device__ __align__(256) hlf g_W1Th[1048576];                     // [2048,512]
__device__ __align__(256) hlf g_W2Th[1048576];                     // [512,2048]
__device__ __align__(256) hlf g_attnh[4194304];
__device__ __align__(256) hlf g_x2h[4194304];
__device__ __align__(256) hlf g_midh[16777216];
__device__ __align__(256) hlf g_ffh[4194304];

// ---------------------------------------------------------------------------
// Helpers
// ---------------------------------------------------------------------------
__device__ __forceinline__ uint32_t smem_u32(const void* p) {
    uint32_t a;
    asm("{ .reg .u64 t; cvta.to.shared.u64 t, %1; cvt.u32.u64 %0, t; }" : "=r"(a) : "l"(p));
    return a;
}
__device__ __forceinline__ float selu_f(float x) {
    const float sc = 1.0507009873554805f, al = 1.6732632423543772f;
    return x > 0.f ? sc * x : sc * al * (expf(x) - 1.f);
}
__device__ __forceinline__ uint32_t packhl(hlf a, hlf b) {
    return ((uint32_t)*(uint16_t*)&b << 16) | (uint32_t)*(uint16_t*)&a;
}
__device__ __forceinline__ uint32_t packf2(float a, float b) {
    hlf ha = __float2half_rn(a), hb = __float2half_rn(b);
    return packhl(ha, hb);
}

#define LDSM_X4(r0, r1, r2, r3, addr) \
    asm volatile("ldmatrix.sync.aligned.m8n8.x4.shared.b16 {%0,%1,%2,%3}, [%4];" \
        : "=r"(r0), "=r"(r1), "=r"(r2), "=r"(r3) : "r"(addr))

#define MMA_F16(d, a, b0, b1) \
    asm volatile("mma.sync.aligned.m16n8k16.row.col.f32.f16.f16.f32 " \
        "{%0,%1,%2,%3}, {%4,%5,%6,%7}, {%8,%9}, {%0,%1,%2,%3};" \
        : "+f"((d)[0]), "+f"((d)[1]), "+f"((d)[2]), "+f"((d)[3]) \
        : "r"((a)[0]), "r"((a)[1]), "r"((a)[2]), "r"((a)[3]), "r"(b0), "r"(b1))

#define CP_ASYNC16(dst, src) \
    asm volatile("cp.async.cg.shared.global [%0], [%1], 16;" :: "r"(dst), "l"(src))
#define CP_COMMIT() asm volatile("cp.async.commit_group;")
#define CP_WAIT1()  asm volatile("cp.async.wait_group 1;")

// ---------------------------------------------------------------------------
// HMMA GEMM, cp.async 3-stage pipeline.
// Block 128x128, 8 warps, warp 64x32, BK=64, 2 CTA/SM.
// C[z] = sum_p A_p[(z>>shA)&mskA] @ B_p[z&mskB]^T (+bias col[zb]/row[za])(+SELU)
// SPLIT: 0 = fp32 out, 2 = fp16 out.
// ---------------------------------------------------------------------------
struct TcPasses { const hlf* A[4]; const hlf* B[4]; };

static constexpr int BKg = 64;
static constexpr int LDSg = BKg + 8;
static constexpr int TILE_B = 128 * LDSg * 2;
static constexpr int STAGES = 3;
static constexpr int SMEM_B_OFF = STAGES * TILE_B;
static constexpr int SMEM_BIAS_OFF = 2 * STAGES * TILE_B;
static constexpr int SMEM_G = SMEM_BIAS_OFF + 128 * 4;

template <int ACT, int SPLIT, int BMODE>   // BMODE: 0 none, 1 col (zb), 2 row (za)
__global__ __launch_bounds__(256, 2) void mma_gemm(
    TcPasses P, int npass,
    float* __restrict__ C, hlf* __restrict__ Chi,
    int K, int lda, int ldb, int ldc,
    long long sA, long long sB, long long sC,
    const float* __restrict__ bias, long long sBias,
    int shA, int mskA, int mskB)
{
    extern __shared__ char smem[];
    float* bias_s = (float*)(smem + SMEM_BIAS_OFF);
    const uint32_t sA0 = smem_u32(smem);
    const uint32_t sB0 = sA0 + SMEM_B_OFF;

    const int tid = threadIdx.x;
    const int lane = tid & 31;
    const int wid = tid >> 5;
    const int wm = (wid & 1) * 64;
    const int wn = (wid >> 1) * 32;
    const int z = blockIdx.z;
    const int za = (z >> shA) & mskA;
    const int zb = z & mskB;
    const int m0 = blockIdx.y * 128, n0 = blockIdx.x * 128;

    if (tid < 128) {
        if (BMODE == 0) bias_s[tid] = 0.f;
        else if (BMODE == 1) bias_s[tid] = bias[(long long)zb * sBias + n0 + tid];
        else bias_s[tid] = bias[(long long)za * sBias + m0 + tid];
    }

    float acc[4][4][4];
#pragma unroll
    for (int i = 0; i < 4; i++)
#pragma unroll
        for (int j = 0; j < 4; j++)
#pragma unroll
            for (int k = 0; k < 4; k++) acc[i][j][k] = 0.f;

    const int cpp = K / BKg;
    const int total = npass * cpp;

    const int crow = tid >> 3;
    const int ccol = (tid & 7) * 8;

    auto loadStage = [&](int c, int stg) {
        int p = c / cpp;
        int k0 = (c - p * cpp) * BKg;
        const hlf* Ab = P.A[p] + (long long)za * sA + k0 + ccol;
        const hlf* Bb = P.B[p] + (long long)zb * sB + k0 + ccol;
        uint32_t da = sA0 + stg * TILE_B + (crow * LDSg + ccol) * 2;
        uint32_t db = sB0 + stg * TILE_B + (crow * LDSg + ccol) * 2;
#pragma unroll
        for (int i = 0; i < 4; i++) {
            int row = crow + i * 32;
            CP_ASYNC16(da + i * 32 * LDSg * 2, Ab + (long long)(m0 + row) * lda);
            CP_ASYNC16(db + i * 32 * LDSg * 2, Bb + (long long)(n0 + row) * ldb);
        }
    };

    loadStage(0, 0); CP_COMMIT();
    loadStage(1, 1); CP_COMMIT();

    const int lrow16 = lane & 15;
    const int lhalf = lane >> 4;

    for (int c = 0; c < total; c++) {
        CP_WAIT1();
        __syncthreads();
        const int stg = c % STAGES;
        const uint32_t aB = sA0 + stg * TILE_B;
        const uint32_t bB = sB0 + stg * TILE_B;
#pragma unroll
        for (int ks = 0; ks < 4; ks++) {
            uint32_t af[4][4];
#pragma unroll
            for (int mi = 0; mi < 4; mi++) {
                uint32_t addr = aB + (uint32_t)(((wm + mi * 16 + lrow16) * LDSg
                                                + ks * 16 + lhalf * 8) * 2);
                LDSM_X4(af[mi][0], af[mi][1], af[mi][2], af[mi][3], addr);
            }
            uint32_t bfr[2][4];
#pragma unroll
            for (int nj = 0; nj < 2; nj++) {
                uint32_t addr = bB + (uint32_t)(((wn + nj * 16 + lrow16) * LDSg
                                                + ks * 16 + lhalf * 8) * 2);
                LDSM_X4(bfr[nj][0], bfr[nj][1], bfr[nj][2], bfr[nj][3], addr);
            }
#pragma unroll
            for (int mi = 0; mi < 4; mi++)
#pragma unroll
                for (int ni = 0; ni < 4; ni++) {
                    const int nj = ni >> 1, sub = ni & 1;
                    MMA_F16(acc[mi][ni], af[mi], bfr[nj][sub], bfr[nj][sub + 2]);
                }
        }
        if (c + 2 < total) loadStage(c + 2, (c + 2) % STAGES);
        CP_COMMIT();
    }

    const int cr = lane >> 2;
    const int cc = (lane & 3) * 2;
#pragma unroll
    for (int mi = 0; mi < 4; mi++) {
#pragma unroll
        for (int ni = 0; ni < 4; ni++) {
            const int bn = wn + ni * 8 + cc;
            const int gn = n0 + bn;
            const int rm = wm + mi * 16 + cr;
            const long long r0 = m0 + rm;
            const long long r1 = r0 + 8;
            float v0 = acc[mi][ni][0], v1 = acc[mi][ni][1];
            float v2 = acc[mi][ni][2], v3 = acc[mi][ni][3];
            if (BMODE == 1) {
                v0 += bias_s[bn]; v1 += bias_s[bn + 1];
                v2 += bias_s[bn]; v3 += bias_s[bn + 1];
            } else if (BMODE == 2) {
                v0 += bias_s[rm]; v1 += bias_s[rm];
                v2 += bias_s[rm + 8]; v3 += bias_s[rm + 8];
            }
            if (ACT == 1) { v0 = selu_f(v0); v1 = selu_f(v1); v2 = selu_f(v2); v3 = selu_f(v3); }
            if (SPLIT == 2) {
                *(uint32_t*)(Chi + (long long)z * sC + r0 * ldc + gn) = packf2(v0, v1);
                *(uint32_t*)(Chi + (long long)z * sC + r1 * ldc + gn) = packf2(v2, v3);
            } else {
                *(float2*)(C + (long long)z * sC + r0 * ldc + gn) = make_float2(v0, v1);
                *(float2*)(C + (long long)z * sC + r1 * ldc + gn) = make_float2(v2, v3);
            }
        }
    }
}

// ---------------------------------------------------------------------------
// Elementwise kernels
// ---------------------------------------------------------------------------
// Merged init: CSf (blocks [0, NB_CS)), BDf (next NB_BD), bias concat (last 16).
static constexpr int NB_CS = (2 * FR * KF) / 256;        // 10368
static constexpr int NB_BD = (2 * 384 * KD + 255) / 256; // 960
__global__ void init_all(hlf* __restrict__ CSf, hlf* __restrict__ BDf,
                         const float* __restrict__ bk, const float* __restrict__ bv,
                         float* __restrict__ bkv)
{
    const int blk = blockIdx.x;
    if (blk < NB_CS) {
        long long idx = (long long)blk * 256 + threadIdx.x;
        int half = (int)(idx / ((long long)FR * KF));
        int rem = (int)(idx % ((long long)FR * KF));
        int i = rem / KF, j = rem % KF;
        float v = 0.f;
        if (j <= 1024) {
            int p = (int)(((long long)i * j) % Sm);
            float x = 2.0f * (float)p / (float)Sm;
            float s, c;
            sincospif(x, &s, &c);
            v = half ? s : c;
        }
        CSf[idx] = __float2half_rn(v);
    } else if (blk < NB_CS + NB_BD) {
        long long idx = (long long)(blk - NB_CS) * 256 + threadIdx.x;
        if (idx >= 2LL * 384 * KD) return;
        int half = (int)(idx / (384 * KD));
        int rem = (int)(idx % (384 * KD));
        int i = rem / KD, k = rem % KD;
        float v = 0.f;
        if (k <= 256) {
            int p = (int)(((long long)i * k) % Dm);
            float x = 2.0f * (float)p / (float)Dm;
            float s, c;
            sincospif(x, &s, &c);
            v = half ? s : c;
        }
        BDf[idx] = __float2half_rn(v);
    } else {
        int i = (blk - NB_CS - NB_BD) * 256 + threadIdx.x;
        if (i < 2048) bkv[i] = bk[i];
        else if (i < 4096) bkv[i] = bv[i - 2048];
    }
}

// Double fold of x_dec (S then D), both halves. One block per (b, j).
// Vectorized uint2 stores (4 halves per thread).
__global__ void xdec_fold2(const float* __restrict__ x, hlf* __restrict__ xdff)
{
    __shared__ float rj[512], rm[512];
    const int j = blockIdx.x % KF;
    const int b = blockIdx.x / KF;
    const int t = threadIdx.x;                 // 128
    hlf* co = xdff + ((long long)(0 * 4 + b) * KF + j) * KD;
    hlf* si = xdff + ((long long)(1 * 4 + b) * KF + j) * KD;
    if (j > 1024) {
        if (t < KD / 4) {
            *(uint2*)(co + t * 4) = make_uint2(0u, 0u);
            *(uint2*)(si + t * 4) = make_uint2(0u, 0u);
        }
        return;
    }
    const float* xb = x + (long long)b * SD;
    ((float4*)rj)[t] = ((const float4*)(xb + (long long)j * Dm))[t];
    if (j >= 1 && j <= 1023)
        ((float4*)rm)[t] = ((const float4*)(xb + (long long)(Sm - j) * Dm))[t];
    else
        ((float4*)rm)[t] = make_float4(0.f, 0.f, 0.f, 0.f);
    __syncthreads();
    if (t < KD / 4) {
        float cv[4], sv[4];
#pragma unroll
        for (int jj = 0; jj < 4; jj++) {
            int k = t * 4 + jj;
            cv[jj] = 0.f; sv[jj] = 0.f;
            if (k == 0) {
                cv[jj] = rj[0] + rm[0];
            } else if (k == 256) {
                cv[jj] = rj[256] + rm[256];
            } else if (k < 256) {
                float yck = rj[k] + rm[k], yck2 = rj[512 - k] + rm[512 - k];
                float ysk = rj[k] - rm[k], ysk2 = rj[512 - k] - rm[512 - k];
                cv[jj] = yck + yck2;
                sv[jj] = ysk - ysk2;
            }
        }
        *(uint2*)(co + t * 4) = make_uint2(packf2(cv[0], cv[1]), packf2(cv[2], cv[3]));
        *(uint2*)(si + t * 4) = make_uint2(packf2(sv[0], sv[1]), packf2(sv[2], sv[3]));
    }
}

// fp32 -> fp16 (hi only), 8 elems/thread
__global__ void split_k8(const float* __restrict__ in, hlf* __restrict__ h, long long n8)
{
    long long i = (long long)blockIdx.x * blockDim.x + threadIdx.x;
    if (i >= n8) return;
    long long base = i * 8;
    float4 a = *(const float4*)(in + base);
    float4 b = *(const float4*)(in + base + 4);
    uint4 ho;
    ho.x = packf2(a.x, a.y); ho.y = packf2(a.z, a.w);
    ho.z = packf2(b.x, b.y); ho.w = packf2(b.z, b.w);
    *(uint4*)(h + base) = ho;
}

// All six weight transposes in one launch; every segment is exactly 1024 tiles.
// Vectorized uint2 output stores (4 consecutive fp16 per thread).
struct WSeg { const float* in; hlf* out; int nTx, nTy, wo; long long sIn, sOut; int R, C; };
struct WPrep { WSeg s[6]; };

__global__ void weights_prep(WPrep P)
{
    __shared__ float t[32][33];
    const int seg = blockIdx.x >> 10;
    const int id = blockIdx.x & 1023;
    const WSeg w = P.s[seg];
    const int tilesPerZ = w.nTx * w.nTy;
    const int bz = id / tilesPerZ;
    const int rem = id % tilesPerZ;
    const int bx = rem % w.nTx;
    const int by = rem / w.nTx;
    const int tx = threadIdx.x, ty = threadIdx.y;
    // load phase: t[rIdx][cIdx] = input value at (row r0+rIdx, col c0+cIdx)
    const int c0 = bx * 32, r0 = by * 32;
    if (!w.wo) {
        const float* ib = w.in + (long long)bz * w.sIn;
#pragma unroll
        for (int i = 0; i < 4; i++)
            t[ty + i * 8][tx] = ib[(long long)(r0 + ty + i * 8) * w.C + c0 + tx];
    } else {
#pragma unroll
        for (int i = 0; i < 4; i++) {
            int d = r0 + ty + i * 8;
            t[ty + i * 8][tx] = w.in[(long long)(d * 4 + bz) * Dm + c0 + tx];
        }
    }
    __syncthreads();
    // write phase: out[(c0+wr)*ldo + r0+wc .. +3] = t[wc..][wr]
    const int tid = ty * 32 + tx;
    const int wr = tid >> 3;        // 0..31 output row within tile
    const int wc = (tid & 7) * 4;   // 0..28 output col within tile
    float v0 = t[wc][wr], v1 = t[wc + 1][wr], v2 = t[wc + 2][wr], v3 = t[wc + 3][wr];
    uint2 o2 = make_uint2(packf2(v0, v1), packf2(v2, v3));
    long long obase = w.wo ? (long long)bz * DD : (long long)bz * w.sOut;
    int ldo = w.wo ? Dm : w.R;
    *(uint2*)(w.out + obase + (long long)(c0 + wr) * ldo + r0 + wc) = o2;
}

// Merged softmax: blocks [0, 4096) -> q (qkh->qsh, h-stride BSD, 4/thread);
// blocks [4096, 6144) -> kT in-place (kvTh, h-stride 4*SD, 8/thread).
__global__ void softmax_all(const hlf* __restrict__ qk, hlf* __restrict__ qs,
                            hlf* __restrict__ kv)
{
    const int blk = blockIdx.x;
    if (blk < 4096) {
        long long i4 = (long long)blk * 256 + threadIdx.x;
        long long base = i4 * 4;
        float v[4][4];
#pragma unroll
        for (int h = 0; h < 4; h++) {
            uint2 raw = *(const uint2*)(qk + h * BSD + base);
            hlf* hp = (hlf*)&raw;
#pragma unroll
            for (int j = 0; j < 4; j++) v[h][j] = __half2float(hp[j]);
        }
#pragma unroll
        for (int j = 0; j < 4; j++) {
            float m = fmaxf(fmaxf(v[0][j], v[1][j]), fmaxf(v[2][j], v[3][j]));
            float e0 = expf(v[0][j] - m), e1 = expf(v[1][j] - m);
            float e2 = expf(v[2][j] - m), e3 = expf(v[3][j] - m);
            float inv = 1.f / (e0 + e1 + e2 + e3);
            v[0][j] = e0 * inv; v[1][j] = e1 * inv; v[2][j] = e2 * inv; v[3][j] = e3 * inv;
        }
#pragma unroll
        for (int h = 0; h < 4; h++) {
            uint2 ho = make_uint2(packf2(v[h][0], v[h][1]), packf2(v[h][2], v[h][3]));
            *(uint2*)(qs + h * BSD + base) = ho;
        }
    } else {
        long long idx = (long long)(blk - 4096) * 256 + threadIdx.x;
        const long long PER_B = SD / 8;
        const int b = (int)(idx / PER_B);
        const long long off = (idx % PER_B) * 8;
        uint4 raw[4];
#pragma unroll
        for (int h = 0; h < 4; h++)
            raw[h] = *(const uint4*)(kv + (long long)(h * 4 + b) * SD + off);
        float v[4][8];
#pragma unroll
        for (int h = 0; h < 4; h++) {
            hlf* hp = (hlf*)&raw[h];
#pragma unroll
            for (int j = 0; j < 8; j++) v[h][j] = __half2float(hp[j]);
        }
#pragma unroll
        for (int j = 0; j < 8; j++) {
            float m = fmaxf(fmaxf(v[0][j], v[1][j]), fmaxf(v[2][j], v[3][j]));
            float e0 = expf(v[0][j] - m), e1 = expf(v[1][j] - m);
            float e2 = expf(v[2][j] - m), e3 = expf(v[3][j] - m);
            float inv = 1.f / (e0 + e1 + e2 + e3);
            v[0][j] = e0 * inv; v[1][j] = e1 * inv; v[2][j] = e2 * inv; v[3][j] = e3 * inv;
        }
#pragma unroll
        for (int h = 0; h < 4; h++) {
            uint4 o;
            o.x = packf2(v[h][0], v[h][1]); o.y = packf2(v[h][2], v[h][3]);
            o.z = packf2(v[h][4], v[h][5]); o.w = packf2(v[h][6], v[h][7]);
            *(uint4*)(kv + (long long)(h * 4 + b) * SD + off) = o;
        }
    }
}

// LN1 fused with FFT quadrant reconstruction; fp16 out only.
__global__ void ln1_fft(const float* __restrict__ x_dec, const float* __restrict__ cps,
                        const float* __restrict__ g, const float* __restrict__ be,
                        hlf* __restrict__ oh)
{
    __shared__ float red[4];
    const long long row = blockIdx.x;        // b*2048 + s
    const int b = (int)(row >> 11);
    const int s = (int)(row & 2047);
    const int t = threadIdx.x;               // 128

    const int ip = (s <= 1024) ? s : (Sm - s);
    const bool fi = (s > 1024);
    const float* cpr = cps + (long long)b * FR * FC + (long long)ip * FC;
    const float* spr = cpr + 4LL * FR * FC;

    float4 vx = ((const float4*)(x_dec + row * Dm))[t];
    float v4[4];
#pragma unroll
    for (int j = 0; j < 4; j++) {
        int d = t * 4 + j;
        int dp = (d <= 256) ? d : (Dm - d);
        bool fd = (d > 256);
        float c = cpr[dp], sv = spr[dp];
        float xfv = c + ((fi != fd) ? sv : -sv);
        v4[j] = ((const float*)&vx)[j] + xfv;
    }

    float ssum = v4[0] + v4[1] + v4[2] + v4[3];
#pragma unroll
    for (int o = 16; o > 0; o >>= 1) ssum += __shfl_xor_sync(0xffffffffu, ssum, o);
    if ((t & 31) == 0) red[t >> 5] = ssum;
    __syncthreads();
    float mu = (red[0] + red[1] + red[2] + red[3]) * (1.f / (float)Dm);
    __syncthreads();
    float d0 = v4[0] - mu, d1 = v4[1] - mu, d2 = v4[2] - mu, d3 = v4[3] - mu;
    float q = d0 * d0 + d1 * d1 + d2 * d2 + d3 * d3;
#pragma unroll
    for (int o = 16; o > 0; o >>= 1) q += __shfl_xor_sync(0xffffffffu, q, o);
    if ((t & 31) == 0) red[t >> 5] = q;
    __syncthreads();
    float var = (red[0] + red[1] + red[2] + red[3]) * (1.f / (float)Dm);
    float rstd = rsqrtf(var + 1e-5f);
    float4 vg = ((const float4*)g)[t];
    float4 vbe = ((const float4*)be)[t];
    float o0 = fmaf(vg.x, d0 * rstd, vbe.x);
    float o1 = fmaf(vg.y, d1 * rstd, vbe.y);
    float o2 = fmaf(vg.z, d2 * rstd, vbe.z);
    float o3 = fmaf(vg.w, d3 * rstd, vbe.w);
    long long o = row * Dm + t * 4;
    *(uint2*)(oh + o) = make_uint2(packf2(o0, o1), packf2(o2, o3));
}

// LN of (a fp16 + b fp16); fp32 out (optional) + fp16 out (optional).
__global__ void ln_hh(const hlf* __restrict__ a, const hlf* __restrict__ bres,
                      const float* __restrict__ g, const float* __restrict__ be,
                      float* __restrict__ out, hlf* __restrict__ oh)
{
    __shared__ float red[4];
    long long row = blockIdx.x;
    int t = threadIdx.x;  // 128
    uint2 var_ = ((const uint2*)(a + row * Dm))[t];
    uint2 vbr = ((const uint2*)(bres + row * Dm))[t];
    hlf* ap = (hlf*)&var_;
    hlf* bp = (hlf*)&vbr;
    float4 v = make_float4(__half2float(ap[0]) + __half2float(bp[0]),
                           __half2float(ap[1]) + __half2float(bp[1]),
                           __half2float(ap[2]) + __half2float(bp[2]),
                           __half2float(ap[3]) + __half2float(bp[3]));
    float s = v.x + v.y + v.z + v.w;
#pragma unroll
    for (int o = 16; o > 0; o >>= 1) s += __shfl_xor_sync(0xffffffffu, s, o);
    if ((t & 31) == 0) red[t >> 5] = s;
    __syncthreads();
    float mu = (red[0] + red[1] + red[2] + red[3]) * (1.f / (float)Dm);
    __syncthreads();
    float d0 = v.x - mu, d1 = v.y - mu, d2 = v.z - mu, d3 = v.w - mu;
    float q = d0 * d0 + d1 * d1 + d2 * d2 + d3 * d3;
#pragma unroll
    for (int o = 16; o > 0; o >>= 1) q += __shfl_xor_sync(0xffffffffu, q, o);
    if ((t & 31) == 0) red[t >> 5] = q;
    __syncthreads();
    float var = (red[0] + red[1] + red[2] + red[3]) * (1.f / (float)Dm);
    float rstd = rsqrtf(var + 1e-5f);
    float4 vg = ((const float4*)g)[t];
    float4 vbe = ((const float4*)be)[t];
    float4 o4;
    o4.x = fmaf(vg.x, d0 * rstd, vbe.x);
    o4.y = fmaf(vg.y, d1 * rstd, vbe.y);
    o4.z = fmaf(vg.z, d2 * rstd, vbe.z);
    o4.w = fmaf(vg.w, d3 * rstd, vbe.w);
    if (out) ((float4*)(out + row * Dm))[t] = o4;
    if (oh) {
        long long o = row * Dm + t * 4;
        *(uint2*)(oh + o) = make_uint2(packf2(o4.x, o4.y), packf2(o4.z, o4.w));
    }
}

// ---------------------------------------------------------------------------
// Host
// ---------------------------------------------------------------------------
static TcPasses mk1(const hlf* Ah, const hlf* Bh) {
    TcPasses P{};
    P.A[0] = Ah; P.B[0] = Bh;
    return P;
}

static void tcg(const TcPasses& P, int np, float* C, hlf* Ch,
                int M, int N, int K, int lda, int ldb, int ldc,
                long long sA, long long sB, long long sC, int batch,
                const float* bias, long long sBias, int act, int split, int bmode,
                int shA = 0, int mskA = 0x7FFFFFFF, int mskB = 0x7FFFFFFF)
{
    dim3 grid(N / 128, M / 128, batch), block(256);
    if (act == 1)
        mma_gemm<1, 2, 1><<<grid, block, SMEM_G>>>(P, np, C, Ch, K, lda, ldb, ldc, sA, sB, sC, bias, sBias, shA, mskA, mskB);
    else if (split == 2 && bmode == 2)
        mma_gemm<0, 2, 2><<<grid, block, SMEM_G>>>(P, np, C, Ch, K, lda, ldb, ldc, sA, sB, sC, bias, sBias, shA, mskA, mskB);
    else if (split == 2 && bmode == 1)
        mma_gemm<0, 2, 1><<<grid, block, SMEM_G>>>(P, np, C, Ch, K, lda, ldb, ldc, sA, sB, sC, bias, sBias, shA, mskA, mskB);
    else if (split == 2)
        mma_gemm<0, 2, 0><<<grid, block, SMEM_G>>>(P, np, C, Ch, K, lda, ldb, ldc, sA, sB, sC, bias, sBias, shA, mskA, mskB);
    else if (bmode == 1)
        mma_gemm<0, 0, 1><<<grid, block, SMEM_G>>>(P, np, C, Ch, K, lda, ldb, ldc, sA, sB, sC, bias, sBias, shA, mskA, mskB);
    else
        mma_gemm<0, 0, 0><<<grid, block, SMEM_G>>>(P, np, C, Ch, K, lda, ldb, ldc, sA, sB, sC, bias, sBias, shA, mskA, mskB);
}

#define GETSYM(var, sym) do { void* _p; cudaGetSymbolAddress(&_p, sym); var = (decltype(var))_p; } while (0)

extern "C" void kernel_launch(void* const* d_in, const int* in_sizes, int n_in,
                              void* d_out, int out_size)
{
    const float* x_enc = (const float*)d_in[0];
    const float* x_dec = (const float*)d_in[1];
    const float* Wq = (const float*)d_in[2];
    const float* bq = (const float*)d_in[3];
    const float* Wk = (const float*)d_in[4];
    const float* bk = (const float*)d_in[5];
    const float* Wv = (const float*)d_in[6];
    const float* bv = (const float*)d_in[7];
    const float* Wo = (const float*)d_in[8];
    const float* bo = (const float*)d_in[9];
    const float* ln1g = (const float*)d_in[10];
    const float* ln1b = (const float*)d_in[11];
    const float* ln2g = (const float*)d_in[12];
    const float* ln2b = (const float*)d_in[13];
    const float* W1 = (const float*)d_in[14];
    const float* b1 = (const float*)d_in[15];
    const float* W2 = (const float*)d_in[16];
    const float* b2 = (const float*)d_in[17];
    const float* ln3g = (const float*)d_in[18];
    const float* ln3b = (const float*)d_in[19];
    float* outp = (float*)d_out;

    hlf *CSf, *BDf, *xdff, *t12Tf, *xqkh, *qkh;
    hlf *qsh, *kvTh, *gcDE, *Mth;
    hlf *WqTh, *WkvTh, *WoTh, *W1Th, *W2Th, *x2h, *midh, *attnh, *ffh;
    float *cps, *bkv;
    GETSYM(CSf, g_CSf); GETSYM(BDf, g_BDf); GETSYM(xdff, g_xdff);
    GETSYM(t12Tf, g_t12Tf);
    GETSYM(cps, g_cps);
    GETSYM(xqkh, g_xqkh); GETSYM(qkh, g_qkh);
    GETSYM(bkv, g_bkv);
    GETSYM(qsh, g_qsh); GETSYM(kvTh, g_kvTh);
    GETSYM(gcDE, g_gcDE); GETSYM(Mth, g_Mth);
    GETSYM(WqTh, g_WqTh); GETSYM(WkvTh, g_WkvTh); GETSYM(WoTh, g_WoTh);
    GETSYM(W1Th, g_W1Th); GETSYM(W2Th, g_W2Th);
    GETSYM(attnh, g_attnh); GETSYM(x2h, g_x2h);
    GETSYM(midh, g_midh); GETSYM(ffh, g_ffh);

    cudaFuncSetAttribute(mma_gemm<0, 0, 0>, cudaFuncAttributeMaxDynamicSharedMemorySize, SMEM_G);
    cudaFuncSetAttribute(mma_gemm<0, 0, 1>, cudaFuncAttributeMaxDynamicSharedMemorySize, SMEM_G);
    cudaFuncSetAttribute(mma_gemm<0, 2, 0>, cudaFuncAttributeMaxDynamicSharedMemorySize, SMEM_G);
    cudaFuncSetAttribute(mma_gemm<0, 2, 1>, cudaFuncAttributeMaxDynamicSharedMemorySize, SMEM_G);
    cudaFuncSetAttribute(mma_gemm<0, 2, 2>, cudaFuncAttributeMaxDynamicSharedMemorySize, SMEM_G);
    cudaFuncSetAttribute(mma_gemm<1, 2, 1>, cudaFuncAttributeMaxDynamicSharedMemorySize, SMEM_G);

    dim3 tb(32, 8);

    // 0) folded DFT matrices + bias concat: one launch
    init_all<<<NB_CS + NB_BD + 16, 256>>>(CSf, BDf, bk, bv, bkv);

    // inputs: x_enc fp16; x_dec double-folded
    split_k8<<<(int)(BSD / 8 / 256), 256>>>(x_enc, xqkh + BSD, BSD / 8);
    xdec_fold2<<<Bm * KF, 128>>>(x_dec, xdff);

    // weight prep: one launch, 6 segments x 1024 tiles
    {
        WPrep P{};
        P.s[0] = {Wq, WqTh, 16, 16, 0, DD, DD, Dm, Dm};
        P.s[1] = {Wk, WkvTh, 16, 16, 0, DD, DD, Dm, Dm};
        P.s[2] = {Wv, WkvTh + 4 * DD, 16, 16, 0, DD, DD, Dm, Dm};
        P.s[3] = {Wo, WoTh, 16, 16, 1, 0, 0, Dm, Dm};
        P.s[4] = {W1, W1Th, 64, 16, 0, 0, 0, Dm, MIDm};
        P.s[5] = {W2, W2Th, 16, 64, 0, 0, 0, MIDm, Dm};
        weights_prep<<<6144, tb>>>(P);
    }

    // 1) t12Tf[z=half*4+b] = BDf[half] @ xdff[z]^T  (M=384, N=1152, K=320, z=8)
    tcg(mk1(BDf, xdff), 1, nullptr, t12Tf,
        384, KF, KD, KD, KD, KF, 384LL * KD, (long long)KF * KD, 384LL * KF, 8,
        nullptr, 0, 0, 2, 0, /*shA=*/2, /*mskA=*/0x7FFFFFFF, /*mskB=*/7);

    // 2) merged cp/sp: cps[z] = CSf[z>>2] @ t12Tf[z]^T  (M=1152,N=384,K=1088,z=8)
    tcg(mk1(CSf, t12Tf), 1, cps, nullptr,
        FR, FC, KFK, KF, KF, FC, (long long)FR * KF, 384LL * KF, (long long)FR * FC, 8,
        nullptr, 0, 0, 0, 0, /*shA=*/2, /*mskA=*/0x7FFFFFFF, /*mskB=*/7);

    // 3) xd = LN1(x_dec + fftmerge(cps)); fp16 only into stacked buffer
    ln1_fft<<<BSm, 128>>>(x_dec, cps, ln1g, ln1b, xqkh);

    // 4) kvT[z=kv*16+h*4+b] = Wkv_{z>>2}^T @ x_enc[b]^T + bkv (row), fp16; z=32
    tcg(mk1(WkvTh, xqkh + BSD), 1, nullptr, kvTh,
        Dm, Sm, Dm, Dm, Dm, Sm, DD, SD, SD, 32, bkv, Dm, 0, 2, 2,
        /*shA=*/2, /*mskA=*/0x7FFFFFFF, /*mskB=*/3);

    // 5) q projections: z=4 (h), 1-pass, fp16 logits
    tcg(mk1(xqkh, WqTh), 1, nullptr, qkh,
        BSm, Dm, Dm, Dm, Dm, Dm, 0, DD, BSD, 4, bq, Dm, 0, 2, 1,
        /*shA=*/0, /*mskA=*/0, /*mskB=*/3);

    // 6) merged softmax over heads: q (->qsh) and kT (in-place)
    softmax_all<<<6144, 256>>>(qkh, qsh, kvTh);

    // 7) gcDE[z][d,e] = ksT @ vsT^T  (M=N=512, K=2048, z=16), fp16 out
    tcg(mk1(kvTh, kvTh + 16 * SD), 1, nullptr, gcDE,
        Dm, Dm, Sm, Sm, Sm, Dm, SD, SD, DD, 16, nullptr, 0, 0, 2, 0);

    // 8) Mt[z][n,d] = WoT_{z>>2} @ gcDE[z]^T  (M=N=K=512, z=16)
    tcg(mk1(WoTh, gcDE), 1, nullptr, Mth,
        Dm, Dm, Dm, Dm, Dm, Dm, DD, DD, DD, 16, nullptr, 0, 0, 2, 0,
        /*shA=*/2, /*mskA=*/0x7FFFFFFF, /*mskB=*/15);

    // 9) attn[b][s,n] = sum_h qs_h[b] @ Mt[h*4+b]^T + bo  (4 passes; z=4), fp16 out
    {
        TcPasses P{};
        for (int h = 0; h < Hn; h++) {
            P.A[h] = qsh + (long long)h * Bm * SD;
            P.B[h] = Mth + (long long)h * Bm * DD;
        }
        tcg(P, 4, nullptr, attnh,
            Sm, Dm, Dm, Dm, Dm, Dm, SD, DD, SD, Bm, bo, 0, 0, 2, 1,
            /*shA=*/0, /*mskA=*/0x7FFFFFFF, /*mskB=*/3);
    }

    // 10) x2 = LN2(xd fp16 + attn fp16); fp16 out only
    ln_hh<<<BSm, 128>>>(xqkh, attnh, ln2g, ln2b, nullptr, x2h);

    // 11) mid = selu(x2 @ W1 + b1), fp16 out, 1-pass
    tcg(mk1(x2h, W1Th), 1, nullptr, midh,
        BSm, MIDm, Dm, Dm, Dm, MIDm, 0, 0, 0, 1, b1, 0, 1, 2, 1);

    // 12) ff = mid @ W2 + b2, fp16 out, 1-pass
    tcg(mk1(midh, W2Th), 1, nullptr, ffh,
        BSm, Dm, MIDm, MIDm, MIDm, Dm, 0, 0, 0, 1, b2, 0, 0, 2, 1);

    // 13) out = LN3(x2 fp16 + ff fp16), fp32 out
    ln_hh<<<BSm, 128>>>(x2h, ffh, ln3g, ln3b, outp, nullptr);
}

// round 17
// speedup vs baseline: 2.7362x; 1.0555x over previous
#include <cuda_runtime.h>
#include <cuda_fp16.h>
#include <math.h>
#include <stdint.h>

typedef __half hlf;

static constexpr int Dm = 512, Hn = 4, MIDm = 2048, Bm = 4, Sm = 2048;
static constexpr int BSm = Bm * Sm;                      // 8192
static constexpr long long BSD = (long long)BSm * Dm;    // 4194304
static constexpr long long SD  = (long long)Sm * Dm;     // 1048576
static constexpr long long DD  = (long long)Dm * Dm;     // 262144

// FFT-symmetry tile sizes
static constexpr int FR = 1152;   // S-axis rows computed (need 0..1024)
static constexpr int FC = 384;    // D-axis cols computed (need 0..256)
static constexpr int KF = 1152;   // folded S length (1025 padded)
static constexpr int KFK = 1088;  // K actually used in cps GEMM
static constexpr int KD = 320;    // folded D length (257 padded)

// ---------------------------------------------------------------------------
// Static device scratch
// ---------------------------------------------------------------------------
__device__ __align__(256) hlf g_CSf[2 * FR * KF];                  // [cos;sin] S-folded
__device__ __align__(256) hlf g_BDf[2 * 384 * KD];                 // [cos;sin] D-folded
__device__ __align__(256) hlf g_xdff[8 * KF * KD];                 // [half*4+b][1152,320]
__device__ __align__(256) hlf g_t12Tf[8 * 384 * KF];               // [half*4+b][384,1152]
__device__ __align__(256) float g_cps[8 * FR * FC];                // cp z=0..3, sp z=4..7
// stacked A: [0..BSD)=LN1(xd) fp16, [BSD..2BSD)=x_enc fp16
__device__ __align__(256) hlf g_xqkh[8388608];
__device__ __align__(256) hlf g_xeT[4194304];                      // [b][D,S] x_enc^T
__device__ __align__(256) hlf g_qkh[16777216];                     // [4][b,s,d] q logits
__device__ __align__(256) hlf g_qsh[16777216];
__device__ __align__(256) hlf g_kTh[16777216];                     // [z=h*4+b][D,S] k
__device__ __align__(256) float g_colsum[8192];                    // [z][d] colsum of ks
__device__ __align__(256) hlf g_kgh[4194304];                      // [z][D,M] = ksT @ xeT^T
__device__ __align__(256) hlf g_gcDE[4194304];                     // [z][D,E]
__device__ __align__(256) hlf g_Mth[4194304];                      // [z][N,D]
__device__ __align__(256) hlf g_WqTh[1048576];                     // [h][512,512]
__device__ __align__(256) hlf g_WkvTh[2097152];                    // [WkT0..3;WvT0..3]
__device__ __align__(256) hlf g_WoTh[1048576];                     // [h][512,512] (n,e)
__device__ __align__(256) hlf g_W1Th[1048576];                     // [2048,512]
__device__ __align__(256) hlf g_W2Th[1048576];                     // [512,2048]
__device__ __align__(256) hlf g_attnh[4194304];
__device__ __align__(256) hlf g_x2h[4194304];
__device__ __align__(256) hlf g_midh[16777216];
__device__ __align__(256) hlf g_ffh[4194304];

// ---------------------------------------------------------------------------
// Helpers
// ---------------------------------------------------------------------------
__device__ __forceinline__ uint32_t smem_u32(const void* p) {
    uint32_t a;
    asm("{ .reg .u64 t; cvta.to.shared.u64 t, %1; cvt.u32.u64 %0, t; }" : "=r"(a) : "l"(p));
    return a;
}
__device__ __forceinline__ float selu_f(float x) {
    const float sc = 1.0507009873554805f, al = 1.6732632423543772f;
    return x > 0.f ? sc * x : sc * al * (expf(x) - 1.f);
}
__device__ __forceinline__ uint32_t packhl(hlf a, hlf b) {
    return ((uint32_t)*(uint16_t*)&b << 16) | (uint32_t)*(uint16_t*)&a;
}
__device__ __forceinline__ uint32_t packf2(float a, float b) {
    hlf ha = __float2half_rn(a), hb = __float2half_rn(b);
    return packhl(ha, hb);
}

#define LDSM_X4(r0, r1, r2, r3, addr) \
    asm volatile("ldmatrix.sync.aligned.m8n8.x4.shared.b16 {%0,%1,%2,%3}, [%4];" \
        : "=r"(r0), "=r"(r1), "=r"(r2), "=r"(r3) : "r"(addr))

#define MMA_F16(d, a, b0, b1) \
    asm volatile("mma.sync.aligned.m16n8k16.row.col.f32.f16.f16.f32 " \
        "{%0,%1,%2,%3}, {%4,%5,%6,%7}, {%8,%9}, {%0,%1,%2,%3};" \
        : "+f"((d)[0]), "+f"((d)[1]), "+f"((d)[2]), "+f"((d)[3]) \
        : "r"((a)[0]), "r"((a)[1]), "r"((a)[2]), "r"((a)[3]), "r"(b0), "r"(b1))

#define CP_ASYNC16(dst, src) \
    asm volatile("cp.async.cg.shared.global [%0], [%1], 16;" :: "r"(dst), "l"(src))
#define CP_COMMIT() asm volatile("cp.async.commit_group;")
#define CP_WAIT1()  asm volatile("cp.async.wait_group 1;")

// ---------------------------------------------------------------------------
// HMMA GEMM, cp.async 3-stage pipeline.
// Block 128x128, 8 warps, warp 64x32, BK=64, 2 CTA/SM.
// C[z] = A[(z>>shA)&mskA] @ B_p[(z>>shB)&mskB]^T (+bias col[zb]/row[za])(+SELU)
// SPLIT: 0 = fp32 out, 2 = fp16 out.
// ---------------------------------------------------------------------------
struct TcPasses { const hlf* A[4]; const hlf* B[4]; };

static constexpr int BKg = 64;
static constexpr int LDSg = BKg + 8;
static constexpr int TILE_B = 128 * LDSg * 2;
static constexpr int STAGES = 3;
static constexpr int SMEM_B_OFF = STAGES * TILE_B;
static constexpr int SMEM_BIAS_OFF = 2 * STAGES * TILE_B;
static constexpr int SMEM_G = SMEM_BIAS_OFF + 128 * 4;

template <int ACT, int SPLIT, int BMODE>   // BMODE: 0 none, 1 col (zb), 2 row (za)
__global__ __launch_bounds__(256, 2) void mma_gemm(
    TcPasses P, int npass,
    float* __restrict__ C, hlf* __restrict__ Chi,
    int K, int lda, int ldb, int ldc,
    long long sA, long long sB, long long sC,
    const float* __restrict__ bias, long long sBias,
    int shA, int mskA, int shB, int mskB)
{
    extern __shared__ char smem[];
    float* bias_s = (float*)(smem + SMEM_BIAS_OFF);
    const uint32_t sA0 = smem_u32(smem);
    const uint32_t sB0 = sA0 + SMEM_B_OFF;

    const int tid = threadIdx.x;
    const int lane = tid & 31;
    const int wid = tid >> 5;
    const int wm = (wid & 1) * 64;
    const int wn = (wid >> 1) * 32;
    const int z = blockIdx.z;
    const int za = (z >> shA) & mskA;
    const int zb = (z >> shB) & mskB;
    const int m0 = blockIdx.y * 128, n0 = blockIdx.x * 128;

    if (tid < 128) {
        if (BMODE == 0) bias_s[tid] = 0.f;
        else if (BMODE == 1) bias_s[tid] = bias[(long long)zb * sBias + n0 + tid];
        else bias_s[tid] = bias[(long long)za * sBias + m0 + tid];
    }

    float acc[4][4][4];
#pragma unroll
    for (int i = 0; i < 4; i++)
#pragma unroll
        for (int j = 0; j < 4; j++)
#pragma unroll
            for (int k = 0; k < 4; k++) acc[i][j][k] = 0.f;

    const int cpp = K / BKg;
    const int total = npass * cpp;

    const int crow = tid >> 3;
    const int ccol = (tid & 7) * 8;

    auto loadStage = [&](int c, int stg) {
        int p = c / cpp;
        int k0 = (c - p * cpp) * BKg;
        const hlf* Ab = P.A[p] + (long long)za * sA + k0 + ccol;
        const hlf* Bb = P.B[p] + (long long)zb * sB + k0 + ccol;
        uint32_t da = sA0 + stg * TILE_B + (crow * LDSg + ccol) * 2;
        uint32_t db = sB0 + stg * TILE_B + (crow * LDSg + ccol) * 2;
#pragma unroll
        for (int i = 0; i < 4; i++) {
            int row = crow + i * 32;
            CP_ASYNC16(da + i * 32 * LDSg * 2, Ab + (long long)(m0 + row) * lda);
            CP_ASYNC16(db + i * 32 * LDSg * 2, Bb + (long long)(n0 + row) * ldb);
        }
    };

    loadStage(0, 0); CP_COMMIT();
    loadStage(1, 1); CP_COMMIT();

    const int lrow16 = lane & 15;
    const int lhalf = lane >> 4;

    for (int c = 0; c < total; c++) {
        CP_WAIT1();
        __syncthreads();
        const int stg = c % STAGES;
        const uint32_t aB = sA0 + stg * TILE_B;
        const uint32_t bB = sB0 + stg * TILE_B;
#pragma unroll
        for (int ks = 0; ks < 4; ks++) {
            uint32_t af[4][4];
#pragma unroll
            for (int mi = 0; mi < 4; mi++) {
                uint32_t addr = aB + (uint32_t)(((wm + mi * 16 + lrow16) * LDSg
                                                + ks * 16 + lhalf * 8) * 2);
                LDSM_X4(af[mi][0], af[mi][1], af[mi][2], af[mi][3], addr);
            }
            uint32_t bfr[2][4];
#pragma unroll
            for (int nj = 0; nj < 2; nj++) {
                uint32_t addr = bB + (uint32_t)(((wn + nj * 16 + lrow16) * LDSg
                                                + ks * 16 + lhalf * 8) * 2);
                LDSM_X4(bfr[nj][0], bfr[nj][1], bfr[nj][2], bfr[nj][3], addr);
            }
#pragma unroll
            for (int mi = 0; mi < 4; mi++)
#pragma unroll
                for (int ni = 0; ni < 4; ni++) {
                    const int nj = ni >> 1, sub = ni & 1;
                    MMA_F16(acc[mi][ni], af[mi], bfr[nj][sub], bfr[nj][sub + 2]);
                }
        }
        if (c + 2 < total) loadStage(c + 2, (c + 2) % STAGES);
        CP_COMMIT();
    }

    const int cr = lane >> 2;
    const int cc = (lane & 3) * 2;
#pragma unroll
    for (int mi = 0; mi < 4; mi++) {
#pragma unroll
        for (int ni = 0; ni < 4; ni++) {
            const int bn = wn + ni * 8 + cc;
            const int gn = n0 + bn;
            const int rm = wm + mi * 16 + cr;
            const long long r0 = m0 + rm;
            const long long r1 = r0 + 8;
            float v0 = acc[mi][ni][0], v1 = acc[mi][ni][1];
            float v2 = acc[mi][ni][2], v3 = acc[mi][ni][3];
            if (BMODE == 1) {
                v0 += bias_s[bn]; v1 += bias_s[bn + 1];
                v2 += bias_s[bn]; v3 += bias_s[bn + 1];
            } else if (BMODE == 2) {
                v0 += bias_s[rm]; v1 += bias_s[rm];
                v2 += bias_s[rm + 8]; v3 += bias_s[rm + 8];
            }
            if (ACT == 1) { v0 = selu_f(v0); v1 = selu_f(v1); v2 = selu_f(v2); v3 = selu_f(v3); }
            if (SPLIT == 2) {
                *(uint32_t*)(Chi + (long long)z * sC + r0 * ldc + gn) = packf2(v0, v1);
                *(uint32_t*)(Chi + (long long)z * sC + r1 * ldc + gn) = packf2(v2, v3);
            } else {
                *(float2*)(C + (long long)z * sC + r0 * ldc + gn) = make_float2(v0, v1);
                *(float2*)(C + (long long)z * sC + r1 * ldc + gn) = make_float2(v2, v3);
            }
        }
    }
}

// ---------------------------------------------------------------------------
// Elementwise kernels
// ---------------------------------------------------------------------------
// Merged init: CSf (blocks [0, NB_CS)), BDf (next NB_BD).
static constexpr int NB_CS = (2 * FR * KF) / 256;        // 10368
static constexpr int NB_BD = (2 * 384 * KD + 255) / 256; // 960
__global__ void init_all(hlf* __restrict__ CSf, hlf* __restrict__ BDf)
{
    const int blk = blockIdx.x;
    if (blk < NB_CS) {
        long long idx = (long long)blk * 256 + threadIdx.x;
        int half = (int)(idx / ((long long)FR * KF));
        int rem = (int)(idx % ((long long)FR * KF));
        int i = rem / KF, j = rem % KF;
        float v = 0.f;
        if (j <= 1024) {
            int p = (int)(((long long)i * j) % Sm);
            float x = 2.0f * (float)p / (float)Sm;
            float s, c;
            sincospif(x, &s, &c);
            v = half ? s : c;
        }
        CSf[idx] = __float2half_rn(v);
    } else {
        long long idx = (long long)(blk - NB_CS) * 256 + threadIdx.x;
        if (idx >= 2LL * 384 * KD) return;
        int half = (int)(idx / (384 * KD));
        int rem = (int)(idx % (384 * KD));
        int i = rem / KD, k = rem % KD;
        float v = 0.f;
        if (k <= 256) {
            int p = (int)(((long long)i * k) % Dm);
            float x = 2.0f * (float)p / (float)Dm;
            float s, c;
            sincospif(x, &s, &c);
            v = half ? s : c;
        }
        BDf[idx] = __float2half_rn(v);
    }
}

// Double fold of x_dec (S then D), both halves. One block per (b, j).
__global__ void xdec_fold2(const float* __restrict__ x, hlf* __restrict__ xdff)
{
    __shared__ float rj[512], rm[512];
    const int j = blockIdx.x % KF;
    const int b = blockIdx.x / KF;
    const int t = threadIdx.x;                 // 128
    hlf* co = xdff + ((long long)(0 * 4 + b) * KF + j) * KD;
    hlf* si = xdff + ((long long)(1 * 4 + b) * KF + j) * KD;
    if (j > 1024) {
        if (t < KD / 4) {
            *(uint2*)(co + t * 4) = make_uint2(0u, 0u);
            *(uint2*)(si + t * 4) = make_uint2(0u, 0u);
        }
        return;
    }
    const float* xb = x + (long long)b * SD;
    ((float4*)rj)[t] = ((const float4*)(xb + (long long)j * Dm))[t];
    if (j >= 1 && j <= 1023)
        ((float4*)rm)[t] = ((const float4*)(xb + (long long)(Sm - j) * Dm))[t];
    else
        ((float4*)rm)[t] = make_float4(0.f, 0.f, 0.f, 0.f);
    __syncthreads();
    if (t < KD / 4) {
        float cv[4], sv[4];
#pragma unroll
        for (int jj = 0; jj < 4; jj++) {
            int k = t * 4 + jj;
            cv[jj] = 0.f; sv[jj] = 0.f;
            if (k == 0) {
                cv[jj] = rj[0] + rm[0];
            } else if (k == 256) {
                cv[jj] = rj[256] + rm[256];
            } else if (k < 256) {
                float yck = rj[k] + rm[k], yck2 = rj[512 - k] + rm[512 - k];
                float ysk = rj[k] - rm[k], ysk2 = rj[512 - k] - rm[512 - k];
                cv[jj] = yck + yck2;
                sv[jj] = ysk - ysk2;
            }
        }
        *(uint2*)(co + t * 4) = make_uint2(packf2(cv[0], cv[1]), packf2(cv[2], cv[3]));
        *(uint2*)(si + t * 4) = make_uint2(packf2(sv[0], sv[1]), packf2(sv[2], sv[3]));
    }
}

// x_enc prep: fp32 [b][s,d] -> fp16 straight (xh) AND fp16 transposed (xT [b][d,s]).
// 32x32 tiles; 1024 tiles per b, 4096 blocks. block (32,8).
__global__ void xenc_prep(const float* __restrict__ x, hlf* __restrict__ xh,
                          hlf* __restrict__ xT)
{
    __shared__ float t[32][33];
    const int b = blockIdx.x >> 10;
    const int id = blockIdx.x & 1023;
    const int bx = id & 15;          // d-tile (0..15)
    const int by = id >> 4;          // s-tile (0..63)
    const int c0 = bx * 32, r0 = by * 32;
    const int tx = threadIdx.x, ty = threadIdx.y;
    const float* xb = x + (long long)b * SD;
#pragma unroll
    for (int i = 0; i < 4; i++)
        t[ty + i * 8][tx] = xb[(long long)(r0 + ty + i * 8) * Dm + c0 + tx];
    __syncthreads();
    const int tid = ty * 32 + tx;
    const int wr = tid >> 3;         // 0..31
    const int wc = (tid & 7) * 4;    // 0..28
    // straight: xh[b][r0+wr][c0+wc..+3]
    {
        float v0 = t[wr][wc], v1 = t[wr][wc + 1], v2 = t[wr][wc + 2], v3 = t[wr][wc + 3];
        *(uint2*)(xh + (long long)b * SD + (long long)(r0 + wr) * Dm + c0 + wc) =
            make_uint2(packf2(v0, v1), packf2(v2, v3));
    }
    // transposed: xT[b][c0+wr][r0+wc..+3]
    {
        float v0 = t[wc][wr], v1 = t[wc + 1][wr], v2 = t[wc + 2][wr], v3 = t[wc + 3][wr];
        *(uint2*)(xT + (long long)b * SD + (long long)(c0 + wr) * Sm + r0 + wc) =
            make_uint2(packf2(v0, v1), packf2(v2, v3));
    }
}

// All six weight transposes in one launch; every segment is exactly 1024 tiles.
struct WSeg { const float* in; hlf* out; int nTx, nTy, wo; long long sIn, sOut; int R, C; };
struct WPrep { WSeg s[6]; };

__global__ void weights_prep(WPrep P)
{
    __shared__ float t[32][33];
    const int seg = blockIdx.x >> 10;
    const int id = blockIdx.x & 1023;
    const WSeg w = P.s[seg];
    const int tilesPerZ = w.nTx * w.nTy;
    const int bz = id / tilesPerZ;
    const int rem = id % tilesPerZ;
    const int bx = rem % w.nTx;
    const int by = rem / w.nTx;
    const int tx = threadIdx.x, ty = threadIdx.y;
    const int c0 = bx * 32, r0 = by * 32;
    if (!w.wo) {
        const float* ib = w.in + (long long)bz * w.sIn;
#pragma unroll
        for (int i = 0; i < 4; i++)
            t[ty + i * 8][tx] = ib[(long long)(r0 + ty + i * 8) * w.C + c0 + tx];
    } else {
#pragma unroll
        for (int i = 0; i < 4; i++) {
            int d = r0 + ty + i * 8;
            t[ty + i * 8][tx] = w.in[(long long)(d * 4 + bz) * Dm + c0 + tx];
        }
    }
    __syncthreads();
    const int tid = ty * 32 + tx;
    const int wr = tid >> 3;
    const int wc = (tid & 7) * 4;
    float v0 = t[wc][wr], v1 = t[wc + 1][wr], v2 = t[wc + 2][wr], v3 = t[wc + 3][wr];
    uint2 o2 = make_uint2(packf2(v0, v1), packf2(v2, v3));
    long long obase = w.wo ? (long long)bz * DD : (long long)bz * w.sOut;
    int ldo = w.wo ? Dm : w.R;
    *(uint2*)(w.out + obase + (long long)(c0 + wr) * ldo + r0 + wc) = o2;
}

// Merged softmax: blocks [0, 4096) -> q (qkh->qsh, h-stride BSD, 4/thread);
// blocks [4096, 6144) -> kT in-place (kTh, h-stride 4*SD, 8/thread) + colsum.
__global__ void softmax_all(const hlf* __restrict__ qk, hlf* __restrict__ qs,
                            hlf* __restrict__ kv, float* __restrict__ colsum)
{
    __shared__ float sred[4][8];
    const int blk = blockIdx.x;
    if (blk < 4096) {
        long long i4 = (long long)blk * 256 + threadIdx.x;
        long long base = i4 * 4;
        float v[4][4];
#pragma unroll
        for (int h = 0; h < 4; h++) {
            uint2 raw = *(const uint2*)(qk + h * BSD + base);
            hlf* hp = (hlf*)&raw;
#pragma unroll
            for (int j = 0; j < 4; j++) v[h][j] = __half2float(hp[j]);
        }
#pragma unroll
        for (int j = 0; j < 4; j++) {
            float m = fmaxf(fmaxf(v[0][j], v[1][j]), fmaxf(v[2][j], v[3][j]));
            float e0 = expf(v[0][j] - m), e1 = expf(v[1][j] - m);
            float e2 = expf(v[2][j] - m), e3 = expf(v[3][j] - m);
            float inv = 1.f / (e0 + e1 + e2 + e3);
            v[0][j] = e0 * inv; v[1][j] = e1 * inv; v[2][j] = e2 * inv; v[3][j] = e3 * inv;
        }
#pragma unroll
        for (int h = 0; h < 4; h++) {
            uint2 ho = make_uint2(packf2(v[h][0], v[h][1]), packf2(v[h][2], v[h][3]));
            *(uint2*)(qs + h * BSD + base) = ho;
        }
    } else {
        // block covers exactly one (b, d) row of 2048 s-elements for each h
        const int blkk = blk - 4096;        // 0..2047
        const int b = blkk >> 9;            // /512
        const int d = blkk & 511;
        const long long off = (long long)d * Sm + (long long)threadIdx.x * 8;
        uint4 raw[4];
#pragma unroll
        for (int h = 0; h < 4; h++)
            raw[h] = *(const uint4*)(kv + (long long)(h * 4 + b) * SD + off);
        float v[4][8];
#pragma unroll
        for (int h = 0; h < 4; h++) {
            hlf* hp = (hlf*)&raw[h];
#pragma unroll
            for (int j = 0; j < 8; j++) v[h][j] = __half2float(hp[j]);
        }
#pragma unroll
        for (int j = 0; j < 8; j++) {
            float m = fmaxf(fmaxf(v[0][j], v[1][j]), fmaxf(v[2][j], v[3][j]));
            float e0 = expf(v[0][j] - m), e1 = expf(v[1][j] - m);
            float e2 = expf(v[2][j] - m), e3 = expf(v[3][j] - m);
            float inv = 1.f / (e0 + e1 + e2 + e3);
            v[0][j] = e0 * inv; v[1][j] = e1 * inv; v[2][j] = e2 * inv; v[3][j] = e3 * inv;
        }
        float part[4];
#pragma unroll
        for (int h = 0; h < 4; h++) {
            uint4 o;
            o.x = packf2(v[h][0], v[h][1]); o.y = packf2(v[h][2], v[h][3]);
            o.z = packf2(v[h][4], v[h][5]); o.w = packf2(v[h][6], v[h][7]);
            *(uint4*)(kv + (long long)(h * 4 + b) * SD + off) = o;
            float p = 0.f;
#pragma unroll
            for (int j = 0; j < 8; j++) p += v[h][j];
            part[h] = p;
        }
        const int lane = threadIdx.x & 31, wid = threadIdx.x >> 5;
#pragma unroll
        for (int h = 0; h < 4; h++) {
#pragma unroll
            for (int o = 16; o > 0; o >>= 1)
                part[h] += __shfl_xor_sync(0xffffffffu, part[h], o);
            if (lane == 0) sred[h][wid] = part[h];
        }
        __syncthreads();
        if (threadIdx.x < 4) {
            float s = 0.f;
#pragma unroll
            for (int wq = 0; wq < 8; wq++) s += sred[threadIdx.x][wq];
            colsum[(long long)(threadIdx.x * 4 + b) * 512 + d] = s;
        }
    }
}

// rank-1 bias correction: gcDE[z][d,e] += colsum[z][d] * bv[z>>2][e]; 8 elems/thread
__global__ void gc_rank1(hlf* __restrict__ gc, const float* __restrict__ colsum,
                         const float* __restrict__ bv)
{
    long long idx = (long long)blockIdx.x * 256 + threadIdx.x;
    long long base = idx * 8;
    int z = (int)(base / DD);
    int rem = (int)(base % DD);
    int d = rem >> 9;
    int e0 = rem & 511;
    float cs = colsum[(long long)z * 512 + d];
    const float* bvh = bv + (long long)(z >> 2) * 512;
    uint4 raw = *(const uint4*)(gc + base);
    hlf* hp = (hlf*)&raw;
    float v[8];
#pragma unroll
    for (int j = 0; j < 8; j++) v[j] = __half2float(hp[j]) + cs * bvh[e0 + j];
    uint4 o;
    o.x = packf2(v[0], v[1]); o.y = packf2(v[2], v[3]);
    o.z = packf2(v[4], v[5]); o.w = packf2(v[6], v[7]);
    *(uint4*)(gc + base) = o;
}

// LN1 fused with FFT quadrant reconstruction; fp16 out only.
__global__ void ln1_fft(const float* __restrict__ x_dec, const float* __restrict__ cps,
                        const float* __restrict__ g, const float* __restrict__ be,
                        hlf* __restrict__ oh)
{
    __shared__ float red[4];
    const long long row = blockIdx.x;        // b*2048 + s
    const int b = (int)(row >> 11);
    const int s = (int)(row & 2047);
    const int t = threadIdx.x;               // 128

    const int ip = (s <= 1024) ? s : (Sm - s);
    const bool fi = (s > 1024);
    const float* cpr = cps + (long long)b * FR * FC + (long long)ip * FC;
    const float* spr = cpr + 4LL * FR * FC;

    float4 vx = ((const float4*)(x_dec + row * Dm))[t];
    float v4[4];
#pragma unroll
    for (int j = 0; j < 4; j++) {
        int d = t * 4 + j;
        int dp = (d <= 256) ? d : (Dm - d);
        bool fd = (d > 256);
        float c = cpr[dp], sv = spr[dp];
        float xfv = c + ((fi != fd) ? sv : -sv);
        v4[j] = ((const float*)&vx)[j] + xfv;
    }

    float ssum = v4[0] + v4[1] + v4[2] + v4[3];
#pragma unroll
    for (int o = 16; o > 0; o >>= 1) ssum += __shfl_xor_sync(0xffffffffu, ssum, o);
    if ((t & 31) == 0) red[t >> 5] = ssum;
    __syncthreads();
    float mu = (red[0] + red[1] + red[2] + red[3]) * (1.f / (float)Dm);
    __syncthreads();
    float d0 = v4[0] - mu, d1 = v4[1] - mu, d2 = v4[2] - mu, d3 = v4[3] - mu;
    float q = d0 * d0 + d1 * d1 + d2 * d2 + d3 * d3;
#pragma unroll
    for (int o = 16; o > 0; o >>= 1) q += __shfl_xor_sync(0xffffffffu, q, o);
    if ((t & 31) == 0) red[t >> 5] = q;
    __syncthreads();
    float var = (red[0] + red[1] + red[2] + red[3]) * (1.f / (float)Dm);
    float rstd = rsqrtf(var + 1e-5f);
    float4 vg = ((const float4*)g)[t];
    float4 vbe = ((const float4*)be)[t];
    float o0 = fmaf(vg.x, d0 * rstd, vbe.x);
    float o1 = fmaf(vg.y, d1 * rstd, vbe.y);
    float o2 = fmaf(vg.z, d2 * rstd, vbe.z);
    float o3 = fmaf(vg.w, d3 * rstd, vbe.w);
    long long o = row * Dm + t * 4;
    *(uint2*)(oh + o) = make_uint2(packf2(o0, o1), packf2(o2, o3));
}

// LN of (a fp16 + b fp16); fp32 out (optional) + fp16 out (optional).
__global__ void ln_hh(const hlf* __restrict__ a, const hlf* __restrict__ bres,
                      const float* __restrict__ g, const float* __restrict__ be,
                      float* __restrict__ out, hlf* __restrict__ oh)
{
    __shared__ float red[4];
    long long row = blockIdx.x;
    int t = threadIdx.x;  // 128
    uint2 var_ = ((const uint2*)(a + row * Dm))[t];
    uint2 vbr = ((const uint2*)(bres + row * Dm))[t];
    hlf* ap = (hlf*)&var_;
    hlf* bp = (hlf*)&vbr;
    float4 v = make_float4(__half2float(ap[0]) + __half2float(bp[0]),
                           __half2float(ap[1]) + __half2float(bp[1]),
                           __half2float(ap[2]) + __half2float(bp[2]),
                           __half2float(ap[3]) + __half2float(bp[3]));
    float s = v.x + v.y + v.z + v.w;
#pragma unroll
    for (int o = 16; o > 0; o >>= 1) s += __shfl_xor_sync(0xffffffffu, s, o);
    if ((t & 31) == 0) red[t >> 5] = s;
    __syncthreads();
    float mu = (red[0] + red[1] + red[2] + red[3]) * (1.f / (float)Dm);
    __syncthreads();
    float d0 = v.x - mu, d1 = v.y - mu, d2 = v.z - mu, d3 = v.w - mu;
    float q = d0 * d0 + d1 * d1 + d2 * d2 + d3 * d3;
#pragma unroll
    for (int o = 16; o > 0; o >>= 1) q += __shfl_xor_sync(0xffffffffu, q, o);
    if ((t & 31) == 0) red[t >> 5] = q;
    __syncthreads();
    float var = (red[0] + red[1] + red[2] + red[3]) * (1.f / (float)Dm);
    float rstd = rsqrtf(var + 1e-5f);
    float4 vg = ((const float4*)g)[t];
    float4 vbe = ((const float4*)be)[t];
    float4 o4;
    o4.x = fmaf(vg.x, d0 * rstd, vbe.x);
    o4.y = fmaf(vg.y, d1 * rstd, vbe.y);
    o4.z = fmaf(vg.z, d2 * rstd, vbe.z);
    o4.w = fmaf(vg.w, d3 * rstd, vbe.w);
    if (out) ((float4*)(out + row * Dm))[t] = o4;
    if (oh) {
        long long o = row * Dm + t * 4;
        *(uint2*)(oh + o) = make_uint2(packf2(o4.x, o4.y), packf2(o4.z, o4.w));
    }
}

// ---------------------------------------------------------------------------
// Host
// ---------------------------------------------------------------------------
static TcPasses mk1(const hlf* Ah, const hlf* Bh) {
    TcPasses P{};
    P.A[0] = Ah; P.B[0] = Bh;
    return P;
}

static void tcg(const TcPasses& P, int np, float* C, hlf* Ch,
                int M, int N, int K, int lda, int ldb, int ldc,
                long long sA, long long sB, long long sC, int batch,
                const float* bias, long long sBias, int act, int split, int bmode,
                int shA = 0, int mskA = 0x7FFFFFFF, int shB = 0, int mskB = 0x7FFFFFFF)
{
    dim3 grid(N / 128, M / 128, batch), block(256);
    if (act == 1)
        mma_gemm<1, 2, 1><<<grid, block, SMEM_G>>>(P, np, C, Ch, K, lda, ldb, ldc, sA, sB, sC, bias, sBias, shA, mskA, shB, mskB);
    else if (split == 2 && bmode == 2)
        mma_gemm<0, 2, 2><<<grid, block, SMEM_G>>>(P, np, C, Ch, K, lda, ldb, ldc, sA, sB, sC, bias, sBias, shA, mskA, shB, mskB);
    else if (split == 2 && bmode == 1)
        mma_gemm<0, 2, 1><<<grid, block, SMEM_G>>>(P, np, C, Ch, K, lda, ldb, ldc, sA, sB, sC, bias, sBias, shA, mskA, shB, mskB);
    else if (split == 2)
        mma_gemm<0, 2, 0><<<grid, block, SMEM_G>>>(P, np, C, Ch, K, lda, ldb, ldc, sA, sB, sC, bias, sBias, shA, mskA, shB, mskB);
    else if (bmode == 1)
        mma_gemm<0, 0, 1><<<grid, block, SMEM_G>>>(P, np, C, Ch, K, lda, ldb, ldc, sA, sB, sC, bias, sBias, shA, mskA, shB, mskB);
    else
        mma_gemm<0, 0, 0><<<grid, block, SMEM_G>>>(P, np, C, Ch, K, lda, ldb, ldc, sA, sB, sC, bias, sBias, shA, mskA, shB, mskB);
}

#define GETSYM(var, sym) do { void* _p; cudaGetSymbolAddress(&_p, sym); var = (decltype(var))_p; } while (0)

extern "C" void kernel_launch(void* const* d_in, const int* in_sizes, int n_in,
                              void* d_out, int out_size)
{
    const float* x_enc = (const float*)d_in[0];
    const float* x_dec = (const float*)d_in[1];
    const float* Wq = (const float*)d_in[2];
    const float* bq = (const float*)d_in[3];
    const float* Wk = (const float*)d_in[4];
    const float* bk = (const float*)d_in[5];
    const float* Wv = (const float*)d_in[6];
    const float* bv = (const float*)d_in[7];
    const float* Wo = (const float*)d_in[8];
    const float* bo = (const float*)d_in[9];
    const float* ln1g = (const float*)d_in[10];
    const float* ln1b = (const float*)d_in[11];
    const float* ln2g = (const float*)d_in[12];
    const float* ln2b = (const float*)d_in[13];
    const float* W1 = (const float*)d_in[14];
    const float* b1 = (const float*)d_in[15];
    const float* W2 = (const float*)d_in[16];
    const float* b2 = (const float*)d_in[17];
    const float* ln3g = (const float*)d_in[18];
    const float* ln3b = (const float*)d_in[19];
    float* outp = (float*)d_out;

    hlf *CSf, *BDf, *xdff, *t12Tf, *xqkh, *xeT, *qkh;
    hlf *qsh, *kTh, *kgh, *gcDE, *Mth;
    hlf *WqTh, *WkvTh, *WoTh, *W1Th, *W2Th, *x2h, *midh, *attnh, *ffh;
    float *cps, *colsum;
    GETSYM(CSf, g_CSf); GETSYM(BDf, g_BDf); GETSYM(xdff, g_xdff);
    GETSYM(t12Tf, g_t12Tf);
    GETSYM(cps, g_cps);
    GETSYM(xqkh, g_xqkh); GETSYM(xeT, g_xeT); GETSYM(qkh, g_qkh);
    GETSYM(qsh, g_qsh); GETSYM(kTh, g_kTh); GETSYM(colsum, g_colsum);
    GETSYM(kgh, g_kgh); GETSYM(gcDE, g_gcDE); GETSYM(Mth, g_Mth);
    GETSYM(WqTh, g_WqTh); GETSYM(WkvTh, g_WkvTh); GETSYM(WoTh, g_WoTh);
    GETSYM(W1Th, g_W1Th); GETSYM(W2Th, g_W2Th);
    GETSYM(attnh, g_attnh); GETSYM(x2h, g_x2h);
    GETSYM(midh, g_midh); GETSYM(ffh, g_ffh);

    cudaFuncSetAttribute(mma_gemm<0, 0, 0>, cudaFuncAttributeMaxDynamicSharedMemorySize, SMEM_G);
    cudaFuncSetAttribute(mma_gemm<0, 0, 1>, cudaFuncAttributeMaxDynamicSharedMemorySize, SMEM_G);
    cudaFuncSetAttribute(mma_gemm<0, 2, 0>, cudaFuncAttributeMaxDynamicSharedMemorySize, SMEM_G);
    cudaFuncSetAttribute(mma_gemm<0, 2, 1>, cudaFuncAttributeMaxDynamicSharedMemorySize, SMEM_G);
    cudaFuncSetAttribute(mma_gemm<0, 2, 2>, cudaFuncAttributeMaxDynamicSharedMemorySize, SMEM_G);
    cudaFuncSetAttribute(mma_gemm<1, 2, 1>, cudaFuncAttributeMaxDynamicSharedMemorySize, SMEM_G);

    dim3 tb(32, 8);

    // 0) folded DFT matrices
    init_all<<<NB_CS + NB_BD, 256>>>(CSf, BDf);

    // inputs: x_enc fp16 straight + transposed; x_dec double-folded
    xenc_prep<<<4096, tb>>>(x_enc, xqkh + BSD, xeT);
    xdec_fold2<<<Bm * KF, 128>>>(x_dec, xdff);

    // weight prep: one launch, 6 segments x 1024 tiles
    {
        WPrep P{};
        P.s[0] = {Wq, WqTh, 16, 16, 0, DD, DD, Dm, Dm};
        P.s[1] = {Wk, WkvTh, 16, 16, 0, DD, DD, Dm, Dm};
        P.s[2] = {Wv, WkvTh + 4 * DD, 16, 16, 0, DD, DD, Dm, Dm};
        P.s[3] = {Wo, WoTh, 16, 16, 1, 0, 0, Dm, Dm};
        P.s[4] = {W1, W1Th, 64, 16, 0, 0, 0, Dm, MIDm};
        P.s[5] = {W2, W2Th, 16, 64, 0, 0, 0, MIDm, Dm};
        weights_prep<<<6144, tb>>>(P);
    }

    // 1) t12Tf[z=half*4+b] = BDf[half] @ xdff[z]^T  (M=384, N=1152, K=320, z=8)
    tcg(mk1(BDf, xdff), 1, nullptr, t12Tf,
        384, KF, KD, KD, KD, KF, 384LL * KD, (long long)KF * KD, 384LL * KF, 8,
        nullptr, 0, 0, 2, 0, /*shA=*/2, 0x7FFFFFFF, /*shB=*/0, /*mskB=*/7);

    // 2) merged cp/sp: cps[z] = CSf[z>>2] @ t12Tf[z]^T  (M=1152,N=384,K=1088,z=8)
    tcg(mk1(CSf, t12Tf), 1, cps, nullptr,
        FR, FC, KFK, KF, KF, FC, (long long)FR * KF, 384LL * KF, (long long)FR * FC, 8,
        nullptr, 0, 0, 0, 0, /*shA=*/2, 0x7FFFFFFF, /*shB=*/0, /*mskB=*/7);

    // 3) xd = LN1(x_dec + fftmerge(cps)); fp16 only into stacked buffer
    ln1_fft<<<BSm, 128>>>(x_dec, cps, ln1g, ln1b, xqkh);

    // 4) kT[z=h*4+b] = WkT_h @ x_enc[b]^T + bk_h (row), fp16; z=16
    tcg(mk1(WkvTh, xqkh + BSD), 1, nullptr, kTh,
        Dm, Sm, Dm, Dm, Dm, Sm, DD, SD, SD, 16, bk, Dm, 0, 2, 2,
        /*shA=*/2, 0x7FFFFFFF, /*shB=*/0, /*mskB=*/3);

    // 5) q projections: z=4 (h), 1-pass, fp16 logits
    tcg(mk1(xqkh, WqTh), 1, nullptr, qkh,
        BSm, Dm, Dm, Dm, Dm, Dm, 0, DD, BSD, 4, bq, Dm, 0, 2, 1,
        /*shA=*/0, /*mskA=*/0, /*shB=*/0, /*mskB=*/3);

    // 6) merged softmax over heads: q (->qsh) and kT (in-place + colsum)
    softmax_all<<<6144, 256>>>(qkh, qsh, kTh, colsum);

    // 7) kg[z][d,m] = ksT[z] @ xeT[b]^T  (M=512, N=512, K=2048, z=16), fp16 out
    tcg(mk1(kTh, xeT), 1, nullptr, kgh,
        Dm, Dm, Sm, Sm, Sm, Dm, SD, SD, DD, 16, nullptr, 0, 0, 2, 0,
        /*shA=*/0, 0x7FFFFFFF, /*shB=*/0, /*mskB=*/3);

    // 8) gcDE[z][d,e] = kg[z] @ WvT_{z>>2}^T  (M=N=K=512, z=16), fp16 out
    tcg(mk1(kgh, WkvTh + 4 * DD), 1, nullptr, gcDE,
        Dm, Dm, Dm, Dm, Dm, Dm, DD, DD, DD, 16, nullptr, 0, 0, 2, 0,
        /*shA=*/0, 0x7FFFFFFF, /*shB=*/2, /*mskB=*/3);

    // 8b) rank-1 bias: gcDE += colsum (x) bv
    gc_rank1<<<2048, 256>>>(gcDE, colsum, bv);

    // 9) Mt[z][n,d] = WoT_{z>>2} @ gcDE[z]^T  (M=N=K=512, z=16)
    tcg(mk1(WoTh, gcDE), 1, nullptr, Mth,
        Dm, Dm, Dm, Dm, Dm, Dm, DD, DD, DD, 16, nullptr, 0, 0, 2, 0,
        /*shA=*/2, 0x7FFFFFFF, /*shB=*/0, /*mskB=*/15);

    // 10) attn[b][s,n] = sum_h qs_h[b] @ Mt[h*4+b]^T + bo  (4 passes; z=4), fp16 out
    {
        TcPasses P{};
        for (int h = 0; h < Hn; h++) {
            P.A[h] = qsh + (long long)h * Bm * SD;
            P.B[h] = Mth + (long long)h * Bm * DD;
        }
        tcg(P, 4, nullptr, attnh,
            Sm, Dm, Dm, Dm, Dm, Dm, SD, DD, SD, Bm, bo, 0, 0, 2, 1,
            /*shA=*/0, 0x7FFFFFFF, /*shB=*/0, /*mskB=*/3);
    }

    // 11) x2 = LN2(xd fp16 + attn fp16); fp16 out
    ln_hh<<<BSm, 128>>>(xqkh, attnh, ln2g, ln2b, nullptr, x2h);

    // 12) mid = selu(x2 @ W1 + b1), fp16 out, 1-pass
    tcg(mk1(x2h, W1Th), 1, nullptr, midh,
        BSm, MIDm, Dm, Dm, Dm, MIDm, 0, 0, 0, 1, b1, 0, 1, 2, 1);

    // 13) ff = mid @ W2 + b2, fp16 out, 1-pass
    tcg(mk1(midh, W2Th), 1, nullptr, ffh,
        BSm, Dm, MIDm, MIDm, MIDm, Dm, 0, 0, 0, 1, b2, 0, 0, 2, 1);

    // 14) out = LN3(x2 fp16 + ff fp16), fp32 out
    ln_hh<<<BSm, 128>>>(x2h, ffh, ln3g, ln3b, outp, nullptr);
}